// round 1
// baseline (speedup 1.0000x reference)
#include <cuda_runtime.h>

// Problem constants
#define Lq     512
#define BATCH  4
#define DMOD   512
#define NH     8
#define DHEAD  64
#define MEMN   3
#define TOTALK 2048
#define SCALEF 0.125f
#define ROWS_X (Lq * BATCH)          // 2048 rows of x / q / vec / y
#define ROWS_C (TOTALK * BATCH)      // 8192 rows of c / kv / rel

// ---------------- scratch (device globals; no cudaMalloc allowed) ----------
__device__ float g_kv [(size_t)ROWS_C * 1024];          // 32 MB  k | v
__device__ float g_rel[(size_t)ROWS_C * 512];           // 16 MB
__device__ float g_q  [(size_t)ROWS_X * 512];           //  4 MB
__device__ float g_ac [(size_t)32 * 512 * 2048];        // 128 MB (later holds prob)
__device__ float g_bd [(size_t)32 * 512 * 2048];        // 128 MB
__device__ float g_vec[(size_t)ROWS_X * 512];           //  4 MB
__device__ float g_y  [(size_t)ROWS_X * 512];           //  4 MB

// ---------------- reductions ----------------
__device__ __forceinline__ float warpRedMax(float v) {
#pragma unroll
    for (int o = 16; o > 0; o >>= 1) v = fmaxf(v, __shfl_xor_sync(0xffffffffu, v, o));
    return v;
}
__device__ __forceinline__ float warpRedSum(float v) {
#pragma unroll
    for (int o = 16; o > 0; o >>= 1) v += __shfl_xor_sync(0xffffffffu, v, o);
    return v;
}
__device__ __forceinline__ float blockRedMax(float v, float* red) {
    v = warpRedMax(v);
    int w = threadIdx.x >> 5, l = threadIdx.x & 31;
    if (!l) red[w] = v;
    __syncthreads();
    if (threadIdx.x < 32) {
        float x = (l < 8) ? red[l] : -1e30f;
        x = warpRedMax(x);
        if (!l) red[0] = x;
    }
    __syncthreads();
    float r = red[0];
    __syncthreads();
    return r;
}
__device__ __forceinline__ float blockRedSum(float v, float* red) {
    v = warpRedSum(v);
    int w = threadIdx.x >> 5, l = threadIdx.x & 31;
    if (!l) red[w] = v;
    __syncthreads();
    if (threadIdx.x < 32) {
        float x = (l < 8) ? red[l] : 0.f;
        x = warpRedSum(x);
        if (!l) red[0] = x;
    }
    __syncthreads();
    float r = red[0];
    __syncthreads();
    return r;
}

// ---------------- generic row-major SGEMM: C = A[MxK] @ B[KxN] (+ Cadd) ----
// 128x128 block tile, BK=8, 256 threads, 8x8 per thread.
__global__ void sgemm128(const float* __restrict__ A, const float* __restrict__ B,
                         const float* __restrict__ Cadd, float* __restrict__ C,
                         int M, int N, int K) {
    __shared__ float As[8][128];
    __shared__ float Bs[8][128];
    int tid = threadIdx.x;
    int m0 = blockIdx.y * 128, n0 = blockIdx.x * 128;

    const float* Ab = A + (size_t)m0 * K;
    const float* Bb = B + n0;

    float acc[8][8];
#pragma unroll
    for (int i = 0; i < 8; i++)
#pragma unroll
        for (int j = 0; j < 8; j++) acc[i][j] = 0.f;

    int ar = tid >> 1, ac = (tid & 1) * 4;     // A tile: 128 rows x 8 k
    int br = tid >> 5, bc = (tid & 31) * 4;    // B tile: 8 k x 128 cols
    int ty = tid >> 4, tx = tid & 15;

    for (int k0 = 0; k0 < K; k0 += 8) {
        float4 av = *(const float4*)(Ab + (size_t)ar * K + k0 + ac);
        As[ac + 0][ar] = av.x; As[ac + 1][ar] = av.y;
        As[ac + 2][ar] = av.z; As[ac + 3][ar] = av.w;
        float4 bv = *(const float4*)(Bb + (size_t)(k0 + br) * N + bc);
        *(float4*)&Bs[br][bc] = bv;
        __syncthreads();
#pragma unroll
        for (int kk = 0; kk < 8; kk++) {
            float a[8], b[8];
            *(float4*)(a)     = *(const float4*)&As[kk][ty * 8];
            *(float4*)(a + 4) = *(const float4*)&As[kk][ty * 8 + 4];
            *(float4*)(b)     = *(const float4*)&Bs[kk][tx * 8];
            *(float4*)(b + 4) = *(const float4*)&Bs[kk][tx * 8 + 4];
#pragma unroll
            for (int i = 0; i < 8; i++)
#pragma unroll
                for (int j = 0; j < 8; j++) acc[i][j] = fmaf(a[i], b[j], acc[i][j]);
        }
        __syncthreads();
    }

#pragma unroll
    for (int i = 0; i < 8; i++) {
        int row = m0 + ty * 8 + i;
        float* crow = C + (size_t)row * N + n0 + tx * 8;
        if (Cadd) {
            const float* arow = Cadd + (size_t)row * N + n0 + tx * 8;
#pragma unroll
            for (int j = 0; j < 8; j++) crow[j] = acc[i][j] + arow[j];
        } else {
            float4 v0 = make_float4(acc[i][0], acc[i][1], acc[i][2], acc[i][3]);
            float4 v1 = make_float4(acc[i][4], acc[i][5], acc[i][6], acc[i][7]);
            *(float4*)(crow)     = v0;
            *(float4*)(crow + 4) = v1;
        }
    }
}

// ---------------- batched attention score GEMM ------------------------------
// For batch bn (b = bn>>3, n = bn&7):
//   C[bn][i][j] = sum_d (Q[i*2048 + b*512 + n*64 + d] + bias[n*64+d]) *
//                 Bm[j*ldb + b*bstride + n*64 + d]
// M = 512 (i), N = 2048 (j or m), K = 64.  Tile 64(i) x 128(j), 256 threads.
__global__ void attn_gemm(const float* __restrict__ Q, const float* __restrict__ bias,
                          const float* __restrict__ Bm, int ldb, int bstride,
                          float* __restrict__ C) {
    __shared__ float As[64][64];    // [d][i]
    __shared__ float Bs[64][128];   // [d][j]
    int bn = blockIdx.z;
    int b = bn >> 3, n = bn & 7;
    int i0 = blockIdx.y * 64;
    int j0 = blockIdx.x * 128;
    int tid = threadIdx.x;

    // Load A (64 i-rows x 64 d) with bias add, transposed into As[d][i]
    {
        int r = tid >> 2;
        int c0 = (tid & 3) * 4;
        const float* qrow = Q + (size_t)(i0 + r) * 2048 + b * 512 + n * 64;
        const float* brow = bias + n * 64;
#pragma unroll
        for (int w = 0; w < 4; w++) {
            int c = c0 + w * 16;
            float4 v = *(const float4*)(qrow + c);
            As[c + 0][r] = v.x + brow[c + 0];
            As[c + 1][r] = v.y + brow[c + 1];
            As[c + 2][r] = v.z + brow[c + 2];
            As[c + 3][r] = v.w + brow[c + 3];
        }
    }
    // Load B (128 j-rows x 64 d) transposed into Bs[d][j]
    {
        int r = tid >> 1;
        int c0 = (tid & 1) * 4;
        const float* brow = Bm + (size_t)(j0 + r) * ldb + b * bstride + n * 64;
#pragma unroll
        for (int w = 0; w < 8; w++) {
            int c = c0 + w * 8;
            float4 v = *(const float4*)(brow + c);
            Bs[c + 0][r] = v.x; Bs[c + 1][r] = v.y;
            Bs[c + 2][r] = v.z; Bs[c + 3][r] = v.w;
        }
    }
    __syncthreads();

    int tx = tid & 15, ty = tid >> 4;
    float acc[4][8];
#pragma unroll
    for (int m = 0; m < 4; m++)
#pragma unroll
        for (int c = 0; c < 8; c++) acc[m][c] = 0.f;

#pragma unroll 16
    for (int d = 0; d < 64; d++) {
        float a[4], bv[8];
        *(float4*)a        = *(const float4*)&As[d][ty * 4];
        *(float4*)(bv)     = *(const float4*)&Bs[d][tx * 8];
        *(float4*)(bv + 4) = *(const float4*)&Bs[d][tx * 8 + 4];
#pragma unroll
        for (int m = 0; m < 4; m++)
#pragma unroll
            for (int c = 0; c < 8; c++) acc[m][c] = fmaf(a[m], bv[c], acc[m][c]);
    }

    float* Cb = C + ((size_t)bn * 512 + i0) * 2048 + j0;
#pragma unroll
    for (int m = 0; m < 4; m++) {
        float* dst = Cb + (size_t)(ty * 4 + m) * 2048 + tx * 8;
        *(float4*)(dst)     = make_float4(acc[m][0], acc[m][1], acc[m][2], acc[m][3]);
        *(float4*)(dst + 4) = make_float4(acc[m][4], acc[m][5], acc[m][6], acc[m][7]);
    }
}

// ---------------- softmax + rel-shift + gates + mask + attn_matrix ----------
// One block per query i. Loops the 32 (b,n) rows; overwrites AC with prob.
__global__ void softmax_kernel(float* __restrict__ AC, const float* __restrict__ BD,
                               const float* __restrict__ ib, float* __restrict__ attn) {
    __shared__ float accv[2048];
    __shared__ float red[32];
    int i = blockIdx.x;
    int tid = threadIdx.x;
    for (int j = tid; j < 2048; j += 256) accv[j] = 0.f;
    __syncthreads();

    int jmax = 3 * Lq + i;   // valid keys: j <= jmax

    for (int bn = 0; bn < 32; bn++) {
        int b = bn >> 3;
        float* acrow = AC + ((size_t)bn * 512 + i) * 2048;
        const float* bdrow = BD + ((size_t)bn * 512 + i) * 2048;
        const float* g = ib + ((size_t)i * BATCH + b) * 4;

        float s[8];
        float mx = -1e30f;
#pragma unroll
        for (int t = 0; t < 8; t++) {
            int j = tid + t * 256;
            if (j <= jmax) {
                int m = j + (Lq - 1) - i;          // rel-shift closed form
                float v = SCALEF * (g[j >> 9] * acrow[j] + g[m >> 9] * bdrow[m]);
                s[t] = v;
                mx = fmaxf(mx, v);
            } else {
                s[t] = -1e30f;
            }
        }
        mx = blockRedMax(mx, red);

        float p[8];
        float sum = 0.f;
#pragma unroll
        for (int t = 0; t < 8; t++) {
            p[t] = (s[t] > -1e29f) ? __expf(s[t] - mx) : 0.f;
            sum += p[t];
        }
        sum = blockRedSum(sum, red);
        float inv = 1.f / sum;
#pragma unroll
        for (int t = 0; t < 8; t++) {
            int j = tid + t * 256;
            float pp = p[t] * inv;
            acrow[j] = pp;          // prob, in place
            accv[j] += pp;          // each thread owns distinct j
        }
        __syncthreads();
    }

    const float invBN = 1.f / 32.f;
    for (int j = tid; j < 2048; j += 256)
        attn[(size_t)i * 2048 + j] = accv[j] * invBN;
}

// ---------------- batched prob @ V ------------------------------------------
// vec[((i)*4+b)*512 + n*64 + d] = sum_j P[bn][i][j] * V[j*4096 + b*1024 + 512 + n*64 + d]
__global__ void pv_gemm(const float* __restrict__ P, const float* __restrict__ KV,
                        float* __restrict__ vec) {
    __shared__ float As[16][64];   // [k][i]
    __shared__ float Bs[16][64];   // [k][d]
    int bn = blockIdx.z;
    int b = bn >> 3, n = bn & 7;
    int i0 = blockIdx.y * 64;
    int tid = threadIdx.x;

    const float* Pb = P + ((size_t)bn * 512 + i0) * 2048;
    const float* Vb = KV + b * 1024 + 512 + n * 64;

    float acc[4][4];
#pragma unroll
    for (int m = 0; m < 4; m++)
#pragma unroll
        for (int c = 0; c < 4; c++) acc[m][c] = 0.f;

    int pr = tid >> 2, pc = (tid & 3) * 4;
    int vr = tid >> 4, vc = (tid & 15) * 4;
    int tx = tid & 15, ty = tid >> 4;

    for (int k0 = 0; k0 < 2048; k0 += 16) {
        float4 pv = *(const float4*)(Pb + (size_t)pr * 2048 + k0 + pc);
        As[pc + 0][pr] = pv.x; As[pc + 1][pr] = pv.y;
        As[pc + 2][pr] = pv.z; As[pc + 3][pr] = pv.w;
        float4 vv = *(const float4*)(Vb + (size_t)(k0 + vr) * 4096 + vc);
        *(float4*)&Bs[vr][vc] = vv;
        __syncthreads();
#pragma unroll
        for (int k = 0; k < 16; k++) {
            float a[4], bv[4];
            *(float4*)a  = *(const float4*)&As[k][ty * 4];
            *(float4*)bv = *(const float4*)&Bs[k][tx * 4];
#pragma unroll
            for (int m = 0; m < 4; m++)
#pragma unroll
                for (int c = 0; c < 4; c++) acc[m][c] = fmaf(a[m], bv[c], acc[m][c]);
        }
        __syncthreads();
    }

#pragma unroll
    for (int m = 0; m < 4; m++) {
        int i = i0 + ty * 4 + m;
        float* dst = vec + ((size_t)i * 4 + b) * 512 + n * 64 + tx * 4;
        *(float4*)dst = make_float4(acc[m][0], acc[m][1], acc[m][2], acc[m][3]);
    }
}

// ---------------- layernorm --------------------------------------------------
__global__ void ln_kernel(const float* __restrict__ y, const float* __restrict__ g,
                          const float* __restrict__ be, float* __restrict__ out) {
    __shared__ float red[32];
    int r = blockIdx.x;
    int tid = threadIdx.x;
    float v0 = y[(size_t)r * 512 + tid];
    float v1 = y[(size_t)r * 512 + tid + 256];
    float mean = blockRedSum(v0 + v1, red) * (1.f / 512.f);
    float d0 = v0 - mean, d1 = v1 - mean;
    float var = blockRedSum(d0 * d0 + d1 * d1, red) * (1.f / 512.f);
    float rstd = rsqrtf(var + 1e-5f);
    out[(size_t)r * 512 + tid]       = d0 * rstd * g[tid] + be[tid];
    out[(size_t)r * 512 + tid + 256] = d1 * rstd * g[tid + 256] + be[tid + 256];
}

// ---------------- launch ------------------------------------------------------
extern "C" void kernel_launch(void* const* d_in, const int* in_sizes, int n_in,
                              void* d_out, int out_size) {
    (void)in_sizes; (void)n_in; (void)out_size;
    const float* x       = (const float*)d_in[0];
    const float* memory  = (const float*)d_in[1];
    const float* pos_emb = (const float*)d_in[2];
    const float* pbu     = (const float*)d_in[3];
    const float* pbv     = (const float*)d_in[4];
    // d_in[5] = mask (recomputed analytically; unused)
    const float* ib      = (const float*)d_in[6];
    const float* W_q     = (const float*)d_in[7];
    const float* W_kv    = (const float*)d_in[8];
    const float* W_rel   = (const float*)d_in[9];
    const float* W_o     = (const float*)d_in[10];
    const float* ln_g    = (const float*)d_in[11];
    const float* ln_b    = (const float*)d_in[12];

    float* out  = (float*)d_out;                       // [L,B,D] = 1048576 floats
    float* attn = out + (size_t)Lq * BATCH * DMOD;     // [L,TOTAL] = 1048576 floats

    float *kv, *rel, *q, *acb, *bdb, *vec, *y;
    cudaGetSymbolAddress((void**)&kv,  g_kv);
    cudaGetSymbolAddress((void**)&rel, g_rel);
    cudaGetSymbolAddress((void**)&q,   g_q);
    cudaGetSymbolAddress((void**)&acb, g_ac);
    cudaGetSymbolAddress((void**)&bdb, g_bd);
    cudaGetSymbolAddress((void**)&vec, g_vec);
    cudaGetSymbolAddress((void**)&y,   g_y);

    // 1) projections
    sgemm128<<<dim3(1024 / 128, 6144 / 128), 256>>>(memory, W_kv, nullptr, kv, 6144, 1024, 512);
    sgemm128<<<dim3(1024 / 128, 2048 / 128), 256>>>(x, W_kv, nullptr, kv + (size_t)6144 * 1024, 2048, 1024, 512);
    sgemm128<<<dim3(512 / 128, 8192 / 128), 256>>>(pos_emb, W_rel, nullptr, rel, 8192, 512, 512);
    sgemm128<<<dim3(512 / 128, 2048 / 128), 256>>>(x, W_q, nullptr, q, 2048, 512, 512);

    // 2) AC = (q+u)·k  and  BDpre = (q+v)·rel   (32 batches)
    attn_gemm<<<dim3(16, 8, 32), 256>>>(q, pbu, kv, 4096, 1024, acb);
    attn_gemm<<<dim3(16, 8, 32), 256>>>(q, pbv, rel, 2048, 512, bdb);

    // 3) gates + rel-shift + mask + softmax; prob overwrites AC; attn_matrix out
    softmax_kernel<<<512, 256>>>(acb, bdb, ib, attn);

    // 4) vec = prob @ v
    pv_gemm<<<dim3(1, 8, 32), 256>>>(acb, kv, vec);

    // 5) y = x + vec @ W_o ; then layernorm -> out
    sgemm128<<<dim3(512 / 128, 2048 / 128), 256>>>(vec, W_o, x, y, 2048, 512, 512);
    ln_kernel<<<2048, 256>>>(y, ln_g, ln_b, out);
}

// round 2
// speedup vs baseline: 2.2563x; 2.2563x over previous
#include <cuda_runtime.h>
#include <stdint.h>

// Problem constants
#define Lq     512
#define BATCH  4
#define DMOD   512
#define NH     8
#define DHEAD  64
#define MEMN   3
#define TOTALK 2048
#define SCALEF 0.125f
#define ROWS_X (Lq * BATCH)          // 2048 rows of x / q / vec / y
#define ROWS_C (TOTALK * BATCH)      // 8192 rows of c / kv / rel

// ---------------- scratch (device globals; no cudaMalloc allowed) ----------
__device__ float g_kv [(size_t)ROWS_C * 1024];          // 32 MB  k | v
__device__ float g_rel[(size_t)ROWS_C * 512];           // 16 MB
__device__ float g_q  [(size_t)ROWS_X * 512];           //  4 MB
__device__ float g_ac [(size_t)32 * 512 * 2048];        // 128 MB (later holds prob)
__device__ float g_bd [(size_t)32 * 512 * 2048];        // 128 MB
__device__ float g_vec[(size_t)ROWS_X * 512];           //  4 MB
__device__ float g_y  [(size_t)ROWS_X * 512];           //  4 MB

// ---------------- tf32 helpers ----------------
__device__ __forceinline__ float tf32f(float x) {
    uint32_t u;
    asm("cvt.rna.tf32.f32 %0, %1;" : "=r"(u) : "f"(x));
    return __uint_as_float(u);
}

__device__ __forceinline__ void mma_tf32(float* d, const uint32_t* a,
                                         const uint32_t* b, const float* c) {
    asm volatile(
        "mma.sync.aligned.m16n8k8.row.col.f32.tf32.tf32.f32 "
        "{%0,%1,%2,%3}, {%4,%5,%6,%7}, {%8,%9}, {%10,%11,%12,%13};"
        : "=f"(d[0]), "=f"(d[1]), "=f"(d[2]), "=f"(d[3])
        : "r"(a[0]), "r"(a[1]), "r"(a[2]), "r"(a[3]),
          "r"(b[0]), "r"(b[1]),
          "f"(c[0]), "f"(c[1]), "f"(c[2]), "f"(c[3]));
}

// ---------------- reductions ----------------
__device__ __forceinline__ float warpRedMax(float v) {
#pragma unroll
    for (int o = 16; o > 0; o >>= 1) v = fmaxf(v, __shfl_xor_sync(0xffffffffu, v, o));
    return v;
}
__device__ __forceinline__ float warpRedSum(float v) {
#pragma unroll
    for (int o = 16; o > 0; o >>= 1) v += __shfl_xor_sync(0xffffffffu, v, o);
    return v;
}
__device__ __forceinline__ float blockRedMax(float v, float* red) {
    v = warpRedMax(v);
    int w = threadIdx.x >> 5, l = threadIdx.x & 31;
    if (!l) red[w] = v;
    __syncthreads();
    if (threadIdx.x < 32) {
        float x = (l < 8) ? red[l] : -1e30f;
        x = warpRedMax(x);
        if (!l) red[0] = x;
    }
    __syncthreads();
    float r = red[0];
    __syncthreads();
    return r;
}
__device__ __forceinline__ float blockRedSum(float v, float* red) {
    v = warpRedSum(v);
    int w = threadIdx.x >> 5, l = threadIdx.x & 31;
    if (!l) red[w] = v;
    __syncthreads();
    if (threadIdx.x < 32) {
        float x = (l < 8) ? red[l] : 0.f;
        x = warpRedSum(x);
        if (!l) red[0] = x;
    }
    __syncthreads();
    float r = red[0];
    __syncthreads();
    return r;
}

// ============================================================================
// tf32 tensor-core GEMM: C[M,N] = A[M,K] @ B[K,N] (+ Cadd), row-major all.
// 128x128 block tile, BK=32, 256 threads (8 warps as 2x4).
// M%128==0, N%128==0, K%32==0.
// ============================================================================
__global__ void gemm_tf32(const float* __restrict__ A, const float* __restrict__ B,
                          const float* __restrict__ Cadd, float* __restrict__ C,
                          int M, int N, int K) {
    __shared__ float As[128 * 36];   // A[m][k], stride 36 -> conflict-free frag loads
    __shared__ float Bs[32 * 136];   // B[k][n], stride 136

    int m0 = blockIdx.y * 128, n0 = blockIdx.x * 128;
    int tid = threadIdx.x;
    int warp = tid >> 5, lane = tid & 31;
    int g = lane >> 2, c = lane & 3;
    int wm = (warp >> 2) * 64;       // warp m-offset (2 warps in m)
    int wn = (warp & 3) * 32;        // warp n-offset (4 warps in n)

    float acc[4][4][4];
#pragma unroll
    for (int mt = 0; mt < 4; mt++)
#pragma unroll
        for (int nt = 0; nt < 4; nt++)
#pragma unroll
            for (int e = 0; e < 4; e++) acc[mt][nt][e] = 0.f;

    for (int k0 = 0; k0 < K; k0 += 32) {
        // load A tile: 128 x 32
#pragma unroll
        for (int w = 0; w < 4; w++) {
            int idx = tid + w * 256;
            int r = idx >> 3, cc = (idx & 7) * 4;
            float4 v = *(const float4*)(A + (size_t)(m0 + r) * K + k0 + cc);
            float* dst = As + r * 36 + cc;
            dst[0] = tf32f(v.x); dst[1] = tf32f(v.y);
            dst[2] = tf32f(v.z); dst[3] = tf32f(v.w);
        }
        // load B tile: 32 x 128
#pragma unroll
        for (int w = 0; w < 4; w++) {
            int idx = tid + w * 256;
            int r = idx >> 5, cc = (idx & 31) * 4;
            float4 v = *(const float4*)(B + (size_t)(k0 + r) * N + n0 + cc);
            float* dst = Bs + r * 136 + cc;
            dst[0] = tf32f(v.x); dst[1] = tf32f(v.y);
            dst[2] = tf32f(v.z); dst[3] = tf32f(v.w);
        }
        __syncthreads();

#pragma unroll
        for (int kk = 0; kk < 4; kk++) {
            int k = kk * 8;
            uint32_t af[4][4], bf[4][2];
#pragma unroll
            for (int mt = 0; mt < 4; mt++) {
                const float* base = As + (wm + mt * 16 + g) * 36 + k + c;
                af[mt][0] = __float_as_uint(base[0]);
                af[mt][1] = __float_as_uint(base[8 * 36]);
                af[mt][2] = __float_as_uint(base[4]);
                af[mt][3] = __float_as_uint(base[8 * 36 + 4]);
            }
#pragma unroll
            for (int nt = 0; nt < 4; nt++) {
                const float* base = Bs + (k + c) * 136 + wn + nt * 8 + g;
                bf[nt][0] = __float_as_uint(base[0]);
                bf[nt][1] = __float_as_uint(base[4 * 136]);
            }
#pragma unroll
            for (int mt = 0; mt < 4; mt++)
#pragma unroll
                for (int nt = 0; nt < 4; nt++)
                    mma_tf32(acc[mt][nt], af[mt], bf[nt], acc[mt][nt]);
        }
        __syncthreads();
    }

    // epilogue
#pragma unroll
    for (int mt = 0; mt < 4; mt++) {
#pragma unroll
        for (int nt = 0; nt < 4; nt++) {
            int row = m0 + wm + mt * 16 + g;
            int col = n0 + wn + nt * 8 + c * 2;
            float* p0 = C + (size_t)row * N + col;
            float* p1 = C + (size_t)(row + 8) * N + col;
            float2 v0 = make_float2(acc[mt][nt][0], acc[mt][nt][1]);
            float2 v1 = make_float2(acc[mt][nt][2], acc[mt][nt][3]);
            if (Cadd) {
                const float* a0 = Cadd + (size_t)row * N + col;
                const float* a1 = Cadd + (size_t)(row + 8) * N + col;
                v0.x += a0[0]; v0.y += a0[1];
                v1.x += a1[0]; v1.y += a1[1];
            }
            *(float2*)p0 = v0;
            *(float2*)p1 = v1;
        }
    }
}

// ============================================================================
// Batched attention score GEMM (tf32). For batch bn (b=bn>>3, n=bn&7):
//   C[bn][i][j] = sum_d (Q[i*2048+b*512+n*64+d] + bias[n*64+d]) *
//                 Bm[j*ldb + b*bstride + n*64 + d]
// Tile 128(i) x 128(j), K=64 single shot. Dynamic smem 69632 B.
// ============================================================================
__global__ void attn_gemm_tf32(const float* __restrict__ Q, const float* __restrict__ bias,
                               const float* __restrict__ Bm, int ldb, int bstride,
                               float* __restrict__ C) {
    extern __shared__ float sm[];
    float* As = sm;                // [128][68]  (q+bias)[i][d]
    float* Bs = sm + 128 * 68;     // [128][68]  B[j][d]

    int bn = blockIdx.z;
    int b = bn >> 3, n = bn & 7;
    int i0 = blockIdx.y * 128, j0 = blockIdx.x * 128;
    int tid = threadIdx.x;
    const float* bias_n = bias + n * 64;

#pragma unroll
    for (int w = 0; w < 8; w++) {
        int idx = tid + w * 256;           // 0..2047
        int r = idx >> 4, c4 = (idx & 15) * 4;
        float4 v = *(const float4*)(Q + (size_t)(i0 + r) * 2048 + b * 512 + n * 64 + c4);
        float4 bb = *(const float4*)(bias_n + c4);
        float* dst = As + r * 68 + c4;
        dst[0] = tf32f(v.x + bb.x); dst[1] = tf32f(v.y + bb.y);
        dst[2] = tf32f(v.z + bb.z); dst[3] = tf32f(v.w + bb.w);
    }
#pragma unroll
    for (int w = 0; w < 8; w++) {
        int idx = tid + w * 256;
        int r = idx >> 4, c4 = (idx & 15) * 4;
        float4 v = *(const float4*)(Bm + (size_t)(j0 + r) * ldb + b * bstride + n * 64 + c4);
        float* dst = Bs + r * 68 + c4;
        dst[0] = tf32f(v.x); dst[1] = tf32f(v.y);
        dst[2] = tf32f(v.z); dst[3] = tf32f(v.w);
    }
    __syncthreads();

    int warp = tid >> 5, lane = tid & 31;
    int g = lane >> 2, c = lane & 3;
    int wm = (warp >> 2) * 64, wn = (warp & 3) * 32;

    float acc[4][4][4];
#pragma unroll
    for (int mt = 0; mt < 4; mt++)
#pragma unroll
        for (int nt = 0; nt < 4; nt++)
#pragma unroll
            for (int e = 0; e < 4; e++) acc[mt][nt][e] = 0.f;

#pragma unroll
    for (int kk = 0; kk < 8; kk++) {
        int k = kk * 8;
        uint32_t af[4][4], bf[4][2];
#pragma unroll
        for (int mt = 0; mt < 4; mt++) {
            const float* base = As + (wm + mt * 16 + g) * 68 + k + c;
            af[mt][0] = __float_as_uint(base[0]);
            af[mt][1] = __float_as_uint(base[8 * 68]);
            af[mt][2] = __float_as_uint(base[4]);
            af[mt][3] = __float_as_uint(base[8 * 68 + 4]);
        }
#pragma unroll
        for (int nt = 0; nt < 4; nt++) {
            const float* base = Bs + (wn + nt * 8 + g) * 68 + k + c;
            bf[nt][0] = __float_as_uint(base[0]);
            bf[nt][1] = __float_as_uint(base[4]);
        }
#pragma unroll
        for (int mt = 0; mt < 4; mt++)
#pragma unroll
            for (int nt = 0; nt < 4; nt++)
                mma_tf32(acc[mt][nt], af[mt], bf[nt], acc[mt][nt]);
    }

    float* Cb = C + ((size_t)bn * 512 + i0) * 2048 + j0;
#pragma unroll
    for (int mt = 0; mt < 4; mt++)
#pragma unroll
        for (int nt = 0; nt < 4; nt++) {
            int row = wm + mt * 16 + g;
            int col = wn + nt * 8 + c * 2;
            *(float2*)(Cb + (size_t)row * 2048 + col) =
                make_float2(acc[mt][nt][0], acc[mt][nt][1]);
            *(float2*)(Cb + (size_t)(row + 8) * 2048 + col) =
                make_float2(acc[mt][nt][2], acc[mt][nt][3]);
        }
}

// ---------------- softmax + rel-shift + gates + mask + attn_matrix ----------
// One block per query i. Loops the 32 (b,n) rows; overwrites AC with prob.
__global__ void softmax_kernel(float* __restrict__ AC, const float* __restrict__ BD,
                               const float* __restrict__ ib, float* __restrict__ attn) {
    __shared__ float accv[2048];
    __shared__ float red[32];
    int i = blockIdx.x;
    int tid = threadIdx.x;
    for (int j = tid; j < 2048; j += 256) accv[j] = 0.f;
    __syncthreads();

    int jmax = 3 * Lq + i;   // valid keys: j <= jmax

    for (int bn = 0; bn < 32; bn++) {
        int b = bn >> 3;
        float* acrow = AC + ((size_t)bn * 512 + i) * 2048;
        const float* bdrow = BD + ((size_t)bn * 512 + i) * 2048;
        const float* g = ib + ((size_t)i * BATCH + b) * 4;

        float s[8];
        float mx = -1e30f;
#pragma unroll
        for (int t = 0; t < 8; t++) {
            int j = tid + t * 256;
            if (j <= jmax) {
                int m = j + (Lq - 1) - i;          // rel-shift closed form
                float v = SCALEF * (g[j >> 9] * acrow[j] + g[m >> 9] * bdrow[m]);
                s[t] = v;
                mx = fmaxf(mx, v);
            } else {
                s[t] = -1e30f;
            }
        }
        mx = blockRedMax(mx, red);

        float p[8];
        float sum = 0.f;
#pragma unroll
        for (int t = 0; t < 8; t++) {
            p[t] = (s[t] > -1e29f) ? __expf(s[t] - mx) : 0.f;
            sum += p[t];
        }
        sum = blockRedSum(sum, red);
        float inv = 1.f / sum;
#pragma unroll
        for (int t = 0; t < 8; t++) {
            int j = tid + t * 256;
            float pp = p[t] * inv;
            acrow[j] = pp;          // prob, in place
            accv[j] += pp;          // each thread owns distinct j
        }
        __syncthreads();
    }

    const float invBN = 1.f / 32.f;
    for (int j = tid; j < 2048; j += 256)
        attn[(size_t)i * 2048 + j] = accv[j] * invBN;
}

// ============================================================================
// Batched prob @ V (tf32):
// vec[((i)*4+b)*512 + n*64 + d] = sum_j P[bn][i][j] * V[j*4096+b*1024+512+n*64+d]
// Block: (i-tile 128, bn). M=128, N=64, K=2048, BK=32. 8 warps as 4(m) x 2(n).
// ============================================================================
__global__ void pv_gemm_tf32(const float* __restrict__ P, const float* __restrict__ KV,
                             float* __restrict__ vec) {
    __shared__ float As[128 * 36];  // P tile: 128 i x 32 j
    __shared__ float Bs[32 * 72];   // V tile: 32 j x 64 d

    int bn = blockIdx.y;
    int b = bn >> 3, n = bn & 7;
    int i0 = blockIdx.x * 128;
    int tid = threadIdx.x;
    int warp = tid >> 5, lane = tid & 31;
    int g = lane >> 2, c = lane & 3;
    int wm = (warp >> 1) * 32;      // 4 warps in m
    int wn = (warp & 1) * 32;       // 2 warps in n

    const float* Pb = P + ((size_t)bn * 512 + i0) * 2048;
    const float* Vb = KV + b * 1024 + 512 + n * 64;

    float acc[2][4][4];
#pragma unroll
    for (int mt = 0; mt < 2; mt++)
#pragma unroll
        for (int nt = 0; nt < 4; nt++)
#pragma unroll
            for (int e = 0; e < 4; e++) acc[mt][nt][e] = 0.f;

    for (int k0 = 0; k0 < 2048; k0 += 32) {
        // P tile 128x32
#pragma unroll
        for (int w = 0; w < 4; w++) {
            int idx = tid + w * 256;
            int r = idx >> 3, cc = (idx & 7) * 4;
            float4 v = *(const float4*)(Pb + (size_t)r * 2048 + k0 + cc);
            float* dst = As + r * 36 + cc;
            dst[0] = tf32f(v.x); dst[1] = tf32f(v.y);
            dst[2] = tf32f(v.z); dst[3] = tf32f(v.w);
        }
        // V tile 32x64
#pragma unroll
        for (int w = 0; w < 2; w++) {
            int idx = tid + w * 256;
            int r = idx >> 4, cc = (idx & 15) * 4;
            float4 v = *(const float4*)(Vb + (size_t)(k0 + r) * 4096 + cc);
            float* dst = Bs + r * 72 + cc;
            dst[0] = tf32f(v.x); dst[1] = tf32f(v.y);
            dst[2] = tf32f(v.z); dst[3] = tf32f(v.w);
        }
        __syncthreads();

#pragma unroll
        for (int kk = 0; kk < 4; kk++) {
            int k = kk * 8;
            uint32_t af[2][4], bf[4][2];
#pragma unroll
            for (int mt = 0; mt < 2; mt++) {
                const float* base = As + (wm + mt * 16 + g) * 36 + k + c;
                af[mt][0] = __float_as_uint(base[0]);
                af[mt][1] = __float_as_uint(base[8 * 36]);
                af[mt][2] = __float_as_uint(base[4]);
                af[mt][3] = __float_as_uint(base[8 * 36 + 4]);
            }
#pragma unroll
            for (int nt = 0; nt < 4; nt++) {
                const float* base = Bs + (k + c) * 72 + wn + nt * 8 + g;
                bf[nt][0] = __float_as_uint(base[0]);
                bf[nt][1] = __float_as_uint(base[4 * 72]);
            }
#pragma unroll
            for (int mt = 0; mt < 2; mt++)
#pragma unroll
                for (int nt = 0; nt < 4; nt++)
                    mma_tf32(acc[mt][nt], af[mt], bf[nt], acc[mt][nt]);
        }
        __syncthreads();
    }

#pragma unroll
    for (int mt = 0; mt < 2; mt++)
#pragma unroll
        for (int nt = 0; nt < 4; nt++) {
            int row = wm + mt * 16 + g;
            int col = wn + nt * 8 + c * 2;
            float* d0 = vec + ((size_t)(i0 + row) * 4 + b) * 512 + n * 64 + col;
            float* d1 = vec + ((size_t)(i0 + row + 8) * 4 + b) * 512 + n * 64 + col;
            *(float2*)d0 = make_float2(acc[mt][nt][0], acc[mt][nt][1]);
            *(float2*)d1 = make_float2(acc[mt][nt][2], acc[mt][nt][3]);
        }
}

// ---------------- layernorm --------------------------------------------------
__global__ void ln_kernel(const float* __restrict__ y, const float* __restrict__ g,
                          const float* __restrict__ be, float* __restrict__ out) {
    __shared__ float red[32];
    int r = blockIdx.x;
    int tid = threadIdx.x;
    float v0 = y[(size_t)r * 512 + tid];
    float v1 = y[(size_t)r * 512 + tid + 256];
    float mean = blockRedSum(v0 + v1, red) * (1.f / 512.f);
    float d0 = v0 - mean, d1 = v1 - mean;
    float var = blockRedSum(d0 * d0 + d1 * d1, red) * (1.f / 512.f);
    float rstd = rsqrtf(var + 1e-5f);
    out[(size_t)r * 512 + tid]       = d0 * rstd * g[tid] + be[tid];
    out[(size_t)r * 512 + tid + 256] = d1 * rstd * g[tid + 256] + be[tid + 256];
}

// ---------------- launch ------------------------------------------------------
extern "C" void kernel_launch(void* const* d_in, const int* in_sizes, int n_in,
                              void* d_out, int out_size) {
    (void)in_sizes; (void)n_in; (void)out_size;
    const float* x       = (const float*)d_in[0];
    const float* memory  = (const float*)d_in[1];
    const float* pos_emb = (const float*)d_in[2];
    const float* pbu     = (const float*)d_in[3];
    const float* pbv     = (const float*)d_in[4];
    // d_in[5] = mask (recomputed analytically; unused)
    const float* ib      = (const float*)d_in[6];
    const float* W_q     = (const float*)d_in[7];
    const float* W_kv    = (const float*)d_in[8];
    const float* W_rel   = (const float*)d_in[9];
    const float* W_o     = (const float*)d_in[10];
    const float* ln_g    = (const float*)d_in[11];
    const float* ln_b    = (const float*)d_in[12];

    float* out  = (float*)d_out;                       // [L,B,D] = 1048576 floats
    float* attn = out + (size_t)Lq * BATCH * DMOD;     // [L,TOTAL] = 1048576 floats

    float *kv, *rel, *q, *acb, *bdb, *vec, *y;
    cudaGetSymbolAddress((void**)&kv,  g_kv);
    cudaGetSymbolAddress((void**)&rel, g_rel);
    cudaGetSymbolAddress((void**)&q,   g_q);
    cudaGetSymbolAddress((void**)&acb, g_ac);
    cudaGetSymbolAddress((void**)&bdb, g_bd);
    cudaGetSymbolAddress((void**)&vec, g_vec);
    cudaGetSymbolAddress((void**)&y,   g_y);

    static bool attr_set = false;
    if (!attr_set) {
        cudaFuncSetAttribute(attn_gemm_tf32,
                             cudaFuncAttributeMaxDynamicSharedMemorySize, 69632);
        attr_set = true;
    }

    // 1) projections (tf32 tensor cores)
    gemm_tf32<<<dim3(8, 48), 256>>>(memory, W_kv, nullptr, kv, 6144, 1024, 512);
    gemm_tf32<<<dim3(8, 16), 256>>>(x, W_kv, nullptr, kv + (size_t)6144 * 1024, 2048, 1024, 512);
    gemm_tf32<<<dim3(4, 64), 256>>>(pos_emb, W_rel, nullptr, rel, 8192, 512, 512);
    gemm_tf32<<<dim3(4, 16), 256>>>(x, W_q, nullptr, q, 2048, 512, 512);

    // 2) AC = (q+u)·k  and  BDpre = (q+v)·rel   (32 batches)
    attn_gemm_tf32<<<dim3(16, 4, 32), 256, 69632>>>(q, pbu, kv, 4096, 1024, acb);
    attn_gemm_tf32<<<dim3(16, 4, 32), 256, 69632>>>(q, pbv, rel, 2048, 512, bdb);

    // 3) gates + rel-shift + mask + softmax; prob overwrites AC; attn_matrix out
    softmax_kernel<<<512, 256>>>(acb, bdb, ib, attn);

    // 4) vec = prob @ v (tf32)
    pv_gemm_tf32<<<dim3(4, 32), 256>>>(acb, kv, vec);

    // 5) y = x + vec @ W_o ; then layernorm -> out
    gemm_tf32<<<dim3(4, 16), 256>>>(vec, W_o, x, y, 2048, 512, 512);
    ln_kernel<<<2048, 256>>>(y, ln_g, ln_b, out);
}

// round 3
// speedup vs baseline: 2.6211x; 1.1617x over previous
#include <cuda_runtime.h>
#include <stdint.h>

// Problem constants
#define Lq     512
#define BATCH  4
#define DMOD   512
#define NH     8
#define DHEAD  64
#define MEMN   3
#define TOTALK 2048
#define SCALEF 0.125f
#define ROWS_X (Lq * BATCH)
#define ROWS_C (TOTALK * BATCH)

// ---------------- scratch ----------------
__device__ float g_kv [(size_t)ROWS_C * 1024];          // 32 MB  k | v
__device__ float g_rel[(size_t)ROWS_C * 512];           // 16 MB
__device__ float g_q  [(size_t)ROWS_X * 512];           //  4 MB
__device__ float g_sc [(size_t)32 * 512 * 2048];        // 128 MB scores -> prob
__device__ float g_vec[(size_t)ROWS_X * 512];           //  4 MB
__device__ float g_y  [(size_t)ROWS_X * 512];           //  4 MB

// ---------------- helpers ----------------
__device__ __forceinline__ float tf32f(float x) {
    uint32_t u;
    asm("cvt.rna.tf32.f32 %0, %1;" : "=r"(u) : "f"(x));
    return __uint_as_float(u);
}

__device__ __forceinline__ void mma_tf32(float* d, const uint32_t* a,
                                         const uint32_t* b, const float* c) {
    asm volatile(
        "mma.sync.aligned.m16n8k8.row.col.f32.tf32.tf32.f32 "
        "{%0,%1,%2,%3}, {%4,%5,%6,%7}, {%8,%9}, {%10,%11,%12,%13};"
        : "=f"(d[0]), "=f"(d[1]), "=f"(d[2]), "=f"(d[3])
        : "r"(a[0]), "r"(a[1]), "r"(a[2]), "r"(a[3]),
          "r"(b[0]), "r"(b[1]),
          "f"(c[0]), "f"(c[1]), "f"(c[2]), "f"(c[3]));
}

__device__ __forceinline__ void cp16(float* dst, const float* src) {
    uint32_t d = (uint32_t)__cvta_generic_to_shared(dst);
    asm volatile("cp.async.cg.shared.global [%0], [%1], 16;" :: "r"(d), "l"(src));
}
#define CP_COMMIT() asm volatile("cp.async.commit_group;")
#define CP_WAIT1()  asm volatile("cp.async.wait_group 1;")

__device__ __forceinline__ float warpRedMax(float v) {
#pragma unroll
    for (int o = 16; o > 0; o >>= 1) v = fmaxf(v, __shfl_xor_sync(0xffffffffu, v, o));
    return v;
}
__device__ __forceinline__ float warpRedSum(float v) {
#pragma unroll
    for (int o = 16; o > 0; o >>= 1) v += __shfl_xor_sync(0xffffffffu, v, o);
    return v;
}
__device__ __forceinline__ float blockRedMax(float v, float* red) {
    v = warpRedMax(v);
    int w = threadIdx.x >> 5, l = threadIdx.x & 31;
    if (!l) red[w] = v;
    __syncthreads();
    if (threadIdx.x < 32) {
        float x = (l < 8) ? red[l] : -1e30f;
        x = warpRedMax(x);
        if (!l) red[0] = x;
    }
    __syncthreads();
    float r = red[0];
    __syncthreads();
    return r;
}
__device__ __forceinline__ float blockRedSum(float v, float* red) {
    v = warpRedSum(v);
    int w = threadIdx.x >> 5, l = threadIdx.x & 31;
    if (!l) red[w] = v;
    __syncthreads();
    if (threadIdx.x < 32) {
        float x = (l < 8) ? red[l] : 0.f;
        x = warpRedSum(x);
        if (!l) red[0] = x;
    }
    __syncthreads();
    float r = red[0];
    __syncthreads();
    return r;
}

// ============================================================================
// Pipelined tf32 GEMM: C = A[MxK] @ B[KxN] (+Cadd). BM=128, BK=32, 2 stages,
// cp.async, 256 threads (8 warps 2x4). BN template = 64 or 128.
// ============================================================================
template <int BN>
__global__ __launch_bounds__(256) void gemm_pipe(
        const float* __restrict__ A, const float* __restrict__ B,
        const float* __restrict__ Cadd, float* __restrict__ C,
        int M, int N, int K) {
    extern __shared__ float sm[];
    const int BST = BN + 8;
    float* As = sm;                    // [2][128*36]
    float* Bs = sm + 2 * 128 * 36;     // [2][32*BST]

    int m0 = blockIdx.y * 128, n0 = blockIdx.x * BN;
    int tid = threadIdx.x;
    int warp = tid >> 5, lane = tid & 31;
    int g = lane >> 2, c = lane & 3;
    int wm = (warp >> 2) * 64;
    int wn = (warp & 3) * (BN / 4);
    const int NT = BN / 32;

    float acc[4][NT][4];
#pragma unroll
    for (int mt = 0; mt < 4; mt++)
#pragma unroll
        for (int nt = 0; nt < NT; nt++)
#pragma unroll
            for (int e = 0; e < 4; e++) acc[mt][nt][e] = 0.f;

    int nk = K >> 5;
    // prologue: stage 0
    {
#pragma unroll
        for (int w = 0; w < 4; w++) {
            int idx = tid + w * 256;
            int r = idx >> 3, cc = (idx & 7) * 4;
            cp16(As + r * 36 + cc, A + (size_t)(m0 + r) * K + cc);
        }
#pragma unroll
        for (int w = 0; w < BN / 32; w++) {
            int idx = tid + w * 256;
            int r = idx / (BN / 4), cc = (idx % (BN / 4)) * 4;
            cp16(Bs + r * BST + cc, B + (size_t)r * N + n0 + cc);
        }
    }
    CP_COMMIT();

    for (int kt = 0; kt < nk; kt++) {
        int cur = kt & 1;
        if (kt + 1 < nk) {
            int nxt = (kt + 1) & 1;
            int k0 = (kt + 1) * 32;
#pragma unroll
            for (int w = 0; w < 4; w++) {
                int idx = tid + w * 256;
                int r = idx >> 3, cc = (idx & 7) * 4;
                cp16(As + nxt * 128 * 36 + r * 36 + cc,
                     A + (size_t)(m0 + r) * K + k0 + cc);
            }
#pragma unroll
            for (int w = 0; w < BN / 32; w++) {
                int idx = tid + w * 256;
                int r = idx / (BN / 4), cc = (idx % (BN / 4)) * 4;
                cp16(Bs + nxt * 32 * BST + r * BST + cc,
                     B + (size_t)(k0 + r) * N + n0 + cc);
            }
        }
        CP_COMMIT();
        CP_WAIT1();
        __syncthreads();

        const float* Ac = As + cur * 128 * 36;
        const float* Bc = Bs + cur * 32 * BST;
#pragma unroll
        for (int kk = 0; kk < 4; kk++) {
            int k = kk * 8;
            uint32_t af[4][4], bf[NT][2];
#pragma unroll
            for (int mt = 0; mt < 4; mt++) {
                const float* base = Ac + (wm + mt * 16 + g) * 36 + k + c;
                af[mt][0] = __float_as_uint(base[0]);
                af[mt][1] = __float_as_uint(base[8 * 36]);
                af[mt][2] = __float_as_uint(base[4]);
                af[mt][3] = __float_as_uint(base[8 * 36 + 4]);
            }
#pragma unroll
            for (int nt = 0; nt < NT; nt++) {
                const float* base = Bc + (k + c) * BST + wn + nt * 8 + g;
                bf[nt][0] = __float_as_uint(base[0]);
                bf[nt][1] = __float_as_uint(base[4 * BST]);
            }
#pragma unroll
            for (int mt = 0; mt < 4; mt++)
#pragma unroll
                for (int nt = 0; nt < NT; nt++)
                    mma_tf32(acc[mt][nt], af[mt], bf[nt], acc[mt][nt]);
        }
        __syncthreads();
    }

#pragma unroll
    for (int mt = 0; mt < 4; mt++)
#pragma unroll
        for (int nt = 0; nt < NT; nt++) {
            int row = m0 + wm + mt * 16 + g;
            int col = n0 + wn + nt * 8 + c * 2;
            float* p0 = C + (size_t)row * N + col;
            float* p1 = C + (size_t)(row + 8) * N + col;
            float2 v0 = make_float2(acc[mt][nt][0], acc[mt][nt][1]);
            float2 v1 = make_float2(acc[mt][nt][2], acc[mt][nt][3]);
            if (Cadd) {
                const float* a0 = Cadd + (size_t)row * N + col;
                const float* a1 = Cadd + (size_t)(row + 8) * N + col;
                v0.x += a0[0]; v0.y += a0[1];
                v1.x += a1[0]; v1.y += a1[1];
            }
            *(float2*)p0 = v0;
            *(float2*)p1 = v1;
        }
}

// ============================================================================
// Fused score kernel: S[bn][i][j] = gA*( (q_i+u)*SCALE . k_j )
//                                 + gB*( (q_i+v)*SCALE . rel_{j+511-i} )
// Tile: 64 i x 128 j per block. BD computed as a 64 x 192 band, staged in smem,
// shifted in the epilogue. Masked j (> 1536+i) get garbage (softmax masks).
// ============================================================================
__global__ __launch_bounds__(256, 1) void score_kernel(
        const float* __restrict__ Q, const float* __restrict__ pbu,
        const float* __restrict__ pbv, const float* __restrict__ KV,
        const float* __restrict__ REL, const float* __restrict__ ib,
        float* __restrict__ S) {
    extern __shared__ float sm[];
    float* qu_s  = sm;                    // [64][68]
    float* qv_s  = qu_s + 64 * 68;        // [64][68]
    float* k_s   = qv_s + 64 * 68;        // [128][68]
    float* rel_s = k_s + 128 * 68;        // [192][68]
    float* bd_s  = rel_s + 192 * 68;      // [64][200]

    int bn = blockIdx.z;
    int b = bn >> 3, n = bn & 7;
    int i0 = blockIdx.y * 64;
    int j0 = blockIdx.x * 128;
    int tid = threadIdx.x;
    int m0 = j0 + 448 - i0;               // band start (>= 0 always)

    // loads
#pragma unroll
    for (int w = 0; w < 4; w++) {          // q rows (both biased copies, scaled)
        int idx = tid + w * 256;
        int r = idx >> 4, c4 = (idx & 15) * 4;
        float4 v = *(const float4*)(Q + (size_t)(i0 + r) * 2048 + b * 512 + n * 64 + c4);
        float4 bu = *(const float4*)(pbu + n * 64 + c4);
        float4 bv = *(const float4*)(pbv + n * 64 + c4);
        float* du = qu_s + r * 68 + c4;
        float* dv = qv_s + r * 68 + c4;
        du[0] = (v.x + bu.x) * SCALEF; du[1] = (v.y + bu.y) * SCALEF;
        du[2] = (v.z + bu.z) * SCALEF; du[3] = (v.w + bu.w) * SCALEF;
        dv[0] = (v.x + bv.x) * SCALEF; dv[1] = (v.y + bv.y) * SCALEF;
        dv[2] = (v.z + bv.z) * SCALEF; dv[3] = (v.w + bv.w) * SCALEF;
    }
#pragma unroll
    for (int w = 0; w < 8; w++) {          // k rows
        int idx = tid + w * 256;
        int r = idx >> 4, c4 = (idx & 15) * 4;
        float4 v = *(const float4*)(KV + (size_t)(j0 + r) * 4096 + b * 1024 + n * 64 + c4);
        float* dst = k_s + r * 68 + c4;
        dst[0] = v.x; dst[1] = v.y; dst[2] = v.z; dst[3] = v.w;
    }
#pragma unroll
    for (int w = 0; w < 12; w++) {         // rel band rows (clamped)
        int idx = tid + w * 256;
        int r = idx >> 4, c4 = (idx & 15) * 4;
        int mr = m0 + r; if (mr > 2047) mr = 2047;
        float4 v = *(const float4*)(REL + (size_t)mr * 2048 + b * 512 + n * 64 + c4);
        float* dst = rel_s + r * 68 + c4;
        dst[0] = v.x; dst[1] = v.y; dst[2] = v.z; dst[3] = v.w;
    }
    __syncthreads();

    int warp = tid >> 5, lane = tid & 31;
    int g = lane >> 2, c = lane & 3;

    // ---- MMA1: BD band = qv . rel  (64 x 192), warps 2(m) x 4(n=48) ----
    {
        int wm2 = (warp >> 2) * 32;
        int wn2 = (warp & 3) * 48;
        float accb[2][6][4];
#pragma unroll
        for (int mt = 0; mt < 2; mt++)
#pragma unroll
            for (int nt = 0; nt < 6; nt++)
#pragma unroll
                for (int e = 0; e < 4; e++) accb[mt][nt][e] = 0.f;

#pragma unroll
        for (int kk = 0; kk < 8; kk++) {
            int k = kk * 8;
            uint32_t af[2][4], bf[6][2];
#pragma unroll
            for (int mt = 0; mt < 2; mt++) {
                const float* base = qv_s + (wm2 + mt * 16 + g) * 68 + k + c;
                af[mt][0] = __float_as_uint(base[0]);
                af[mt][1] = __float_as_uint(base[8 * 68]);
                af[mt][2] = __float_as_uint(base[4]);
                af[mt][3] = __float_as_uint(base[8 * 68 + 4]);
            }
#pragma unroll
            for (int nt = 0; nt < 6; nt++) {
                const float* base = rel_s + (wn2 + nt * 8 + g) * 68 + k + c;
                bf[nt][0] = __float_as_uint(base[0]);
                bf[nt][1] = __float_as_uint(base[4]);
            }
#pragma unroll
            for (int mt = 0; mt < 2; mt++)
#pragma unroll
                for (int nt = 0; nt < 6; nt++)
                    mma_tf32(accb[mt][nt], af[mt], bf[nt], accb[mt][nt]);
        }
        // stage to smem
#pragma unroll
        for (int mt = 0; mt < 2; mt++)
#pragma unroll
            for (int nt = 0; nt < 6; nt++) {
                int row = wm2 + mt * 16 + g;
                int col = wn2 + nt * 8 + c * 2;
                bd_s[row * 200 + col]           = accb[mt][nt][0];
                bd_s[row * 200 + col + 1]       = accb[mt][nt][1];
                bd_s[(row + 8) * 200 + col]     = accb[mt][nt][2];
                bd_s[(row + 8) * 200 + col + 1] = accb[mt][nt][3];
            }
    }
    __syncthreads();

    // ---- MMA2: AC = qu . k (64 x 128), warps 2(m) x 4(n=32) + epilogue ----
    {
        int wm = (warp >> 2) * 32;
        int wn = (warp & 3) * 32;
        float acca[2][4][4];
#pragma unroll
        for (int mt = 0; mt < 2; mt++)
#pragma unroll
            for (int nt = 0; nt < 4; nt++)
#pragma unroll
                for (int e = 0; e < 4; e++) acca[mt][nt][e] = 0.f;

#pragma unroll
        for (int kk = 0; kk < 8; kk++) {
            int k = kk * 8;
            uint32_t af[2][4], bf[4][2];
#pragma unroll
            for (int mt = 0; mt < 2; mt++) {
                const float* base = qu_s + (wm + mt * 16 + g) * 68 + k + c;
                af[mt][0] = __float_as_uint(base[0]);
                af[mt][1] = __float_as_uint(base[8 * 68]);
                af[mt][2] = __float_as_uint(base[4]);
                af[mt][3] = __float_as_uint(base[8 * 68 + 4]);
            }
#pragma unroll
            for (int nt = 0; nt < 4; nt++) {
                const float* base = k_s + (wn + nt * 8 + g) * 68 + k + c;
                bf[nt][0] = __float_as_uint(base[0]);
                bf[nt][1] = __float_as_uint(base[4]);
            }
#pragma unroll
            for (int mt = 0; mt < 2; mt++)
#pragma unroll
                for (int nt = 0; nt < 4; nt++)
                    mma_tf32(acca[mt][nt], af[mt], bf[nt], acca[mt][nt]);
        }

        // epilogue: combine with shifted BD + gates, write S
        float* Sb = S + ((size_t)bn * 512 + i0) * 2048 + j0;
#pragma unroll
        for (int mt = 0; mt < 2; mt++)
#pragma unroll
            for (int nt = 0; nt < 4; nt++) {
#pragma unroll
                for (int half = 0; half < 2; half++) {
                    int i_loc = wm + mt * 16 + g + half * 8;
                    int i = i0 + i_loc;
                    const float* gp = ib + ((size_t)i * 4 + b) * 4;
                    float a0 = acca[mt][nt][half * 2];
                    float a1 = acca[mt][nt][half * 2 + 1];
#pragma unroll
                    for (int e = 0; e < 2; e++) {
                        int j_loc = wn + nt * 8 + c * 2 + e;
                        int j = j0 + j_loc;
                        int m = j + 511 - i;
                        int segB = m >> 9; if (segB > 3) segB = 3;
                        float bd = bd_s[i_loc * 200 + (j_loc + 63 - i_loc)];
                        float ac = e ? a1 : a0;
                        Sb[(size_t)i_loc * 2048 + j_loc] =
                            gp[j >> 9] * ac + gp[segB] * bd;
                    }
                }
            }
    }
}

// ---------------- softmax (scores pre-gated/scaled/shifted) -----------------
__global__ void softmax_kernel(float* __restrict__ S, float* __restrict__ attn) {
    __shared__ float accv[2048];
    __shared__ float red[32];
    int i = blockIdx.x;
    int tid = threadIdx.x;
    for (int j = tid; j < 2048; j += 256) accv[j] = 0.f;
    __syncthreads();

    int jmax = 3 * Lq + i;

    for (int bn = 0; bn < 32; bn++) {
        float* srow = S + ((size_t)bn * 512 + i) * 2048;

        float s[8];
        float mx = -1e30f;
#pragma unroll
        for (int t = 0; t < 8; t++) {
            int j = tid + t * 256;
            if (j <= jmax) {
                float v = srow[j];
                s[t] = v;
                mx = fmaxf(mx, v);
            } else {
                s[t] = -1e30f;
            }
        }
        mx = blockRedMax(mx, red);

        float p[8];
        float sum = 0.f;
#pragma unroll
        for (int t = 0; t < 8; t++) {
            p[t] = (s[t] > -1e29f) ? __expf(s[t] - mx) : 0.f;
            sum += p[t];
        }
        sum = blockRedSum(sum, red);
        float inv = 1.f / sum;
#pragma unroll
        for (int t = 0; t < 8; t++) {
            int j = tid + t * 256;
            float pp = p[t] * inv;
            srow[j] = pp;
            accv[j] += pp;
        }
        __syncthreads();
    }

    const float invBN = 1.f / 32.f;
    for (int j = tid; j < 2048; j += 256)
        attn[(size_t)i * 2048 + j] = accv[j] * invBN;
}

// ============================================================================
// Batched prob @ V (tf32)
// ============================================================================
__global__ void pv_gemm_tf32(const float* __restrict__ P, const float* __restrict__ KV,
                             float* __restrict__ vec) {
    __shared__ float As[128 * 36];
    __shared__ float Bs[32 * 72];

    int bn = blockIdx.y;
    int b = bn >> 3, n = bn & 7;
    int i0 = blockIdx.x * 128;
    int tid = threadIdx.x;
    int warp = tid >> 5, lane = tid & 31;
    int g = lane >> 2, c = lane & 3;
    int wm = (warp >> 1) * 32;
    int wn = (warp & 1) * 32;

    const float* Pb = P + ((size_t)bn * 512 + i0) * 2048;
    const float* Vb = KV + b * 1024 + 512 + n * 64;

    float acc[2][4][4];
#pragma unroll
    for (int mt = 0; mt < 2; mt++)
#pragma unroll
        for (int nt = 0; nt < 4; nt++)
#pragma unroll
            for (int e = 0; e < 4; e++) acc[mt][nt][e] = 0.f;

    for (int k0 = 0; k0 < 2048; k0 += 32) {
#pragma unroll
        for (int w = 0; w < 4; w++) {
            int idx = tid + w * 256;
            int r = idx >> 3, cc = (idx & 7) * 4;
            float4 v = *(const float4*)(Pb + (size_t)r * 2048 + k0 + cc);
            float* dst = As + r * 36 + cc;
            dst[0] = v.x; dst[1] = v.y; dst[2] = v.z; dst[3] = v.w;
        }
#pragma unroll
        for (int w = 0; w < 2; w++) {
            int idx = tid + w * 256;
            int r = idx >> 4, cc = (idx & 15) * 4;
            float4 v = *(const float4*)(Vb + (size_t)(k0 + r) * 4096 + cc);
            float* dst = Bs + r * 72 + cc;
            dst[0] = v.x; dst[1] = v.y; dst[2] = v.z; dst[3] = v.w;
        }
        __syncthreads();

#pragma unroll
        for (int kk = 0; kk < 4; kk++) {
            int k = kk * 8;
            uint32_t af[2][4], bf[4][2];
#pragma unroll
            for (int mt = 0; mt < 2; mt++) {
                const float* base = As + (wm + mt * 16 + g) * 36 + k + c;
                af[mt][0] = __float_as_uint(base[0]);
                af[mt][1] = __float_as_uint(base[8 * 36]);
                af[mt][2] = __float_as_uint(base[4]);
                af[mt][3] = __float_as_uint(base[8 * 36 + 4]);
            }
#pragma unroll
            for (int nt = 0; nt < 4; nt++) {
                const float* base = Bs + (k + c) * 72 + wn + nt * 8 + g;
                bf[nt][0] = __float_as_uint(base[0]);
                bf[nt][1] = __float_as_uint(base[4 * 72]);
            }
#pragma unroll
            for (int mt = 0; mt < 2; mt++)
#pragma unroll
                for (int nt = 0; nt < 4; nt++)
                    mma_tf32(acc[mt][nt], af[mt], bf[nt], acc[mt][nt]);
        }
        __syncthreads();
    }

#pragma unroll
    for (int mt = 0; mt < 2; mt++)
#pragma unroll
        for (int nt = 0; nt < 4; nt++) {
            int row = wm + mt * 16 + g;
            int col = wn + nt * 8 + c * 2;
            float* d0 = vec + ((size_t)(i0 + row) * 4 + b) * 512 + n * 64 + col;
            float* d1 = vec + ((size_t)(i0 + row + 8) * 4 + b) * 512 + n * 64 + col;
            *(float2*)d0 = make_float2(acc[mt][nt][0], acc[mt][nt][1]);
            *(float2*)d1 = make_float2(acc[mt][nt][2], acc[mt][nt][3]);
        }
}

// ---------------- layernorm ----------------
__global__ void ln_kernel(const float* __restrict__ y, const float* __restrict__ g,
                          const float* __restrict__ be, float* __restrict__ out) {
    __shared__ float red[32];
    int r = blockIdx.x;
    int tid = threadIdx.x;
    float v0 = y[(size_t)r * 512 + tid];
    float v1 = y[(size_t)r * 512 + tid + 256];
    float mean = blockRedSum(v0 + v1, red) * (1.f / 512.f);
    float d0 = v0 - mean, d1 = v1 - mean;
    float var = blockRedSum(d0 * d0 + d1 * d1, red) * (1.f / 512.f);
    float rstd = rsqrtf(var + 1e-5f);
    out[(size_t)r * 512 + tid]       = d0 * rstd * g[tid] + be[tid];
    out[(size_t)r * 512 + tid + 256] = d1 * rstd * g[tid + 256] + be[tid + 256];
}

// ---------------- launch ----------------
#define SMEM_G128 ((2 * 128 * 36 + 2 * 32 * 136) * 4)   // 71680
#define SMEM_G64  ((2 * 128 * 36 + 2 * 32 * 72) * 4)    // 55296
#define SMEM_SC   ((64*68 + 64*68 + 128*68 + 192*68 + 64*200) * 4)  // 173056

extern "C" void kernel_launch(void* const* d_in, const int* in_sizes, int n_in,
                              void* d_out, int out_size) {
    (void)in_sizes; (void)n_in; (void)out_size;
    const float* x       = (const float*)d_in[0];
    const float* memory  = (const float*)d_in[1];
    const float* pos_emb = (const float*)d_in[2];
    const float* pbu     = (const float*)d_in[3];
    const float* pbv     = (const float*)d_in[4];
    const float* ib      = (const float*)d_in[6];
    const float* W_q     = (const float*)d_in[7];
    const float* W_kv    = (const float*)d_in[8];
    const float* W_rel   = (const float*)d_in[9];
    const float* W_o     = (const float*)d_in[10];
    const float* ln_g    = (const float*)d_in[11];
    const float* ln_b    = (const float*)d_in[12];

    float* out  = (float*)d_out;
    float* attn = out + (size_t)Lq * BATCH * DMOD;

    float *kv, *rel, *q, *sc, *vec, *y;
    cudaGetSymbolAddress((void**)&kv,  g_kv);
    cudaGetSymbolAddress((void**)&rel, g_rel);
    cudaGetSymbolAddress((void**)&q,   g_q);
    cudaGetSymbolAddress((void**)&sc,  g_sc);
    cudaGetSymbolAddress((void**)&vec, g_vec);
    cudaGetSymbolAddress((void**)&y,   g_y);

    static bool attr_set = false;
    if (!attr_set) {
        cudaFuncSetAttribute(gemm_pipe<128>,
                             cudaFuncAttributeMaxDynamicSharedMemorySize, SMEM_G128);
        cudaFuncSetAttribute(gemm_pipe<64>,
                             cudaFuncAttributeMaxDynamicSharedMemorySize, SMEM_G64);
        cudaFuncSetAttribute(score_kernel,
                             cudaFuncAttributeMaxDynamicSharedMemorySize, SMEM_SC);
        attr_set = true;
    }

    // 1) projections
    gemm_pipe<128><<<dim3(8, 48), 256, SMEM_G128>>>(memory, W_kv, nullptr, kv, 6144, 1024, 512);
    gemm_pipe<128><<<dim3(8, 16), 256, SMEM_G128>>>(x, W_kv, nullptr, kv + (size_t)6144 * 1024, 2048, 1024, 512);
    gemm_pipe<128><<<dim3(4, 64), 256, SMEM_G128>>>(pos_emb, W_rel, nullptr, rel, 8192, 512, 512);
    gemm_pipe<64><<<dim3(8, 16), 256, SMEM_G64>>>(x, W_q, nullptr, q, 2048, 512, 512);

    // 2) fused scores (AC + shifted BD + gates + scale)
    score_kernel<<<dim3(16, 8, 32), 256, SMEM_SC>>>(q, pbu, pbv, kv, rel, ib, sc);

    // 3) masked softmax; prob overwrites scores; attn_matrix out
    softmax_kernel<<<512, 256>>>(sc, attn);

    // 4) vec = prob @ v
    pv_gemm_tf32<<<dim3(4, 32), 256>>>(sc, kv, vec);

    // 5) y = x + vec @ W_o ; layernorm
    gemm_pipe<64><<<dim3(8, 16), 256, SMEM_G64>>>(vec, W_o, x, y, 2048, 512, 512);
    ln_kernel<<<2048, 256>>>(y, ln_g, ln_b, out);
}

// round 4
// speedup vs baseline: 2.8366x; 1.0822x over previous
#include <cuda_runtime.h>
#include <cuda_fp16.h>
#include <stdint.h>

// Problem constants
#define Lq     512
#define BATCH  4
#define SCALEF 0.125f
#define ROWS_X (Lq * BATCH)
#define ROWS_C (2048 * BATCH)

// ---------------- scratch ----------------
__device__ float  g_kv  [(size_t)ROWS_C * 1024];        // 32 MB  k | v
__device__ float  g_rel [(size_t)ROWS_C * 512];         // 16 MB
__device__ float  g_q   [(size_t)ROWS_X * 512];         //  4 MB
__device__ float  g_sc  [(size_t)32 * 512 * 2048];      // 128 MB raw scores
__device__ __half g_prob[(size_t)32 * 512 * 2048];      // 64 MB prob (fp16)
__device__ float  g_vec [(size_t)ROWS_X * 512];         //  4 MB
__device__ float  g_y   [(size_t)ROWS_X * 512];         //  4 MB

// ---------------- helpers ----------------
__device__ __forceinline__ void mma_tf32(float* d, const uint32_t* a,
                                         const uint32_t* b, const float* c) {
    asm volatile(
        "mma.sync.aligned.m16n8k8.row.col.f32.tf32.tf32.f32 "
        "{%0,%1,%2,%3}, {%4,%5,%6,%7}, {%8,%9}, {%10,%11,%12,%13};"
        : "=f"(d[0]), "=f"(d[1]), "=f"(d[2]), "=f"(d[3])
        : "r"(a[0]), "r"(a[1]), "r"(a[2]), "r"(a[3]),
          "r"(b[0]), "r"(b[1]),
          "f"(c[0]), "f"(c[1]), "f"(c[2]), "f"(c[3]));
}

__device__ __forceinline__ void mma_f16(float* d, const uint32_t* a,
                                        const uint32_t* b, const float* c) {
    asm volatile(
        "mma.sync.aligned.m16n8k16.row.col.f32.f16.f16.f32 "
        "{%0,%1,%2,%3}, {%4,%5,%6,%7}, {%8,%9}, {%10,%11,%12,%13};"
        : "=f"(d[0]), "=f"(d[1]), "=f"(d[2]), "=f"(d[3])
        : "r"(a[0]), "r"(a[1]), "r"(a[2]), "r"(a[3]),
          "r"(b[0]), "r"(b[1]),
          "f"(c[0]), "f"(c[1]), "f"(c[2]), "f"(c[3]));
}

__device__ __forceinline__ void cp16(float* dst, const float* src) {
    uint32_t d = (uint32_t)__cvta_generic_to_shared(dst);
    asm volatile("cp.async.cg.shared.global [%0], [%1], 16;" :: "r"(d), "l"(src));
}
#define CP_COMMIT() asm volatile("cp.async.commit_group;")
#define CP_WAIT1()  asm volatile("cp.async.wait_group 1;")

__device__ __forceinline__ float warpRedMax(float v) {
#pragma unroll
    for (int o = 16; o > 0; o >>= 1) v = fmaxf(v, __shfl_xor_sync(0xffffffffu, v, o));
    return v;
}
__device__ __forceinline__ float warpRedSum(float v) {
#pragma unroll
    for (int o = 16; o > 0; o >>= 1) v += __shfl_xor_sync(0xffffffffu, v, o);
    return v;
}
__device__ __forceinline__ float blockRedMax(float v, float* red) {
    v = warpRedMax(v);
    int w = threadIdx.x >> 5, l = threadIdx.x & 31;
    if (!l) red[w] = v;
    __syncthreads();
    if (threadIdx.x < 32) {
        float x = (l < 8) ? red[l] : -1e30f;
        x = warpRedMax(x);
        if (!l) red[0] = x;
    }
    __syncthreads();
    float r = red[0];
    __syncthreads();
    return r;
}
__device__ __forceinline__ float blockRedSum(float v, float* red) {
    v = warpRedSum(v);
    int w = threadIdx.x >> 5, l = threadIdx.x & 31;
    if (!l) red[w] = v;
    __syncthreads();
    if (threadIdx.x < 32) {
        float x = (l < 8) ? red[l] : 0.f;
        x = warpRedSum(x);
        if (!l) red[0] = x;
    }
    __syncthreads();
    float r = red[0];
    __syncthreads();
    return r;
}

// ============================================================================
// Combined projection kernel: up to 4 independent GEMMs (BM=128, BN=128,
// K=512) dispatched by block range in one launch. tf32, 2-stage cp.async.
// ============================================================================
struct Desc {
    const float* A; const float* B; float* C;
    int N, K, nblk, blk0;
};

__global__ __launch_bounds__(256) void proj_multi(Desc d0, Desc d1, Desc d2, Desc d3) {
    extern __shared__ float sm[];
    float* As = sm;                    // [2][128*36]
    float* Bs = sm + 2 * 128 * 36;     // [2][32*136]

    Desc d = d3;
    int bid = blockIdx.x;
    if (bid < d1.blk0) d = d0;
    else if (bid < d2.blk0) d = d1;
    else if (bid < d3.blk0) d = d2;
    int local = bid - d.blk0;
    int m0 = (local / d.nblk) * 128, n0 = (local % d.nblk) * 128;
    const int N = d.N, K = d.K;

    int tid = threadIdx.x;
    int warp = tid >> 5, lane = tid & 31;
    int g = lane >> 2, c = lane & 3;
    int wm = (warp >> 2) * 64;
    int wn = (warp & 3) * 32;

    float acc[4][4][4];
#pragma unroll
    for (int mt = 0; mt < 4; mt++)
#pragma unroll
        for (int nt = 0; nt < 4; nt++)
#pragma unroll
            for (int e = 0; e < 4; e++) acc[mt][nt][e] = 0.f;

    int nk = K >> 5;
    {
#pragma unroll
        for (int w = 0; w < 4; w++) {
            int idx = tid + w * 256;
            int r = idx >> 3, cc = (idx & 7) * 4;
            cp16(As + r * 36 + cc, d.A + (size_t)(m0 + r) * K + cc);
        }
#pragma unroll
        for (int w = 0; w < 4; w++) {
            int idx = tid + w * 256;
            int r = idx >> 5, cc = (idx & 31) * 4;
            cp16(Bs + r * 136 + cc, d.B + (size_t)r * N + n0 + cc);
        }
    }
    CP_COMMIT();

    for (int kt = 0; kt < nk; kt++) {
        int cur = kt & 1;
        if (kt + 1 < nk) {
            int nxt = (kt + 1) & 1;
            int k0 = (kt + 1) * 32;
#pragma unroll
            for (int w = 0; w < 4; w++) {
                int idx = tid + w * 256;
                int r = idx >> 3, cc = (idx & 7) * 4;
                cp16(As + nxt * 128 * 36 + r * 36 + cc,
                     d.A + (size_t)(m0 + r) * K + k0 + cc);
            }
#pragma unroll
            for (int w = 0; w < 4; w++) {
                int idx = tid + w * 256;
                int r = idx >> 5, cc = (idx & 31) * 4;
                cp16(Bs + nxt * 32 * 136 + r * 136 + cc,
                     d.B + (size_t)(k0 + r) * N + n0 + cc);
            }
        }
        CP_COMMIT();
        CP_WAIT1();
        __syncthreads();

        const float* Ac = As + cur * 128 * 36;
        const float* Bc = Bs + cur * 32 * 136;
#pragma unroll
        for (int kk = 0; kk < 4; kk++) {
            int k = kk * 8;
            uint32_t af[4][4], bf[4][2];
#pragma unroll
            for (int mt = 0; mt < 4; mt++) {
                const float* base = Ac + (wm + mt * 16 + g) * 36 + k + c;
                af[mt][0] = __float_as_uint(base[0]);
                af[mt][1] = __float_as_uint(base[8 * 36]);
                af[mt][2] = __float_as_uint(base[4]);
                af[mt][3] = __float_as_uint(base[8 * 36 + 4]);
            }
#pragma unroll
            for (int nt = 0; nt < 4; nt++) {
                const float* base = Bc + (k + c) * 136 + wn + nt * 8 + g;
                bf[nt][0] = __float_as_uint(base[0]);
                bf[nt][1] = __float_as_uint(base[4 * 136]);
            }
#pragma unroll
            for (int mt = 0; mt < 4; mt++)
#pragma unroll
                for (int nt = 0; nt < 4; nt++)
                    mma_tf32(acc[mt][nt], af[mt], bf[nt], acc[mt][nt]);
        }
        __syncthreads();
    }

#pragma unroll
    for (int mt = 0; mt < 4; mt++)
#pragma unroll
        for (int nt = 0; nt < 4; nt++) {
            int row = m0 + wm + mt * 16 + g;
            int col = n0 + wn + nt * 8 + c * 2;
            *(float2*)(d.C + (size_t)row * N + col) =
                make_float2(acc[mt][nt][0], acc[mt][nt][1]);
            *(float2*)(d.C + (size_t)(row + 8) * N + col) =
                make_float2(acc[mt][nt][2], acc[mt][nt][3]);
        }
}

// ============================================================================
// Pipelined tf32 GEMM, BN=64 (for W_o with residual add)
// ============================================================================
__global__ __launch_bounds__(256) void gemm64(
        const float* __restrict__ A, const float* __restrict__ B,
        const float* __restrict__ Cadd, float* __restrict__ C,
        int M, int N, int K) {
    extern __shared__ float sm[];
    const int BST = 72;
    float* As = sm;
    float* Bs = sm + 2 * 128 * 36;

    int m0 = blockIdx.y * 128, n0 = blockIdx.x * 64;
    int tid = threadIdx.x;
    int warp = tid >> 5, lane = tid & 31;
    int g = lane >> 2, c = lane & 3;
    int wm = (warp >> 2) * 64;
    int wn = (warp & 3) * 16;

    float acc[4][2][4];
#pragma unroll
    for (int mt = 0; mt < 4; mt++)
#pragma unroll
        for (int nt = 0; nt < 2; nt++)
#pragma unroll
            for (int e = 0; e < 4; e++) acc[mt][nt][e] = 0.f;

    int nk = K >> 5;
    {
#pragma unroll
        for (int w = 0; w < 4; w++) {
            int idx = tid + w * 256;
            int r = idx >> 3, cc = (idx & 7) * 4;
            cp16(As + r * 36 + cc, A + (size_t)(m0 + r) * K + cc);
        }
#pragma unroll
        for (int w = 0; w < 2; w++) {
            int idx = tid + w * 256;
            int r = idx >> 4, cc = (idx & 15) * 4;
            cp16(Bs + r * BST + cc, B + (size_t)r * N + n0 + cc);
        }
    }
    CP_COMMIT();

    for (int kt = 0; kt < nk; kt++) {
        int cur = kt & 1;
        if (kt + 1 < nk) {
            int nxt = (kt + 1) & 1;
            int k0 = (kt + 1) * 32;
#pragma unroll
            for (int w = 0; w < 4; w++) {
                int idx = tid + w * 256;
                int r = idx >> 3, cc = (idx & 7) * 4;
                cp16(As + nxt * 128 * 36 + r * 36 + cc,
                     A + (size_t)(m0 + r) * K + k0 + cc);
            }
#pragma unroll
            for (int w = 0; w < 2; w++) {
                int idx = tid + w * 256;
                int r = idx >> 4, cc = (idx & 15) * 4;
                cp16(Bs + nxt * 32 * BST + r * BST + cc,
                     B + (size_t)(k0 + r) * N + n0 + cc);
            }
        }
        CP_COMMIT();
        CP_WAIT1();
        __syncthreads();

        const float* Ac = As + cur * 128 * 36;
        const float* Bc = Bs + cur * 32 * BST;
#pragma unroll
        for (int kk = 0; kk < 4; kk++) {
            int k = kk * 8;
            uint32_t af[4][4], bf[2][2];
#pragma unroll
            for (int mt = 0; mt < 4; mt++) {
                const float* base = Ac + (wm + mt * 16 + g) * 36 + k + c;
                af[mt][0] = __float_as_uint(base[0]);
                af[mt][1] = __float_as_uint(base[8 * 36]);
                af[mt][2] = __float_as_uint(base[4]);
                af[mt][3] = __float_as_uint(base[8 * 36 + 4]);
            }
#pragma unroll
            for (int nt = 0; nt < 2; nt++) {
                const float* base = Bc + (k + c) * BST + wn + nt * 8 + g;
                bf[nt][0] = __float_as_uint(base[0]);
                bf[nt][1] = __float_as_uint(base[4 * BST]);
            }
#pragma unroll
            for (int mt = 0; mt < 4; mt++)
#pragma unroll
                for (int nt = 0; nt < 2; nt++)
                    mma_tf32(acc[mt][nt], af[mt], bf[nt], acc[mt][nt]);
        }
        __syncthreads();
    }

#pragma unroll
    for (int mt = 0; mt < 4; mt++)
#pragma unroll
        for (int nt = 0; nt < 2; nt++) {
            int row = m0 + wm + mt * 16 + g;
            int col = n0 + wn + nt * 8 + c * 2;
            float* p0 = C + (size_t)row * N + col;
            float* p1 = C + (size_t)(row + 8) * N + col;
            float2 v0 = make_float2(acc[mt][nt][0], acc[mt][nt][1]);
            float2 v1 = make_float2(acc[mt][nt][2], acc[mt][nt][3]);
            if (Cadd) {
                const float* a0 = Cadd + (size_t)row * N + col;
                const float* a1 = Cadd + (size_t)(row + 8) * N + col;
                v0.x += a0[0]; v0.y += a0[1];
                v1.x += a1[0]; v1.y += a1[1];
            }
            *(float2*)p0 = v0;
            *(float2*)p1 = v1;
        }
}

// ============================================================================
// Fused score kernel (merged AC/BD MMA loops for ILP)
// ============================================================================
__global__ __launch_bounds__(256, 1) void score_kernel(
        const float* __restrict__ Q, const float* __restrict__ pbu,
        const float* __restrict__ pbv, const float* __restrict__ KV,
        const float* __restrict__ REL, const float* __restrict__ ib,
        float* __restrict__ S) {
    extern __shared__ float sm[];
    float* qu_s  = sm;                    // [64][68]
    float* qv_s  = qu_s + 64 * 68;        // [64][68]
    float* k_s   = qv_s + 64 * 68;        // [128][68]
    float* rel_s = k_s + 128 * 68;        // [192][68]
    float* bd_s  = rel_s + 192 * 68;      // [64][200]

    int bn = blockIdx.z;
    int b = bn >> 3, n = bn & 7;
    int i0 = blockIdx.y * 64;
    int j0 = blockIdx.x * 128;
    int tid = threadIdx.x;
    int m0 = j0 + 448 - i0;

#pragma unroll
    for (int w = 0; w < 4; w++) {
        int idx = tid + w * 256;
        int r = idx >> 4, c4 = (idx & 15) * 4;
        float4 v = *(const float4*)(Q + (size_t)(i0 + r) * 2048 + b * 512 + n * 64 + c4);
        float4 bu = *(const float4*)(pbu + n * 64 + c4);
        float4 bv = *(const float4*)(pbv + n * 64 + c4);
        float* du = qu_s + r * 68 + c4;
        float* dv = qv_s + r * 68 + c4;
        du[0] = (v.x + bu.x) * SCALEF; du[1] = (v.y + bu.y) * SCALEF;
        du[2] = (v.z + bu.z) * SCALEF; du[3] = (v.w + bu.w) * SCALEF;
        dv[0] = (v.x + bv.x) * SCALEF; dv[1] = (v.y + bv.y) * SCALEF;
        dv[2] = (v.z + bv.z) * SCALEF; dv[3] = (v.w + bv.w) * SCALEF;
    }
#pragma unroll
    for (int w = 0; w < 8; w++) {
        int idx = tid + w * 256;
        int r = idx >> 4, c4 = (idx & 15) * 4;
        float4 v = *(const float4*)(KV + (size_t)(j0 + r) * 4096 + b * 1024 + n * 64 + c4);
        float* dst = k_s + r * 68 + c4;
        dst[0] = v.x; dst[1] = v.y; dst[2] = v.z; dst[3] = v.w;
    }
#pragma unroll
    for (int w = 0; w < 12; w++) {
        int idx = tid + w * 256;
        int r = idx >> 4, c4 = (idx & 15) * 4;
        int mr = m0 + r; if (mr > 2047) mr = 2047;
        float4 v = *(const float4*)(REL + (size_t)mr * 2048 + b * 512 + n * 64 + c4);
        float* dst = rel_s + r * 68 + c4;
        dst[0] = v.x; dst[1] = v.y; dst[2] = v.z; dst[3] = v.w;
    }
    __syncthreads();

    int warp = tid >> 5, lane = tid & 31;
    int g = lane >> 2, c = lane & 3;
    int wm  = (warp >> 2) * 32;
    int wnB = (warp & 3) * 48;
    int wnA = (warp & 3) * 32;

    float accb[2][6][4];
    float acca[2][4][4];
#pragma unroll
    for (int mt = 0; mt < 2; mt++) {
#pragma unroll
        for (int nt = 0; nt < 6; nt++)
#pragma unroll
            for (int e = 0; e < 4; e++) accb[mt][nt][e] = 0.f;
#pragma unroll
        for (int nt = 0; nt < 4; nt++)
#pragma unroll
            for (int e = 0; e < 4; e++) acca[mt][nt][e] = 0.f;
    }

#pragma unroll
    for (int kk = 0; kk < 8; kk++) {
        int k = kk * 8;
        uint32_t au[2][4], av[2][4], bk[4][2], br[6][2];
#pragma unroll
        for (int mt = 0; mt < 2; mt++) {
            const float* bu = qu_s + (wm + mt * 16 + g) * 68 + k + c;
            const float* bv = qv_s + (wm + mt * 16 + g) * 68 + k + c;
            au[mt][0] = __float_as_uint(bu[0]);
            au[mt][1] = __float_as_uint(bu[8 * 68]);
            au[mt][2] = __float_as_uint(bu[4]);
            au[mt][3] = __float_as_uint(bu[8 * 68 + 4]);
            av[mt][0] = __float_as_uint(bv[0]);
            av[mt][1] = __float_as_uint(bv[8 * 68]);
            av[mt][2] = __float_as_uint(bv[4]);
            av[mt][3] = __float_as_uint(bv[8 * 68 + 4]);
        }
#pragma unroll
        for (int nt = 0; nt < 4; nt++) {
            const float* base = k_s + (wnA + nt * 8 + g) * 68 + k + c;
            bk[nt][0] = __float_as_uint(base[0]);
            bk[nt][1] = __float_as_uint(base[4]);
        }
#pragma unroll
        for (int nt = 0; nt < 6; nt++) {
            const float* base = rel_s + (wnB + nt * 8 + g) * 68 + k + c;
            br[nt][0] = __float_as_uint(base[0]);
            br[nt][1] = __float_as_uint(base[4]);
        }
#pragma unroll
        for (int mt = 0; mt < 2; mt++) {
#pragma unroll
            for (int nt = 0; nt < 6; nt++)
                mma_tf32(accb[mt][nt], av[mt], br[nt], accb[mt][nt]);
#pragma unroll
            for (int nt = 0; nt < 4; nt++)
                mma_tf32(acca[mt][nt], au[mt], bk[nt], acca[mt][nt]);
        }
    }

    // stage BD band
#pragma unroll
    for (int mt = 0; mt < 2; mt++)
#pragma unroll
        for (int nt = 0; nt < 6; nt++) {
            int row = wm + mt * 16 + g;
            int col = wnB + nt * 8 + c * 2;
            bd_s[row * 200 + col]           = accb[mt][nt][0];
            bd_s[row * 200 + col + 1]       = accb[mt][nt][1];
            bd_s[(row + 8) * 200 + col]     = accb[mt][nt][2];
            bd_s[(row + 8) * 200 + col + 1] = accb[mt][nt][3];
        }
    __syncthreads();

    // epilogue: combine with shifted BD + gates, write S
    float* Sb = S + ((size_t)bn * 512 + i0) * 2048 + j0;
#pragma unroll
    for (int mt = 0; mt < 2; mt++)
#pragma unroll
        for (int nt = 0; nt < 4; nt++) {
#pragma unroll
            for (int half = 0; half < 2; half++) {
                int i_loc = wm + mt * 16 + g + half * 8;
                int i = i0 + i_loc;
                const float* gp = ib + ((size_t)i * 4 + b) * 4;
                float a0 = acca[mt][nt][half * 2];
                float a1 = acca[mt][nt][half * 2 + 1];
#pragma unroll
                for (int e = 0; e < 2; e++) {
                    int j_loc = wnA + nt * 8 + c * 2 + e;
                    int j = j0 + j_loc;
                    int m = j + 511 - i;
                    int segB = m >> 9; if (segB > 3) segB = 3;
                    float bd = bd_s[i_loc * 200 + (j_loc + 63 - i_loc)];
                    float ac = e ? a1 : a0;
                    Sb[(size_t)i_loc * 2048 + j_loc] =
                        gp[j >> 9] * ac + gp[segB] * bd;
                }
            }
        }
}

// ---------------- softmax: prob out fp16, attn_matrix inline ----------------
__global__ void softmax_kernel(const float* __restrict__ S, __half* __restrict__ P,
                               float* __restrict__ attn) {
    __shared__ float accv[2048];
    __shared__ float red[32];
    int i = blockIdx.x;
    int tid = threadIdx.x;
    for (int j = tid; j < 2048; j += 256) accv[j] = 0.f;
    __syncthreads();

    int jmax = 3 * Lq + i;

    for (int bn = 0; bn < 32; bn++) {
        const float* srow = S + ((size_t)bn * 512 + i) * 2048;
        __half* prow = P + ((size_t)bn * 512 + i) * 2048;

        float s[8];
        float mx = -1e30f;
#pragma unroll
        for (int t = 0; t < 8; t++) {
            int j = tid + t * 256;
            if (j <= jmax) {
                float v = srow[j];
                s[t] = v;
                mx = fmaxf(mx, v);
            } else {
                s[t] = -1e30f;
            }
        }
        mx = blockRedMax(mx, red);

        float p[8];
        float sum = 0.f;
#pragma unroll
        for (int t = 0; t < 8; t++) {
            p[t] = (s[t] > -1e29f) ? __expf(s[t] - mx) : 0.f;
            sum += p[t];
        }
        sum = blockRedSum(sum, red);
        float inv = 1.f / sum;
#pragma unroll
        for (int t = 0; t < 8; t++) {
            int j = tid + t * 256;
            float pp = p[t] * inv;
            prow[j] = __float2half_rn(pp);
            accv[j] += pp;
        }
        __syncthreads();
    }

    const float invBN = 1.f / 32.f;
    for (int j = tid; j < 2048; j += 256)
        attn[(size_t)i * 2048 + j] = accv[j] * invBN;
}

// ============================================================================
// Batched prob(fp16) @ V : fp16 MMA m16n8k16, fp32 accum.
// vec[((i)*4+b)*512 + n*64 + d] = sum_j P[bn][i][j] * V[j*4096+b*1024+512+n*64+d]
// ============================================================================
__global__ __launch_bounds__(256) void pv_fp16(const __half* __restrict__ P,
                                               const float* __restrict__ KV,
                                               float* __restrict__ vec) {
    __shared__ __half As[128 * 40];   // P tile: 128 i x 32 j (stride 40)
    __shared__ __half VsT[64 * 40];   // V tile transposed: 64 d x 32 j

    int bn = blockIdx.y;
    int b = bn >> 3, n = bn & 7;
    int i0 = blockIdx.x * 128;
    int tid = threadIdx.x;
    int warp = tid >> 5, lane = tid & 31;
    int g = lane >> 2, c = lane & 3;
    int wm = (warp >> 1) * 32;   // 4 warps in m
    int wn = (warp & 1) * 32;    // 2 warps in n

    const __half* Pb = P + ((size_t)bn * 512 + i0) * 2048;
    const float* Vb = KV + b * 1024 + 512 + n * 64;

    float acc[2][4][4];
#pragma unroll
    for (int mt = 0; mt < 2; mt++)
#pragma unroll
        for (int nt = 0; nt < 4; nt++)
#pragma unroll
            for (int e = 0; e < 4; e++) acc[mt][nt][e] = 0.f;

    for (int k0 = 0; k0 < 2048; k0 += 32) {
        // P tile: 128 rows x 32 halves = 512 uint4
#pragma unroll
        for (int w = 0; w < 2; w++) {
            int idx = tid + w * 256;
            int r = idx >> 2, c8 = (idx & 3) * 8;
            uint4 v = *(const uint4*)(Pb + (size_t)r * 2048 + k0 + c8);
            *(uint4*)(As + r * 40 + c8) = v;
        }
        // V tile: 32 j x 64 d floats -> fp16 transposed
#pragma unroll
        for (int w = 0; w < 2; w++) {
            int idx = tid + w * 256;
            int r = idx >> 4, cd = (idx & 15) * 4;
            float4 v = *(const float4*)(Vb + (size_t)(k0 + r) * 4096 + cd);
            VsT[(cd + 0) * 40 + r] = __float2half_rn(v.x);
            VsT[(cd + 1) * 40 + r] = __float2half_rn(v.y);
            VsT[(cd + 2) * 40 + r] = __float2half_rn(v.z);
            VsT[(cd + 3) * 40 + r] = __float2half_rn(v.w);
        }
        __syncthreads();

#pragma unroll
        for (int kk = 0; kk < 2; kk++) {
            int k = kk * 16;
            uint32_t af[2][4], bf[4][2];
#pragma unroll
            for (int mt = 0; mt < 2; mt++) {
                const __half* base = As + (wm + mt * 16 + g) * 40 + k + c * 2;
                af[mt][0] = *(const uint32_t*)(base);
                af[mt][1] = *(const uint32_t*)(base + 8 * 40);
                af[mt][2] = *(const uint32_t*)(base + 8);
                af[mt][3] = *(const uint32_t*)(base + 8 * 40 + 8);
            }
#pragma unroll
            for (int nt = 0; nt < 4; nt++) {
                const __half* base = VsT + (wn + nt * 8 + g) * 40 + k + c * 2;
                bf[nt][0] = *(const uint32_t*)(base);
                bf[nt][1] = *(const uint32_t*)(base + 8);
            }
#pragma unroll
            for (int mt = 0; mt < 2; mt++)
#pragma unroll
                for (int nt = 0; nt < 4; nt++)
                    mma_f16(acc[mt][nt], af[mt], bf[nt], acc[mt][nt]);
        }
        __syncthreads();
    }

#pragma unroll
    for (int mt = 0; mt < 2; mt++)
#pragma unroll
        for (int nt = 0; nt < 4; nt++) {
            int row = wm + mt * 16 + g;
            int col = wn + nt * 8 + c * 2;
            float* d0 = vec + ((size_t)(i0 + row) * 4 + b) * 512 + n * 64 + col;
            float* d1 = vec + ((size_t)(i0 + row + 8) * 4 + b) * 512 + n * 64 + col;
            *(float2*)d0 = make_float2(acc[mt][nt][0], acc[mt][nt][1]);
            *(float2*)d1 = make_float2(acc[mt][nt][2], acc[mt][nt][3]);
        }
}

// ---------------- layernorm ----------------
__global__ void ln_kernel(const float* __restrict__ y, const float* __restrict__ g,
                          const float* __restrict__ be, float* __restrict__ out) {
    __shared__ float red[32];
    int r = blockIdx.x;
    int tid = threadIdx.x;
    float v0 = y[(size_t)r * 512 + tid];
    float v1 = y[(size_t)r * 512 + tid + 256];
    float mean = blockRedSum(v0 + v1, red) * (1.f / 512.f);
    float d0 = v0 - mean, d1 = v1 - mean;
    float var = blockRedSum(d0 * d0 + d1 * d1, red) * (1.f / 512.f);
    float rstd = rsqrtf(var + 1e-5f);
    out[(size_t)r * 512 + tid]       = d0 * rstd * g[tid] + be[tid];
    out[(size_t)r * 512 + tid + 256] = d1 * rstd * g[tid + 256] + be[tid + 256];
}

// ---------------- launch ----------------
#define SMEM_G128 ((2 * 128 * 36 + 2 * 32 * 136) * 4)   // 71680
#define SMEM_G64  ((2 * 128 * 36 + 2 * 32 * 72) * 4)    // 55296
#define SMEM_SC   ((64*68 + 64*68 + 128*68 + 192*68 + 64*200) * 4)  // 173056

extern "C" void kernel_launch(void* const* d_in, const int* in_sizes, int n_in,
                              void* d_out, int out_size) {
    (void)in_sizes; (void)n_in; (void)out_size;
    const float* x       = (const float*)d_in[0];
    const float* memory  = (const float*)d_in[1];
    const float* pos_emb = (const float*)d_in[2];
    const float* pbu     = (const float*)d_in[3];
    const float* pbv     = (const float*)d_in[4];
    const float* ib      = (const float*)d_in[6];
    const float* W_q     = (const float*)d_in[7];
    const float* W_kv    = (const float*)d_in[8];
    const float* W_rel   = (const float*)d_in[9];
    const float* W_o     = (const float*)d_in[10];
    const float* ln_g    = (const float*)d_in[11];
    const float* ln_b    = (const float*)d_in[12];

    float* out  = (float*)d_out;
    float* attn = out + (size_t)Lq * BATCH * 512;

    float *kv, *rel, *q, *sc, *vec, *y;
    __half* prob;
    cudaGetSymbolAddress((void**)&kv,   g_kv);
    cudaGetSymbolAddress((void**)&rel,  g_rel);
    cudaGetSymbolAddress((void**)&q,    g_q);
    cudaGetSymbolAddress((void**)&sc,   g_sc);
    cudaGetSymbolAddress((void**)&prob, g_prob);
    cudaGetSymbolAddress((void**)&vec,  g_vec);
    cudaGetSymbolAddress((void**)&y,    g_y);

    static bool attr_set = false;
    if (!attr_set) {
        cudaFuncSetAttribute(proj_multi,
                             cudaFuncAttributeMaxDynamicSharedMemorySize, SMEM_G128);
        cudaFuncSetAttribute(gemm64,
                             cudaFuncAttributeMaxDynamicSharedMemorySize, SMEM_G64);
        cudaFuncSetAttribute(score_kernel,
                             cudaFuncAttributeMaxDynamicSharedMemorySize, SMEM_SC);
        attr_set = true;
    }

    // 1) all 4 projections in one launch
    // kv:   memory[6144,512] @ W_kv[512,1024]   -> 48x8 = 384 blocks, blk0 0
    // xkv:  x[2048,512] @ W_kv                  -> 16x8 = 128 blocks, blk0 384
    // rel:  pos_emb[8192,512] @ W_rel[512,512]  -> 64x4 = 256 blocks, blk0 512
    // q:    x[2048,512] @ W_q[512,512]          -> 16x4 =  64 blocks, blk0 768
    Desc d0 = { memory,  W_kv,  kv,                        1024, 512, 8, 0 };
    Desc d1 = { x,       W_kv,  kv + (size_t)6144 * 1024,  1024, 512, 8, 384 };
    Desc d2 = { pos_emb, W_rel, rel,                       512,  512, 4, 512 };
    Desc d3 = { x,       W_q,   q,                         512,  512, 4, 768 };
    proj_multi<<<832, 256, SMEM_G128>>>(d0, d1, d2, d3);

    // 2) fused scores (AC + shifted BD + gates + scale)
    score_kernel<<<dim3(16, 8, 32), 256, SMEM_SC>>>(q, pbu, pbv, kv, rel, ib, sc);

    // 3) masked softmax -> prob (fp16) + attn_matrix
    softmax_kernel<<<512, 256>>>(sc, prob, attn);

    // 4) vec = prob @ v (fp16 MMA)
    pv_fp16<<<dim3(4, 32), 256>>>(prob, kv, vec);

    // 5) y = x + vec @ W_o ; layernorm
    gemm64<<<dim3(8, 16), 256, SMEM_G64>>>(vec, W_o, x, y, 2048, 512, 512);
    ln_kernel<<<2048, 256>>>(y, ln_g, ln_b, out);
}

// round 5
// speedup vs baseline: 3.3770x; 1.1905x over previous
#include <cuda_runtime.h>
#include <cuda_fp16.h>
#include <stdint.h>

// Problem constants
#define Lq     512
#define BATCH  4
#define SCALEF 0.125f
#define ROWS_X (Lq * BATCH)
#define ROWS_C (2048 * BATCH)

// ---------------- scratch ----------------
__device__ float  g_kv  [(size_t)ROWS_C * 1024];        // 32 MB  k | v
__device__ float  g_rel [(size_t)ROWS_C * 512];         // 16 MB
__device__ float  g_q   [(size_t)ROWS_X * 512];         //  4 MB
__device__ float  g_sc  [(size_t)32 * 512 * 2048];      // 128 MB raw scores
__device__ __half g_prob[(size_t)32 * 512 * 2048];      // 64 MB prob (fp16)
__device__ float  g_vec [(size_t)ROWS_X * 512];         //  4 MB
__device__ float  g_y   [(size_t)ROWS_X * 512];         //  4 MB

// ---------------- helpers ----------------
__device__ __forceinline__ void mma_tf32(float* d, const uint32_t* a,
                                         const uint32_t* b, const float* c) {
    asm volatile(
        "mma.sync.aligned.m16n8k8.row.col.f32.tf32.tf32.f32 "
        "{%0,%1,%2,%3}, {%4,%5,%6,%7}, {%8,%9}, {%10,%11,%12,%13};"
        : "=f"(d[0]), "=f"(d[1]), "=f"(d[2]), "=f"(d[3])
        : "r"(a[0]), "r"(a[1]), "r"(a[2]), "r"(a[3]),
          "r"(b[0]), "r"(b[1]),
          "f"(c[0]), "f"(c[1]), "f"(c[2]), "f"(c[3]));
}

__device__ __forceinline__ void mma_f16(float* d, const uint32_t* a,
                                        const uint32_t* b, const float* c) {
    asm volatile(
        "mma.sync.aligned.m16n8k16.row.col.f32.f16.f16.f32 "
        "{%0,%1,%2,%3}, {%4,%5,%6,%7}, {%8,%9}, {%10,%11,%12,%13};"
        : "=f"(d[0]), "=f"(d[1]), "=f"(d[2]), "=f"(d[3])
        : "r"(a[0]), "r"(a[1]), "r"(a[2]), "r"(a[3]),
          "r"(b[0]), "r"(b[1]),
          "f"(c[0]), "f"(c[1]), "f"(c[2]), "f"(c[3]));
}

__device__ __forceinline__ void cp16(float* dst, const float* src) {
    uint32_t d = (uint32_t)__cvta_generic_to_shared(dst);
    asm volatile("cp.async.cg.shared.global [%0], [%1], 16;" :: "r"(d), "l"(src));
}
__device__ __forceinline__ void cp16g(void* dst, const void* src) {
    uint32_t d = (uint32_t)__cvta_generic_to_shared(dst);
    asm volatile("cp.async.cg.shared.global [%0], [%1], 16;" :: "r"(d), "l"(src));
}
#define CP_COMMIT() asm volatile("cp.async.commit_group;")
#define CP_WAIT1()  asm volatile("cp.async.wait_group 1;")

__device__ __forceinline__ uint32_t packh2(float x, float y) {
    __half2 h = __floats2half2_rn(x, y);
    return *(uint32_t*)&h;
}

__device__ __forceinline__ float warpRedMax(float v) {
#pragma unroll
    for (int o = 16; o > 0; o >>= 1) v = fmaxf(v, __shfl_xor_sync(0xffffffffu, v, o));
    return v;
}
__device__ __forceinline__ float warpRedSum(float v) {
#pragma unroll
    for (int o = 16; o > 0; o >>= 1) v += __shfl_xor_sync(0xffffffffu, v, o);
    return v;
}
// paired block reductions: warp0 reduces a, warp1 reduces b; red has 64 slots
__device__ __forceinline__ float2 blockRedMax2(float a, float b, float* red) {
    a = warpRedMax(a); b = warpRedMax(b);
    int w = threadIdx.x >> 5, l = threadIdx.x & 31;
    if (!l) { red[w] = a; red[32 + w] = b; }
    __syncthreads();
    if (threadIdx.x < 64) {
        int wi = threadIdx.x >> 5;
        float x = (l < 8) ? red[wi * 32 + l] : -1e30f;
        x = warpRedMax(x);
        if (!l) red[wi * 32] = x;
    }
    __syncthreads();
    float2 r = make_float2(red[0], red[32]);
    __syncthreads();
    return r;
}
__device__ __forceinline__ float2 blockRedSum2(float a, float b, float* red) {
    a = warpRedSum(a); b = warpRedSum(b);
    int w = threadIdx.x >> 5, l = threadIdx.x & 31;
    if (!l) { red[w] = a; red[32 + w] = b; }
    __syncthreads();
    if (threadIdx.x < 64) {
        int wi = threadIdx.x >> 5;
        float x = (l < 8) ? red[wi * 32 + l] : 0.f;
        x = warpRedSum(x);
        if (!l) red[wi * 32] = x;
    }
    __syncthreads();
    float2 r = make_float2(red[0], red[32]);
    __syncthreads();
    return r;
}
__device__ __forceinline__ float blockRedSum(float v, float* red) {
    v = warpRedSum(v);
    int w = threadIdx.x >> 5, l = threadIdx.x & 31;
    if (!l) red[w] = v;
    __syncthreads();
    if (threadIdx.x < 32) {
        float x = (l < 8) ? red[l] : 0.f;
        x = warpRedSum(x);
        if (!l) red[0] = x;
    }
    __syncthreads();
    float r = red[0];
    __syncthreads();
    return r;
}

// ============================================================================
// Combined projection kernel (4 GEMMs, one launch). tf32, 2-stage cp.async.
// ============================================================================
struct Desc {
    const float* A; const float* B; float* C;
    int N, K, nblk, blk0;
};

__global__ __launch_bounds__(256) void proj_multi(Desc d0, Desc d1, Desc d2, Desc d3) {
    extern __shared__ float sm[];
    float* As = sm;                    // [2][128*36]
    float* Bs = sm + 2 * 128 * 36;     // [2][32*136]

    Desc d = d3;
    int bid = blockIdx.x;
    if (bid < d1.blk0) d = d0;
    else if (bid < d2.blk0) d = d1;
    else if (bid < d3.blk0) d = d2;
    int local = bid - d.blk0;
    int m0 = (local / d.nblk) * 128, n0 = (local % d.nblk) * 128;
    const int N = d.N, K = d.K;

    int tid = threadIdx.x;
    int warp = tid >> 5, lane = tid & 31;
    int g = lane >> 2, c = lane & 3;
    int wm = (warp >> 2) * 64;
    int wn = (warp & 3) * 32;

    float acc[4][4][4];
#pragma unroll
    for (int mt = 0; mt < 4; mt++)
#pragma unroll
        for (int nt = 0; nt < 4; nt++)
#pragma unroll
            for (int e = 0; e < 4; e++) acc[mt][nt][e] = 0.f;

    int nk = K >> 5;
    {
#pragma unroll
        for (int w = 0; w < 4; w++) {
            int idx = tid + w * 256;
            int r = idx >> 3, cc = (idx & 7) * 4;
            cp16(As + r * 36 + cc, d.A + (size_t)(m0 + r) * K + cc);
        }
#pragma unroll
        for (int w = 0; w < 4; w++) {
            int idx = tid + w * 256;
            int r = idx >> 5, cc = (idx & 31) * 4;
            cp16(Bs + r * 136 + cc, d.B + (size_t)r * N + n0 + cc);
        }
    }
    CP_COMMIT();

    for (int kt = 0; kt < nk; kt++) {
        int cur = kt & 1;
        if (kt + 1 < nk) {
            int nxt = (kt + 1) & 1;
            int k0 = (kt + 1) * 32;
#pragma unroll
            for (int w = 0; w < 4; w++) {
                int idx = tid + w * 256;
                int r = idx >> 3, cc = (idx & 7) * 4;
                cp16(As + nxt * 128 * 36 + r * 36 + cc,
                     d.A + (size_t)(m0 + r) * K + k0 + cc);
            }
#pragma unroll
            for (int w = 0; w < 4; w++) {
                int idx = tid + w * 256;
                int r = idx >> 5, cc = (idx & 31) * 4;
                cp16(Bs + nxt * 32 * 136 + r * 136 + cc,
                     d.B + (size_t)(k0 + r) * N + n0 + cc);
            }
        }
        CP_COMMIT();
        CP_WAIT1();
        __syncthreads();

        const float* Ac = As + cur * 128 * 36;
        const float* Bc = Bs + cur * 32 * 136;
#pragma unroll
        for (int kk = 0; kk < 4; kk++) {
            int k = kk * 8;
            uint32_t af[4][4], bf[4][2];
#pragma unroll
            for (int mt = 0; mt < 4; mt++) {
                const float* base = Ac + (wm + mt * 16 + g) * 36 + k + c;
                af[mt][0] = __float_as_uint(base[0]);
                af[mt][1] = __float_as_uint(base[8 * 36]);
                af[mt][2] = __float_as_uint(base[4]);
                af[mt][3] = __float_as_uint(base[8 * 36 + 4]);
            }
#pragma unroll
            for (int nt = 0; nt < 4; nt++) {
                const float* base = Bc + (k + c) * 136 + wn + nt * 8 + g;
                bf[nt][0] = __float_as_uint(base[0]);
                bf[nt][1] = __float_as_uint(base[4 * 136]);
            }
#pragma unroll
            for (int mt = 0; mt < 4; mt++)
#pragma unroll
                for (int nt = 0; nt < 4; nt++)
                    mma_tf32(acc[mt][nt], af[mt], bf[nt], acc[mt][nt]);
        }
        __syncthreads();
    }

#pragma unroll
    for (int mt = 0; mt < 4; mt++)
#pragma unroll
        for (int nt = 0; nt < 4; nt++) {
            int row = m0 + wm + mt * 16 + g;
            int col = n0 + wn + nt * 8 + c * 2;
            *(float2*)(d.C + (size_t)row * N + col) =
                make_float2(acc[mt][nt][0], acc[mt][nt][1]);
            *(float2*)(d.C + (size_t)(row + 8) * N + col) =
                make_float2(acc[mt][nt][2], acc[mt][nt][3]);
        }
}

// ============================================================================
// Pipelined tf32 GEMM, BN=64 (for W_o with residual add)
// ============================================================================
__global__ __launch_bounds__(256) void gemm64(
        const float* __restrict__ A, const float* __restrict__ B,
        const float* __restrict__ Cadd, float* __restrict__ C,
        int M, int N, int K) {
    extern __shared__ float sm[];
    const int BST = 72;
    float* As = sm;
    float* Bs = sm + 2 * 128 * 36;

    int m0 = blockIdx.y * 128, n0 = blockIdx.x * 64;
    int tid = threadIdx.x;
    int warp = tid >> 5, lane = tid & 31;
    int g = lane >> 2, c = lane & 3;
    int wm = (warp >> 2) * 64;
    int wn = (warp & 3) * 16;

    float acc[4][2][4];
#pragma unroll
    for (int mt = 0; mt < 4; mt++)
#pragma unroll
        for (int nt = 0; nt < 2; nt++)
#pragma unroll
            for (int e = 0; e < 4; e++) acc[mt][nt][e] = 0.f;

    int nk = K >> 5;
    {
#pragma unroll
        for (int w = 0; w < 4; w++) {
            int idx = tid + w * 256;
            int r = idx >> 3, cc = (idx & 7) * 4;
            cp16(As + r * 36 + cc, A + (size_t)(m0 + r) * K + cc);
        }
#pragma unroll
        for (int w = 0; w < 2; w++) {
            int idx = tid + w * 256;
            int r = idx >> 4, cc = (idx & 15) * 4;
            cp16(Bs + r * BST + cc, B + (size_t)r * N + n0 + cc);
        }
    }
    CP_COMMIT();

    for (int kt = 0; kt < nk; kt++) {
        int cur = kt & 1;
        if (kt + 1 < nk) {
            int nxt = (kt + 1) & 1;
            int k0 = (kt + 1) * 32;
#pragma unroll
            for (int w = 0; w < 4; w++) {
                int idx = tid + w * 256;
                int r = idx >> 3, cc = (idx & 7) * 4;
                cp16(As + nxt * 128 * 36 + r * 36 + cc,
                     A + (size_t)(m0 + r) * K + k0 + cc);
            }
#pragma unroll
            for (int w = 0; w < 2; w++) {
                int idx = tid + w * 256;
                int r = idx >> 4, cc = (idx & 15) * 4;
                cp16(Bs + nxt * 32 * BST + r * BST + cc,
                     B + (size_t)(k0 + r) * N + n0 + cc);
            }
        }
        CP_COMMIT();
        CP_WAIT1();
        __syncthreads();

        const float* Ac = As + cur * 128 * 36;
        const float* Bc = Bs + cur * 32 * BST;
#pragma unroll
        for (int kk = 0; kk < 4; kk++) {
            int k = kk * 8;
            uint32_t af[4][4], bf[2][2];
#pragma unroll
            for (int mt = 0; mt < 4; mt++) {
                const float* base = Ac + (wm + mt * 16 + g) * 36 + k + c;
                af[mt][0] = __float_as_uint(base[0]);
                af[mt][1] = __float_as_uint(base[8 * 36]);
                af[mt][2] = __float_as_uint(base[4]);
                af[mt][3] = __float_as_uint(base[8 * 36 + 4]);
            }
#pragma unroll
            for (int nt = 0; nt < 2; nt++) {
                const float* base = Bc + (k + c) * BST + wn + nt * 8 + g;
                bf[nt][0] = __float_as_uint(base[0]);
                bf[nt][1] = __float_as_uint(base[4 * BST]);
            }
#pragma unroll
            for (int mt = 0; mt < 4; mt++)
#pragma unroll
                for (int nt = 0; nt < 2; nt++)
                    mma_tf32(acc[mt][nt], af[mt], bf[nt], acc[mt][nt]);
        }
        __syncthreads();
    }

#pragma unroll
    for (int mt = 0; mt < 4; mt++)
#pragma unroll
        for (int nt = 0; nt < 2; nt++) {
            int row = m0 + wm + mt * 16 + g;
            int col = n0 + wn + nt * 8 + c * 2;
            float* p0 = C + (size_t)row * N + col;
            float* p1 = C + (size_t)(row + 8) * N + col;
            float2 v0 = make_float2(acc[mt][nt][0], acc[mt][nt][1]);
            float2 v1 = make_float2(acc[mt][nt][2], acc[mt][nt][3]);
            if (Cadd) {
                const float* a0 = Cadd + (size_t)row * N + col;
                const float* a1 = Cadd + (size_t)(row + 8) * N + col;
                v0.x += a0[0]; v0.y += a0[1];
                v1.x += a1[0]; v1.y += a1[1];
            }
            *(float2*)p0 = v0;
            *(float2*)p1 = v1;
        }
}

// ============================================================================
// Fused score kernel (merged AC/BD MMA loops for ILP)
// ============================================================================
__global__ __launch_bounds__(256, 1) void score_kernel(
        const float* __restrict__ Q, const float* __restrict__ pbu,
        const float* __restrict__ pbv, const float* __restrict__ KV,
        const float* __restrict__ REL, const float* __restrict__ ib,
        float* __restrict__ S) {
    extern __shared__ float sm[];
    float* qu_s  = sm;                    // [64][68]
    float* qv_s  = qu_s + 64 * 68;        // [64][68]
    float* k_s   = qv_s + 64 * 68;        // [128][68]
    float* rel_s = k_s + 128 * 68;        // [192][68]
    float* bd_s  = rel_s + 192 * 68;      // [64][200]

    int bn = blockIdx.z;
    int b = bn >> 3, n = bn & 7;
    int i0 = blockIdx.y * 64;
    int j0 = blockIdx.x * 128;
    int tid = threadIdx.x;
    int m0 = j0 + 448 - i0;

#pragma unroll
    for (int w = 0; w < 4; w++) {
        int idx = tid + w * 256;
        int r = idx >> 4, c4 = (idx & 15) * 4;
        float4 v = *(const float4*)(Q + (size_t)(i0 + r) * 2048 + b * 512 + n * 64 + c4);
        float4 bu = *(const float4*)(pbu + n * 64 + c4);
        float4 bv = *(const float4*)(pbv + n * 64 + c4);
        float* du = qu_s + r * 68 + c4;
        float* dv = qv_s + r * 68 + c4;
        du[0] = (v.x + bu.x) * SCALEF; du[1] = (v.y + bu.y) * SCALEF;
        du[2] = (v.z + bu.z) * SCALEF; du[3] = (v.w + bu.w) * SCALEF;
        dv[0] = (v.x + bv.x) * SCALEF; dv[1] = (v.y + bv.y) * SCALEF;
        dv[2] = (v.z + bv.z) * SCALEF; dv[3] = (v.w + bv.w) * SCALEF;
    }
#pragma unroll
    for (int w = 0; w < 8; w++) {
        int idx = tid + w * 256;
        int r = idx >> 4, c4 = (idx & 15) * 4;
        float4 v = *(const float4*)(KV + (size_t)(j0 + r) * 4096 + b * 1024 + n * 64 + c4);
        float* dst = k_s + r * 68 + c4;
        dst[0] = v.x; dst[1] = v.y; dst[2] = v.z; dst[3] = v.w;
    }
#pragma unroll
    for (int w = 0; w < 12; w++) {
        int idx = tid + w * 256;
        int r = idx >> 4, c4 = (idx & 15) * 4;
        int mr = m0 + r; if (mr > 2047) mr = 2047;
        float4 v = *(const float4*)(REL + (size_t)mr * 2048 + b * 512 + n * 64 + c4);
        float* dst = rel_s + r * 68 + c4;
        dst[0] = v.x; dst[1] = v.y; dst[2] = v.z; dst[3] = v.w;
    }
    __syncthreads();

    int warp = tid >> 5, lane = tid & 31;
    int g = lane >> 2, c = lane & 3;
    int wm  = (warp >> 2) * 32;
    int wnB = (warp & 3) * 48;
    int wnA = (warp & 3) * 32;

    float accb[2][6][4];
    float acca[2][4][4];
#pragma unroll
    for (int mt = 0; mt < 2; mt++) {
#pragma unroll
        for (int nt = 0; nt < 6; nt++)
#pragma unroll
            for (int e = 0; e < 4; e++) accb[mt][nt][e] = 0.f;
#pragma unroll
        for (int nt = 0; nt < 4; nt++)
#pragma unroll
            for (int e = 0; e < 4; e++) acca[mt][nt][e] = 0.f;
    }

#pragma unroll
    for (int kk = 0; kk < 8; kk++) {
        int k = kk * 8;
        uint32_t au[2][4], av[2][4], bk[4][2], br[6][2];
#pragma unroll
        for (int mt = 0; mt < 2; mt++) {
            const float* bu = qu_s + (wm + mt * 16 + g) * 68 + k + c;
            const float* bv = qv_s + (wm + mt * 16 + g) * 68 + k + c;
            au[mt][0] = __float_as_uint(bu[0]);
            au[mt][1] = __float_as_uint(bu[8 * 68]);
            au[mt][2] = __float_as_uint(bu[4]);
            au[mt][3] = __float_as_uint(bu[8 * 68 + 4]);
            av[mt][0] = __float_as_uint(bv[0]);
            av[mt][1] = __float_as_uint(bv[8 * 68]);
            av[mt][2] = __float_as_uint(bv[4]);
            av[mt][3] = __float_as_uint(bv[8 * 68 + 4]);
        }
#pragma unroll
        for (int nt = 0; nt < 4; nt++) {
            const float* base = k_s + (wnA + nt * 8 + g) * 68 + k + c;
            bk[nt][0] = __float_as_uint(base[0]);
            bk[nt][1] = __float_as_uint(base[4]);
        }
#pragma unroll
        for (int nt = 0; nt < 6; nt++) {
            const float* base = rel_s + (wnB + nt * 8 + g) * 68 + k + c;
            br[nt][0] = __float_as_uint(base[0]);
            br[nt][1] = __float_as_uint(base[4]);
        }
#pragma unroll
        for (int mt = 0; mt < 2; mt++) {
#pragma unroll
            for (int nt = 0; nt < 6; nt++)
                mma_tf32(accb[mt][nt], av[mt], br[nt], accb[mt][nt]);
#pragma unroll
            for (int nt = 0; nt < 4; nt++)
                mma_tf32(acca[mt][nt], au[mt], bk[nt], acca[mt][nt]);
        }
    }

#pragma unroll
    for (int mt = 0; mt < 2; mt++)
#pragma unroll
        for (int nt = 0; nt < 6; nt++) {
            int row = wm + mt * 16 + g;
            int col = wnB + nt * 8 + c * 2;
            bd_s[row * 200 + col]           = accb[mt][nt][0];
            bd_s[row * 200 + col + 1]       = accb[mt][nt][1];
            bd_s[(row + 8) * 200 + col]     = accb[mt][nt][2];
            bd_s[(row + 8) * 200 + col + 1] = accb[mt][nt][3];
        }
    __syncthreads();

    float* Sb = S + ((size_t)bn * 512 + i0) * 2048 + j0;
#pragma unroll
    for (int mt = 0; mt < 2; mt++)
#pragma unroll
        for (int nt = 0; nt < 4; nt++) {
#pragma unroll
            for (int half = 0; half < 2; half++) {
                int i_loc = wm + mt * 16 + g + half * 8;
                int i = i0 + i_loc;
                const float* gp = ib + ((size_t)i * 4 + b) * 4;
                float a0 = acca[mt][nt][half * 2];
                float a1 = acca[mt][nt][half * 2 + 1];
#pragma unroll
                for (int e = 0; e < 2; e++) {
                    int j_loc = wnA + nt * 8 + c * 2 + e;
                    int j = j0 + j_loc;
                    int m = j + 511 - i;
                    int segB = m >> 9; if (segB > 3) segB = 3;
                    float bd = bd_s[i_loc * 200 + (j_loc + 63 - i_loc)];
                    float ac = e ? a1 : a0;
                    Sb[(size_t)i_loc * 2048 + j_loc] =
                        gp[j >> 9] * ac + gp[segB] * bd;
                }
            }
        }
}

// ---------------- softmax: 2 bn-rows/iter, paired reductions ----------------
__global__ void softmax_kernel(const float* __restrict__ S, __half* __restrict__ P,
                               float* __restrict__ attn) {
    __shared__ float accv[2048];
    __shared__ float red[64];
    int i = blockIdx.x;
    int tid = threadIdx.x;
    for (int j = tid; j < 2048; j += 256) accv[j] = 0.f;
    __syncthreads();

    int jmax = 3 * Lq + i;

    for (int bn = 0; bn < 32; bn += 2) {
        const float* srow0 = S + ((size_t)bn * 512 + i) * 2048;
        const float* srow1 = srow0 + (size_t)512 * 2048;
        __half* prow0 = P + ((size_t)bn * 512 + i) * 2048;
        __half* prow1 = prow0 + (size_t)512 * 2048;

        float s0[8], s1[8];
        float mx0 = -1e30f, mx1 = -1e30f;
#pragma unroll
        for (int t = 0; t < 8; t++) {
            int j = tid + t * 256;
            if (j <= jmax) {
                s0[t] = srow0[j];
                s1[t] = srow1[j];
                mx0 = fmaxf(mx0, s0[t]);
                mx1 = fmaxf(mx1, s1[t]);
            } else {
                s0[t] = -1e30f;
                s1[t] = -1e30f;
            }
        }
        float2 mx = blockRedMax2(mx0, mx1, red);

        float p0[8], p1[8];
        float sum0 = 0.f, sum1 = 0.f;
#pragma unroll
        for (int t = 0; t < 8; t++) {
            p0[t] = (s0[t] > -1e29f) ? __expf(s0[t] - mx.x) : 0.f;
            p1[t] = (s1[t] > -1e29f) ? __expf(s1[t] - mx.y) : 0.f;
            sum0 += p0[t];
            sum1 += p1[t];
        }
        float2 sum = blockRedSum2(sum0, sum1, red);
        float inv0 = 1.f / sum.x, inv1 = 1.f / sum.y;
#pragma unroll
        for (int t = 0; t < 8; t++) {
            int j = tid + t * 256;
            float pp0 = p0[t] * inv0;
            float pp1 = p1[t] * inv1;
            prow0[j] = __float2half_rn(pp0);
            prow1[j] = __float2half_rn(pp1);
            accv[j] += pp0 + pp1;
        }
        __syncthreads();
    }

    const float invBN = 1.f / 32.f;
    for (int j = tid; j < 2048; j += 256)
        attn[(size_t)i * 2048 + j] = accv[j] * invBN;
}

// ============================================================================
// Batched prob(fp16) @ V : 64x64 tile, BK=64, 2-stage cp.async pipeline.
// A = P fp16 [i][j]; B = V fp32 [j][d] in smem, converted to half in regs.
// vec[((i)*4+b)*512 + n*64 + d] = sum_j P[bn][i][j] * V[j*4096+b*1024+512+n*64+d]
// ============================================================================
#define PV_PST 72
#define PV_VST 68
__global__ __launch_bounds__(256) void pv_fp16(const __half* __restrict__ P,
                                               const float* __restrict__ KV,
                                               float* __restrict__ vec) {
    extern __shared__ char smraw[];
    __half* Ps = (__half*)smraw;                          // [2][64*72] halves
    float*  Vs = (float*)(smraw + 2 * 64 * PV_PST * 2);   // [2][64*68] floats

    int bn = blockIdx.y;
    int b = bn >> 3, n = bn & 7;
    int i0 = blockIdx.x * 64;
    int tid = threadIdx.x;
    int warp = tid >> 5, lane = tid & 31;
    int g = lane >> 2, c = lane & 3;
    int wm = (warp >> 1) * 16;    // 4 warps in m (64 rows)
    int wn = (warp & 1) * 32;     // 2 warps in n (64 cols)

    const __half* Pb = P + ((size_t)bn * 512 + i0) * 2048;
    const float* Vb = KV + b * 1024 + 512 + n * 64;

    float acc[4][4];
#pragma unroll
    for (int nt = 0; nt < 4; nt++)
#pragma unroll
        for (int e = 0; e < 4; e++) acc[nt][e] = 0.f;

    // stage loader
    auto loadP = [&](int st, int k0) {
#pragma unroll
        for (int w = 0; w < 2; w++) {
            int idx = tid + w * 256;           // 0..511
            int r = idx >> 3, ch = (idx & 7) * 8;
            cp16g(Ps + (size_t)st * 64 * PV_PST + r * PV_PST + ch,
                  Pb + (size_t)r * 2048 + k0 + ch);
        }
    };
    auto loadV = [&](int st, int k0) {
#pragma unroll
        for (int w = 0; w < 4; w++) {
            int idx = tid + w * 256;           // 0..1023
            int r = idx >> 4, ch = (idx & 15) * 4;
            cp16g(Vs + (size_t)st * 64 * PV_VST + r * PV_VST + ch,
                  Vb + (size_t)(k0 + r) * 4096 + ch);
        }
    };

    loadP(0, 0); loadV(0, 0);
    CP_COMMIT();

    for (int kt = 0; kt < 32; kt++) {
        int cur = kt & 1;
        if (kt + 1 < 32) {
            int nxt = (kt + 1) & 1;
            loadP(nxt, (kt + 1) * 64);
            loadV(nxt, (kt + 1) * 64);
        }
        CP_COMMIT();
        CP_WAIT1();
        __syncthreads();

        const __half* Pc = Ps + (size_t)cur * 64 * PV_PST;
        const float* Vc = Vs + (size_t)cur * 64 * PV_VST;
#pragma unroll
        for (int kk = 0; kk < 4; kk++) {
            int k = kk * 16;
            uint32_t af[4];
            const __half* base = Pc + (wm + g) * PV_PST + k + c * 2;
            af[0] = *(const uint32_t*)(base);
            af[1] = *(const uint32_t*)(base + 8 * PV_PST);
            af[2] = *(const uint32_t*)(base + 8);
            af[3] = *(const uint32_t*)(base + 8 * PV_PST + 8);
            uint32_t bf[4][2];
#pragma unroll
            for (int nt = 0; nt < 4; nt++) {
                int d = wn + nt * 8 + g;
                const float* vb = Vc + (k + c * 2) * PV_VST + d;
                bf[nt][0] = packh2(vb[0], vb[PV_VST]);
                bf[nt][1] = packh2(vb[8 * PV_VST], vb[9 * PV_VST]);
            }
#pragma unroll
            for (int nt = 0; nt < 4; nt++)
                mma_f16(acc[nt], af, bf[nt], acc[nt]);
        }
        __syncthreads();
    }

#pragma unroll
    for (int nt = 0; nt < 4; nt++) {
        int i = i0 + wm + g;
        int col = n * 64 + wn + nt * 8 + c * 2;
        float* d0 = vec + ((size_t)i * 4 + b) * 512 + col;
        float* d1 = vec + ((size_t)(i + 8) * 4 + b) * 512 + col;
        *(float2*)d0 = make_float2(acc[nt][0], acc[nt][1]);
        *(float2*)d1 = make_float2(acc[nt][2], acc[nt][3]);
    }
}

// ---------------- layernorm ----------------
__global__ void ln_kernel(const float* __restrict__ y, const float* __restrict__ g,
                          const float* __restrict__ be, float* __restrict__ out) {
    __shared__ float red[32];
    int r = blockIdx.x;
    int tid = threadIdx.x;
    float v0 = y[(size_t)r * 512 + tid];
    float v1 = y[(size_t)r * 512 + tid + 256];
    float mean = blockRedSum(v0 + v1, red) * (1.f / 512.f);
    float d0 = v0 - mean, d1 = v1 - mean;
    float var = blockRedSum(d0 * d0 + d1 * d1, red) * (1.f / 512.f);
    float rstd = rsqrtf(var + 1e-5f);
    out[(size_t)r * 512 + tid]       = d0 * rstd * g[tid] + be[tid];
    out[(size_t)r * 512 + tid + 256] = d1 * rstd * g[tid + 256] + be[tid + 256];
}

// ---------------- launch ----------------
#define SMEM_G128 ((2 * 128 * 36 + 2 * 32 * 136) * 4)   // 71680
#define SMEM_G64  ((2 * 128 * 36 + 2 * 32 * 72) * 4)    // 55296
#define SMEM_SC   ((64*68 + 64*68 + 128*68 + 192*68 + 64*200) * 4)  // 173056
#define SMEM_PV   (2 * 64 * PV_PST * 2 + 2 * 64 * PV_VST * 4)       // 53248

extern "C" void kernel_launch(void* const* d_in, const int* in_sizes, int n_in,
                              void* d_out, int out_size) {
    (void)in_sizes; (void)n_in; (void)out_size;
    const float* x       = (const float*)d_in[0];
    const float* memory  = (const float*)d_in[1];
    const float* pos_emb = (const float*)d_in[2];
    const float* pbu     = (const float*)d_in[3];
    const float* pbv     = (const float*)d_in[4];
    const float* ib      = (const float*)d_in[6];
    const float* W_q     = (const float*)d_in[7];
    const float* W_kv    = (const float*)d_in[8];
    const float* W_rel   = (const float*)d_in[9];
    const float* W_o     = (const float*)d_in[10];
    const float* ln_g    = (const float*)d_in[11];
    const float* ln_b    = (const float*)d_in[12];

    float* out  = (float*)d_out;
    float* attn = out + (size_t)Lq * BATCH * 512;

    float *kv, *rel, *q, *sc, *vec, *y;
    __half* prob;
    cudaGetSymbolAddress((void**)&kv,   g_kv);
    cudaGetSymbolAddress((void**)&rel,  g_rel);
    cudaGetSymbolAddress((void**)&q,    g_q);
    cudaGetSymbolAddress((void**)&sc,   g_sc);
    cudaGetSymbolAddress((void**)&prob, g_prob);
    cudaGetSymbolAddress((void**)&vec,  g_vec);
    cudaGetSymbolAddress((void**)&y,    g_y);

    static bool attr_set = false;
    if (!attr_set) {
        cudaFuncSetAttribute(proj_multi,
                             cudaFuncAttributeMaxDynamicSharedMemorySize, SMEM_G128);
        cudaFuncSetAttribute(gemm64,
                             cudaFuncAttributeMaxDynamicSharedMemorySize, SMEM_G64);
        cudaFuncSetAttribute(score_kernel,
                             cudaFuncAttributeMaxDynamicSharedMemorySize, SMEM_SC);
        cudaFuncSetAttribute(pv_fp16,
                             cudaFuncAttributeMaxDynamicSharedMemorySize, SMEM_PV);
        attr_set = true;
    }

    // 1) all 4 projections in one launch
    Desc d0 = { memory,  W_kv,  kv,                        1024, 512, 8, 0 };
    Desc d1 = { x,       W_kv,  kv + (size_t)6144 * 1024,  1024, 512, 8, 384 };
    Desc d2 = { pos_emb, W_rel, rel,                       512,  512, 4, 512 };
    Desc d3 = { x,       W_q,   q,                         512,  512, 4, 768 };
    proj_multi<<<832, 256, SMEM_G128>>>(d0, d1, d2, d3);

    // 2) fused scores
    score_kernel<<<dim3(16, 8, 32), 256, SMEM_SC>>>(q, pbu, pbv, kv, rel, ib, sc);

    // 3) masked softmax -> prob (fp16) + attn_matrix
    softmax_kernel<<<512, 256>>>(sc, prob, attn);

    // 4) vec = prob @ v (fp16 MMA, pipelined)
    pv_fp16<<<dim3(8, 32), 256, SMEM_PV>>>(prob, kv, vec);

    // 5) y = x + vec @ W_o ; layernorm
    gemm64<<<dim3(8, 16), 256, SMEM_G64>>>(vec, W_o, x, y, 2048, 512, 512);
    ln_kernel<<<2048, 256>>>(y, ln_g, ln_b, out);
}

// round 7
// speedup vs baseline: 4.3297x; 1.2821x over previous
#include <cuda_runtime.h>
#include <cuda_fp16.h>
#include <stdint.h>

// Problem constants
#define Lq     512
#define BATCH  4
#define SCALEF 0.125f

// ---------------- scratch ----------------
__device__ __half g_kv  [(size_t)8192 * 1024];          // 16 MB  k | v (fp16)
__device__ __half g_rel [(size_t)8192 * 512];           //  8 MB  (fp16)
__device__ float  g_q   [(size_t)2048 * 512];           //  4 MB
__device__ float  g_sc  [(size_t)32 * 512 * 2048];      // 128 MB raw scores
__device__ __half g_prob[(size_t)32 * 512 * 2048];      // 64 MB prob (fp16)
__device__ float  g_vec [(size_t)2048 * 512];           //  4 MB
__device__ float  g_y   [(size_t)2048 * 512];           //  4 MB

// ---------------- helpers ----------------
__device__ __forceinline__ void mma_tf32(float* d, const uint32_t* a,
                                         const uint32_t* b, const float* c) {
    asm volatile(
        "mma.sync.aligned.m16n8k8.row.col.f32.tf32.tf32.f32 "
        "{%0,%1,%2,%3}, {%4,%5,%6,%7}, {%8,%9}, {%10,%11,%12,%13};"
        : "=f"(d[0]), "=f"(d[1]), "=f"(d[2]), "=f"(d[3])
        : "r"(a[0]), "r"(a[1]), "r"(a[2]), "r"(a[3]),
          "r"(b[0]), "r"(b[1]),
          "f"(c[0]), "f"(c[1]), "f"(c[2]), "f"(c[3]));
}

__device__ __forceinline__ void mma_f16(float* d, const uint32_t* a,
                                        const uint32_t* b, const float* c) {
    asm volatile(
        "mma.sync.aligned.m16n8k16.row.col.f32.f16.f16.f32 "
        "{%0,%1,%2,%3}, {%4,%5,%6,%7}, {%8,%9}, {%10,%11,%12,%13};"
        : "=f"(d[0]), "=f"(d[1]), "=f"(d[2]), "=f"(d[3])
        : "r"(a[0]), "r"(a[1]), "r"(a[2]), "r"(a[3]),
          "r"(b[0]), "r"(b[1]),
          "f"(c[0]), "f"(c[1]), "f"(c[2]), "f"(c[3]));
}

__device__ __forceinline__ void ldsm_x4_t(uint32_t& r0, uint32_t& r1,
                                          uint32_t& r2, uint32_t& r3, uint32_t addr) {
    asm volatile("ldmatrix.sync.aligned.m8n8.x4.trans.shared.b16 {%0,%1,%2,%3}, [%4];"
                 : "=r"(r0), "=r"(r1), "=r"(r2), "=r"(r3) : "r"(addr));
}

__device__ __forceinline__ void cp16(void* dst, const void* src) {
    uint32_t d = (uint32_t)__cvta_generic_to_shared(dst);
    asm volatile("cp.async.cg.shared.global [%0], [%1], 16;" :: "r"(d), "l"(src));
}
#define CP_COMMIT() asm volatile("cp.async.commit_group;")
#define CP_WAIT1()  asm volatile("cp.async.wait_group 1;")

__device__ __forceinline__ float warpRedMax(float v) {
#pragma unroll
    for (int o = 16; o > 0; o >>= 1) v = fmaxf(v, __shfl_xor_sync(0xffffffffu, v, o));
    return v;
}
__device__ __forceinline__ float warpRedSum(float v) {
#pragma unroll
    for (int o = 16; o > 0; o >>= 1) v += __shfl_xor_sync(0xffffffffu, v, o);
    return v;
}
__device__ __forceinline__ float2 blockRedMax2(float a, float b, float* red) {
    a = warpRedMax(a); b = warpRedMax(b);
    int w = threadIdx.x >> 5, l = threadIdx.x & 31;
    if (!l) { red[w] = a; red[32 + w] = b; }
    __syncthreads();
    if (threadIdx.x < 64) {
        int wi = threadIdx.x >> 5;
        float x = (l < 8) ? red[wi * 32 + l] : -1e30f;
        x = warpRedMax(x);
        if (!l) red[wi * 32] = x;
    }
    __syncthreads();
    float2 r = make_float2(red[0], red[32]);
    __syncthreads();
    return r;
}
__device__ __forceinline__ float2 blockRedSum2(float a, float b, float* red) {
    a = warpRedSum(a); b = warpRedSum(b);
    int w = threadIdx.x >> 5, l = threadIdx.x & 31;
    if (!l) { red[w] = a; red[32 + w] = b; }
    __syncthreads();
    if (threadIdx.x < 64) {
        int wi = threadIdx.x >> 5;
        float x = (l < 8) ? red[wi * 32 + l] : 0.f;
        x = warpRedSum(x);
        if (!l) red[wi * 32] = x;
    }
    __syncthreads();
    float2 r = make_float2(red[0], red[32]);
    __syncthreads();
    return r;
}
__device__ __forceinline__ float blockRedSum(float v, float* red) {
    v = warpRedSum(v);
    int w = threadIdx.x >> 5, l = threadIdx.x & 31;
    if (!l) red[w] = v;
    __syncthreads();
    if (threadIdx.x < 32) {
        float x = (l < 8) ? red[l] : 0.f;
        x = warpRedSum(x);
        if (!l) red[0] = x;
    }
    __syncthreads();
    float r = red[0];
    __syncthreads();
    return r;
}

// ============================================================================
// Combined projection kernel (4 GEMMs, one launch). tf32, 2-stage cp.async.
// h flag: output fp16.
// ============================================================================
struct Desc {
    const float* A; const float* B; void* C;
    int N, K, nblk, blk0, h;
};

__global__ __launch_bounds__(256) void proj_multi(Desc d0, Desc d1, Desc d2, Desc d3) {
    extern __shared__ float sm[];
    float* As = sm;                    // [2][128*36]
    float* Bs = sm + 2 * 128 * 36;     // [2][32*136]

    Desc d = d3;
    int bid = blockIdx.x;
    if (bid < d1.blk0) d = d0;
    else if (bid < d2.blk0) d = d1;
    else if (bid < d3.blk0) d = d2;
    int local = bid - d.blk0;
    int m0 = (local / d.nblk) * 128, n0 = (local % d.nblk) * 128;
    const int N = d.N, K = d.K;

    int tid = threadIdx.x;
    int warp = tid >> 5, lane = tid & 31;
    int g = lane >> 2, c = lane & 3;
    int wm = (warp >> 2) * 64;
    int wn = (warp & 3) * 32;

    float acc[4][4][4];
#pragma unroll
    for (int mt = 0; mt < 4; mt++)
#pragma unroll
        for (int nt = 0; nt < 4; nt++)
#pragma unroll
            for (int e = 0; e < 4; e++) acc[mt][nt][e] = 0.f;

    int nk = K >> 5;
    {
#pragma unroll
        for (int w = 0; w < 4; w++) {
            int idx = tid + w * 256;
            int r = idx >> 3, cc = (idx & 7) * 4;
            cp16(As + r * 36 + cc, d.A + (size_t)(m0 + r) * K + cc);
        }
#pragma unroll
        for (int w = 0; w < 4; w++) {
            int idx = tid + w * 256;
            int r = idx >> 5, cc = (idx & 31) * 4;
            cp16(Bs + r * 136 + cc, d.B + (size_t)r * N + n0 + cc);
        }
    }
    CP_COMMIT();

    for (int kt = 0; kt < nk; kt++) {
        int cur = kt & 1;
        if (kt + 1 < nk) {
            int nxt = (kt + 1) & 1;
            int k0 = (kt + 1) * 32;
#pragma unroll
            for (int w = 0; w < 4; w++) {
                int idx = tid + w * 256;
                int r = idx >> 3, cc = (idx & 7) * 4;
                cp16(As + nxt * 128 * 36 + r * 36 + cc,
                     d.A + (size_t)(m0 + r) * K + k0 + cc);
            }
#pragma unroll
            for (int w = 0; w < 4; w++) {
                int idx = tid + w * 256;
                int r = idx >> 5, cc = (idx & 31) * 4;
                cp16(Bs + nxt * 32 * 136 + r * 136 + cc,
                     d.B + (size_t)(k0 + r) * N + n0 + cc);
            }
        }
        CP_COMMIT();
        CP_WAIT1();
        __syncthreads();

        const float* Ac = As + cur * 128 * 36;
        const float* Bc = Bs + cur * 32 * 136;
#pragma unroll
        for (int kk = 0; kk < 4; kk++) {
            int k = kk * 8;
            uint32_t af[4][4], bf[4][2];
#pragma unroll
            for (int mt = 0; mt < 4; mt++) {
                const float* base = Ac + (wm + mt * 16 + g) * 36 + k + c;
                af[mt][0] = __float_as_uint(base[0]);
                af[mt][1] = __float_as_uint(base[8 * 36]);
                af[mt][2] = __float_as_uint(base[4]);
                af[mt][3] = __float_as_uint(base[8 * 36 + 4]);
            }
#pragma unroll
            for (int nt = 0; nt < 4; nt++) {
                const float* base = Bc + (k + c) * 136 + wn + nt * 8 + g;
                bf[nt][0] = __float_as_uint(base[0]);
                bf[nt][1] = __float_as_uint(base[4 * 136]);
            }
#pragma unroll
            for (int mt = 0; mt < 4; mt++)
#pragma unroll
                for (int nt = 0; nt < 4; nt++)
                    mma_tf32(acc[mt][nt], af[mt], bf[nt], acc[mt][nt]);
        }
        __syncthreads();
    }

#pragma unroll
    for (int mt = 0; mt < 4; mt++)
#pragma unroll
        for (int nt = 0; nt < 4; nt++) {
            int row = m0 + wm + mt * 16 + g;
            int col = n0 + wn + nt * 8 + c * 2;
            if (d.h) {
                __half* Ch = (__half*)d.C;
                *(__half2*)(Ch + (size_t)row * N + col) =
                    __floats2half2_rn(acc[mt][nt][0], acc[mt][nt][1]);
                *(__half2*)(Ch + (size_t)(row + 8) * N + col) =
                    __floats2half2_rn(acc[mt][nt][2], acc[mt][nt][3]);
            } else {
                float* Cf = (float*)d.C;
                *(float2*)(Cf + (size_t)row * N + col) =
                    make_float2(acc[mt][nt][0], acc[mt][nt][1]);
                *(float2*)(Cf + (size_t)(row + 8) * N + col) =
                    make_float2(acc[mt][nt][2], acc[mt][nt][3]);
            }
        }
}

// ============================================================================
// Pipelined tf32 GEMM, BN=64 (for W_o with residual add)
// ============================================================================
__global__ __launch_bounds__(256) void gemm64(
        const float* __restrict__ A, const float* __restrict__ B,
        const float* __restrict__ Cadd, float* __restrict__ C,
        int M, int N, int K) {
    extern __shared__ float sm[];
    const int BST = 72;
    float* As = sm;
    float* Bs = sm + 2 * 128 * 36;

    int m0 = blockIdx.y * 128, n0 = blockIdx.x * 64;
    int tid = threadIdx.x;
    int warp = tid >> 5, lane = tid & 31;
    int g = lane >> 2, c = lane & 3;
    int wm = (warp >> 2) * 64;
    int wn = (warp & 3) * 16;

    float acc[4][2][4];
#pragma unroll
    for (int mt = 0; mt < 4; mt++)
#pragma unroll
        for (int nt = 0; nt < 2; nt++)
#pragma unroll
            for (int e = 0; e < 4; e++) acc[mt][nt][e] = 0.f;

    int nk = K >> 5;
    {
#pragma unroll
        for (int w = 0; w < 4; w++) {
            int idx = tid + w * 256;
            int r = idx >> 3, cc = (idx & 7) * 4;
            cp16(As + r * 36 + cc, A + (size_t)(m0 + r) * K + cc);
        }
#pragma unroll
        for (int w = 0; w < 2; w++) {
            int idx = tid + w * 256;
            int r = idx >> 4, cc = (idx & 15) * 4;
            cp16(Bs + r * BST + cc, B + (size_t)r * N + n0 + cc);
        }
    }
    CP_COMMIT();

    for (int kt = 0; kt < nk; kt++) {
        int cur = kt & 1;
        if (kt + 1 < nk) {
            int nxt = (kt + 1) & 1;
            int k0 = (kt + 1) * 32;
#pragma unroll
            for (int w = 0; w < 4; w++) {
                int idx = tid + w * 256;
                int r = idx >> 3, cc = (idx & 7) * 4;
                cp16(As + nxt * 128 * 36 + r * 36 + cc,
                     A + (size_t)(m0 + r) * K + k0 + cc);
            }
#pragma unroll
            for (int w = 0; w < 2; w++) {
                int idx = tid + w * 256;
                int r = idx >> 4, cc = (idx & 15) * 4;
                cp16(Bs + nxt * 32 * BST + r * BST + cc,
                     B + (size_t)(k0 + r) * N + n0 + cc);
            }
        }
        CP_COMMIT();
        CP_WAIT1();
        __syncthreads();

        const float* Ac = As + cur * 128 * 36;
        const float* Bc = Bs + cur * 32 * BST;
#pragma unroll
        for (int kk = 0; kk < 4; kk++) {
            int k = kk * 8;
            uint32_t af[4][4], bf[2][2];
#pragma unroll
            for (int mt = 0; mt < 4; mt++) {
                const float* base = Ac + (wm + mt * 16 + g) * 36 + k + c;
                af[mt][0] = __float_as_uint(base[0]);
                af[mt][1] = __float_as_uint(base[8 * 36]);
                af[mt][2] = __float_as_uint(base[4]);
                af[mt][3] = __float_as_uint(base[8 * 36 + 4]);
            }
#pragma unroll
            for (int nt = 0; nt < 2; nt++) {
                const float* base = Bc + (k + c) * BST + wn + nt * 8 + g;
                bf[nt][0] = __float_as_uint(base[0]);
                bf[nt][1] = __float_as_uint(base[4 * BST]);
            }
#pragma unroll
            for (int mt = 0; mt < 4; mt++)
#pragma unroll
                for (int nt = 0; nt < 2; nt++)
                    mma_tf32(acc[mt][nt], af[mt], bf[nt], acc[mt][nt]);
        }
        __syncthreads();
    }

#pragma unroll
    for (int mt = 0; mt < 4; mt++)
#pragma unroll
        for (int nt = 0; nt < 2; nt++) {
            int row = m0 + wm + mt * 16 + g;
            int col = n0 + wn + nt * 8 + c * 2;
            float* p0 = C + (size_t)row * N + col;
            float* p1 = C + (size_t)(row + 8) * N + col;
            float2 v0 = make_float2(acc[mt][nt][0], acc[mt][nt][1]);
            float2 v1 = make_float2(acc[mt][nt][2], acc[mt][nt][3]);
            if (Cadd) {
                const float* a0 = Cadd + (size_t)row * N + col;
                const float* a1 = Cadd + (size_t)(row + 8) * N + col;
                v0.x += a0[0]; v0.y += a0[1];
                v1.x += a1[0]; v1.y += a1[1];
            }
            *(float2*)p0 = v0;
            *(float2*)p1 = v1;
        }
}

// ============================================================================
// Fused score kernel, fp16 MMA (m16n8k16). Tile 64 i x 128 j, BD band 192.
// ============================================================================
__global__ __launch_bounds__(256, 1) void score_kernel(
        const float* __restrict__ Q, const float* __restrict__ pbu,
        const float* __restrict__ pbv, const __half* __restrict__ KV,
        const __half* __restrict__ REL, const float* __restrict__ ib,
        float* __restrict__ S) {
    extern __shared__ char smraw[];
    __half* qu_s  = (__half*)smraw;          // [64][72]
    __half* qv_s  = qu_s + 64 * 72;          // [64][72]
    __half* k_s   = qv_s + 64 * 72;          // [128][72]
    __half* rel_s = k_s + 128 * 72;          // [192][72]
    float*  bd_s  = (float*)(rel_s + 192 * 72);  // [64][200] fp32

    int bn = blockIdx.z;
    int b = bn >> 3, n = bn & 7;
    int i0 = blockIdx.y * 64;
    int j0 = blockIdx.x * 128;
    int tid = threadIdx.x;
    int m0 = j0 + 448 - i0;

    // q (+bias, *scale) -> fp16 smem, both copies
#pragma unroll
    for (int w = 0; w < 4; w++) {
        int idx = tid + w * 256;
        int r = idx >> 4, c4 = (idx & 15) * 4;
        float4 v = *(const float4*)(Q + (size_t)(i0 + r) * 2048 + b * 512 + n * 64 + c4);
        float4 bu = *(const float4*)(pbu + n * 64 + c4);
        float4 bv = *(const float4*)(pbv + n * 64 + c4);
        *(__half2*)(qu_s + r * 72 + c4) =
            __floats2half2_rn((v.x + bu.x) * SCALEF, (v.y + bu.y) * SCALEF);
        *(__half2*)(qu_s + r * 72 + c4 + 2) =
            __floats2half2_rn((v.z + bu.z) * SCALEF, (v.w + bu.w) * SCALEF);
        *(__half2*)(qv_s + r * 72 + c4) =
            __floats2half2_rn((v.x + bv.x) * SCALEF, (v.y + bv.y) * SCALEF);
        *(__half2*)(qv_s + r * 72 + c4 + 2) =
            __floats2half2_rn((v.z + bv.z) * SCALEF, (v.w + bv.w) * SCALEF);
    }
    // k rows (fp16, 16B chunks)
#pragma unroll
    for (int w = 0; w < 4; w++) {
        int idx = tid + w * 256;
        int r = idx >> 3, ch = (idx & 7) * 8;
        *(uint4*)(k_s + r * 72 + ch) =
            *(const uint4*)(KV + (size_t)(j0 + r) * 4096 + b * 1024 + n * 64 + ch);
    }
    // rel band rows (clamped)
#pragma unroll
    for (int w = 0; w < 6; w++) {
        int idx = tid + w * 256;
        int r = idx >> 3, ch = (idx & 7) * 8;
        int mr = m0 + r; if (mr > 2047) mr = 2047;
        *(uint4*)(rel_s + r * 72 + ch) =
            *(const uint4*)(REL + (size_t)mr * 2048 + b * 512 + n * 64 + ch);
    }
    __syncthreads();

    int warp = tid >> 5, lane = tid & 31;
    int g = lane >> 2, c = lane & 3;
    int wm  = (warp >> 2) * 32;
    int wnB = (warp & 3) * 48;
    int wnA = (warp & 3) * 32;

    float accb[2][6][4];
    float acca[2][4][4];
#pragma unroll
    for (int mt = 0; mt < 2; mt++) {
#pragma unroll
        for (int nt = 0; nt < 6; nt++)
#pragma unroll
            for (int e = 0; e < 4; e++) accb[mt][nt][e] = 0.f;
#pragma unroll
        for (int nt = 0; nt < 4; nt++)
#pragma unroll
            for (int e = 0; e < 4; e++) acca[mt][nt][e] = 0.f;
    }

#pragma unroll
    for (int kk = 0; kk < 4; kk++) {
        int k = kk * 16;
        uint32_t au[2][4], av[2][4], bk[4][2], br[6][2];
#pragma unroll
        for (int mt = 0; mt < 2; mt++) {
            const __half* bu = qu_s + (wm + mt * 16 + g) * 72 + k + 2 * c;
            const __half* bv = qv_s + (wm + mt * 16 + g) * 72 + k + 2 * c;
            au[mt][0] = *(const uint32_t*)(bu);
            au[mt][1] = *(const uint32_t*)(bu + 8 * 72);
            au[mt][2] = *(const uint32_t*)(bu + 8);
            au[mt][3] = *(const uint32_t*)(bu + 8 * 72 + 8);
            av[mt][0] = *(const uint32_t*)(bv);
            av[mt][1] = *(const uint32_t*)(bv + 8 * 72);
            av[mt][2] = *(const uint32_t*)(bv + 8);
            av[mt][3] = *(const uint32_t*)(bv + 8 * 72 + 8);
        }
#pragma unroll
        for (int nt = 0; nt < 4; nt++) {
            const __half* base = k_s + (wnA + nt * 8 + g) * 72 + k + 2 * c;
            bk[nt][0] = *(const uint32_t*)(base);
            bk[nt][1] = *(const uint32_t*)(base + 8);
        }
#pragma unroll
        for (int nt = 0; nt < 6; nt++) {
            const __half* base = rel_s + (wnB + nt * 8 + g) * 72 + k + 2 * c;
            br[nt][0] = *(const uint32_t*)(base);
            br[nt][1] = *(const uint32_t*)(base + 8);
        }
#pragma unroll
        for (int mt = 0; mt < 2; mt++) {
#pragma unroll
            for (int nt = 0; nt < 4; nt++)
                mma_f16(acca[mt][nt], au[mt], bk[nt], acca[mt][nt]);
#pragma unroll
            for (int nt = 0; nt < 6; nt++)
                mma_f16(accb[mt][nt], av[mt], br[nt], accb[mt][nt]);
        }
    }

    // stage BD band (fp32)
#pragma unroll
    for (int mt = 0; mt < 2; mt++)
#pragma unroll
        for (int nt = 0; nt < 6; nt++) {
            int row = wm + mt * 16 + g;
            int col = wnB + nt * 8 + c * 2;
            *(float2*)(bd_s + row * 200 + col) =
                make_float2(accb[mt][nt][0], accb[mt][nt][1]);
            *(float2*)(bd_s + (row + 8) * 200 + col) =
                make_float2(accb[mt][nt][2], accb[mt][nt][3]);
        }
    __syncthreads();

    // epilogue: combine with shifted BD + gates, write S
    float* Sb = S + ((size_t)bn * 512 + i0) * 2048 + j0;
#pragma unroll
    for (int mt = 0; mt < 2; mt++)
#pragma unroll
        for (int nt = 0; nt < 4; nt++) {
#pragma unroll
            for (int half = 0; half < 2; half++) {
                int i_loc = wm + mt * 16 + g + half * 8;
                int i = i0 + i_loc;
                const float* gp = ib + ((size_t)i * 4 + b) * 4;
                float a0 = acca[mt][nt][half * 2];
                float a1 = acca[mt][nt][half * 2 + 1];
                float s2[2];
#pragma unroll
                for (int e = 0; e < 2; e++) {
                    int j_loc = wnA + nt * 8 + c * 2 + e;
                    int j = j0 + j_loc;
                    int m = j + 511 - i;
                    int segB = m >> 9; if (segB > 3) segB = 3;
                    float bd = bd_s[i_loc * 200 + (j_loc + 63 - i_loc)];
                    float ac = e ? a1 : a0;
                    s2[e] = gp[j >> 9] * ac + gp[segB] * bd;
                }
                *(float2*)(Sb + (size_t)i_loc * 2048 + wnA + nt * 8 + c * 2) =
                    make_float2(s2[0], s2[1]);
            }
        }
}

// ---------------- softmax: 2 bn-rows/iter, paired reductions ----------------
__global__ void softmax_kernel(const float* __restrict__ S, __half* __restrict__ P,
                               float* __restrict__ attn) {
    __shared__ float accv[2048];
    __shared__ float red[64];
    int i = blockIdx.x;
    int tid = threadIdx.x;
    for (int j = tid; j < 2048; j += 256) accv[j] = 0.f;
    __syncthreads();

    int jmax = 3 * Lq + i;

    for (int bn = 0; bn < 32; bn += 2) {
        const float* srow0 = S + ((size_t)bn * 512 + i) * 2048;
        const float* srow1 = srow0 + (size_t)512 * 2048;
        __half* prow0 = P + ((size_t)bn * 512 + i) * 2048;
        __half* prow1 = prow0 + (size_t)512 * 2048;

        float s0[8], s1[8];
        float mx0 = -1e30f, mx1 = -1e30f;
#pragma unroll
        for (int t = 0; t < 8; t++) {
            int j = tid + t * 256;
            if (j <= jmax) {
                s0[t] = srow0[j];
                s1[t] = srow1[j];
                mx0 = fmaxf(mx0, s0[t]);
                mx1 = fmaxf(mx1, s1[t]);
            } else {
                s0[t] = -1e30f;
                s1[t] = -1e30f;
            }
        }
        float2 mx = blockRedMax2(mx0, mx1, red);

        float p0[8], p1[8];
        float sum0 = 0.f, sum1 = 0.f;
#pragma unroll
        for (int t = 0; t < 8; t++) {
            p0[t] = (s0[t] > -1e29f) ? __expf(s0[t] - mx.x) : 0.f;
            p1[t] = (s1[t] > -1e29f) ? __expf(s1[t] - mx.y) : 0.f;
            sum0 += p0[t];
            sum1 += p1[t];
        }
        float2 sum = blockRedSum2(sum0, sum1, red);
        float inv0 = 1.f / sum.x, inv1 = 1.f / sum.y;
#pragma unroll
        for (int t = 0; t < 8; t++) {
            int j = tid + t * 256;
            float pp0 = p0[t] * inv0;
            float pp1 = p1[t] * inv1;
            prow0[j] = __float2half_rn(pp0);
            prow1[j] = __float2half_rn(pp1);
            accv[j] += pp0 + pp1;
        }
        __syncthreads();
    }

    const float invBN = 1.f / 32.f;
    for (int j = tid; j < 2048; j += 256)
        attn[(size_t)i * 2048 + j] = accv[j] * invBN;
}

// ============================================================================
// Batched prob(fp16) @ V(fp16): 64x64 tile, BK=64, 2-stage cp.async,
// ldmatrix.x4.trans for B fragments.
// ============================================================================
#define PV_ST 72
__global__ __launch_bounds__(256) void pv_fp16(const __half* __restrict__ P,
                                               const __half* __restrict__ KV,
                                               float* __restrict__ vec) {
    extern __shared__ char smraw[];
    __half* Ps = (__half*)smraw;              // [2][64*72]
    __half* Vs = Ps + 2 * 64 * PV_ST;         // [2][64*72]

    int bn = blockIdx.y;
    int b = bn >> 3, n = bn & 7;
    int i0 = blockIdx.x * 64;
    int tid = threadIdx.x;
    int warp = tid >> 5, lane = tid & 31;
    int g = lane >> 2, c = lane & 3;
    int wm = (warp >> 1) * 16;    // 4 warps in m
    int wn = (warp & 1) * 32;     // 2 warps in n

    // ldmatrix lane mapping
    int mat = lane >> 3;
    int lrow = (mat & 1) * 8 + (lane & 7);
    int lcol = (mat >> 1) * 8;

    const __half* Pb = P + ((size_t)bn * 512 + i0) * 2048;
    const __half* Vb = KV + b * 1024 + 512 + n * 64;

    float acc[4][4];
#pragma unroll
    for (int nt = 0; nt < 4; nt++)
#pragma unroll
        for (int e = 0; e < 4; e++) acc[nt][e] = 0.f;

    auto loadStage = [&](int st, int k0) {
#pragma unroll
        for (int w = 0; w < 2; w++) {
            int idx = tid + w * 256;
            int r = idx >> 3, ch = (idx & 7) * 8;
            cp16(Ps + st * 64 * PV_ST + r * PV_ST + ch,
                 Pb + (size_t)r * 2048 + k0 + ch);
        }
#pragma unroll
        for (int w = 0; w < 2; w++) {
            int idx = tid + w * 256;
            int r = idx >> 3, ch = (idx & 7) * 8;
            cp16(Vs + st * 64 * PV_ST + r * PV_ST + ch,
                 Vb + (size_t)(k0 + r) * 4096 + ch);
        }
    };

    loadStage(0, 0);
    CP_COMMIT();

    for (int kt = 0; kt < 32; kt++) {
        int cur = kt & 1;
        if (kt + 1 < 32) loadStage((kt + 1) & 1, (kt + 1) * 64);
        CP_COMMIT();
        CP_WAIT1();
        __syncthreads();

        const __half* Pc = Ps + cur * 64 * PV_ST;
        const __half* Vc = Vs + cur * 64 * PV_ST;
        uint32_t vbase = (uint32_t)__cvta_generic_to_shared(Vc);
#pragma unroll
        for (int kk = 0; kk < 4; kk++) {
            int k = kk * 16;
            uint32_t af[4];
            const __half* base = Pc + (wm + g) * PV_ST + k + c * 2;
            af[0] = *(const uint32_t*)(base);
            af[1] = *(const uint32_t*)(base + 8 * PV_ST);
            af[2] = *(const uint32_t*)(base + 8);
            af[3] = *(const uint32_t*)(base + 8 * PV_ST + 8);

            uint32_t bf[4][2];
#pragma unroll
            for (int p = 0; p < 2; p++) {
                uint32_t addr = vbase +
                    (uint32_t)(((k + lrow) * PV_ST + wn + p * 16 + lcol) * 2);
                uint32_t r0, r1, r2, r3;
                ldsm_x4_t(r0, r1, r2, r3, addr);
                bf[2 * p][0] = r0; bf[2 * p][1] = r1;
                bf[2 * p + 1][0] = r2; bf[2 * p + 1][1] = r3;
            }
#pragma unroll
            for (int nt = 0; nt < 4; nt++)
                mma_f16(acc[nt], af, bf[nt], acc[nt]);
        }
        __syncthreads();
    }

#pragma unroll
    for (int nt = 0; nt < 4; nt++) {
        int i = i0 + wm + g;
        int col = n * 64 + wn + nt * 8 + c * 2;
        float* d0 = vec + ((size_t)i * 4 + b) * 512 + col;
        float* d1 = vec + ((size_t)(i + 8) * 4 + b) * 512 + col;
        *(float2*)d0 = make_float2(acc[nt][0], acc[nt][1]);
        *(float2*)d1 = make_float2(acc[nt][2], acc[nt][3]);
    }
}

// ---------------- layernorm ----------------
__global__ void ln_kernel(const float* __restrict__ y, const float* __restrict__ g,
                          const float* __restrict__ be, float* __restrict__ out) {
    __shared__ float red[32];
    int r = blockIdx.x;
    int tid = threadIdx.x;
    float v0 = y[(size_t)r * 512 + tid];
    float v1 = y[(size_t)r * 512 + tid + 256];
    float mean = blockRedSum(v0 + v1, red) * (1.f / 512.f);
    float d0 = v0 - mean, d1 = v1 - mean;
    float var = blockRedSum(d0 * d0 + d1 * d1, red) * (1.f / 512.f);
    float rstd = rsqrtf(var + 1e-5f);
    out[(size_t)r * 512 + tid]       = d0 * rstd * g[tid] + be[tid];
    out[(size_t)r * 512 + tid + 256] = d1 * rstd * g[tid + 256] + be[tid + 256];
}

// ---------------- launch ----------------
#define SMEM_G128 ((2 * 128 * 36 + 2 * 32 * 136) * 4)              // 71680
#define SMEM_G64  ((2 * 128 * 36 + 2 * 32 * 72) * 4)               // 55296
#define SMEM_SC   ((64*72*2 + 128*72 + 192*72) * 2 + 64*200*4)     // 115712
#define SMEM_PV   (4 * 64 * PV_ST * 2)                             // 36864

extern "C" void kernel_launch(void* const* d_in, const int* in_sizes, int n_in,
                              void* d_out, int out_size) {
    (void)in_sizes; (void)n_in; (void)out_size;
    const float* x       = (const float*)d_in[0];
    const float* memory  = (const float*)d_in[1];
    const float* pos_emb = (const float*)d_in[2];
    const float* pbu     = (const float*)d_in[3];
    const float* pbv     = (const float*)d_in[4];
    const float* ib      = (const float*)d_in[6];
    const float* W_q     = (const float*)d_in[7];
    const float* W_kv    = (const float*)d_in[8];
    const float* W_rel   = (const float*)d_in[9];
    const float* W_o     = (const float*)d_in[10];
    const float* ln_g    = (const float*)d_in[11];
    const float* ln_b    = (const float*)d_in[12];

    float* out  = (float*)d_out;
    float* attn = out + (size_t)Lq * BATCH * 512;

    __half *kvh, *relh, *prob;
    float *q, *sc, *vec, *y;
    cudaGetSymbolAddress((void**)&kvh,  g_kv);
    cudaGetSymbolAddress((void**)&relh, g_rel);
    cudaGetSymbolAddress((void**)&q,    g_q);
    cudaGetSymbolAddress((void**)&sc,   g_sc);
    cudaGetSymbolAddress((void**)&prob, g_prob);
    cudaGetSymbolAddress((void**)&vec,  g_vec);
    cudaGetSymbolAddress((void**)&y,    g_y);

    static bool attr_set = false;
    if (!attr_set) {
        cudaFuncSetAttribute(proj_multi,
                             cudaFuncAttributeMaxDynamicSharedMemorySize, SMEM_G128);
        cudaFuncSetAttribute(gemm64,
                             cudaFuncAttributeMaxDynamicSharedMemorySize, SMEM_G64);
        cudaFuncSetAttribute(score_kernel,
                             cudaFuncAttributeMaxDynamicSharedMemorySize, SMEM_SC);
        cudaFuncSetAttribute(pv_fp16,
                             cudaFuncAttributeMaxDynamicSharedMemorySize, SMEM_PV);
        attr_set = true;
    }

    // 1) all 4 projections in one launch (kv, rel out fp16; q out fp32)
    Desc d0 = { memory,  W_kv,  (void*)kvh,                        1024, 512, 8, 0,   1 };
    Desc d1 = { x,       W_kv,  (void*)(kvh + (size_t)6144 * 1024),1024, 512, 8, 384, 1 };
    Desc d2 = { pos_emb, W_rel, (void*)relh,                       512,  512, 4, 512, 1 };
    Desc d3 = { x,       W_q,   (void*)q,                          512,  512, 4, 768, 0 };
    proj_multi<<<832, 256, SMEM_G128>>>(d0, d1, d2, d3);

    // 2) fused scores (fp16 MMA)
    score_kernel<<<dim3(16, 8, 32), 256, SMEM_SC>>>(q, pbu, pbv, kvh, relh, ib, sc);

    // 3) masked softmax -> prob (fp16) + attn_matrix
    softmax_kernel<<<512, 256>>>(sc, prob, attn);

    // 4) vec = prob @ v (fp16 MMA, ldmatrix, pipelined)
    pv_fp16<<<dim3(8, 32), 256, SMEM_PV>>>(prob, kvh, vec);

    // 5) y = x + vec @ W_o ; layernorm
    gemm64<<<dim3(8, 16), 256, SMEM_G64>>>(vec, W_o, x, y, 2048, 512, 512);
    ln_kernel<<<2048, 256>>>(y, ln_g, ln_b, out);
}

// round 8
// speedup vs baseline: 4.6037x; 1.0633x over previous
#include <cuda_runtime.h>
#include <cuda_fp16.h>
#include <stdint.h>

// Problem constants
#define Lq     512
#define BATCH  4
#define SCALEF 0.125f

// ---------------- scratch ----------------
__device__ __half g_kv  [(size_t)8192 * 1024];          // 16 MB  k | v (fp16)
__device__ __half g_rel [(size_t)8192 * 512];           //  8 MB  (fp16)
__device__ float  g_q   [(size_t)2048 * 512];           //  4 MB
__device__ __half g_prob[(size_t)32 * 512 * 2048];      // 64 MB unnormalized exp (fp16)
__device__ float  g_rsum[(size_t)32 * 512];             // 64 KB reciprocal row sums
__device__ float  g_vec [(size_t)2048 * 512];           //  4 MB
__device__ float  g_y   [(size_t)2048 * 512];           //  4 MB

// ---------------- helpers ----------------
__device__ __forceinline__ void mma_tf32(float* d, const uint32_t* a,
                                         const uint32_t* b, const float* c) {
    asm volatile(
        "mma.sync.aligned.m16n8k8.row.col.f32.tf32.tf32.f32 "
        "{%0,%1,%2,%3}, {%4,%5,%6,%7}, {%8,%9}, {%10,%11,%12,%13};"
        : "=f"(d[0]), "=f"(d[1]), "=f"(d[2]), "=f"(d[3])
        : "r"(a[0]), "r"(a[1]), "r"(a[2]), "r"(a[3]),
          "r"(b[0]), "r"(b[1]),
          "f"(c[0]), "f"(c[1]), "f"(c[2]), "f"(c[3]));
}

__device__ __forceinline__ void mma_f16(float* d, const uint32_t* a,
                                        const uint32_t* b, const float* c) {
    asm volatile(
        "mma.sync.aligned.m16n8k16.row.col.f32.f16.f16.f32 "
        "{%0,%1,%2,%3}, {%4,%5,%6,%7}, {%8,%9}, {%10,%11,%12,%13};"
        : "=f"(d[0]), "=f"(d[1]), "=f"(d[2]), "=f"(d[3])
        : "r"(a[0]), "r"(a[1]), "r"(a[2]), "r"(a[3]),
          "r"(b[0]), "r"(b[1]),
          "f"(c[0]), "f"(c[1]), "f"(c[2]), "f"(c[3]));
}

__device__ __forceinline__ void ldsm_x4_t(uint32_t& r0, uint32_t& r1,
                                          uint32_t& r2, uint32_t& r3, uint32_t addr) {
    asm volatile("ldmatrix.sync.aligned.m8n8.x4.trans.shared.b16 {%0,%1,%2,%3}, [%4];"
                 : "=r"(r0), "=r"(r1), "=r"(r2), "=r"(r3) : "r"(addr));
}

__device__ __forceinline__ void cp16(void* dst, const void* src) {
    uint32_t d = (uint32_t)__cvta_generic_to_shared(dst);
    asm volatile("cp.async.cg.shared.global [%0], [%1], 16;" :: "r"(d), "l"(src));
}
#define CP_COMMIT() asm volatile("cp.async.commit_group;")
#define CP_WAIT1()  asm volatile("cp.async.wait_group 1;")

__device__ __forceinline__ float warpRedSum(float v) {
#pragma unroll
    for (int o = 16; o > 0; o >>= 1) v += __shfl_xor_sync(0xffffffffu, v, o);
    return v;
}
__device__ __forceinline__ float blockRedSum(float v, float* red) {
    v = warpRedSum(v);
    int w = threadIdx.x >> 5, l = threadIdx.x & 31;
    if (!l) red[w] = v;
    __syncthreads();
    if (threadIdx.x < 32) {
        float x = (l < 8) ? red[l] : 0.f;
        x = warpRedSum(x);
        if (!l) red[0] = x;
    }
    __syncthreads();
    float r = red[0];
    __syncthreads();
    return r;
}

// ============================================================================
// Combined projection kernel (4 GEMMs, one launch). tf32, 2-stage cp.async.
// ============================================================================
struct Desc {
    const float* A; const float* B; void* C;
    int N, K, nblk, blk0, h;
};

__global__ __launch_bounds__(256) void proj_multi(Desc d0, Desc d1, Desc d2, Desc d3) {
    extern __shared__ float sm[];
    float* As = sm;                    // [2][128*36]
    float* Bs = sm + 2 * 128 * 36;     // [2][32*136]

    Desc d = d3;
    int bid = blockIdx.x;
    if (bid < d1.blk0) d = d0;
    else if (bid < d2.blk0) d = d1;
    else if (bid < d3.blk0) d = d2;
    int local = bid - d.blk0;
    int m0 = (local / d.nblk) * 128, n0 = (local % d.nblk) * 128;
    const int N = d.N, K = d.K;

    int tid = threadIdx.x;
    int warp = tid >> 5, lane = tid & 31;
    int g = lane >> 2, c = lane & 3;
    int wm = (warp >> 2) * 64;
    int wn = (warp & 3) * 32;

    float acc[4][4][4];
#pragma unroll
    for (int mt = 0; mt < 4; mt++)
#pragma unroll
        for (int nt = 0; nt < 4; nt++)
#pragma unroll
            for (int e = 0; e < 4; e++) acc[mt][nt][e] = 0.f;

    int nk = K >> 5;
    {
#pragma unroll
        for (int w = 0; w < 4; w++) {
            int idx = tid + w * 256;
            int r = idx >> 3, cc = (idx & 7) * 4;
            cp16(As + r * 36 + cc, d.A + (size_t)(m0 + r) * K + cc);
        }
#pragma unroll
        for (int w = 0; w < 4; w++) {
            int idx = tid + w * 256;
            int r = idx >> 5, cc = (idx & 31) * 4;
            cp16(Bs + r * 136 + cc, d.B + (size_t)r * N + n0 + cc);
        }
    }
    CP_COMMIT();

    for (int kt = 0; kt < nk; kt++) {
        int cur = kt & 1;
        if (kt + 1 < nk) {
            int nxt = (kt + 1) & 1;
            int k0 = (kt + 1) * 32;
#pragma unroll
            for (int w = 0; w < 4; w++) {
                int idx = tid + w * 256;
                int r = idx >> 3, cc = (idx & 7) * 4;
                cp16(As + nxt * 128 * 36 + r * 36 + cc,
                     d.A + (size_t)(m0 + r) * K + k0 + cc);
            }
#pragma unroll
            for (int w = 0; w < 4; w++) {
                int idx = tid + w * 256;
                int r = idx >> 5, cc = (idx & 31) * 4;
                cp16(Bs + nxt * 32 * 136 + r * 136 + cc,
                     d.B + (size_t)(k0 + r) * N + n0 + cc);
            }
        }
        CP_COMMIT();
        CP_WAIT1();
        __syncthreads();

        const float* Ac = As + cur * 128 * 36;
        const float* Bc = Bs + cur * 32 * 136;
#pragma unroll
        for (int kk = 0; kk < 4; kk++) {
            int k = kk * 8;
            uint32_t af[4][4], bf[4][2];
#pragma unroll
            for (int mt = 0; mt < 4; mt++) {
                const float* base = Ac + (wm + mt * 16 + g) * 36 + k + c;
                af[mt][0] = __float_as_uint(base[0]);
                af[mt][1] = __float_as_uint(base[8 * 36]);
                af[mt][2] = __float_as_uint(base[4]);
                af[mt][3] = __float_as_uint(base[8 * 36 + 4]);
            }
#pragma unroll
            for (int nt = 0; nt < 4; nt++) {
                const float* base = Bc + (k + c) * 136 + wn + nt * 8 + g;
                bf[nt][0] = __float_as_uint(base[0]);
                bf[nt][1] = __float_as_uint(base[4 * 136]);
            }
#pragma unroll
            for (int mt = 0; mt < 4; mt++)
#pragma unroll
                for (int nt = 0; nt < 4; nt++)
                    mma_tf32(acc[mt][nt], af[mt], bf[nt], acc[mt][nt]);
        }
        __syncthreads();
    }

#pragma unroll
    for (int mt = 0; mt < 4; mt++)
#pragma unroll
        for (int nt = 0; nt < 4; nt++) {
            int row = m0 + wm + mt * 16 + g;
            int col = n0 + wn + nt * 8 + c * 2;
            if (d.h) {
                __half* Ch = (__half*)d.C;
                *(__half2*)(Ch + (size_t)row * N + col) =
                    __floats2half2_rn(acc[mt][nt][0], acc[mt][nt][1]);
                *(__half2*)(Ch + (size_t)(row + 8) * N + col) =
                    __floats2half2_rn(acc[mt][nt][2], acc[mt][nt][3]);
            } else {
                float* Cf = (float*)d.C;
                *(float2*)(Cf + (size_t)row * N + col) =
                    make_float2(acc[mt][nt][0], acc[mt][nt][1]);
                *(float2*)(Cf + (size_t)(row + 8) * N + col) =
                    make_float2(acc[mt][nt][2], acc[mt][nt][3]);
            }
        }
}

// ============================================================================
// Pipelined tf32 GEMM, BN=64 (for W_o with residual add)
// ============================================================================
__global__ __launch_bounds__(256) void gemm64(
        const float* __restrict__ A, const float* __restrict__ B,
        const float* __restrict__ Cadd, float* __restrict__ C,
        int M, int N, int K) {
    extern __shared__ float sm[];
    const int BST = 72;
    float* As = sm;
    float* Bs = sm + 2 * 128 * 36;

    int m0 = blockIdx.y * 128, n0 = blockIdx.x * 64;
    int tid = threadIdx.x;
    int warp = tid >> 5, lane = tid & 31;
    int g = lane >> 2, c = lane & 3;
    int wm = (warp >> 2) * 64;
    int wn = (warp & 3) * 16;

    float acc[4][2][4];
#pragma unroll
    for (int mt = 0; mt < 4; mt++)
#pragma unroll
        for (int nt = 0; nt < 2; nt++)
#pragma unroll
            for (int e = 0; e < 4; e++) acc[mt][nt][e] = 0.f;

    int nk = K >> 5;
    {
#pragma unroll
        for (int w = 0; w < 4; w++) {
            int idx = tid + w * 256;
            int r = idx >> 3, cc = (idx & 7) * 4;
            cp16(As + r * 36 + cc, A + (size_t)(m0 + r) * K + cc);
        }
#pragma unroll
        for (int w = 0; w < 2; w++) {
            int idx = tid + w * 256;
            int r = idx >> 4, cc = (idx & 15) * 4;
            cp16(Bs + r * BST + cc, B + (size_t)r * N + n0 + cc);
        }
    }
    CP_COMMIT();

    for (int kt = 0; kt < nk; kt++) {
        int cur = kt & 1;
        if (kt + 1 < nk) {
            int nxt = (kt + 1) & 1;
            int k0 = (kt + 1) * 32;
#pragma unroll
            for (int w = 0; w < 4; w++) {
                int idx = tid + w * 256;
                int r = idx >> 3, cc = (idx & 7) * 4;
                cp16(As + nxt * 128 * 36 + r * 36 + cc,
                     A + (size_t)(m0 + r) * K + k0 + cc);
            }
#pragma unroll
            for (int w = 0; w < 2; w++) {
                int idx = tid + w * 256;
                int r = idx >> 4, cc = (idx & 15) * 4;
                cp16(Bs + nxt * 32 * BST + r * BST + cc,
                     B + (size_t)(k0 + r) * N + n0 + cc);
            }
        }
        CP_COMMIT();
        CP_WAIT1();
        __syncthreads();

        const float* Ac = As + cur * 128 * 36;
        const float* Bc = Bs + cur * 32 * BST;
#pragma unroll
        for (int kk = 0; kk < 4; kk++) {
            int k = kk * 8;
            uint32_t af[4][4], bf[2][2];
#pragma unroll
            for (int mt = 0; mt < 4; mt++) {
                const float* base = Ac + (wm + mt * 16 + g) * 36 + k + c;
                af[mt][0] = __float_as_uint(base[0]);
                af[mt][1] = __float_as_uint(base[8 * 36]);
                af[mt][2] = __float_as_uint(base[4]);
                af[mt][3] = __float_as_uint(base[8 * 36 + 4]);
            }
#pragma unroll
            for (int nt = 0; nt < 2; nt++) {
                const float* base = Bc + (k + c) * BST + wn + nt * 8 + g;
                bf[nt][0] = __float_as_uint(base[0]);
                bf[nt][1] = __float_as_uint(base[4 * BST]);
            }
#pragma unroll
            for (int mt = 0; mt < 4; mt++)
#pragma unroll
                for (int nt = 0; nt < 2; nt++)
                    mma_tf32(acc[mt][nt], af[mt], bf[nt], acc[mt][nt]);
        }
        __syncthreads();
    }

#pragma unroll
    for (int mt = 0; mt < 4; mt++)
#pragma unroll
        for (int nt = 0; nt < 2; nt++) {
            int row = m0 + wm + mt * 16 + g;
            int col = n0 + wn + nt * 8 + c * 2;
            float* p0 = C + (size_t)row * N + col;
            float* p1 = C + (size_t)(row + 8) * N + col;
            float2 v0 = make_float2(acc[mt][nt][0], acc[mt][nt][1]);
            float2 v1 = make_float2(acc[mt][nt][2], acc[mt][nt][3]);
            if (Cadd) {
                const float* a0 = Cadd + (size_t)row * N + col;
                const float* a1 = Cadd + (size_t)(row + 8) * N + col;
                v0.x += a0[0]; v0.y += a0[1];
                v1.x += a1[0]; v1.y += a1[1];
            }
            *(float2*)p0 = v0;
            *(float2*)p1 = v1;
        }
}

// ============================================================================
// FUSED score + exp kernel. Block = (i-tile 64, bn). Sweeps all 16 j-tiles
// with 2-stage cp.async pipeline on k/rel. Writes unnormalized exp(score)
// as fp16 to P; writes reciprocal row-sums to rsum. No max-shift (scores
// are O(1); softmax is shift-invariant).
// ============================================================================
__global__ __launch_bounds__(256, 1) void score_softmax(
        const float* __restrict__ Q, const float* __restrict__ pbu,
        const float* __restrict__ pbv, const __half* __restrict__ KV,
        const __half* __restrict__ REL, const float* __restrict__ ib,
        __half* __restrict__ P, float* __restrict__ rsum) {
    extern __shared__ char smraw[];
    __half* qu_s  = (__half*)smraw;               // [64][72]
    __half* qv_s  = qu_s + 64 * 72;               // [64][72]
    __half* k_s   = qv_s + 64 * 72;               // [2][128*72]
    __half* rel_s = k_s + 2 * 128 * 72;           // [2][192*72]
    float*  bd_s  = (float*)(rel_s + 2 * 192 * 72);  // [64][200]
    float*  rows  = bd_s + 64 * 200;              // [64]

    int bn = blockIdx.y;
    int b = bn >> 3, n = bn & 7;
    int i0 = blockIdx.x * 64;
    int tid = threadIdx.x;

    // q (+bias, *scale) -> fp16 smem; init row sums
    if (tid < 64) rows[tid] = 0.f;
#pragma unroll
    for (int w = 0; w < 4; w++) {
        int idx = tid + w * 256;
        int r = idx >> 4, c4 = (idx & 15) * 4;
        float4 v = *(const float4*)(Q + (size_t)(i0 + r) * 2048 + b * 512 + n * 64 + c4);
        float4 bu = *(const float4*)(pbu + n * 64 + c4);
        float4 bv = *(const float4*)(pbv + n * 64 + c4);
        *(__half2*)(qu_s + r * 72 + c4) =
            __floats2half2_rn((v.x + bu.x) * SCALEF, (v.y + bu.y) * SCALEF);
        *(__half2*)(qu_s + r * 72 + c4 + 2) =
            __floats2half2_rn((v.z + bu.z) * SCALEF, (v.w + bu.w) * SCALEF);
        *(__half2*)(qv_s + r * 72 + c4) =
            __floats2half2_rn((v.x + bv.x) * SCALEF, (v.y + bv.y) * SCALEF);
        *(__half2*)(qv_s + r * 72 + c4 + 2) =
            __floats2half2_rn((v.z + bv.z) * SCALEF, (v.w + bv.w) * SCALEF);
    }

    const __half* Kb = KV + b * 1024 + n * 64;
    const __half* Rb = REL + b * 512 + n * 64;

    // stage loaders (cp.async): k tile 128 rows x 64 halves; rel band 192 rows
    auto loadK = [&](int st, int j0) {
#pragma unroll
        for (int w = 0; w < 4; w++) {
            int idx = tid + w * 256;
            int r = idx >> 3, ch = (idx & 7) * 8;
            cp16(k_s + st * 128 * 72 + r * 72 + ch,
                 Kb + (size_t)(j0 + r) * 4096 + ch);
        }
    };
    auto loadR = [&](int st, int j0) {
        int m0 = j0 + 448 - i0;
#pragma unroll
        for (int w = 0; w < 6; w++) {
            int idx = tid + w * 256;
            int r = idx >> 3, ch = (idx & 7) * 8;
            int mr = m0 + r; if (mr > 2047) mr = 2047;
            cp16(rel_s + st * 192 * 72 + r * 72 + ch,
                 Rb + (size_t)mr * 2048 + ch);
        }
    };

    loadK(0, 0); loadR(0, 0);
    CP_COMMIT();

    int warp = tid >> 5, lane = tid & 31;
    int g = lane >> 2, c = lane & 3;
    int wm  = (warp >> 2) * 32;
    int wnB = (warp & 3) * 48;
    int wnA = (warp & 3) * 32;

    float rs[4] = {0.f, 0.f, 0.f, 0.f};   // per-thread row-sum partials
    __half* Pb = P + ((size_t)bn * 512 + i0) * 2048;

    for (int jt = 0; jt < 16; jt++) {
        int cur = jt & 1;
        if (jt + 1 < 16) {
            int nxt = (jt + 1) & 1;
            loadK(nxt, (jt + 1) * 128);
            loadR(nxt, (jt + 1) * 128);
        }
        CP_COMMIT();
        CP_WAIT1();
        __syncthreads();

        const __half* kc = k_s + cur * 128 * 72;
        const __half* rc = rel_s + cur * 192 * 72;

        float accb[2][6][4];
        float acca[2][4][4];
#pragma unroll
        for (int mt = 0; mt < 2; mt++) {
#pragma unroll
            for (int nt = 0; nt < 6; nt++)
#pragma unroll
                for (int e = 0; e < 4; e++) accb[mt][nt][e] = 0.f;
#pragma unroll
            for (int nt = 0; nt < 4; nt++)
#pragma unroll
                for (int e = 0; e < 4; e++) acca[mt][nt][e] = 0.f;
        }

#pragma unroll
        for (int kk = 0; kk < 4; kk++) {
            int k = kk * 16;
            uint32_t au[2][4], av[2][4], bk[4][2], br[6][2];
#pragma unroll
            for (int mt = 0; mt < 2; mt++) {
                const __half* bu = qu_s + (wm + mt * 16 + g) * 72 + k + 2 * c;
                const __half* bv = qv_s + (wm + mt * 16 + g) * 72 + k + 2 * c;
                au[mt][0] = *(const uint32_t*)(bu);
                au[mt][1] = *(const uint32_t*)(bu + 8 * 72);
                au[mt][2] = *(const uint32_t*)(bu + 8);
                au[mt][3] = *(const uint32_t*)(bu + 8 * 72 + 8);
                av[mt][0] = *(const uint32_t*)(bv);
                av[mt][1] = *(const uint32_t*)(bv + 8 * 72);
                av[mt][2] = *(const uint32_t*)(bv + 8);
                av[mt][3] = *(const uint32_t*)(bv + 8 * 72 + 8);
            }
#pragma unroll
            for (int nt = 0; nt < 4; nt++) {
                const __half* base = kc + (wnA + nt * 8 + g) * 72 + k + 2 * c;
                bk[nt][0] = *(const uint32_t*)(base);
                bk[nt][1] = *(const uint32_t*)(base + 8);
            }
#pragma unroll
            for (int nt = 0; nt < 6; nt++) {
                const __half* base = rc + (wnB + nt * 8 + g) * 72 + k + 2 * c;
                br[nt][0] = *(const uint32_t*)(base);
                br[nt][1] = *(const uint32_t*)(base + 8);
            }
#pragma unroll
            for (int mt = 0; mt < 2; mt++) {
#pragma unroll
                for (int nt = 0; nt < 4; nt++)
                    mma_f16(acca[mt][nt], au[mt], bk[nt], acca[mt][nt]);
#pragma unroll
                for (int nt = 0; nt < 6; nt++)
                    mma_f16(accb[mt][nt], av[mt], br[nt], accb[mt][nt]);
            }
        }

        // stage BD band
#pragma unroll
        for (int mt = 0; mt < 2; mt++)
#pragma unroll
            for (int nt = 0; nt < 6; nt++) {
                int row = wm + mt * 16 + g;
                int col = wnB + nt * 8 + c * 2;
                *(float2*)(bd_s + row * 200 + col) =
                    make_float2(accb[mt][nt][0], accb[mt][nt][1]);
                *(float2*)(bd_s + (row + 8) * 200 + col) =
                    make_float2(accb[mt][nt][2], accb[mt][nt][3]);
            }
        __syncthreads();

        // epilogue: gates + shift + mask + exp -> P (fp16), accumulate sums
        int j0 = jt * 128;
#pragma unroll
        for (int mt = 0; mt < 2; mt++)
#pragma unroll
            for (int nt = 0; nt < 4; nt++) {
#pragma unroll
                for (int half = 0; half < 2; half++) {
                    int i_loc = wm + mt * 16 + g + half * 8;
                    int i = i0 + i_loc;
                    const float* gp = ib + ((size_t)i * 4 + b) * 4;
                    int jmax = 1536 + i;
                    float a0 = acca[mt][nt][half * 2];
                    float a1 = acca[mt][nt][half * 2 + 1];
                    float pe[2];
#pragma unroll
                    for (int e = 0; e < 2; e++) {
                        int j_loc = wnA + nt * 8 + c * 2 + e;
                        int j = j0 + j_loc;
                        int m = j + 511 - i;
                        int segB = m >> 9; if (segB > 3) segB = 3;
                        float bd = bd_s[i_loc * 200 + (j_loc + 63 - i_loc)];
                        float ac = e ? a1 : a0;
                        float s = gp[j >> 9] * ac + gp[segB] * bd;
                        pe[e] = (j <= jmax) ? __expf(s) : 0.f;
                    }
                    rs[mt * 2 + half] += pe[0] + pe[1];
                    *(__half2*)(Pb + (size_t)i_loc * 2048 + j0 + wnA + nt * 8 + c * 2) =
                        __floats2half2_rn(pe[0], pe[1]);
                }
            }
        __syncthreads();
    }

    // reduce row sums (16 threads contribute per row)
#pragma unroll
    for (int mt = 0; mt < 2; mt++)
#pragma unroll
        for (int half = 0; half < 2; half++) {
            int i_loc = wm + mt * 16 + g + half * 8;
            atomicAdd(&rows[i_loc], rs[mt * 2 + half]);
        }
    __syncthreads();
    if (tid < 64)
        rsum[(size_t)bn * 512 + i0 + tid] = 1.f / rows[tid];
}

// ---------------- attn matrix: mean over bn of normalized prob --------------
__global__ void attn_kernel(const __half* __restrict__ P,
                            const float* __restrict__ rsum,
                            float* __restrict__ attn) {
    int i = blockIdx.x;
    int tid = threadIdx.x;
    float acc[8] = {0.f, 0.f, 0.f, 0.f, 0.f, 0.f, 0.f, 0.f};
#pragma unroll 4
    for (int bn = 0; bn < 32; bn++) {
        float inv = rsum[(size_t)bn * 512 + i];
        const __half* prow = P + ((size_t)bn * 512 + i) * 2048 + tid * 8;
        uint4 raw = *(const uint4*)prow;
        const __half2* h2 = (const __half2*)&raw;
#pragma unroll
        for (int e = 0; e < 4; e++) {
            float2 f = __half22float2(h2[e]);
            acc[e * 2]     += inv * f.x;
            acc[e * 2 + 1] += inv * f.y;
        }
    }
    float* dst = attn + (size_t)i * 2048 + tid * 8;
#pragma unroll
    for (int e = 0; e < 8; e++) dst[e] = acc[e] * (1.f / 32.f);
}

// ============================================================================
// Batched Pexp(fp16) @ V(fp16): 64x64 tile, BK=64, 2-stage cp.async,
// ldmatrix.x4.trans for B fragments. Normalizes by rsum in epilogue.
// ============================================================================
#define PV_ST 72
__global__ __launch_bounds__(256) void pv_fp16(const __half* __restrict__ P,
                                               const __half* __restrict__ KV,
                                               const float* __restrict__ rsum,
                                               float* __restrict__ vec) {
    extern __shared__ char smraw[];
    __half* Ps = (__half*)smraw;              // [2][64*72]
    __half* Vs = Ps + 2 * 64 * PV_ST;         // [2][64*72]

    int bn = blockIdx.y;
    int b = bn >> 3, n = bn & 7;
    int i0 = blockIdx.x * 64;
    int tid = threadIdx.x;
    int warp = tid >> 5, lane = tid & 31;
    int g = lane >> 2, c = lane & 3;
    int wm = (warp >> 1) * 16;
    int wn = (warp & 1) * 32;

    int mat = lane >> 3;
    int lrow = (mat & 1) * 8 + (lane & 7);
    int lcol = (mat >> 1) * 8;

    const __half* Pb = P + ((size_t)bn * 512 + i0) * 2048;
    const __half* Vb = KV + b * 1024 + 512 + n * 64;

    float acc[4][4];
#pragma unroll
    for (int nt = 0; nt < 4; nt++)
#pragma unroll
        for (int e = 0; e < 4; e++) acc[nt][e] = 0.f;

    auto loadStage = [&](int st, int k0) {
#pragma unroll
        for (int w = 0; w < 2; w++) {
            int idx = tid + w * 256;
            int r = idx >> 3, ch = (idx & 7) * 8;
            cp16(Ps + st * 64 * PV_ST + r * PV_ST + ch,
                 Pb + (size_t)r * 2048 + k0 + ch);
        }
#pragma unroll
        for (int w = 0; w < 2; w++) {
            int idx = tid + w * 256;
            int r = idx >> 3, ch = (idx & 7) * 8;
            cp16(Vs + st * 64 * PV_ST + r * PV_ST + ch,
                 Vb + (size_t)(k0 + r) * 4096 + ch);
        }
    };

    loadStage(0, 0);
    CP_COMMIT();

    for (int kt = 0; kt < 32; kt++) {
        int cur = kt & 1;
        if (kt + 1 < 32) loadStage((kt + 1) & 1, (kt + 1) * 64);
        CP_COMMIT();
        CP_WAIT1();
        __syncthreads();

        const __half* Pc = Ps + cur * 64 * PV_ST;
        const __half* Vc = Vs + cur * 64 * PV_ST;
        uint32_t vbase = (uint32_t)__cvta_generic_to_shared(Vc);
#pragma unroll
        for (int kk = 0; kk < 4; kk++) {
            int k = kk * 16;
            uint32_t af[4];
            const __half* base = Pc + (wm + g) * PV_ST + k + c * 2;
            af[0] = *(const uint32_t*)(base);
            af[1] = *(const uint32_t*)(base + 8 * PV_ST);
            af[2] = *(const uint32_t*)(base + 8);
            af[3] = *(const uint32_t*)(base + 8 * PV_ST + 8);

            uint32_t bf[4][2];
#pragma unroll
            for (int p = 0; p < 2; p++) {
                uint32_t addr = vbase +
                    (uint32_t)(((k + lrow) * PV_ST + wn + p * 16 + lcol) * 2);
                uint32_t r0, r1, r2, r3;
                ldsm_x4_t(r0, r1, r2, r3, addr);
                bf[2 * p][0] = r0; bf[2 * p][1] = r1;
                bf[2 * p + 1][0] = r2; bf[2 * p + 1][1] = r3;
            }
#pragma unroll
            for (int nt = 0; nt < 4; nt++)
                mma_f16(acc[nt], af, bf[nt], acc[nt]);
        }
        __syncthreads();
    }

    int i = i0 + wm + g;
    float inv0 = rsum[(size_t)bn * 512 + i];
    float inv1 = rsum[(size_t)bn * 512 + i + 8];
#pragma unroll
    for (int nt = 0; nt < 4; nt++) {
        int col = n * 64 + wn + nt * 8 + c * 2;
        float* d0 = vec + ((size_t)i * 4 + b) * 512 + col;
        float* d1 = vec + ((size_t)(i + 8) * 4 + b) * 512 + col;
        *(float2*)d0 = make_float2(acc[nt][0] * inv0, acc[nt][1] * inv0);
        *(float2*)d1 = make_float2(acc[nt][2] * inv1, acc[nt][3] * inv1);
    }
}

// ---------------- layernorm ----------------
__global__ void ln_kernel(const float* __restrict__ y, const float* __restrict__ g,
                          const float* __restrict__ be, float* __restrict__ out) {
    __shared__ float red[32];
    int r = blockIdx.x;
    int tid = threadIdx.x;
    float v0 = y[(size_t)r * 512 + tid];
    float v1 = y[(size_t)r * 512 + tid + 256];
    float mean = blockRedSum(v0 + v1, red) * (1.f / 512.f);
    float d0 = v0 - mean, d1 = v1 - mean;
    float var = blockRedSum(d0 * d0 + d1 * d1, red) * (1.f / 512.f);
    float rstd = rsqrtf(var + 1e-5f);
    out[(size_t)r * 512 + tid]       = d0 * rstd * g[tid] + be[tid];
    out[(size_t)r * 512 + tid + 256] = d1 * rstd * g[tid + 256] + be[tid + 256];
}

// ---------------- launch ----------------
#define SMEM_G128 ((2 * 128 * 36 + 2 * 32 * 136) * 4)              // 71680
#define SMEM_G64  ((2 * 128 * 36 + 2 * 32 * 72) * 4)               // 55296
#define SMEM_SS   ((64*72*2 + 2*128*72 + 2*192*72) * 2 + 64*200*4 + 64*4)  // 162304
#define SMEM_PV   (4 * 64 * PV_ST * 2)                             // 36864

extern "C" void kernel_launch(void* const* d_in, const int* in_sizes, int n_in,
                              void* d_out, int out_size) {
    (void)in_sizes; (void)n_in; (void)out_size;
    const float* x       = (const float*)d_in[0];
    const float* memory  = (const float*)d_in[1];
    const float* pos_emb = (const float*)d_in[2];
    const float* pbu     = (const float*)d_in[3];
    const float* pbv     = (const float*)d_in[4];
    const float* ib      = (const float*)d_in[6];
    const float* W_q     = (const float*)d_in[7];
    const float* W_kv    = (const float*)d_in[8];
    const float* W_rel   = (const float*)d_in[9];
    const float* W_o     = (const float*)d_in[10];
    const float* ln_g    = (const float*)d_in[11];
    const float* ln_b    = (const float*)d_in[12];

    float* out  = (float*)d_out;
    float* attn = out + (size_t)Lq * BATCH * 512;

    __half *kvh, *relh, *prob;
    float *q, *rs, *vec, *y;
    cudaGetSymbolAddress((void**)&kvh,  g_kv);
    cudaGetSymbolAddress((void**)&relh, g_rel);
    cudaGetSymbolAddress((void**)&q,    g_q);
    cudaGetSymbolAddress((void**)&prob, g_prob);
    cudaGetSymbolAddress((void**)&rs,   g_rsum);
    cudaGetSymbolAddress((void**)&vec,  g_vec);
    cudaGetSymbolAddress((void**)&y,    g_y);

    static bool attr_set = false;
    if (!attr_set) {
        cudaFuncSetAttribute(proj_multi,
                             cudaFuncAttributeMaxDynamicSharedMemorySize, SMEM_G128);
        cudaFuncSetAttribute(gemm64,
                             cudaFuncAttributeMaxDynamicSharedMemorySize, SMEM_G64);
        cudaFuncSetAttribute(score_softmax,
                             cudaFuncAttributeMaxDynamicSharedMemorySize, SMEM_SS);
        cudaFuncSetAttribute(pv_fp16,
                             cudaFuncAttributeMaxDynamicSharedMemorySize, SMEM_PV);
        attr_set = true;
    }

    // 1) all 4 projections in one launch (kv, rel out fp16; q out fp32)
    Desc d0 = { memory,  W_kv,  (void*)kvh,                        1024, 512, 8, 0,   1 };
    Desc d1 = { x,       W_kv,  (void*)(kvh + (size_t)6144 * 1024),1024, 512, 8, 384, 1 };
    Desc d2 = { pos_emb, W_rel, (void*)relh,                       512,  512, 4, 512, 1 };
    Desc d3 = { x,       W_q,   (void*)q,                          512,  512, 4, 768, 0 };
    proj_multi<<<832, 256, SMEM_G128>>>(d0, d1, d2, d3);

    // 2) fused scores + exp + row sums (fp16 MMA, full-row blocks)
    score_softmax<<<dim3(8, 32), 256, SMEM_SS>>>(q, pbu, pbv, kvh, relh, ib, prob, rs);

    // 3) attn matrix from normalized prob
    attn_kernel<<<512, 256>>>(prob, rs, attn);

    // 4) vec = prob @ v (fp16 MMA, ldmatrix, pipelined), normalized in epilogue
    pv_fp16<<<dim3(8, 32), 256, SMEM_PV>>>(prob, kvh, rs, vec);

    // 5) y = x + vec @ W_o ; layernorm
    gemm64<<<dim3(8, 16), 256, SMEM_G64>>>(vec, W_o, x, y, 2048, 512, 512);
    ln_kernel<<<2048, 256>>>(y, ln_g, ln_b, out);
}

// round 9
// speedup vs baseline: 4.7302x; 1.0275x over previous
#include <cuda_runtime.h>
#include <cuda_fp16.h>
#include <stdint.h>

// Problem constants
#define Lq     512
#define BATCH  4
#define SCALEF 0.125f
#define LOG2E  1.4426950408889634f

// ---------------- scratch ----------------
__device__ __half g_kv  [(size_t)8192 * 1024];          // 16 MB  k | v (fp16)
__device__ __half g_rel [(size_t)8192 * 512];           //  8 MB  (fp16)
__device__ float  g_q   [(size_t)2048 * 512];           //  4 MB
__device__ __half g_prob[(size_t)32 * 512 * 2048];      // 64 MB unnormalized exp (fp16)
__device__ float  g_rsum[(size_t)32 * 512];             // 64 KB reciprocal row sums
__device__ float  g_vec [(size_t)2048 * 512];           //  4 MB
__device__ float  g_y   [(size_t)2048 * 512];           //  4 MB

// ---------------- helpers ----------------
__device__ __forceinline__ void mma_tf32(float* d, const uint32_t* a,
                                         const uint32_t* b, const float* c) {
    asm volatile(
        "mma.sync.aligned.m16n8k8.row.col.f32.tf32.tf32.f32 "
        "{%0,%1,%2,%3}, {%4,%5,%6,%7}, {%8,%9}, {%10,%11,%12,%13};"
        : "=f"(d[0]), "=f"(d[1]), "=f"(d[2]), "=f"(d[3])
        : "r"(a[0]), "r"(a[1]), "r"(a[2]), "r"(a[3]),
          "r"(b[0]), "r"(b[1]),
          "f"(c[0]), "f"(c[1]), "f"(c[2]), "f"(c[3]));
}

__device__ __forceinline__ void mma_f16(float* d, const uint32_t* a,
                                        const uint32_t* b, const float* c) {
    asm volatile(
        "mma.sync.aligned.m16n8k16.row.col.f32.f16.f16.f32 "
        "{%0,%1,%2,%3}, {%4,%5,%6,%7}, {%8,%9}, {%10,%11,%12,%13};"
        : "=f"(d[0]), "=f"(d[1]), "=f"(d[2]), "=f"(d[3])
        : "r"(a[0]), "r"(a[1]), "r"(a[2]), "r"(a[3]),
          "r"(b[0]), "r"(b[1]),
          "f"(c[0]), "f"(c[1]), "f"(c[2]), "f"(c[3]));
}

__device__ __forceinline__ void ldsm_x4_t(uint32_t& r0, uint32_t& r1,
                                          uint32_t& r2, uint32_t& r3, uint32_t addr) {
    asm volatile("ldmatrix.sync.aligned.m8n8.x4.trans.shared.b16 {%0,%1,%2,%3}, [%4];"
                 : "=r"(r0), "=r"(r1), "=r"(r2), "=r"(r3) : "r"(addr));
}

__device__ __forceinline__ void cp16(void* dst, const void* src) {
    uint32_t d = (uint32_t)__cvta_generic_to_shared(dst);
    asm volatile("cp.async.cg.shared.global [%0], [%1], 16;" :: "r"(d), "l"(src));
}
#define CP_COMMIT() asm volatile("cp.async.commit_group;")
#define CP_WAIT1()  asm volatile("cp.async.wait_group 1;")
#define CP_WAIT2()  asm volatile("cp.async.wait_group 2;")

__device__ __forceinline__ float ex2f(float x) {
    float r;
    asm("ex2.approx.f32 %0, %1;" : "=f"(r) : "f"(x));
    return r;
}

__device__ __forceinline__ float warpRedSum(float v) {
#pragma unroll
    for (int o = 16; o > 0; o >>= 1) v += __shfl_xor_sync(0xffffffffu, v, o);
    return v;
}
__device__ __forceinline__ float blockRedSum(float v, float* red) {
    v = warpRedSum(v);
    int w = threadIdx.x >> 5, l = threadIdx.x & 31;
    if (!l) red[w] = v;
    __syncthreads();
    if (threadIdx.x < 32) {
        float x = (l < 8) ? red[l] : 0.f;
        x = warpRedSum(x);
        if (!l) red[0] = x;
    }
    __syncthreads();
    float r = red[0];
    __syncthreads();
    return r;
}

// ============================================================================
// Combined projection kernel (4 GEMMs, one launch). tf32, 3-stage cp.async.
// ============================================================================
struct Desc {
    const float* A; const float* B; void* C;
    int N, K, nblk, blk0, h;
};

__global__ __launch_bounds__(256) void proj_multi(Desc d0, Desc d1, Desc d2, Desc d3) {
    extern __shared__ float sm[];
    float* As = sm;                    // [3][128*36]
    float* Bs = sm + 3 * 128 * 36;     // [3][32*136]

    Desc d = d3;
    int bid = blockIdx.x;
    if (bid < d1.blk0) d = d0;
    else if (bid < d2.blk0) d = d1;
    else if (bid < d3.blk0) d = d2;
    int local = bid - d.blk0;
    int m0 = (local / d.nblk) * 128, n0 = (local % d.nblk) * 128;
    const int N = d.N, K = d.K;

    int tid = threadIdx.x;
    int warp = tid >> 5, lane = tid & 31;
    int g = lane >> 2, c = lane & 3;
    int wm = (warp >> 2) * 64;
    int wn = (warp & 3) * 32;

    float acc[4][4][4];
#pragma unroll
    for (int mt = 0; mt < 4; mt++)
#pragma unroll
        for (int nt = 0; nt < 4; nt++)
#pragma unroll
            for (int e = 0; e < 4; e++) acc[mt][nt][e] = 0.f;

    int nk = K >> 5;
    auto loadStage = [&](int st, int k0) {
#pragma unroll
        for (int w = 0; w < 4; w++) {
            int idx = tid + w * 256;
            int r = idx >> 3, cc = (idx & 7) * 4;
            cp16(As + st * 128 * 36 + r * 36 + cc,
                 d.A + (size_t)(m0 + r) * K + k0 + cc);
        }
#pragma unroll
        for (int w = 0; w < 4; w++) {
            int idx = tid + w * 256;
            int r = idx >> 5, cc = (idx & 31) * 4;
            cp16(Bs + st * 32 * 136 + r * 136 + cc,
                 d.B + (size_t)(k0 + r) * N + n0 + cc);
        }
    };

    loadStage(0, 0);
    CP_COMMIT();
    loadStage(1, 32);
    CP_COMMIT();

    int st = 0;
    for (int kt = 0; kt < nk; kt++) {
        if (kt + 2 < nk) {
            int s2 = (st + 2) % 3;
            loadStage(s2, (kt + 2) * 32);
        }
        CP_COMMIT();
        CP_WAIT2();
        __syncthreads();

        const float* Ac = As + st * 128 * 36;
        const float* Bc = Bs + st * 32 * 136;
#pragma unroll
        for (int kk = 0; kk < 4; kk++) {
            int k = kk * 8;
            uint32_t af[4][4], bf[4][2];
#pragma unroll
            for (int mt = 0; mt < 4; mt++) {
                const float* base = Ac + (wm + mt * 16 + g) * 36 + k + c;
                af[mt][0] = __float_as_uint(base[0]);
                af[mt][1] = __float_as_uint(base[8 * 36]);
                af[mt][2] = __float_as_uint(base[4]);
                af[mt][3] = __float_as_uint(base[8 * 36 + 4]);
            }
#pragma unroll
            for (int nt = 0; nt < 4; nt++) {
                const float* base = Bc + (k + c) * 136 + wn + nt * 8 + g;
                bf[nt][0] = __float_as_uint(base[0]);
                bf[nt][1] = __float_as_uint(base[4 * 136]);
            }
#pragma unroll
            for (int mt = 0; mt < 4; mt++)
#pragma unroll
                for (int nt = 0; nt < 4; nt++)
                    mma_tf32(acc[mt][nt], af[mt], bf[nt], acc[mt][nt]);
        }
        __syncthreads();
        st = (st + 1) % 3;
    }

#pragma unroll
    for (int mt = 0; mt < 4; mt++)
#pragma unroll
        for (int nt = 0; nt < 4; nt++) {
            int row = m0 + wm + mt * 16 + g;
            int col = n0 + wn + nt * 8 + c * 2;
            if (d.h) {
                __half* Ch = (__half*)d.C;
                *(__half2*)(Ch + (size_t)row * N + col) =
                    __floats2half2_rn(acc[mt][nt][0], acc[mt][nt][1]);
                *(__half2*)(Ch + (size_t)(row + 8) * N + col) =
                    __floats2half2_rn(acc[mt][nt][2], acc[mt][nt][3]);
            } else {
                float* Cf = (float*)d.C;
                *(float2*)(Cf + (size_t)row * N + col) =
                    make_float2(acc[mt][nt][0], acc[mt][nt][1]);
                *(float2*)(Cf + (size_t)(row + 8) * N + col) =
                    make_float2(acc[mt][nt][2], acc[mt][nt][3]);
            }
        }
}

// ============================================================================
// Pipelined tf32 GEMM, BN=64 (for W_o with residual add)
// ============================================================================
__global__ __launch_bounds__(256) void gemm64(
        const float* __restrict__ A, const float* __restrict__ B,
        const float* __restrict__ Cadd, float* __restrict__ C,
        int M, int N, int K) {
    extern __shared__ float sm[];
    const int BST = 72;
    float* As = sm;
    float* Bs = sm + 2 * 128 * 36;

    int m0 = blockIdx.y * 128, n0 = blockIdx.x * 64;
    int tid = threadIdx.x;
    int warp = tid >> 5, lane = tid & 31;
    int g = lane >> 2, c = lane & 3;
    int wm = (warp >> 2) * 64;
    int wn = (warp & 3) * 16;

    float acc[4][2][4];
#pragma unroll
    for (int mt = 0; mt < 4; mt++)
#pragma unroll
        for (int nt = 0; nt < 2; nt++)
#pragma unroll
            for (int e = 0; e < 4; e++) acc[mt][nt][e] = 0.f;

    int nk = K >> 5;
    {
#pragma unroll
        for (int w = 0; w < 4; w++) {
            int idx = tid + w * 256;
            int r = idx >> 3, cc = (idx & 7) * 4;
            cp16(As + r * 36 + cc, A + (size_t)(m0 + r) * K + cc);
        }
#pragma unroll
        for (int w = 0; w < 2; w++) {
            int idx = tid + w * 256;
            int r = idx >> 4, cc = (idx & 15) * 4;
            cp16(Bs + r * BST + cc, B + (size_t)r * N + n0 + cc);
        }
    }
    CP_COMMIT();

    for (int kt = 0; kt < nk; kt++) {
        int cur = kt & 1;
        if (kt + 1 < nk) {
            int nxt = (kt + 1) & 1;
            int k0 = (kt + 1) * 32;
#pragma unroll
            for (int w = 0; w < 4; w++) {
                int idx = tid + w * 256;
                int r = idx >> 3, cc = (idx & 7) * 4;
                cp16(As + nxt * 128 * 36 + r * 36 + cc,
                     A + (size_t)(m0 + r) * K + k0 + cc);
            }
#pragma unroll
            for (int w = 0; w < 2; w++) {
                int idx = tid + w * 256;
                int r = idx >> 4, cc = (idx & 15) * 4;
                cp16(Bs + nxt * 32 * BST + r * BST + cc,
                     B + (size_t)(k0 + r) * N + n0 + cc);
            }
        }
        CP_COMMIT();
        CP_WAIT1();
        __syncthreads();

        const float* Ac = As + cur * 128 * 36;
        const float* Bc = Bs + cur * 32 * BST;
#pragma unroll
        for (int kk = 0; kk < 4; kk++) {
            int k = kk * 8;
            uint32_t af[4][4], bf[2][2];
#pragma unroll
            for (int mt = 0; mt < 4; mt++) {
                const float* base = Ac + (wm + mt * 16 + g) * 36 + k + c;
                af[mt][0] = __float_as_uint(base[0]);
                af[mt][1] = __float_as_uint(base[8 * 36]);
                af[mt][2] = __float_as_uint(base[4]);
                af[mt][3] = __float_as_uint(base[8 * 36 + 4]);
            }
#pragma unroll
            for (int nt = 0; nt < 2; nt++) {
                const float* base = Bc + (k + c) * BST + wn + nt * 8 + g;
                bf[nt][0] = __float_as_uint(base[0]);
                bf[nt][1] = __float_as_uint(base[4 * BST]);
            }
#pragma unroll
            for (int mt = 0; mt < 4; mt++)
#pragma unroll
                for (int nt = 0; nt < 2; nt++)
                    mma_tf32(acc[mt][nt], af[mt], bf[nt], acc[mt][nt]);
        }
        __syncthreads();
    }

#pragma unroll
    for (int mt = 0; mt < 4; mt++)
#pragma unroll
        for (int nt = 0; nt < 2; nt++) {
            int row = m0 + wm + mt * 16 + g;
            int col = n0 + wn + nt * 8 + c * 2;
            float* p0 = C + (size_t)row * N + col;
            float* p1 = C + (size_t)(row + 8) * N + col;
            float2 v0 = make_float2(acc[mt][nt][0], acc[mt][nt][1]);
            float2 v1 = make_float2(acc[mt][nt][2], acc[mt][nt][3]);
            if (Cadd) {
                const float* a0 = Cadd + (size_t)row * N + col;
                const float* a1 = Cadd + (size_t)(row + 8) * N + col;
                v0.x += a0[0]; v0.y += a0[1];
                v1.x += a1[0]; v1.y += a1[1];
            }
            *(float2*)p0 = v0;
            *(float2*)p1 = v1;
        }
}

// ============================================================================
// FLASH-FUSED score + exp + PV kernel. Block = (i-tile 64, bn).
// Sweeps 16 j-tiles; per tile: AC + BD-band MMA -> gates/shift/mask/exp ->
// writes unnormalized exp to P (fp16), feeds the same fragments directly as
// MMA A-operands against V (ldmatrix.trans) accumulating vec in registers.
// Epilogue: cross-warp reduce vec, normalize by row sums, write vec + rsum.
// exp computed as ex2 (log2e folded into q scaling).
// ============================================================================
__global__ __launch_bounds__(256, 1) void score_pv(
        const float* __restrict__ Q, const float* __restrict__ pbu,
        const float* __restrict__ pbv, const __half* __restrict__ KV,
        const __half* __restrict__ REL, const float* __restrict__ ib,
        __half* __restrict__ P, float* __restrict__ rsum,
        float* __restrict__ vec) {
    extern __shared__ char smraw[];
    __half* qu_s  = (__half*)smraw;               // [64][72]
    __half* qv_s  = qu_s + 64 * 72;               // [64][72]
    __half* k_s   = qv_s + 64 * 72;               // [2][128*72]
    __half* v_s   = k_s + 2 * 128 * 72;           // [2][128*72]
    __half* rel_s = v_s + 2 * 128 * 72;           // [2][192*72]
    float*  bd_s  = (float*)(rel_s + 2 * 192 * 72);  // [64][200]
    float*  vb    = bd_s + 64 * 200;              // [64][68]
    float*  rows  = vb + 64 * 68;                 // [64]

    int bn = blockIdx.y;
    int b = bn >> 3, n = bn & 7;
    int i0 = blockIdx.x * 64;
    int tid = threadIdx.x;

    // init row sums + vec buffer
    if (tid < 64) rows[tid] = 0.f;
#pragma unroll
    for (int w = 0; w < 17; w++) {
        int idx = tid + w * 256;
        if (idx < 64 * 68) vb[idx] = 0.f;
    }

    // q (+bias, *scale*log2e) -> fp16 smem, both copies
    const float QS = SCALEF * LOG2E;
#pragma unroll
    for (int w = 0; w < 4; w++) {
        int idx = tid + w * 256;
        int r = idx >> 4, c4 = (idx & 15) * 4;
        float4 v = *(const float4*)(Q + (size_t)(i0 + r) * 2048 + b * 512 + n * 64 + c4);
        float4 bu = *(const float4*)(pbu + n * 64 + c4);
        float4 bv = *(const float4*)(pbv + n * 64 + c4);
        *(__half2*)(qu_s + r * 72 + c4) =
            __floats2half2_rn((v.x + bu.x) * QS, (v.y + bu.y) * QS);
        *(__half2*)(qu_s + r * 72 + c4 + 2) =
            __floats2half2_rn((v.z + bu.z) * QS, (v.w + bu.w) * QS);
        *(__half2*)(qv_s + r * 72 + c4) =
            __floats2half2_rn((v.x + bv.x) * QS, (v.y + bv.y) * QS);
        *(__half2*)(qv_s + r * 72 + c4 + 2) =
            __floats2half2_rn((v.z + bv.z) * QS, (v.w + bv.w) * QS);
    }

    const __half* Kb = KV + b * 1024 + n * 64;
    const __half* Vb = KV + b * 1024 + 512 + n * 64;
    const __half* Rb = REL + b * 512 + n * 64;

    auto loadK = [&](int st, int j0) {
#pragma unroll
        for (int w = 0; w < 4; w++) {
            int idx = tid + w * 256;
            int r = idx >> 3, ch = (idx & 7) * 8;
            cp16(k_s + st * 128 * 72 + r * 72 + ch,
                 Kb + (size_t)(j0 + r) * 4096 + ch);
        }
    };
    auto loadV = [&](int st, int j0) {
#pragma unroll
        for (int w = 0; w < 4; w++) {
            int idx = tid + w * 256;
            int r = idx >> 3, ch = (idx & 7) * 8;
            cp16(v_s + st * 128 * 72 + r * 72 + ch,
                 Vb + (size_t)(j0 + r) * 4096 + ch);
        }
    };
    auto loadR = [&](int st, int j0) {
        int m0 = j0 + 448 - i0;
#pragma unroll
        for (int w = 0; w < 6; w++) {
            int idx = tid + w * 256;
            int r = idx >> 3, ch = (idx & 7) * 8;
            int mr = m0 + r; if (mr > 2047) mr = 2047;
            cp16(rel_s + st * 192 * 72 + r * 72 + ch,
                 Rb + (size_t)mr * 2048 + ch);
        }
    };

    loadK(0, 0); loadV(0, 0); loadR(0, 0);
    CP_COMMIT();

    int warp = tid >> 5, lane = tid & 31;
    int g = lane >> 2, c = lane & 3;
    int wm  = (warp >> 2) * 32;
    int wnB = (warp & 3) * 48;
    int wnA = (warp & 3) * 32;

    // ldmatrix lane mapping
    int mat = lane >> 3;
    int lrow = (mat & 1) * 8 + (lane & 7);
    int lcol = (mat >> 1) * 8;

    float rs[4] = {0.f, 0.f, 0.f, 0.f};
    float pvacc[2][8][4];
#pragma unroll
    for (int mt = 0; mt < 2; mt++)
#pragma unroll
        for (int nd = 0; nd < 8; nd++)
#pragma unroll
            for (int e = 0; e < 4; e++) pvacc[mt][nd][e] = 0.f;

    __half* Pb = P + ((size_t)bn * 512 + i0) * 2048;

    for (int jt = 0; jt < 16; jt++) {
        int cur = jt & 1;
        if (jt + 1 < 16) {
            int nxt = (jt + 1) & 1;
            loadK(nxt, (jt + 1) * 128);
            loadV(nxt, (jt + 1) * 128);
            loadR(nxt, (jt + 1) * 128);
        }
        CP_COMMIT();
        CP_WAIT1();
        __syncthreads();

        const __half* kc = k_s + cur * 128 * 72;
        const __half* rc = rel_s + cur * 192 * 72;

        float accb[2][6][4];
        float acca[2][4][4];
#pragma unroll
        for (int mt = 0; mt < 2; mt++) {
#pragma unroll
            for (int nt = 0; nt < 6; nt++)
#pragma unroll
                for (int e = 0; e < 4; e++) accb[mt][nt][e] = 0.f;
#pragma unroll
            for (int nt = 0; nt < 4; nt++)
#pragma unroll
                for (int e = 0; e < 4; e++) acca[mt][nt][e] = 0.f;
        }

#pragma unroll
        for (int kk = 0; kk < 4; kk++) {
            int k = kk * 16;
            uint32_t au[2][4], av[2][4], bk[4][2], br[6][2];
#pragma unroll
            for (int mt = 0; mt < 2; mt++) {
                const __half* bu = qu_s + (wm + mt * 16 + g) * 72 + k + 2 * c;
                const __half* bv = qv_s + (wm + mt * 16 + g) * 72 + k + 2 * c;
                au[mt][0] = *(const uint32_t*)(bu);
                au[mt][1] = *(const uint32_t*)(bu + 8 * 72);
                au[mt][2] = *(const uint32_t*)(bu + 8);
                au[mt][3] = *(const uint32_t*)(bu + 8 * 72 + 8);
                av[mt][0] = *(const uint32_t*)(bv);
                av[mt][1] = *(const uint32_t*)(bv + 8 * 72);
                av[mt][2] = *(const uint32_t*)(bv + 8);
                av[mt][3] = *(const uint32_t*)(bv + 8 * 72 + 8);
            }
#pragma unroll
            for (int nt = 0; nt < 4; nt++) {
                const __half* base = kc + (wnA + nt * 8 + g) * 72 + k + 2 * c;
                bk[nt][0] = *(const uint32_t*)(base);
                bk[nt][1] = *(const uint32_t*)(base + 8);
            }
#pragma unroll
            for (int nt = 0; nt < 6; nt++) {
                const __half* base = rc + (wnB + nt * 8 + g) * 72 + k + 2 * c;
                br[nt][0] = *(const uint32_t*)(base);
                br[nt][1] = *(const uint32_t*)(base + 8);
            }
#pragma unroll
            for (int mt = 0; mt < 2; mt++) {
#pragma unroll
                for (int nt = 0; nt < 4; nt++)
                    mma_f16(acca[mt][nt], au[mt], bk[nt], acca[mt][nt]);
#pragma unroll
                for (int nt = 0; nt < 6; nt++)
                    mma_f16(accb[mt][nt], av[mt], br[nt], accb[mt][nt]);
            }
        }

        // stage BD band
#pragma unroll
        for (int mt = 0; mt < 2; mt++)
#pragma unroll
            for (int nt = 0; nt < 6; nt++) {
                int row = wm + mt * 16 + g;
                int col = wnB + nt * 8 + c * 2;
                *(float2*)(bd_s + row * 200 + col) =
                    make_float2(accb[mt][nt][0], accb[mt][nt][1]);
                *(float2*)(bd_s + (row + 8) * 200 + col) =
                    make_float2(accb[mt][nt][2], accb[mt][nt][3]);
            }
        __syncthreads();

        // epilogue: gates + shift + mask + ex2 -> P (fp16) + keep fragments
        int j0 = jt * 128;
        uint32_t pe2[2][4][2];   // [mt][nt][half] = half2(pe0, pe1)
#pragma unroll
        for (int mt = 0; mt < 2; mt++)
#pragma unroll
            for (int nt = 0; nt < 4; nt++) {
#pragma unroll
                for (int half = 0; half < 2; half++) {
                    int i_loc = wm + mt * 16 + g + half * 8;
                    int i = i0 + i_loc;
                    const float* gp = ib + ((size_t)i * 4 + b) * 4;
                    int jmax = 1536 + i;
                    float a0 = acca[mt][nt][half * 2];
                    float a1 = acca[mt][nt][half * 2 + 1];
                    float pe[2];
#pragma unroll
                    for (int e = 0; e < 2; e++) {
                        int j_loc = wnA + nt * 8 + c * 2 + e;
                        int j = j0 + j_loc;
                        int m = j + 511 - i;
                        int segB = m >> 9; if (segB > 3) segB = 3;
                        float bd = bd_s[i_loc * 200 + (j_loc + 63 - i_loc)];
                        float ac = e ? a1 : a0;
                        float s = gp[j >> 9] * ac + gp[segB] * bd;
                        pe[e] = (j <= jmax) ? ex2f(s) : 0.f;
                    }
                    rs[mt * 2 + half] += pe[0] + pe[1];
                    __half2 h2 = __floats2half2_rn(pe[0], pe[1]);
                    pe2[mt][nt][half] = *(uint32_t*)&h2;
                    *(__half2*)(Pb + (size_t)i_loc * 2048 + j0 + wnA + nt * 8 + c * 2) = h2;
                }
            }

        // PV: A = exp'd fragments (k-slice = warp's 32 j-cols), B = V (ldmatrix)
        {
            uint32_t vbase = (uint32_t)__cvta_generic_to_shared(v_s + cur * 128 * 72);
#pragma unroll
            for (int kk2 = 0; kk2 < 2; kk2++) {
                uint32_t bf[8][2];
#pragma unroll
                for (int p = 0; p < 4; p++) {
                    uint32_t addr = vbase +
                        (uint32_t)(((wnA + kk2 * 16 + lrow) * 72 + p * 16 + lcol) * 2);
                    uint32_t r0, r1, r2, r3;
                    ldsm_x4_t(r0, r1, r2, r3, addr);
                    bf[2 * p][0] = r0; bf[2 * p][1] = r1;
                    bf[2 * p + 1][0] = r2; bf[2 * p + 1][1] = r3;
                }
#pragma unroll
                for (int mt = 0; mt < 2; mt++) {
                    uint32_t af[4];
                    af[0] = pe2[mt][2 * kk2][0];
                    af[1] = pe2[mt][2 * kk2][1];
                    af[2] = pe2[mt][2 * kk2 + 1][0];
                    af[3] = pe2[mt][2 * kk2 + 1][1];
#pragma unroll
                    for (int nd = 0; nd < 8; nd++)
                        mma_f16(pvacc[mt][nd], af, bf[nd], pvacc[mt][nd]);
                }
            }
        }
        __syncthreads();
    }

    // row sums
#pragma unroll
    for (int mt = 0; mt < 2; mt++)
#pragma unroll
        for (int half = 0; half < 2; half++) {
            int i_loc = wm + mt * 16 + g + half * 8;
            atomicAdd(&rows[i_loc], rs[mt * 2 + half]);
        }
    __syncthreads();
    if (tid < 64) rows[tid] = 1.f / rows[tid];   // now reciprocal

    // cross-warp vec reduction (4 rounds over wnA groups)
    for (int r = 0; r < 4; r++) {
        if ((warp & 3) == r) {
#pragma unroll
            for (int mt = 0; mt < 2; mt++)
#pragma unroll
                for (int nd = 0; nd < 8; nd++)
#pragma unroll
                    for (int e = 0; e < 4; e++) {
                        int row = wm + mt * 16 + g + ((e >> 1) ? 8 : 0);
                        int col = nd * 8 + c * 2 + (e & 1);
                        vb[row * 68 + col] += pvacc[mt][nd][e];
                    }
        }
        __syncthreads();
    }

    // normalize + write vec and rsum
#pragma unroll
    for (int t = 0; t < 16; t++) {
        int e = tid + t * 256;              // 0..4095
        int row = e >> 6, col = e & 63;
        vec[((size_t)(i0 + row) * 4 + b) * 512 + n * 64 + col] =
            vb[row * 68 + col] * rows[row];
    }
    if (tid < 64)
        rsum[(size_t)bn * 512 + i0 + tid] = rows[tid];
}

// ---------------- attn matrix: mean over bn of normalized prob --------------
__global__ void attn_kernel(const __half* __restrict__ P,
                            const float* __restrict__ rsum,
                            float* __restrict__ attn) {
    int i = blockIdx.x;
    int tid = threadIdx.x;
    float acc[8] = {0.f, 0.f, 0.f, 0.f, 0.f, 0.f, 0.f, 0.f};
#pragma unroll 4
    for (int bn = 0; bn < 32; bn++) {
        float inv = rsum[(size_t)bn * 512 + i];
        const __half* prow = P + ((size_t)bn * 512 + i) * 2048 + tid * 8;
        uint4 raw = *(const uint4*)prow;
        const __half2* h2 = (const __half2*)&raw;
#pragma unroll
        for (int e = 0; e < 4; e++) {
            float2 f = __half22float2(h2[e]);
            acc[e * 2]     += inv * f.x;
            acc[e * 2 + 1] += inv * f.y;
        }
    }
    float* dst = attn + (size_t)i * 2048 + tid * 8;
#pragma unroll
    for (int e = 0; e < 8; e++) dst[e] = acc[e] * (1.f / 32.f);
}

// ---------------- layernorm ----------------
__global__ void ln_kernel(const float* __restrict__ y, const float* __restrict__ g,
                          const float* __restrict__ be, float* __restrict__ out) {
    __shared__ float red[32];
    int r = blockIdx.x;
    int tid = threadIdx.x;
    float v0 = y[(size_t)r * 512 + tid];
    float v1 = y[(size_t)r * 512 + tid + 256];
    float mean = blockRedSum(v0 + v1, red) * (1.f / 512.f);
    float d0 = v0 - mean, d1 = v1 - mean;
    float var = blockRedSum(d0 * d0 + d1 * d1, red) * (1.f / 512.f);
    float rstd = rsqrtf(var + 1e-5f);
    out[(size_t)r * 512 + tid]       = d0 * rstd * g[tid] + be[tid];
    out[(size_t)r * 512 + tid + 256] = d1 * rstd * g[tid + 256] + be[tid + 256];
}

// ---------------- launch ----------------
#define SMEM_P3  ((3 * 128 * 36 + 3 * 32 * 136) * 4)               // 107520
#define SMEM_G64 ((2 * 128 * 36 + 2 * 32 * 72) * 4)                // 55296
#define SMEM_SPV ((64*72*2 + 2*128*72 + 2*128*72 + 2*192*72) * 2 \
                  + (64*200 + 64*68 + 64) * 4)                     // 216320

extern "C" void kernel_launch(void* const* d_in, const int* in_sizes, int n_in,
                              void* d_out, int out_size) {
    (void)in_sizes; (void)n_in; (void)out_size;
    const float* x       = (const float*)d_in[0];
    const float* memory  = (const float*)d_in[1];
    const float* pos_emb = (const float*)d_in[2];
    const float* pbu     = (const float*)d_in[3];
    const float* pbv     = (const float*)d_in[4];
    const float* ib      = (const float*)d_in[6];
    const float* W_q     = (const float*)d_in[7];
    const float* W_kv    = (const float*)d_in[8];
    const float* W_rel   = (const float*)d_in[9];
    const float* W_o     = (const float*)d_in[10];
    const float* ln_g    = (const float*)d_in[11];
    const float* ln_b    = (const float*)d_in[12];

    float* out  = (float*)d_out;
    float* attn = out + (size_t)Lq * BATCH * 512;

    __half *kvh, *relh, *prob;
    float *q, *rs, *vec, *y;
    cudaGetSymbolAddress((void**)&kvh,  g_kv);
    cudaGetSymbolAddress((void**)&relh, g_rel);
    cudaGetSymbolAddress((void**)&q,    g_q);
    cudaGetSymbolAddress((void**)&prob, g_prob);
    cudaGetSymbolAddress((void**)&rs,   g_rsum);
    cudaGetSymbolAddress((void**)&vec,  g_vec);
    cudaGetSymbolAddress((void**)&y,    g_y);

    static bool attr_set = false;
    if (!attr_set) {
        cudaFuncSetAttribute(proj_multi,
                             cudaFuncAttributeMaxDynamicSharedMemorySize, SMEM_P3);
        cudaFuncSetAttribute(gemm64,
                             cudaFuncAttributeMaxDynamicSharedMemorySize, SMEM_G64);
        cudaFuncSetAttribute(score_pv,
                             cudaFuncAttributeMaxDynamicSharedMemorySize, SMEM_SPV);
        attr_set = true;
    }

    // 1) all 4 projections in one launch (kv, rel out fp16; q out fp32)
    Desc d0 = { memory,  W_kv,  (void*)kvh,                        1024, 512, 8, 0,   1 };
    Desc d1 = { x,       W_kv,  (void*)(kvh + (size_t)6144 * 1024),1024, 512, 8, 384, 1 };
    Desc d2 = { pos_emb, W_rel, (void*)relh,                       512,  512, 4, 512, 1 };
    Desc d3 = { x,       W_q,   (void*)q,                          512,  512, 4, 768, 0 };
    proj_multi<<<832, 256, SMEM_P3>>>(d0, d1, d2, d3);

    // 2) fused scores + exp + PV (writes prob, rsum, vec)
    score_pv<<<dim3(8, 32), 256, SMEM_SPV>>>(q, pbu, pbv, kvh, relh, ib,
                                             prob, rs, vec);

    // 3) attn matrix from normalized prob
    attn_kernel<<<512, 256>>>(prob, rs, attn);

    // 4) y = x + vec @ W_o ; layernorm
    gemm64<<<dim3(8, 16), 256, SMEM_G64>>>(vec, W_o, x, y, 2048, 512, 512);
    ln_kernel<<<2048, 256>>>(y, ln_g, ln_b, out);
}

// round 10
// speedup vs baseline: 5.1965x; 1.0986x over previous
#include <cuda_runtime.h>
#include <cuda_fp16.h>
#include <stdint.h>

// Problem constants
#define Lq     512
#define BATCH  4
#define SCALEF 0.125f
#define LOG2E  1.4426950408889634f

// ---------------- scratch ----------------
__device__ __half g_kv  [(size_t)8192 * 1024];          // 16 MB  k | v (fp16)
__device__ __half g_rel [(size_t)8192 * 512];           //  8 MB  (fp16)
__device__ float  g_q   [(size_t)2048 * 512];           //  4 MB
__device__ __half g_prob[(size_t)32 * 512 * 2048];      // 64 MB unnormalized exp (fp16)
__device__ float  g_rsum[(size_t)32 * 512];             // 64 KB reciprocal row sums
__device__ float  g_vec [(size_t)2048 * 512];           //  4 MB
__device__ float  g_y   [(size_t)2048 * 512];           //  4 MB

// ---------------- helpers ----------------
__device__ __forceinline__ void mma_tf32(float* d, const uint32_t* a,
                                         const uint32_t* b, const float* c) {
    asm volatile(
        "mma.sync.aligned.m16n8k8.row.col.f32.tf32.tf32.f32 "
        "{%0,%1,%2,%3}, {%4,%5,%6,%7}, {%8,%9}, {%10,%11,%12,%13};"
        : "=f"(d[0]), "=f"(d[1]), "=f"(d[2]), "=f"(d[3])
        : "r"(a[0]), "r"(a[1]), "r"(a[2]), "r"(a[3]),
          "r"(b[0]), "r"(b[1]),
          "f"(c[0]), "f"(c[1]), "f"(c[2]), "f"(c[3]));
}

__device__ __forceinline__ void mma_f16(float* d, const uint32_t* a,
                                        const uint32_t* b, const float* c) {
    asm volatile(
        "mma.sync.aligned.m16n8k16.row.col.f32.f16.f16.f32 "
        "{%0,%1,%2,%3}, {%4,%5,%6,%7}, {%8,%9}, {%10,%11,%12,%13};"
        : "=f"(d[0]), "=f"(d[1]), "=f"(d[2]), "=f"(d[3])
        : "r"(a[0]), "r"(a[1]), "r"(a[2]), "r"(a[3]),
          "r"(b[0]), "r"(b[1]),
          "f"(c[0]), "f"(c[1]), "f"(c[2]), "f"(c[3]));
}

__device__ __forceinline__ void ldsm_x4_t(uint32_t& r0, uint32_t& r1,
                                          uint32_t& r2, uint32_t& r3, uint32_t addr) {
    asm volatile("ldmatrix.sync.aligned.m8n8.x4.trans.shared.b16 {%0,%1,%2,%3}, [%4];"
                 : "=r"(r0), "=r"(r1), "=r"(r2), "=r"(r3) : "r"(addr));
}

__device__ __forceinline__ void cp16(void* dst, const void* src) {
    uint32_t d = (uint32_t)__cvta_generic_to_shared(dst);
    asm volatile("cp.async.cg.shared.global [%0], [%1], 16;" :: "r"(d), "l"(src));
}
#define CP_COMMIT() asm volatile("cp.async.commit_group;")
#define CP_WAIT1()  asm volatile("cp.async.wait_group 1;")
#define CP_WAIT2()  asm volatile("cp.async.wait_group 2;")

__device__ __forceinline__ float ex2f(float x) {
    float r;
    asm("ex2.approx.f32 %0, %1;" : "=f"(r) : "f"(x));
    return r;
}

__device__ __forceinline__ float warpRedSum(float v) {
#pragma unroll
    for (int o = 16; o > 0; o >>= 1) v += __shfl_xor_sync(0xffffffffu, v, o);
    return v;
}
__device__ __forceinline__ float blockRedSum(float v, float* red) {
    v = warpRedSum(v);
    int w = threadIdx.x >> 5, l = threadIdx.x & 31;
    if (!l) red[w] = v;
    __syncthreads();
    if (threadIdx.x < 32) {
        float x = (l < 8) ? red[l] : 0.f;
        x = warpRedSum(x);
        if (!l) red[0] = x;
    }
    __syncthreads();
    float r = red[0];
    __syncthreads();
    return r;
}

// ============================================================================
// Combined projection kernel (4 GEMMs, one launch). tf32, 3-stage cp.async.
// ============================================================================
struct Desc {
    const float* A; const float* B; void* C;
    int N, K, nblk, blk0, h;
};

__global__ __launch_bounds__(256) void proj_multi(Desc d0, Desc d1, Desc d2, Desc d3) {
    extern __shared__ float sm[];
    float* As = sm;                    // [3][128*36]
    float* Bs = sm + 3 * 128 * 36;     // [3][32*136]

    Desc d = d3;
    int bid = blockIdx.x;
    if (bid < d1.blk0) d = d0;
    else if (bid < d2.blk0) d = d1;
    else if (bid < d3.blk0) d = d2;
    int local = bid - d.blk0;
    int m0 = (local / d.nblk) * 128, n0 = (local % d.nblk) * 128;
    const int N = d.N, K = d.K;

    int tid = threadIdx.x;
    int warp = tid >> 5, lane = tid & 31;
    int g = lane >> 2, c = lane & 3;
    int wm = (warp >> 2) * 64;
    int wn = (warp & 3) * 32;

    float acc[4][4][4];
#pragma unroll
    for (int mt = 0; mt < 4; mt++)
#pragma unroll
        for (int nt = 0; nt < 4; nt++)
#pragma unroll
            for (int e = 0; e < 4; e++) acc[mt][nt][e] = 0.f;

    int nk = K >> 5;
    auto loadStage = [&](int st, int k0) {
#pragma unroll
        for (int w = 0; w < 4; w++) {
            int idx = tid + w * 256;
            int r = idx >> 3, cc = (idx & 7) * 4;
            cp16(As + st * 128 * 36 + r * 36 + cc,
                 d.A + (size_t)(m0 + r) * K + k0 + cc);
        }
#pragma unroll
        for (int w = 0; w < 4; w++) {
            int idx = tid + w * 256;
            int r = idx >> 5, cc = (idx & 31) * 4;
            cp16(Bs + st * 32 * 136 + r * 136 + cc,
                 d.B + (size_t)(k0 + r) * N + n0 + cc);
        }
    };

    loadStage(0, 0);
    CP_COMMIT();
    loadStage(1, 32);
    CP_COMMIT();

    int st = 0;
    for (int kt = 0; kt < nk; kt++) {
        if (kt + 2 < nk) {
            int s2 = (st + 2) % 3;
            loadStage(s2, (kt + 2) * 32);
        }
        CP_COMMIT();
        CP_WAIT2();
        __syncthreads();

        const float* Ac = As + st * 128 * 36;
        const float* Bc = Bs + st * 32 * 136;
#pragma unroll
        for (int kk = 0; kk < 4; kk++) {
            int k = kk * 8;
            uint32_t af[4][4], bf[4][2];
#pragma unroll
            for (int mt = 0; mt < 4; mt++) {
                const float* base = Ac + (wm + mt * 16 + g) * 36 + k + c;
                af[mt][0] = __float_as_uint(base[0]);
                af[mt][1] = __float_as_uint(base[8 * 36]);
                af[mt][2] = __float_as_uint(base[4]);
                af[mt][3] = __float_as_uint(base[8 * 36 + 4]);
            }
#pragma unroll
            for (int nt = 0; nt < 4; nt++) {
                const float* base = Bc + (k + c) * 136 + wn + nt * 8 + g;
                bf[nt][0] = __float_as_uint(base[0]);
                bf[nt][1] = __float_as_uint(base[4 * 136]);
            }
#pragma unroll
            for (int mt = 0; mt < 4; mt++)
#pragma unroll
                for (int nt = 0; nt < 4; nt++)
                    mma_tf32(acc[mt][nt], af[mt], bf[nt], acc[mt][nt]);
        }
        __syncthreads();
        st = (st + 1) % 3;
    }

#pragma unroll
    for (int mt = 0; mt < 4; mt++)
#pragma unroll
        for (int nt = 0; nt < 4; nt++) {
            int row = m0 + wm + mt * 16 + g;
            int col = n0 + wn + nt * 8 + c * 2;
            if (d.h) {
                __half* Ch = (__half*)d.C;
                *(__half2*)(Ch + (size_t)row * N + col) =
                    __floats2half2_rn(acc[mt][nt][0], acc[mt][nt][1]);
                *(__half2*)(Ch + (size_t)(row + 8) * N + col) =
                    __floats2half2_rn(acc[mt][nt][2], acc[mt][nt][3]);
            } else {
                float* Cf = (float*)d.C;
                *(float2*)(Cf + (size_t)row * N + col) =
                    make_float2(acc[mt][nt][0], acc[mt][nt][1]);
                *(float2*)(Cf + (size_t)(row + 8) * N + col) =
                    make_float2(acc[mt][nt][2], acc[mt][nt][3]);
            }
        }
}

// ============================================================================
// Pipelined tf32 GEMM, BN=64 (for W_o with residual add)
// ============================================================================
__global__ __launch_bounds__(256) void gemm64(
        const float* __restrict__ A, const float* __restrict__ B,
        const float* __restrict__ Cadd, float* __restrict__ C,
        int M, int N, int K) {
    extern __shared__ float sm[];
    const int BST = 72;
    float* As = sm;
    float* Bs = sm + 2 * 128 * 36;

    int m0 = blockIdx.y * 128, n0 = blockIdx.x * 64;
    int tid = threadIdx.x;
    int warp = tid >> 5, lane = tid & 31;
    int g = lane >> 2, c = lane & 3;
    int wm = (warp >> 2) * 64;
    int wn = (warp & 3) * 16;

    float acc[4][2][4];
#pragma unroll
    for (int mt = 0; mt < 4; mt++)
#pragma unroll
        for (int nt = 0; nt < 2; nt++)
#pragma unroll
            for (int e = 0; e < 4; e++) acc[mt][nt][e] = 0.f;

    int nk = K >> 5;
    {
#pragma unroll
        for (int w = 0; w < 4; w++) {
            int idx = tid + w * 256;
            int r = idx >> 3, cc = (idx & 7) * 4;
            cp16(As + r * 36 + cc, A + (size_t)(m0 + r) * K + cc);
        }
#pragma unroll
        for (int w = 0; w < 2; w++) {
            int idx = tid + w * 256;
            int r = idx >> 4, cc = (idx & 15) * 4;
            cp16(Bs + r * BST + cc, B + (size_t)r * N + n0 + cc);
        }
    }
    CP_COMMIT();

    for (int kt = 0; kt < nk; kt++) {
        int cur = kt & 1;
        if (kt + 1 < nk) {
            int nxt = (kt + 1) & 1;
            int k0 = (kt + 1) * 32;
#pragma unroll
            for (int w = 0; w < 4; w++) {
                int idx = tid + w * 256;
                int r = idx >> 3, cc = (idx & 7) * 4;
                cp16(As + nxt * 128 * 36 + r * 36 + cc,
                     A + (size_t)(m0 + r) * K + k0 + cc);
            }
#pragma unroll
            for (int w = 0; w < 2; w++) {
                int idx = tid + w * 256;
                int r = idx >> 4, cc = (idx & 15) * 4;
                cp16(Bs + nxt * 32 * BST + r * BST + cc,
                     B + (size_t)(k0 + r) * N + n0 + cc);
            }
        }
        CP_COMMIT();
        CP_WAIT1();
        __syncthreads();

        const float* Ac = As + cur * 128 * 36;
        const float* Bc = Bs + cur * 32 * BST;
#pragma unroll
        for (int kk = 0; kk < 4; kk++) {
            int k = kk * 8;
            uint32_t af[4][4], bf[2][2];
#pragma unroll
            for (int mt = 0; mt < 4; mt++) {
                const float* base = Ac + (wm + mt * 16 + g) * 36 + k + c;
                af[mt][0] = __float_as_uint(base[0]);
                af[mt][1] = __float_as_uint(base[8 * 36]);
                af[mt][2] = __float_as_uint(base[4]);
                af[mt][3] = __float_as_uint(base[8 * 36 + 4]);
            }
#pragma unroll
            for (int nt = 0; nt < 2; nt++) {
                const float* base = Bc + (k + c) * BST + wn + nt * 8 + g;
                bf[nt][0] = __float_as_uint(base[0]);
                bf[nt][1] = __float_as_uint(base[4 * BST]);
            }
#pragma unroll
            for (int mt = 0; mt < 4; mt++)
#pragma unroll
                for (int nt = 0; nt < 2; nt++)
                    mma_tf32(acc[mt][nt], af[mt], bf[nt], acc[mt][nt]);
        }
        __syncthreads();
    }

#pragma unroll
    for (int mt = 0; mt < 4; mt++)
#pragma unroll
        for (int nt = 0; nt < 2; nt++) {
            int row = m0 + wm + mt * 16 + g;
            int col = n0 + wn + nt * 8 + c * 2;
            float* p0 = C + (size_t)row * N + col;
            float* p1 = C + (size_t)(row + 8) * N + col;
            float2 v0 = make_float2(acc[mt][nt][0], acc[mt][nt][1]);
            float2 v1 = make_float2(acc[mt][nt][2], acc[mt][nt][3]);
            if (Cadd) {
                const float* a0 = Cadd + (size_t)row * N + col;
                const float* a1 = Cadd + (size_t)(row + 8) * N + col;
                v0.x += a0[0]; v0.y += a0[1];
                v1.x += a1[0]; v1.y += a1[1];
            }
            *(float2*)p0 = v0;
            *(float2*)p1 = v1;
        }
}

// ============================================================================
// FLASH-FUSED score + exp + PV kernel, 512 threads (16 warps: 4 m x 4 j).
// Gates staged in smem; segA hoisted per tile; fully-masked tiles skipped
// (P zero-filled cheaply). vb aliases bd_s.
// ============================================================================
__global__ __launch_bounds__(512, 1) void score_pv(
        const float* __restrict__ Q, const float* __restrict__ pbu,
        const float* __restrict__ pbv, const __half* __restrict__ KV,
        const __half* __restrict__ REL, const float* __restrict__ ib,
        __half* __restrict__ P, float* __restrict__ rsum,
        float* __restrict__ vec) {
    extern __shared__ char smraw[];
    __half* qu_s  = (__half*)smraw;               // [64][72]
    __half* qv_s  = qu_s + 64 * 72;               // [64][72]
    __half* k_s   = qv_s + 64 * 72;               // [2][128*72]
    __half* v_s   = k_s + 2 * 128 * 72;           // [2][128*72]
    __half* rel_s = v_s + 2 * 128 * 72;           // [2][192*72]
    float*  bd_s  = (float*)(rel_s + 2 * 192 * 72);  // [64][200]; vb aliases
    float*  rows  = bd_s + 64 * 200;              // [64]
    float*  gate_s = rows + 64;                   // [64][4]

    int bn = blockIdx.y;
    int b = bn >> 3, n = bn & 7;
    int i0 = blockIdx.x * 64;
    int tid = threadIdx.x;

    if (tid < 64) rows[tid] = 0.f;
    if (tid < 256)
        gate_s[tid] = ib[((size_t)(i0 + (tid >> 2)) * 4 + b) * 4 + (tid & 3)];

    // q (+bias, *scale*log2e) -> fp16 smem, both copies
    const float QS = SCALEF * LOG2E;
#pragma unroll
    for (int w = 0; w < 2; w++) {
        int idx = tid + w * 512;
        int r = idx >> 4, c4 = (idx & 15) * 4;
        float4 v = *(const float4*)(Q + (size_t)(i0 + r) * 2048 + b * 512 + n * 64 + c4);
        float4 bu = *(const float4*)(pbu + n * 64 + c4);
        float4 bv = *(const float4*)(pbv + n * 64 + c4);
        *(__half2*)(qu_s + r * 72 + c4) =
            __floats2half2_rn((v.x + bu.x) * QS, (v.y + bu.y) * QS);
        *(__half2*)(qu_s + r * 72 + c4 + 2) =
            __floats2half2_rn((v.z + bu.z) * QS, (v.w + bu.w) * QS);
        *(__half2*)(qv_s + r * 72 + c4) =
            __floats2half2_rn((v.x + bv.x) * QS, (v.y + bv.y) * QS);
        *(__half2*)(qv_s + r * 72 + c4 + 2) =
            __floats2half2_rn((v.z + bv.z) * QS, (v.w + bv.w) * QS);
    }

    const __half* Kb = KV + b * 1024 + n * 64;
    const __half* Vb = KV + b * 1024 + 512 + n * 64;
    const __half* Rb = REL + b * 512 + n * 64;

    auto loadK = [&](int st, int j0) {
#pragma unroll
        for (int w = 0; w < 2; w++) {
            int idx = tid + w * 512;
            int r = idx >> 3, ch = (idx & 7) * 8;
            cp16(k_s + st * 128 * 72 + r * 72 + ch,
                 Kb + (size_t)(j0 + r) * 4096 + ch);
        }
    };
    auto loadV = [&](int st, int j0) {
#pragma unroll
        for (int w = 0; w < 2; w++) {
            int idx = tid + w * 512;
            int r = idx >> 3, ch = (idx & 7) * 8;
            cp16(v_s + st * 128 * 72 + r * 72 + ch,
                 Vb + (size_t)(j0 + r) * 4096 + ch);
        }
    };
    auto loadR = [&](int st, int j0) {
        int m0 = j0 + 448 - i0;
#pragma unroll
        for (int w = 0; w < 3; w++) {
            int idx = tid + w * 512;
            int r = idx >> 3, ch = (idx & 7) * 8;
            int mr = m0 + r; if (mr > 2047) mr = 2047;
            cp16(rel_s + st * 192 * 72 + r * 72 + ch,
                 Rb + (size_t)mr * 2048 + ch);
        }
    };

    int ntiles = ((1599 + i0) >> 7) + 1;
    if (ntiles > 16) ntiles = 16;

    loadK(0, 0); loadV(0, 0); loadR(0, 0);
    CP_COMMIT();

    int warp = tid >> 5, lane = tid & 31;
    int g = lane >> 2, c = lane & 3;
    int wm  = (warp >> 2) * 16;         // 4 m-groups x 16 rows
    int wj  = warp & 3;                 // 4 j-groups
    int wnA = wj * 32;
    int wnB = wj * 48;

    int mat = lane >> 3;
    int lrow = (mat & 1) * 8 + (lane & 7);
    int lcol = (mat >> 1) * 8;

    float rs[2] = {0.f, 0.f};
    float pvacc[8][4];
#pragma unroll
    for (int nd = 0; nd < 8; nd++)
#pragma unroll
        for (int e = 0; e < 4; e++) pvacc[nd][e] = 0.f;

    __half* Pb = P + ((size_t)bn * 512 + i0) * 2048;

    for (int jt = 0; jt < ntiles; jt++) {
        int cur = jt & 1;
        if (jt + 1 < ntiles) {
            int nxt = (jt + 1) & 1;
            loadK(nxt, (jt + 1) * 128);
            loadV(nxt, (jt + 1) * 128);
            loadR(nxt, (jt + 1) * 128);
        }
        CP_COMMIT();
        CP_WAIT1();
        __syncthreads();

        const __half* kc = k_s + cur * 128 * 72;
        const __half* rc = rel_s + cur * 192 * 72;

        float accb[6][4];
        float acca[4][4];
#pragma unroll
        for (int nt = 0; nt < 6; nt++)
#pragma unroll
            for (int e = 0; e < 4; e++) accb[nt][e] = 0.f;
#pragma unroll
        for (int nt = 0; nt < 4; nt++)
#pragma unroll
            for (int e = 0; e < 4; e++) acca[nt][e] = 0.f;

#pragma unroll
        for (int kk = 0; kk < 4; kk++) {
            int k = kk * 16;
            uint32_t au[4], av[4], bk[4][2], br[6][2];
            {
                const __half* bu = qu_s + (wm + g) * 72 + k + 2 * c;
                const __half* bv = qv_s + (wm + g) * 72 + k + 2 * c;
                au[0] = *(const uint32_t*)(bu);
                au[1] = *(const uint32_t*)(bu + 8 * 72);
                au[2] = *(const uint32_t*)(bu + 8);
                au[3] = *(const uint32_t*)(bu + 8 * 72 + 8);
                av[0] = *(const uint32_t*)(bv);
                av[1] = *(const uint32_t*)(bv + 8 * 72);
                av[2] = *(const uint32_t*)(bv + 8);
                av[3] = *(const uint32_t*)(bv + 8 * 72 + 8);
            }
#pragma unroll
            for (int nt = 0; nt < 4; nt++) {
                const __half* base = kc + (wnA + nt * 8 + g) * 72 + k + 2 * c;
                bk[nt][0] = *(const uint32_t*)(base);
                bk[nt][1] = *(const uint32_t*)(base + 8);
            }
#pragma unroll
            for (int nt = 0; nt < 6; nt++) {
                const __half* base = rc + (wnB + nt * 8 + g) * 72 + k + 2 * c;
                br[nt][0] = *(const uint32_t*)(base);
                br[nt][1] = *(const uint32_t*)(base + 8);
            }
#pragma unroll
            for (int nt = 0; nt < 4; nt++)
                mma_f16(acca[nt], au, bk[nt], acca[nt]);
#pragma unroll
            for (int nt = 0; nt < 6; nt++)
                mma_f16(accb[nt], av, br[nt], accb[nt]);
        }

        // stage BD band
#pragma unroll
        for (int nt = 0; nt < 6; nt++) {
            int row = wm + g;
            int col = wnB + nt * 8 + c * 2;
            *(float2*)(bd_s + row * 200 + col) =
                make_float2(accb[nt][0], accb[nt][1]);
            *(float2*)(bd_s + (row + 8) * 200 + col) =
                make_float2(accb[nt][2], accb[nt][3]);
        }
        __syncthreads();

        // epilogue: gates + shift + mask + ex2 -> P (fp16) + keep fragments
        int j0 = jt * 128;
        int segA = j0 >> 9;                      // constant within tile
        uint32_t pe2[4][2];
#pragma unroll
        for (int half = 0; half < 2; half++) {
            int i_loc = wm + g + half * 8;
            int i = i0 + i_loc;
            int jmax = 1536 + i;
            float gA = gate_s[i_loc * 4 + segA];
            const float* gt = gate_s + i_loc * 4;
#pragma unroll
            for (int nt = 0; nt < 4; nt++) {
                float a0 = acca[nt][half * 2];
                float a1 = acca[nt][half * 2 + 1];
                float pe[2];
#pragma unroll
                for (int e = 0; e < 2; e++) {
                    int j_loc = wnA + nt * 8 + c * 2 + e;
                    int j = j0 + j_loc;
                    int m = j + 511 - i;
                    int segB = m >> 9; if (segB > 3) segB = 3;
                    float bd = bd_s[i_loc * 200 + (j_loc + 63 - i_loc)];
                    float ac = e ? a1 : a0;
                    float s = gA * ac + gt[segB] * bd;
                    pe[e] = (j <= jmax) ? ex2f(s) : 0.f;
                }
                rs[half] += pe[0] + pe[1];
                __half2 h2 = __floats2half2_rn(pe[0], pe[1]);
                pe2[nt][half] = *(uint32_t*)&h2;
                *(__half2*)(Pb + (size_t)i_loc * 2048 + j0 + wnA + nt * 8 + c * 2) = h2;
            }
        }

        // PV: A = exp'd fragments, B = V (ldmatrix.trans)
        {
            uint32_t vbase = (uint32_t)__cvta_generic_to_shared(v_s + cur * 128 * 72);
#pragma unroll
            for (int kk2 = 0; kk2 < 2; kk2++) {
                uint32_t bf[8][2];
#pragma unroll
                for (int p = 0; p < 4; p++) {
                    uint32_t addr = vbase +
                        (uint32_t)(((wnA + kk2 * 16 + lrow) * 72 + p * 16 + lcol) * 2);
                    uint32_t r0, r1, r2, r3;
                    ldsm_x4_t(r0, r1, r2, r3, addr);
                    bf[2 * p][0] = r0; bf[2 * p][1] = r1;
                    bf[2 * p + 1][0] = r2; bf[2 * p + 1][1] = r3;
                }
                uint32_t af[4];
                af[0] = pe2[2 * kk2][0];
                af[1] = pe2[2 * kk2][1];
                af[2] = pe2[2 * kk2 + 1][0];
                af[3] = pe2[2 * kk2 + 1][1];
#pragma unroll
                for (int nd = 0; nd < 8; nd++)
                    mma_f16(pvacc[nd], af, bf[nd], pvacc[nd]);
            }
        }
        __syncthreads();
    }

    // zero-fill P for fully masked tiles (skipped above)
    {
        __half2 hz = __floats2half2_rn(0.f, 0.f);
        for (int jt = ntiles; jt < 16; jt++) {
            int j0 = jt * 128;
#pragma unroll
            for (int half = 0; half < 2; half++) {
                int i_loc = wm + g + half * 8;
#pragma unroll
                for (int nt = 0; nt < 4; nt++)
                    *(__half2*)(Pb + (size_t)i_loc * 2048 + j0 + wnA + nt * 8 + c * 2) = hz;
            }
        }
    }

    // row sums
    atomicAdd(&rows[wm + g], rs[0]);
    atomicAdd(&rows[wm + g + 8], rs[1]);
    __syncthreads();
    if (tid < 64) rows[tid] = 1.f / rows[tid];

    // vb aliases bd_s (bd no longer needed)
    float* vb = bd_s;
    for (int idx = tid; idx < 64 * 68; idx += 512) vb[idx] = 0.f;
    __syncthreads();

    // cross-warp vec reduction over the 4 j-groups
    for (int r = 0; r < 4; r++) {
        if (wj == r) {
#pragma unroll
            for (int nd = 0; nd < 8; nd++)
#pragma unroll
                for (int e = 0; e < 4; e++) {
                    int row = wm + g + ((e >> 1) ? 8 : 0);
                    int col = nd * 8 + c * 2 + (e & 1);
                    vb[row * 68 + col] += pvacc[nd][e];
                }
        }
        __syncthreads();
    }

    // normalize + write vec and rsum
#pragma unroll
    for (int t = 0; t < 8; t++) {
        int e = tid + t * 512;              // 0..4095
        int row = e >> 6, col = e & 63;
        vec[((size_t)(i0 + row) * 4 + b) * 512 + n * 64 + col] =
            vb[row * 68 + col] * rows[row];
    }
    if (tid < 64)
        rsum[(size_t)bn * 512 + i0 + tid] = rows[tid];
}

// ---------------- attn matrix: mean over bn of normalized prob --------------
__global__ void attn_kernel(const __half* __restrict__ P,
                            const float* __restrict__ rsum,
                            float* __restrict__ attn) {
    int i = blockIdx.x;
    int tid = threadIdx.x;
    float acc[8] = {0.f, 0.f, 0.f, 0.f, 0.f, 0.f, 0.f, 0.f};
#pragma unroll 4
    for (int bn = 0; bn < 32; bn++) {
        float inv = rsum[(size_t)bn * 512 + i];
        const __half* prow = P + ((size_t)bn * 512 + i) * 2048 + tid * 8;
        uint4 raw = *(const uint4*)prow;
        const __half2* h2 = (const __half2*)&raw;
#pragma unroll
        for (int e = 0; e < 4; e++) {
            float2 f = __half22float2(h2[e]);
            acc[e * 2]     += inv * f.x;
            acc[e * 2 + 1] += inv * f.y;
        }
    }
    float* dst = attn + (size_t)i * 2048 + tid * 8;
#pragma unroll
    for (int e = 0; e < 8; e++) dst[e] = acc[e] * (1.f / 32.f);
}

// ---------------- layernorm ----------------
__global__ void ln_kernel(const float* __restrict__ y, const float* __restrict__ g,
                          const float* __restrict__ be, float* __restrict__ out) {
    __shared__ float red[32];
    int r = blockIdx.x;
    int tid = threadIdx.x;
    float v0 = y[(size_t)r * 512 + tid];
    float v1 = y[(size_t)r * 512 + tid + 256];
    float mean = blockRedSum(v0 + v1, red) * (1.f / 512.f);
    float d0 = v0 - mean, d1 = v1 - mean;
    float var = blockRedSum(d0 * d0 + d1 * d1, red) * (1.f / 512.f);
    float rstd = rsqrtf(var + 1e-5f);
    out[(size_t)r * 512 + tid]       = d0 * rstd * g[tid] + be[tid];
    out[(size_t)r * 512 + tid + 256] = d1 * rstd * g[tid + 256] + be[tid + 256];
}

// ---------------- launch ----------------
#define SMEM_P3  ((3 * 128 * 36 + 3 * 32 * 136) * 4)               // 107520
#define SMEM_G64 ((2 * 128 * 36 + 2 * 32 * 72) * 4)                // 55296
#define SMEM_SPV ((64*72*2 + 2*128*72 + 2*128*72 + 2*192*72) * 2 \
                  + (64*200 + 64 + 256) * 4)                       // 199936

extern "C" void kernel_launch(void* const* d_in, const int* in_sizes, int n_in,
                              void* d_out, int out_size) {
    (void)in_sizes; (void)n_in; (void)out_size;
    const float* x       = (const float*)d_in[0];
    const float* memory  = (const float*)d_in[1];
    const float* pos_emb = (const float*)d_in[2];
    const float* pbu     = (const float*)d_in[3];
    const float* pbv     = (const float*)d_in[4];
    const float* ib      = (const float*)d_in[6];
    const float* W_q     = (const float*)d_in[7];
    const float* W_kv    = (const float*)d_in[8];
    const float* W_rel   = (const float*)d_in[9];
    const float* W_o     = (const float*)d_in[10];
    const float* ln_g    = (const float*)d_in[11];
    const float* ln_b    = (const float*)d_in[12];

    float* out  = (float*)d_out;
    float* attn = out + (size_t)Lq * BATCH * 512;

    __half *kvh, *relh, *prob;
    float *q, *rs, *vec, *y;
    cudaGetSymbolAddress((void**)&kvh,  g_kv);
    cudaGetSymbolAddress((void**)&relh, g_rel);
    cudaGetSymbolAddress((void**)&q,    g_q);
    cudaGetSymbolAddress((void**)&prob, g_prob);
    cudaGetSymbolAddress((void**)&rs,   g_rsum);
    cudaGetSymbolAddress((void**)&vec,  g_vec);
    cudaGetSymbolAddress((void**)&y,    g_y);

    static bool attr_set = false;
    if (!attr_set) {
        cudaFuncSetAttribute(proj_multi,
                             cudaFuncAttributeMaxDynamicSharedMemorySize, SMEM_P3);
        cudaFuncSetAttribute(gemm64,
                             cudaFuncAttributeMaxDynamicSharedMemorySize, SMEM_G64);
        cudaFuncSetAttribute(score_pv,
                             cudaFuncAttributeMaxDynamicSharedMemorySize, SMEM_SPV);
        attr_set = true;
    }

    // 1) all 4 projections in one launch (kv, rel out fp16; q out fp32)
    Desc d0 = { memory,  W_kv,  (void*)kvh,                        1024, 512, 8, 0,   1 };
    Desc d1 = { x,       W_kv,  (void*)(kvh + (size_t)6144 * 1024),1024, 512, 8, 384, 1 };
    Desc d2 = { pos_emb, W_rel, (void*)relh,                       512,  512, 4, 512, 1 };
    Desc d3 = { x,       W_q,   (void*)q,                          512,  512, 4, 768, 0 };
    proj_multi<<<832, 256, SMEM_P3>>>(d0, d1, d2, d3);

    // 2) fused scores + exp + PV (writes prob, rsum, vec), 512 threads
    score_pv<<<dim3(8, 32), 512, SMEM_SPV>>>(q, pbu, pbv, kvh, relh, ib,
                                             prob, rs, vec);

    // 3) attn matrix from normalized prob
    attn_kernel<<<512, 256>>>(prob, rs, attn);

    // 4) y = x + vec @ W_o ; layernorm
    gemm64<<<dim3(8, 16), 256, SMEM_G64>>>(vec, W_o, x, y, 2048, 512, 512);
    ln_kernel<<<2048, 256>>>(y, ln_g, ln_b, out);
}

// round 11
// speedup vs baseline: 5.9127x; 1.1378x over previous
#include <cuda_runtime.h>
#include <cuda_fp16.h>
#include <stdint.h>

// Problem constants
#define Lq     512
#define BATCH  4
#define SCALEF 0.125f
#define LOG2E  1.4426950408889634f

// ---------------- scratch ----------------
__device__ __half g_memh[(size_t)6144 * 512];           // memory fp16
__device__ __half g_xh  [(size_t)2048 * 512];           // x fp16
__device__ __half g_posh[(size_t)8192 * 512];           // pos_emb fp16
__device__ __half g_wkvh[(size_t)512 * 1024];
__device__ __half g_wrelh[(size_t)512 * 512];
__device__ __half g_wqh [(size_t)512 * 512];
__device__ __half g_woh [(size_t)512 * 512];
__device__ __half g_kv  [(size_t)8192 * 1024];          // 16 MB  k | v (fp16)
__device__ __half g_rel [(size_t)8192 * 512];           //  8 MB  (fp16)
__device__ float  g_q   [(size_t)2048 * 512];           //  4 MB
__device__ __half g_prob[(size_t)32 * 512 * 2048];      // 64 MB unnormalized exp
__device__ float  g_rsum[(size_t)32 * 512];             // 64 KB reciprocal row sums
__device__ __half g_vec [(size_t)2048 * 512];           //  2 MB (fp16)
__device__ float  g_y   [(size_t)2048 * 512];           //  4 MB

// ---------------- helpers ----------------
__device__ __forceinline__ void mma_f16(float* d, const uint32_t* a,
                                        const uint32_t* b, const float* c) {
    asm volatile(
        "mma.sync.aligned.m16n8k16.row.col.f32.f16.f16.f32 "
        "{%0,%1,%2,%3}, {%4,%5,%6,%7}, {%8,%9}, {%10,%11,%12,%13};"
        : "=f"(d[0]), "=f"(d[1]), "=f"(d[2]), "=f"(d[3])
        : "r"(a[0]), "r"(a[1]), "r"(a[2]), "r"(a[3]),
          "r"(b[0]), "r"(b[1]),
          "f"(c[0]), "f"(c[1]), "f"(c[2]), "f"(c[3]));
}

__device__ __forceinline__ void ldsm_x4_t(uint32_t& r0, uint32_t& r1,
                                          uint32_t& r2, uint32_t& r3, uint32_t addr) {
    asm volatile("ldmatrix.sync.aligned.m8n8.x4.trans.shared.b16 {%0,%1,%2,%3}, [%4];"
                 : "=r"(r0), "=r"(r1), "=r"(r2), "=r"(r3) : "r"(addr));
}

__device__ __forceinline__ void cp16(void* dst, const void* src) {
    uint32_t d = (uint32_t)__cvta_generic_to_shared(dst);
    asm volatile("cp.async.cg.shared.global [%0], [%1], 16;" :: "r"(d), "l"(src));
}
#define CP_COMMIT() asm volatile("cp.async.commit_group;")
#define CP_WAIT1()  asm volatile("cp.async.wait_group 1;")
#define CP_WAIT2()  asm volatile("cp.async.wait_group 2;")

__device__ __forceinline__ float ex2f(float x) {
    float r;
    asm("ex2.approx.f32 %0, %1;" : "=f"(r) : "f"(x));
    return r;
}

__device__ __forceinline__ float warpRedSum(float v) {
#pragma unroll
    for (int o = 16; o > 0; o >>= 1) v += __shfl_xor_sync(0xffffffffu, v, o);
    return v;
}
__device__ __forceinline__ float blockRedSum(float v, float* red) {
    v = warpRedSum(v);
    int w = threadIdx.x >> 5, l = threadIdx.x & 31;
    if (!l) red[w] = v;
    __syncthreads();
    if (threadIdx.x < 32) {
        float x = (l < 8) ? red[l] : 0.f;
        x = warpRedSum(x);
        if (!l) red[0] = x;
    }
    __syncthreads();
    float r = red[0];
    __syncthreads();
    return r;
}

// ============================================================================
// Fused float->half conversion (7 arrays, one launch, float4 granularity)
// ============================================================================
struct ConvJob {
    const float* src[7];
    __half* dst[7];
    int n4[7];       // element count / 4
};

__global__ void conv_f2h(ConvJob j, int total4) {
    int idx = blockIdx.x * blockDim.x + threadIdx.x;
    if (idx >= total4) return;
    int off = idx, seg = 0;
#pragma unroll
    for (int s = 0; s < 6; s++)
        if (off >= j.n4[seg]) { off -= j.n4[seg]; seg++; }
    float4 v = ((const float4*)j.src[seg])[off];
    __half2* d = (__half2*)j.dst[seg] + off * 2;
    d[0] = __floats2half2_rn(v.x, v.y);
    d[1] = __floats2half2_rn(v.z, v.w);
}

// ============================================================================
// fp16 projection kernel (4 GEMMs, one launch). 3-stage cp.async,
// BM=128, BN=128, BK=32, 256 threads (8 warps 2m x 4n). ldmatrix.trans B.
// ============================================================================
struct DescH {
    const __half* A; const __half* B; void* C;
    int N, K, nblk, blk0, h;
};

#define PA_ST 40
#define PB_ST 136
__global__ __launch_bounds__(256) void proj_h(DescH d0, DescH d1, DescH d2, DescH d3) {
    extern __shared__ char smraw[];
    __half* As = (__half*)smraw;               // [3][128*40]
    __half* Bs = As + 3 * 128 * PA_ST;         // [3][32*136]

    DescH d = d3;
    int bid = blockIdx.x;
    if (bid < d1.blk0) d = d0;
    else if (bid < d2.blk0) d = d1;
    else if (bid < d3.blk0) d = d2;
    int local = bid - d.blk0;
    int m0 = (local / d.nblk) * 128, n0 = (local % d.nblk) * 128;
    const int N = d.N, K = d.K;

    int tid = threadIdx.x;
    int warp = tid >> 5, lane = tid & 31;
    int g = lane >> 2, c = lane & 3;
    int wm = (warp >> 2) * 64;
    int wn = (warp & 3) * 32;
    int mat = lane >> 3;
    int lrow = (mat & 1) * 8 + (lane & 7);
    int lcol = (mat >> 1) * 8;

    float acc[4][4][4];
#pragma unroll
    for (int mt = 0; mt < 4; mt++)
#pragma unroll
        for (int nt = 0; nt < 4; nt++)
#pragma unroll
            for (int e = 0; e < 4; e++) acc[mt][nt][e] = 0.f;

    int nk = K >> 5;
    auto loadStage = [&](int st, int k0) {
#pragma unroll
        for (int w = 0; w < 2; w++) {
            int idx = tid + w * 256;
            int r = idx >> 2, ch = (idx & 3) * 8;
            cp16(As + st * 128 * PA_ST + r * PA_ST + ch,
                 d.A + (size_t)(m0 + r) * K + k0 + ch);
        }
#pragma unroll
        for (int w = 0; w < 2; w++) {
            int idx = tid + w * 256;
            int r = idx >> 4, ch = (idx & 15) * 8;
            cp16(Bs + st * 32 * PB_ST + r * PB_ST + ch,
                 d.B + (size_t)(k0 + r) * N + n0 + ch);
        }
    };

    loadStage(0, 0);
    CP_COMMIT();
    loadStage(1, 32);
    CP_COMMIT();

    int st = 0;
    for (int kt = 0; kt < nk; kt++) {
        if (kt + 2 < nk) loadStage((st + 2) % 3, (kt + 2) * 32);
        CP_COMMIT();
        CP_WAIT2();
        __syncthreads();

        const __half* Ac = As + st * 128 * PA_ST;
        uint32_t bbase = (uint32_t)__cvta_generic_to_shared(Bs + st * 32 * PB_ST);
#pragma unroll
        for (int ks = 0; ks < 2; ks++) {
            int k = ks * 16;
            uint32_t af[4][4], bf[4][2];
#pragma unroll
            for (int mt = 0; mt < 4; mt++) {
                const __half* base = Ac + (wm + mt * 16 + g) * PA_ST + k + 2 * c;
                af[mt][0] = *(const uint32_t*)(base);
                af[mt][1] = *(const uint32_t*)(base + 8 * PA_ST);
                af[mt][2] = *(const uint32_t*)(base + 8);
                af[mt][3] = *(const uint32_t*)(base + 8 * PA_ST + 8);
            }
#pragma unroll
            for (int p = 0; p < 2; p++) {
                uint32_t addr = bbase +
                    (uint32_t)(((k + lrow) * PB_ST + wn + p * 16 + lcol) * 2);
                uint32_t r0, r1, r2, r3;
                ldsm_x4_t(r0, r1, r2, r3, addr);
                bf[2 * p][0] = r0; bf[2 * p][1] = r1;
                bf[2 * p + 1][0] = r2; bf[2 * p + 1][1] = r3;
            }
#pragma unroll
            for (int mt = 0; mt < 4; mt++)
#pragma unroll
                for (int nt = 0; nt < 4; nt++)
                    mma_f16(acc[mt][nt], af[mt], bf[nt], acc[mt][nt]);
        }
        __syncthreads();
        st = (st + 1) % 3;
    }

#pragma unroll
    for (int mt = 0; mt < 4; mt++)
#pragma unroll
        for (int nt = 0; nt < 4; nt++) {
            int row = m0 + wm + mt * 16 + g;
            int col = n0 + wn + nt * 8 + c * 2;
            if (d.h) {
                __half* Ch = (__half*)d.C;
                *(__half2*)(Ch + (size_t)row * N + col) =
                    __floats2half2_rn(acc[mt][nt][0], acc[mt][nt][1]);
                *(__half2*)(Ch + (size_t)(row + 8) * N + col) =
                    __floats2half2_rn(acc[mt][nt][2], acc[mt][nt][3]);
            } else {
                float* Cf = (float*)d.C;
                *(float2*)(Cf + (size_t)row * N + col) =
                    make_float2(acc[mt][nt][0], acc[mt][nt][1]);
                *(float2*)(Cf + (size_t)(row + 8) * N + col) =
                    make_float2(acc[mt][nt][2], acc[mt][nt][3]);
            }
        }
}

// ============================================================================
// fp16 GEMM BN=64 with fp32 residual add (W_o): y = vec @ W_o + x
// ============================================================================
#define GB_ST 72
__global__ __launch_bounds__(256) void gemm64_h(
        const __half* __restrict__ A, const __half* __restrict__ B,
        const float* __restrict__ Cadd, float* __restrict__ C,
        int M, int N, int K) {
    extern __shared__ char smraw[];
    __half* As = (__half*)smraw;               // [2][128*40]
    __half* Bs = As + 2 * 128 * PA_ST;         // [2][32*72]

    int m0 = blockIdx.y * 128, n0 = blockIdx.x * 64;
    int tid = threadIdx.x;
    int warp = tid >> 5, lane = tid & 31;
    int g = lane >> 2, c = lane & 3;
    int wm = (warp >> 2) * 64;
    int wn = (warp & 3) * 16;
    int mat = lane >> 3;
    int lrow = (mat & 1) * 8 + (lane & 7);
    int lcol = (mat >> 1) * 8;

    float acc[4][2][4];
#pragma unroll
    for (int mt = 0; mt < 4; mt++)
#pragma unroll
        for (int nt = 0; nt < 2; nt++)
#pragma unroll
            for (int e = 0; e < 4; e++) acc[mt][nt][e] = 0.f;

    int nk = K >> 5;
    auto loadStage = [&](int st, int k0) {
#pragma unroll
        for (int w = 0; w < 2; w++) {
            int idx = tid + w * 256;
            int r = idx >> 2, ch = (idx & 3) * 8;
            cp16(As + st * 128 * PA_ST + r * PA_ST + ch,
                 A + (size_t)(m0 + r) * K + k0 + ch);
        }
        {
            int r = tid >> 3, ch = (tid & 7) * 8;
            if (r < 32)
                cp16(Bs + st * 32 * GB_ST + r * GB_ST + ch,
                     B + (size_t)(k0 + r) * N + n0 + ch);
        }
    };

    loadStage(0, 0);
    CP_COMMIT();

    for (int kt = 0; kt < nk; kt++) {
        int cur = kt & 1;
        if (kt + 1 < nk) loadStage((kt + 1) & 1, (kt + 1) * 32);
        CP_COMMIT();
        CP_WAIT1();
        __syncthreads();

        const __half* Ac = As + cur * 128 * PA_ST;
        uint32_t bbase = (uint32_t)__cvta_generic_to_shared(Bs + cur * 32 * GB_ST);
#pragma unroll
        for (int ks = 0; ks < 2; ks++) {
            int k = ks * 16;
            uint32_t af[4][4], bf[2][2];
#pragma unroll
            for (int mt = 0; mt < 4; mt++) {
                const __half* base = Ac + (wm + mt * 16 + g) * PA_ST + k + 2 * c;
                af[mt][0] = *(const uint32_t*)(base);
                af[mt][1] = *(const uint32_t*)(base + 8 * PA_ST);
                af[mt][2] = *(const uint32_t*)(base + 8);
                af[mt][3] = *(const uint32_t*)(base + 8 * PA_ST + 8);
            }
            {
                uint32_t addr = bbase +
                    (uint32_t)(((k + lrow) * GB_ST + wn + lcol) * 2);
                uint32_t r0, r1, r2, r3;
                ldsm_x4_t(r0, r1, r2, r3, addr);
                bf[0][0] = r0; bf[0][1] = r1;
                bf[1][0] = r2; bf[1][1] = r3;
            }
#pragma unroll
            for (int mt = 0; mt < 4; mt++)
#pragma unroll
                for (int nt = 0; nt < 2; nt++)
                    mma_f16(acc[mt][nt], af[mt], bf[nt], acc[mt][nt]);
        }
        __syncthreads();
    }

#pragma unroll
    for (int mt = 0; mt < 4; mt++)
#pragma unroll
        for (int nt = 0; nt < 2; nt++) {
            int row = m0 + wm + mt * 16 + g;
            int col = n0 + wn + nt * 8 + c * 2;
            const float* a0 = Cadd + (size_t)row * N + col;
            const float* a1 = Cadd + (size_t)(row + 8) * N + col;
            *(float2*)(C + (size_t)row * N + col) =
                make_float2(acc[mt][nt][0] + a0[0], acc[mt][nt][1] + a0[1]);
            *(float2*)(C + (size_t)(row + 8) * N + col) =
                make_float2(acc[mt][nt][2] + a1[0], acc[mt][nt][3] + a1[1]);
        }
}

// ============================================================================
// FLASH-FUSED score + exp + PV kernel, 512 threads (16 warps: 4 m x 4 j).
// vec out fp16.
// ============================================================================
__global__ __launch_bounds__(512, 1) void score_pv(
        const float* __restrict__ Q, const float* __restrict__ pbu,
        const float* __restrict__ pbv, const __half* __restrict__ KV,
        const __half* __restrict__ REL, const float* __restrict__ ib,
        __half* __restrict__ P, float* __restrict__ rsum,
        __half* __restrict__ vec) {
    extern __shared__ char smraw[];
    __half* qu_s  = (__half*)smraw;               // [64][72]
    __half* qv_s  = qu_s + 64 * 72;               // [64][72]
    __half* k_s   = qv_s + 64 * 72;               // [2][128*72]
    __half* v_s   = k_s + 2 * 128 * 72;           // [2][128*72]
    __half* rel_s = v_s + 2 * 128 * 72;           // [2][192*72]
    float*  bd_s  = (float*)(rel_s + 2 * 192 * 72);  // [64][200]; vb aliases
    float*  rows  = bd_s + 64 * 200;              // [64]
    float*  gate_s = rows + 64;                   // [64][4]

    int bn = blockIdx.y;
    int b = bn >> 3, n = bn & 7;
    int i0 = blockIdx.x * 64;
    int tid = threadIdx.x;

    if (tid < 64) rows[tid] = 0.f;
    if (tid < 256)
        gate_s[tid] = ib[((size_t)(i0 + (tid >> 2)) * 4 + b) * 4 + (tid & 3)];

    const float QS = SCALEF * LOG2E;
#pragma unroll
    for (int w = 0; w < 2; w++) {
        int idx = tid + w * 512;
        int r = idx >> 4, c4 = (idx & 15) * 4;
        float4 v = *(const float4*)(Q + (size_t)(i0 + r) * 2048 + b * 512 + n * 64 + c4);
        float4 bu = *(const float4*)(pbu + n * 64 + c4);
        float4 bv = *(const float4*)(pbv + n * 64 + c4);
        *(__half2*)(qu_s + r * 72 + c4) =
            __floats2half2_rn((v.x + bu.x) * QS, (v.y + bu.y) * QS);
        *(__half2*)(qu_s + r * 72 + c4 + 2) =
            __floats2half2_rn((v.z + bu.z) * QS, (v.w + bu.w) * QS);
        *(__half2*)(qv_s + r * 72 + c4) =
            __floats2half2_rn((v.x + bv.x) * QS, (v.y + bv.y) * QS);
        *(__half2*)(qv_s + r * 72 + c4 + 2) =
            __floats2half2_rn((v.z + bv.z) * QS, (v.w + bv.w) * QS);
    }

    const __half* Kb = KV + b * 1024 + n * 64;
    const __half* Vb = KV + b * 1024 + 512 + n * 64;
    const __half* Rb = REL + b * 512 + n * 64;

    auto loadK = [&](int st, int j0) {
#pragma unroll
        for (int w = 0; w < 2; w++) {
            int idx = tid + w * 512;
            int r = idx >> 3, ch = (idx & 7) * 8;
            cp16(k_s + st * 128 * 72 + r * 72 + ch,
                 Kb + (size_t)(j0 + r) * 4096 + ch);
        }
    };
    auto loadV = [&](int st, int j0) {
#pragma unroll
        for (int w = 0; w < 2; w++) {
            int idx = tid + w * 512;
            int r = idx >> 3, ch = (idx & 7) * 8;
            cp16(v_s + st * 128 * 72 + r * 72 + ch,
                 Vb + (size_t)(j0 + r) * 4096 + ch);
        }
    };
    auto loadR = [&](int st, int j0) {
        int m0 = j0 + 448 - i0;
#pragma unroll
        for (int w = 0; w < 3; w++) {
            int idx = tid + w * 512;
            int r = idx >> 3, ch = (idx & 7) * 8;
            int mr = m0 + r; if (mr > 2047) mr = 2047;
            cp16(rel_s + st * 192 * 72 + r * 72 + ch,
                 Rb + (size_t)mr * 2048 + ch);
        }
    };

    int ntiles = ((1599 + i0) >> 7) + 1;
    if (ntiles > 16) ntiles = 16;

    loadK(0, 0); loadV(0, 0); loadR(0, 0);
    CP_COMMIT();

    int warp = tid >> 5, lane = tid & 31;
    int g = lane >> 2, c = lane & 3;
    int wm  = (warp >> 2) * 16;
    int wj  = warp & 3;
    int wnA = wj * 32;
    int wnB = wj * 48;

    int mat = lane >> 3;
    int lrow = (mat & 1) * 8 + (lane & 7);
    int lcol = (mat >> 1) * 8;

    float rs[2] = {0.f, 0.f};
    float pvacc[8][4];
#pragma unroll
    for (int nd = 0; nd < 8; nd++)
#pragma unroll
        for (int e = 0; e < 4; e++) pvacc[nd][e] = 0.f;

    __half* Pb = P + ((size_t)bn * 512 + i0) * 2048;

    for (int jt = 0; jt < ntiles; jt++) {
        int cur = jt & 1;
        if (jt + 1 < ntiles) {
            int nxt = (jt + 1) & 1;
            loadK(nxt, (jt + 1) * 128);
            loadV(nxt, (jt + 1) * 128);
            loadR(nxt, (jt + 1) * 128);
        }
        CP_COMMIT();
        CP_WAIT1();
        __syncthreads();

        const __half* kc = k_s + cur * 128 * 72;
        const __half* rc = rel_s + cur * 192 * 72;

        float accb[6][4];
        float acca[4][4];
#pragma unroll
        for (int nt = 0; nt < 6; nt++)
#pragma unroll
            for (int e = 0; e < 4; e++) accb[nt][e] = 0.f;
#pragma unroll
        for (int nt = 0; nt < 4; nt++)
#pragma unroll
            for (int e = 0; e < 4; e++) acca[nt][e] = 0.f;

#pragma unroll
        for (int kk = 0; kk < 4; kk++) {
            int k = kk * 16;
            uint32_t au[4], av[4], bk[4][2], br[6][2];
            {
                const __half* bu = qu_s + (wm + g) * 72 + k + 2 * c;
                const __half* bv = qv_s + (wm + g) * 72 + k + 2 * c;
                au[0] = *(const uint32_t*)(bu);
                au[1] = *(const uint32_t*)(bu + 8 * 72);
                au[2] = *(const uint32_t*)(bu + 8);
                au[3] = *(const uint32_t*)(bu + 8 * 72 + 8);
                av[0] = *(const uint32_t*)(bv);
                av[1] = *(const uint32_t*)(bv + 8 * 72);
                av[2] = *(const uint32_t*)(bv + 8);
                av[3] = *(const uint32_t*)(bv + 8 * 72 + 8);
            }
#pragma unroll
            for (int nt = 0; nt < 4; nt++) {
                const __half* base = kc + (wnA + nt * 8 + g) * 72 + k + 2 * c;
                bk[nt][0] = *(const uint32_t*)(base);
                bk[nt][1] = *(const uint32_t*)(base + 8);
            }
#pragma unroll
            for (int nt = 0; nt < 6; nt++) {
                const __half* base = rc + (wnB + nt * 8 + g) * 72 + k + 2 * c;
                br[nt][0] = *(const uint32_t*)(base);
                br[nt][1] = *(const uint32_t*)(base + 8);
            }
#pragma unroll
            for (int nt = 0; nt < 4; nt++)
                mma_f16(acca[nt], au, bk[nt], acca[nt]);
#pragma unroll
            for (int nt = 0; nt < 6; nt++)
                mma_f16(accb[nt], av, br[nt], accb[nt]);
        }

#pragma unroll
        for (int nt = 0; nt < 6; nt++) {
            int row = wm + g;
            int col = wnB + nt * 8 + c * 2;
            *(float2*)(bd_s + row * 200 + col) =
                make_float2(accb[nt][0], accb[nt][1]);
            *(float2*)(bd_s + (row + 8) * 200 + col) =
                make_float2(accb[nt][2], accb[nt][3]);
        }
        __syncthreads();

        int j0 = jt * 128;
        int segA = j0 >> 9;
        uint32_t pe2[4][2];
#pragma unroll
        for (int half = 0; half < 2; half++) {
            int i_loc = wm + g + half * 8;
            int i = i0 + i_loc;
            int jmax = 1536 + i;
            float gA = gate_s[i_loc * 4 + segA];
            const float* gt = gate_s + i_loc * 4;
#pragma unroll
            for (int nt = 0; nt < 4; nt++) {
                float a0 = acca[nt][half * 2];
                float a1 = acca[nt][half * 2 + 1];
                float pe[2];
#pragma unroll
                for (int e = 0; e < 2; e++) {
                    int j_loc = wnA + nt * 8 + c * 2 + e;
                    int j = j0 + j_loc;
                    int m = j + 511 - i;
                    int segB = m >> 9; if (segB > 3) segB = 3;
                    float bd = bd_s[i_loc * 200 + (j_loc + 63 - i_loc)];
                    float ac = e ? a1 : a0;
                    float s = gA * ac + gt[segB] * bd;
                    pe[e] = (j <= jmax) ? ex2f(s) : 0.f;
                }
                rs[half] += pe[0] + pe[1];
                __half2 h2 = __floats2half2_rn(pe[0], pe[1]);
                pe2[nt][half] = *(uint32_t*)&h2;
                *(__half2*)(Pb + (size_t)i_loc * 2048 + j0 + wnA + nt * 8 + c * 2) = h2;
            }
        }

        {
            uint32_t vbase = (uint32_t)__cvta_generic_to_shared(v_s + cur * 128 * 72);
#pragma unroll
            for (int kk2 = 0; kk2 < 2; kk2++) {
                uint32_t bf[8][2];
#pragma unroll
                for (int p = 0; p < 4; p++) {
                    uint32_t addr = vbase +
                        (uint32_t)(((wnA + kk2 * 16 + lrow) * 72 + p * 16 + lcol) * 2);
                    uint32_t r0, r1, r2, r3;
                    ldsm_x4_t(r0, r1, r2, r3, addr);
                    bf[2 * p][0] = r0; bf[2 * p][1] = r1;
                    bf[2 * p + 1][0] = r2; bf[2 * p + 1][1] = r3;
                }
                uint32_t af[4];
                af[0] = pe2[2 * kk2][0];
                af[1] = pe2[2 * kk2][1];
                af[2] = pe2[2 * kk2 + 1][0];
                af[3] = pe2[2 * kk2 + 1][1];
#pragma unroll
                for (int nd = 0; nd < 8; nd++)
                    mma_f16(pvacc[nd], af, bf[nd], pvacc[nd]);
            }
        }
        __syncthreads();
    }

    // zero-fill P for skipped tiles
    {
        __half2 hz = __floats2half2_rn(0.f, 0.f);
        for (int jt = ntiles; jt < 16; jt++) {
            int j0 = jt * 128;
#pragma unroll
            for (int half = 0; half < 2; half++) {
                int i_loc = wm + g + half * 8;
#pragma unroll
                for (int nt = 0; nt < 4; nt++)
                    *(__half2*)(Pb + (size_t)i_loc * 2048 + j0 + wnA + nt * 8 + c * 2) = hz;
            }
        }
    }

    atomicAdd(&rows[wm + g], rs[0]);
    atomicAdd(&rows[wm + g + 8], rs[1]);
    __syncthreads();
    if (tid < 64) rows[tid] = 1.f / rows[tid];

    float* vb = bd_s;
    for (int idx = tid; idx < 64 * 68; idx += 512) vb[idx] = 0.f;
    __syncthreads();

    for (int r = 0; r < 4; r++) {
        if (wj == r) {
#pragma unroll
            for (int nd = 0; nd < 8; nd++)
#pragma unroll
                for (int e = 0; e < 4; e++) {
                    int row = wm + g + ((e >> 1) ? 8 : 0);
                    int col = nd * 8 + c * 2 + (e & 1);
                    vb[row * 68 + col] += pvacc[nd][e];
                }
        }
        __syncthreads();
    }

    // normalize + write vec (fp16) and rsum
#pragma unroll
    for (int t = 0; t < 4; t++) {
        int e = tid + t * 512;              // 0..2047 half2 pairs
        int row = e >> 5, cp = e & 31;
        float inv = rows[row];
        float v0 = vb[row * 68 + cp * 2] * inv;
        float v1 = vb[row * 68 + cp * 2 + 1] * inv;
        *(__half2*)(vec + ((size_t)(i0 + row) * 4 + b) * 512 + n * 64 + cp * 2) =
            __floats2half2_rn(v0, v1);
    }
    if (tid < 64)
        rsum[(size_t)bn * 512 + i0 + tid] = rows[tid];
}

// ---------------- attn matrix: mean over bn of normalized prob --------------
__global__ void attn_kernel(const __half* __restrict__ P,
                            const float* __restrict__ rsum,
                            float* __restrict__ attn) {
    int i = blockIdx.x;
    int tid = threadIdx.x;
    float acc[8] = {0.f, 0.f, 0.f, 0.f, 0.f, 0.f, 0.f, 0.f};
#pragma unroll 4
    for (int bn = 0; bn < 32; bn++) {
        float inv = rsum[(size_t)bn * 512 + i];
        const __half* prow = P + ((size_t)bn * 512 + i) * 2048 + tid * 8;
        uint4 raw = *(const uint4*)prow;
        const __half2* h2 = (const __half2*)&raw;
#pragma unroll
        for (int e = 0; e < 4; e++) {
            float2 f = __half22float2(h2[e]);
            acc[e * 2]     += inv * f.x;
            acc[e * 2 + 1] += inv * f.y;
        }
    }
    float* dst = attn + (size_t)i * 2048 + tid * 8;
#pragma unroll
    for (int e = 0; e < 8; e++) dst[e] = acc[e] * (1.f / 32.f);
}

// ---------------- layernorm ----------------
__global__ void ln_kernel(const float* __restrict__ y, const float* __restrict__ g,
                          const float* __restrict__ be, float* __restrict__ out) {
    __shared__ float red[32];
    int r = blockIdx.x;
    int tid = threadIdx.x;
    float v0 = y[(size_t)r * 512 + tid];
    float v1 = y[(size_t)r * 512 + tid + 256];
    float mean = blockRedSum(v0 + v1, red) * (1.f / 512.f);
    float d0 = v0 - mean, d1 = v1 - mean;
    float var = blockRedSum(d0 * d0 + d1 * d1, red) * (1.f / 512.f);
    float rstd = rsqrtf(var + 1e-5f);
    out[(size_t)r * 512 + tid]       = d0 * rstd * g[tid] + be[tid];
    out[(size_t)r * 512 + tid + 256] = d1 * rstd * g[tid + 256] + be[tid + 256];
}

// ---------------- launch ----------------
#define SMEM_PH  ((3 * 128 * PA_ST + 3 * 32 * PB_ST) * 2)          // 56832
#define SMEM_GH  ((2 * 128 * PA_ST + 2 * 32 * GB_ST) * 2)          // 29696
#define SMEM_SPV ((64*72*2 + 2*128*72 + 2*128*72 + 2*192*72) * 2 \
                  + (64*200 + 64 + 256) * 4)                       // 199936

extern "C" void kernel_launch(void* const* d_in, const int* in_sizes, int n_in,
                              void* d_out, int out_size) {
    (void)in_sizes; (void)n_in; (void)out_size;
    const float* x       = (const float*)d_in[0];
    const float* memory  = (const float*)d_in[1];
    const float* pos_emb = (const float*)d_in[2];
    const float* pbu     = (const float*)d_in[3];
    const float* pbv     = (const float*)d_in[4];
    const float* ib      = (const float*)d_in[6];
    const float* W_q     = (const float*)d_in[7];
    const float* W_kv    = (const float*)d_in[8];
    const float* W_rel   = (const float*)d_in[9];
    const float* W_o     = (const float*)d_in[10];
    const float* ln_g    = (const float*)d_in[11];
    const float* ln_b    = (const float*)d_in[12];

    float* out  = (float*)d_out;
    float* attn = out + (size_t)Lq * BATCH * 512;

    __half *memh, *xh, *posh, *wkvh, *wrelh, *wqh, *woh;
    __half *kvh, *relh, *prob, *vec;
    float *q, *rs, *y;
    cudaGetSymbolAddress((void**)&memh,  g_memh);
    cudaGetSymbolAddress((void**)&xh,    g_xh);
    cudaGetSymbolAddress((void**)&posh,  g_posh);
    cudaGetSymbolAddress((void**)&wkvh,  g_wkvh);
    cudaGetSymbolAddress((void**)&wrelh, g_wrelh);
    cudaGetSymbolAddress((void**)&wqh,   g_wqh);
    cudaGetSymbolAddress((void**)&woh,   g_woh);
    cudaGetSymbolAddress((void**)&kvh,   g_kv);
    cudaGetSymbolAddress((void**)&relh,  g_rel);
    cudaGetSymbolAddress((void**)&q,     g_q);
    cudaGetSymbolAddress((void**)&prob,  g_prob);
    cudaGetSymbolAddress((void**)&rs,    g_rsum);
    cudaGetSymbolAddress((void**)&vec,   g_vec);
    cudaGetSymbolAddress((void**)&y,     g_y);

    static bool attr_set = false;
    if (!attr_set) {
        cudaFuncSetAttribute(proj_h,
                             cudaFuncAttributeMaxDynamicSharedMemorySize, SMEM_PH);
        cudaFuncSetAttribute(gemm64_h,
                             cudaFuncAttributeMaxDynamicSharedMemorySize, SMEM_GH);
        cudaFuncSetAttribute(score_pv,
                             cudaFuncAttributeMaxDynamicSharedMemorySize, SMEM_SPV);
        attr_set = true;
    }

    // 0) convert fp32 inputs -> fp16
    ConvJob cj;
    cj.src[0] = memory;  cj.dst[0] = memh;  cj.n4[0] = 6144 * 512 / 4;
    cj.src[1] = x;       cj.dst[1] = xh;    cj.n4[1] = 2048 * 512 / 4;
    cj.src[2] = pos_emb; cj.dst[2] = posh;  cj.n4[2] = 8192 * 512 / 4;
    cj.src[3] = W_kv;    cj.dst[3] = wkvh;  cj.n4[3] = 512 * 1024 / 4;
    cj.src[4] = W_rel;   cj.dst[4] = wrelh; cj.n4[4] = 512 * 512 / 4;
    cj.src[5] = W_q;     cj.dst[5] = wqh;   cj.n4[5] = 512 * 512 / 4;
    cj.src[6] = W_o;     cj.dst[6] = woh;   cj.n4[6] = 512 * 512 / 4;
    int total4 = (6144 * 512 + 2048 * 512 + 8192 * 512 +
                  512 * 1024 + 3 * 512 * 512) / 4;
    conv_f2h<<<(total4 + 255) / 256, 256>>>(cj, total4);

    // 1) all 4 projections (fp16 MMA), one launch
    DescH d0 = { memh, wkvh,  (void*)kvh,                         1024, 512, 8, 0,   1 };
    DescH d1 = { xh,   wkvh,  (void*)(kvh + (size_t)6144 * 1024), 1024, 512, 8, 384, 1 };
    DescH d2 = { posh, wrelh, (void*)relh,                        512,  512, 4, 512, 1 };
    DescH d3 = { xh,   wqh,   (void*)q,                           512,  512, 4, 768, 0 };
    proj_h<<<832, 256, SMEM_PH>>>(d0, d1, d2, d3);

    // 2) fused scores + exp + PV (writes prob, rsum, vec fp16)
    score_pv<<<dim3(8, 32), 512, SMEM_SPV>>>(q, pbu, pbv, kvh, relh, ib,
                                             prob, rs, vec);

    // 3) attn matrix from normalized prob
    attn_kernel<<<512, 256>>>(prob, rs, attn);

    // 4) y = x + vec @ W_o (fp16 MMA) ; layernorm
    gemm64_h<<<dim3(8, 16), 256, SMEM_GH>>>(vec, woh, x, y, 2048, 512, 512);
    ln_kernel<<<2048, 256>>>(y, ln_g, ln_b, out);
}

// round 12
// speedup vs baseline: 5.9163x; 1.0006x over previous
#include <cuda_runtime.h>
#include <cuda_fp16.h>
#include <stdint.h>

// Problem constants
#define Lq     512
#define BATCH  4
#define SCALEF 0.125f
#define LOG2E  1.4426950408889634f

// ---------------- scratch ----------------
__device__ __half g_memh[(size_t)6144 * 512];
__device__ __half g_xh  [(size_t)2048 * 512];
__device__ __half g_posh[(size_t)8192 * 512];
__device__ __half g_wkvh[(size_t)512 * 1024];
__device__ __half g_wrelh[(size_t)512 * 512];
__device__ __half g_wqh [(size_t)512 * 512];
__device__ __half g_woh [(size_t)512 * 512];
__device__ __half g_kv  [(size_t)8192 * 1024];
__device__ __half g_rel [(size_t)8192 * 512];
__device__ float  g_q   [(size_t)2048 * 512];
__device__ __half g_prob[(size_t)32 * 512 * 2048];
__device__ float  g_rsum[(size_t)32 * 512];
__device__ __half g_vec [(size_t)2048 * 512];
__device__ float  g_y   [(size_t)2048 * 512];

// ---------------- helpers ----------------
__device__ __forceinline__ void mma_f16(float* d, const uint32_t* a,
                                        const uint32_t* b, const float* c) {
    asm volatile(
        "mma.sync.aligned.m16n8k16.row.col.f32.f16.f16.f32 "
        "{%0,%1,%2,%3}, {%4,%5,%6,%7}, {%8,%9}, {%10,%11,%12,%13};"
        : "=f"(d[0]), "=f"(d[1]), "=f"(d[2]), "=f"(d[3])
        : "r"(a[0]), "r"(a[1]), "r"(a[2]), "r"(a[3]),
          "r"(b[0]), "r"(b[1]),
          "f"(c[0]), "f"(c[1]), "f"(c[2]), "f"(c[3]));
}

__device__ __forceinline__ void ldsm_x4_t(uint32_t& r0, uint32_t& r1,
                                          uint32_t& r2, uint32_t& r3, uint32_t addr) {
    asm volatile("ldmatrix.sync.aligned.m8n8.x4.trans.shared.b16 {%0,%1,%2,%3}, [%4];"
                 : "=r"(r0), "=r"(r1), "=r"(r2), "=r"(r3) : "r"(addr));
}

__device__ __forceinline__ void cp16(void* dst, const void* src) {
    uint32_t d = (uint32_t)__cvta_generic_to_shared(dst);
    asm volatile("cp.async.cg.shared.global [%0], [%1], 16;" :: "r"(d), "l"(src));
}
#define CP_COMMIT() asm volatile("cp.async.commit_group;")
#define CP_WAIT1()  asm volatile("cp.async.wait_group 1;")
#define CP_WAIT2()  asm volatile("cp.async.wait_group 2;")

__device__ __forceinline__ float ex2f(float x) {
    float r;
    asm("ex2.approx.f32 %0, %1;" : "=f"(r) : "f"(x));
    return r;
}

__device__ __forceinline__ float warpRedSum(float v) {
#pragma unroll
    for (int o = 16; o > 0; o >>= 1) v += __shfl_xor_sync(0xffffffffu, v, o);
    return v;
}
__device__ __forceinline__ float blockRedSum(float v, float* red) {
    v = warpRedSum(v);
    int w = threadIdx.x >> 5, l = threadIdx.x & 31;
    if (!l) red[w] = v;
    __syncthreads();
    if (threadIdx.x < 32) {
        float x = (l < 8) ? red[l] : 0.f;
        x = warpRedSum(x);
        if (!l) red[0] = x;
    }
    __syncthreads();
    float r = red[0];
    __syncthreads();
    return r;
}

// ============================================================================
// Fused float->half conversion (7 arrays)
// ============================================================================
struct ConvJob {
    const float* src[7];
    __half* dst[7];
    int n4[7];
};

__global__ void conv_f2h(ConvJob j, int total4) {
    int idx = blockIdx.x * blockDim.x + threadIdx.x;
    if (idx >= total4) return;
    int off = idx, seg = 0;
#pragma unroll
    for (int s = 0; s < 6; s++)
        if (off >= j.n4[seg]) { off -= j.n4[seg]; seg++; }
    float4 v = ((const float4*)j.src[seg])[off];
    __half2* d = (__half2*)j.dst[seg] + off * 2;
    d[0] = __floats2half2_rn(v.x, v.y);
    d[1] = __floats2half2_rn(v.z, v.w);
}

// ============================================================================
// fp16 projection kernel (4 GEMMs, one launch). 3-stage cp.async.
// ============================================================================
struct DescH {
    const __half* A; const __half* B; void* C;
    int N, K, nblk, blk0, h;
};

#define PA_ST 40
#define PB_ST 136
__global__ __launch_bounds__(256) void proj_h(DescH d0, DescH d1, DescH d2, DescH d3) {
    extern __shared__ char smraw[];
    __half* As = (__half*)smraw;
    __half* Bs = As + 3 * 128 * PA_ST;

    DescH d = d3;
    int bid = blockIdx.x;
    if (bid < d1.blk0) d = d0;
    else if (bid < d2.blk0) d = d1;
    else if (bid < d3.blk0) d = d2;
    int local = bid - d.blk0;
    int m0 = (local / d.nblk) * 128, n0 = (local % d.nblk) * 128;
    const int N = d.N, K = d.K;

    int tid = threadIdx.x;
    int warp = tid >> 5, lane = tid & 31;
    int g = lane >> 2, c = lane & 3;
    int wm = (warp >> 2) * 64;
    int wn = (warp & 3) * 32;
    int mat = lane >> 3;
    int lrow = (mat & 1) * 8 + (lane & 7);
    int lcol = (mat >> 1) * 8;

    float acc[4][4][4];
#pragma unroll
    for (int mt = 0; mt < 4; mt++)
#pragma unroll
        for (int nt = 0; nt < 4; nt++)
#pragma unroll
            for (int e = 0; e < 4; e++) acc[mt][nt][e] = 0.f;

    int nk = K >> 5;
    auto loadStage = [&](int st, int k0) {
#pragma unroll
        for (int w = 0; w < 2; w++) {
            int idx = tid + w * 256;
            int r = idx >> 2, ch = (idx & 3) * 8;
            cp16(As + st * 128 * PA_ST + r * PA_ST + ch,
                 d.A + (size_t)(m0 + r) * K + k0 + ch);
        }
#pragma unroll
        for (int w = 0; w < 2; w++) {
            int idx = tid + w * 256;
            int r = idx >> 4, ch = (idx & 15) * 8;
            cp16(Bs + st * 32 * PB_ST + r * PB_ST + ch,
                 d.B + (size_t)(k0 + r) * N + n0 + ch);
        }
    };

    loadStage(0, 0);
    CP_COMMIT();
    loadStage(1, 32);
    CP_COMMIT();

    int st = 0;
    for (int kt = 0; kt < nk; kt++) {
        if (kt + 2 < nk) loadStage((st + 2) % 3, (kt + 2) * 32);
        CP_COMMIT();
        CP_WAIT2();
        __syncthreads();

        const __half* Ac = As + st * 128 * PA_ST;
        uint32_t bbase = (uint32_t)__cvta_generic_to_shared(Bs + st * 32 * PB_ST);
#pragma unroll
        for (int ks = 0; ks < 2; ks++) {
            int k = ks * 16;
            uint32_t af[4][4], bf[4][2];
#pragma unroll
            for (int mt = 0; mt < 4; mt++) {
                const __half* base = Ac + (wm + mt * 16 + g) * PA_ST + k + 2 * c;
                af[mt][0] = *(const uint32_t*)(base);
                af[mt][1] = *(const uint32_t*)(base + 8 * PA_ST);
                af[mt][2] = *(const uint32_t*)(base + 8);
                af[mt][3] = *(const uint32_t*)(base + 8 * PA_ST + 8);
            }
#pragma unroll
            for (int p = 0; p < 2; p++) {
                uint32_t addr = bbase +
                    (uint32_t)(((k + lrow) * PB_ST + wn + p * 16 + lcol) * 2);
                uint32_t r0, r1, r2, r3;
                ldsm_x4_t(r0, r1, r2, r3, addr);
                bf[2 * p][0] = r0; bf[2 * p][1] = r1;
                bf[2 * p + 1][0] = r2; bf[2 * p + 1][1] = r3;
            }
#pragma unroll
            for (int mt = 0; mt < 4; mt++)
#pragma unroll
                for (int nt = 0; nt < 4; nt++)
                    mma_f16(acc[mt][nt], af[mt], bf[nt], acc[mt][nt]);
        }
        __syncthreads();
        st = (st + 1) % 3;
    }

#pragma unroll
    for (int mt = 0; mt < 4; mt++)
#pragma unroll
        for (int nt = 0; nt < 4; nt++) {
            int row = m0 + wm + mt * 16 + g;
            int col = n0 + wn + nt * 8 + c * 2;
            if (d.h) {
                __half* Ch = (__half*)d.C;
                *(__half2*)(Ch + (size_t)row * N + col) =
                    __floats2half2_rn(acc[mt][nt][0], acc[mt][nt][1]);
                *(__half2*)(Ch + (size_t)(row + 8) * N + col) =
                    __floats2half2_rn(acc[mt][nt][2], acc[mt][nt][3]);
            } else {
                float* Cf = (float*)d.C;
                *(float2*)(Cf + (size_t)row * N + col) =
                    make_float2(acc[mt][nt][0], acc[mt][nt][1]);
                *(float2*)(Cf + (size_t)(row + 8) * N + col) =
                    make_float2(acc[mt][nt][2], acc[mt][nt][3]);
            }
        }
}

// ============================================================================
// fp16 GEMM BN=64 with fp32 residual add (W_o)
// ============================================================================
#define GB_ST 72
__global__ __launch_bounds__(256) void gemm64_h(
        const __half* __restrict__ A, const __half* __restrict__ B,
        const float* __restrict__ Cadd, float* __restrict__ C,
        int M, int N, int K) {
    extern __shared__ char smraw[];
    __half* As = (__half*)smraw;
    __half* Bs = As + 2 * 128 * PA_ST;

    int m0 = blockIdx.y * 128, n0 = blockIdx.x * 64;
    int tid = threadIdx.x;
    int warp = tid >> 5, lane = tid & 31;
    int g = lane >> 2, c = lane & 3;
    int wm = (warp >> 2) * 64;
    int wn = (warp & 3) * 16;
    int mat = lane >> 3;
    int lrow = (mat & 1) * 8 + (lane & 7);
    int lcol = (mat >> 1) * 8;

    float acc[4][2][4];
#pragma unroll
    for (int mt = 0; mt < 4; mt++)
#pragma unroll
        for (int nt = 0; nt < 2; nt++)
#pragma unroll
            for (int e = 0; e < 4; e++) acc[mt][nt][e] = 0.f;

    int nk = K >> 5;
    auto loadStage = [&](int st, int k0) {
#pragma unroll
        for (int w = 0; w < 2; w++) {
            int idx = tid + w * 256;
            int r = idx >> 2, ch = (idx & 3) * 8;
            cp16(As + st * 128 * PA_ST + r * PA_ST + ch,
                 A + (size_t)(m0 + r) * K + k0 + ch);
        }
        {
            int r = tid >> 3, ch = (tid & 7) * 8;
            if (r < 32)
                cp16(Bs + st * 32 * GB_ST + r * GB_ST + ch,
                     B + (size_t)(k0 + r) * N + n0 + ch);
        }
    };

    loadStage(0, 0);
    CP_COMMIT();

    for (int kt = 0; kt < nk; kt++) {
        int cur = kt & 1;
        if (kt + 1 < nk) loadStage((kt + 1) & 1, (kt + 1) * 32);
        CP_COMMIT();
        CP_WAIT1();
        __syncthreads();

        const __half* Ac = As + cur * 128 * PA_ST;
        uint32_t bbase = (uint32_t)__cvta_generic_to_shared(Bs + cur * 32 * GB_ST);
#pragma unroll
        for (int ks = 0; ks < 2; ks++) {
            int k = ks * 16;
            uint32_t af[4][4], bf[2][2];
#pragma unroll
            for (int mt = 0; mt < 4; mt++) {
                const __half* base = Ac + (wm + mt * 16 + g) * PA_ST + k + 2 * c;
                af[mt][0] = *(const uint32_t*)(base);
                af[mt][1] = *(const uint32_t*)(base + 8 * PA_ST);
                af[mt][2] = *(const uint32_t*)(base + 8);
                af[mt][3] = *(const uint32_t*)(base + 8 * PA_ST + 8);
            }
            {
                uint32_t addr = bbase +
                    (uint32_t)(((k + lrow) * GB_ST + wn + lcol) * 2);
                uint32_t r0, r1, r2, r3;
                ldsm_x4_t(r0, r1, r2, r3, addr);
                bf[0][0] = r0; bf[0][1] = r1;
                bf[1][0] = r2; bf[1][1] = r3;
            }
#pragma unroll
            for (int mt = 0; mt < 4; mt++)
#pragma unroll
                for (int nt = 0; nt < 2; nt++)
                    mma_f16(acc[mt][nt], af[mt], bf[nt], acc[mt][nt]);
        }
        __syncthreads();
    }

#pragma unroll
    for (int mt = 0; mt < 4; mt++)
#pragma unroll
        for (int nt = 0; nt < 2; nt++) {
            int row = m0 + wm + mt * 16 + g;
            int col = n0 + wn + nt * 8 + c * 2;
            const float* a0 = Cadd + (size_t)row * N + col;
            const float* a1 = Cadd + (size_t)(row + 8) * N + col;
            *(float2*)(C + (size_t)row * N + col) =
                make_float2(acc[mt][nt][0] + a0[0], acc[mt][nt][1] + a0[1]);
            *(float2*)(C + (size_t)(row + 8) * N + col) =
                make_float2(acc[mt][nt][2] + a1[0], acc[mt][nt][3] + a1[1]);
        }
}

// ============================================================================
// FLASH-FUSED score + exp + PV kernel, 512 threads (16 warps: 4 m x 4 j).
// BD computed in NON-OVERLAPPING 128-col m-chunks (ring of 2): chunk jt+1
// computed during tile jt (chunk 0 in prologue); epilogue of tile jt reads
// chunk jt (off<128) and chunk jt+1 (off>=128). Saves 1/3 of BD MMAs and
// rel traffic vs the 192-band scheme.
// ============================================================================
__global__ __launch_bounds__(512, 1) void score_pv(
        const float* __restrict__ Q, const float* __restrict__ pbu,
        const float* __restrict__ pbv, const __half* __restrict__ KV,
        const __half* __restrict__ REL, const float* __restrict__ ib,
        __half* __restrict__ P, float* __restrict__ rsum,
        __half* __restrict__ vec) {
    extern __shared__ char smraw[];
    __half* qu_s  = (__half*)smraw;               // [64][72]
    __half* qv_s  = qu_s + 64 * 72;               // [64][72]
    __half* k_s   = qv_s + 64 * 72;               // [2][128*72]
    __half* v_s   = k_s + 2 * 128 * 72;           // [2][128*72]
    __half* rel_s = v_s + 2 * 128 * 72;           // [2][128*72]
    float*  bd_s  = (float*)(rel_s + 2 * 128 * 72);  // [2][64*132]
    float*  rows  = bd_s + 2 * 64 * 132;          // [64]
    float*  gate_s = rows + 64;                   // [64][4]

    int bn = blockIdx.y;
    int b = bn >> 3, n = bn & 7;
    int i0 = blockIdx.x * 64;
    int tid = threadIdx.x;
    int m_base = 448 - i0;

    if (tid < 64) rows[tid] = 0.f;
    if (tid < 256)
        gate_s[tid] = ib[((size_t)(i0 + (tid >> 2)) * 4 + b) * 4 + (tid & 3)];

    const float QS = SCALEF * LOG2E;
#pragma unroll
    for (int w = 0; w < 2; w++) {
        int idx = tid + w * 512;
        int r = idx >> 4, c4 = (idx & 15) * 4;
        float4 v = *(const float4*)(Q + (size_t)(i0 + r) * 2048 + b * 512 + n * 64 + c4);
        float4 bu = *(const float4*)(pbu + n * 64 + c4);
        float4 bv = *(const float4*)(pbv + n * 64 + c4);
        *(__half2*)(qu_s + r * 72 + c4) =
            __floats2half2_rn((v.x + bu.x) * QS, (v.y + bu.y) * QS);
        *(__half2*)(qu_s + r * 72 + c4 + 2) =
            __floats2half2_rn((v.z + bu.z) * QS, (v.w + bu.w) * QS);
        *(__half2*)(qv_s + r * 72 + c4) =
            __floats2half2_rn((v.x + bv.x) * QS, (v.y + bv.y) * QS);
        *(__half2*)(qv_s + r * 72 + c4 + 2) =
            __floats2half2_rn((v.z + bv.z) * QS, (v.w + bv.w) * QS);
    }

    const __half* Kb = KV + b * 1024 + n * 64;
    const __half* Vb = KV + b * 1024 + 512 + n * 64;
    const __half* Rb = REL + b * 512 + n * 64;

    auto loadK = [&](int st, int j0) {
#pragma unroll
        for (int w = 0; w < 2; w++) {
            int idx = tid + w * 512;
            int r = idx >> 3, ch = (idx & 7) * 8;
            cp16(k_s + st * 128 * 72 + r * 72 + ch,
                 Kb + (size_t)(j0 + r) * 4096 + ch);
        }
    };
    auto loadV = [&](int st, int j0) {
#pragma unroll
        for (int w = 0; w < 2; w++) {
            int idx = tid + w * 512;
            int r = idx >> 3, ch = (idx & 7) * 8;
            cp16(v_s + st * 128 * 72 + r * 72 + ch,
                 Vb + (size_t)(j0 + r) * 4096 + ch);
        }
    };
    auto loadR = [&](int chunk) {
        int st = chunk & 1;
        int mc = m_base + chunk * 128;
#pragma unroll
        for (int w = 0; w < 2; w++) {
            int idx = tid + w * 512;
            int r = idx >> 3, ch = (idx & 7) * 8;
            int mr = mc + r; if (mr > 2047) mr = 2047;
            cp16(rel_s + st * 128 * 72 + r * 72 + ch,
                 Rb + (size_t)mr * 2048 + ch);
        }
    };

    int ntiles = ((1599 + i0) >> 7) + 1;
    if (ntiles > 16) ntiles = 16;

    int warp = tid >> 5, lane = tid & 31;
    int g = lane >> 2, c = lane & 3;
    int wm  = (warp >> 2) * 16;
    int wj  = warp & 3;
    int wnA = wj * 32;

    int mat = lane >> 3;
    int lrow = (mat & 1) * 8 + (lane & 7);
    int lcol = (mat >> 1) * 8;

    // BD chunk compute (chunk data already in rel_s[chunk&1]); stores to bd_s[chunk&1]
    auto computeBD = [&](int chunk) {
        const __half* rc = rel_s + (chunk & 1) * 128 * 72;
        float accb[4][4];
#pragma unroll
        for (int nt = 0; nt < 4; nt++)
#pragma unroll
            for (int e = 0; e < 4; e++) accb[nt][e] = 0.f;
#pragma unroll
        for (int kk = 0; kk < 4; kk++) {
            int k = kk * 16;
            uint32_t av[4], br[4][2];
            const __half* bv = qv_s + (wm + g) * 72 + k + 2 * c;
            av[0] = *(const uint32_t*)(bv);
            av[1] = *(const uint32_t*)(bv + 8 * 72);
            av[2] = *(const uint32_t*)(bv + 8);
            av[3] = *(const uint32_t*)(bv + 8 * 72 + 8);
#pragma unroll
            for (int nt = 0; nt < 4; nt++) {
                const __half* base = rc + (wnA + nt * 8 + g) * 72 + k + 2 * c;
                br[nt][0] = *(const uint32_t*)(base);
                br[nt][1] = *(const uint32_t*)(base + 8);
            }
#pragma unroll
            for (int nt = 0; nt < 4; nt++)
                mma_f16(accb[nt], av, br[nt], accb[nt]);
        }
        float* bdo = bd_s + (chunk & 1) * 64 * 132;
#pragma unroll
        for (int nt = 0; nt < 4; nt++) {
            int row = wm + g;
            int col = wnA + nt * 8 + c * 2;
            *(float2*)(bdo + row * 132 + col) = make_float2(accb[nt][0], accb[nt][1]);
            *(float2*)(bdo + (row + 8) * 132 + col) = make_float2(accb[nt][2], accb[nt][3]);
        }
    };

    // prologue: G0 = {R chunk0}; G1 = {K0, V0, R chunk1}
    loadR(0);
    CP_COMMIT();
    loadK(0, 0); loadV(0, 0); loadR(1);
    CP_COMMIT();
    CP_WAIT1();              // chunk0 arrived
    __syncthreads();
    computeBD(0);            // -> bd_s[0]; visible after tile-0 mid sync

    float rs[2] = {0.f, 0.f};
    float pvacc[8][4];
#pragma unroll
    for (int nd = 0; nd < 8; nd++)
#pragma unroll
        for (int e = 0; e < 4; e++) pvacc[nd][e] = 0.f;

    __half* Pb = P + ((size_t)bn * 512 + i0) * 2048;

    for (int jt = 0; jt < ntiles; jt++) {
        int cur = jt & 1;
        // issue next loads: K/V tile jt+1, rel chunk jt+2
        if (jt + 1 < ntiles) {
            loadK((jt + 1) & 1, (jt + 1) * 128);
            loadV((jt + 1) & 1, (jt + 1) * 128);
        }
        if (jt + 2 <= ntiles) loadR(jt + 2);
        CP_COMMIT();
        CP_WAIT1();          // K/V(jt) + R(jt+1) arrived
        __syncthreads();

        const __half* kc = k_s + cur * 128 * 72;

        // AC (this tile) + BD (chunk jt+1), interleaved
        {
            const __half* rc = rel_s + ((jt + 1) & 1) * 128 * 72;
            float acca[4][4], accb[4][4];
#pragma unroll
            for (int nt = 0; nt < 4; nt++)
#pragma unroll
                for (int e = 0; e < 4; e++) { acca[nt][e] = 0.f; accb[nt][e] = 0.f; }

#pragma unroll
            for (int kk = 0; kk < 4; kk++) {
                int k = kk * 16;
                uint32_t au[4], av[4], bk[4][2], br[4][2];
                {
                    const __half* bu = qu_s + (wm + g) * 72 + k + 2 * c;
                    const __half* bv = qv_s + (wm + g) * 72 + k + 2 * c;
                    au[0] = *(const uint32_t*)(bu);
                    au[1] = *(const uint32_t*)(bu + 8 * 72);
                    au[2] = *(const uint32_t*)(bu + 8);
                    au[3] = *(const uint32_t*)(bu + 8 * 72 + 8);
                    av[0] = *(const uint32_t*)(bv);
                    av[1] = *(const uint32_t*)(bv + 8 * 72);
                    av[2] = *(const uint32_t*)(bv + 8);
                    av[3] = *(const uint32_t*)(bv + 8 * 72 + 8);
                }
#pragma unroll
                for (int nt = 0; nt < 4; nt++) {
                    const __half* base = kc + (wnA + nt * 8 + g) * 72 + k + 2 * c;
                    bk[nt][0] = *(const uint32_t*)(base);
                    bk[nt][1] = *(const uint32_t*)(base + 8);
                }
#pragma unroll
                for (int nt = 0; nt < 4; nt++) {
                    const __half* base = rc + (wnA + nt * 8 + g) * 72 + k + 2 * c;
                    br[nt][0] = *(const uint32_t*)(base);
                    br[nt][1] = *(const uint32_t*)(base + 8);
                }
#pragma unroll
                for (int nt = 0; nt < 4; nt++) {
                    mma_f16(acca[nt], au, bk[nt], acca[nt]);
                    mma_f16(accb[nt], av, br[nt], accb[nt]);
                }
            }

            // store BD chunk jt+1
            float* bdo = bd_s + ((jt + 1) & 1) * 64 * 132;
#pragma unroll
            for (int nt = 0; nt < 4; nt++) {
                int row = wm + g;
                int col = wnA + nt * 8 + c * 2;
                *(float2*)(bdo + row * 132 + col) = make_float2(accb[nt][0], accb[nt][1]);
                *(float2*)(bdo + (row + 8) * 132 + col) = make_float2(accb[nt][2], accb[nt][3]);
            }
            __syncthreads();   // BD chunks jt, jt+1 now visible to all warps

            // epilogue: gates + shift + mask + ex2 -> P + PV fragments
            int j0 = jt * 128;
            int segA = j0 >> 9;
            const float* bd_lo = bd_s + (jt & 1) * 64 * 132;
            const float* bd_hi = bd_s + ((jt + 1) & 1) * 64 * 132;
            uint32_t pe2[4][2];
#pragma unroll
            for (int half = 0; half < 2; half++) {
                int i_loc = wm + g + half * 8;
                int i = i0 + i_loc;
                int jmax = 1536 + i;
                float gA = gate_s[i_loc * 4 + segA];
                const float* gt = gate_s + i_loc * 4;
#pragma unroll
                for (int nt = 0; nt < 4; nt++) {
                    float a0 = acca[nt][half * 2];
                    float a1 = acca[nt][half * 2 + 1];
                    float pe[2];
#pragma unroll
                    for (int e = 0; e < 2; e++) {
                        int j_loc = wnA + nt * 8 + c * 2 + e;
                        int j = j0 + j_loc;
                        int m = j + 511 - i;
                        int segB = m >> 9; if (segB > 3) segB = 3;
                        int off = j_loc + 63 - i_loc;
                        float bd = (off < 128) ? bd_lo[i_loc * 132 + off]
                                               : bd_hi[i_loc * 132 + off - 128];
                        float ac = e ? a1 : a0;
                        float s = gA * ac + gt[segB] * bd;
                        pe[e] = (j <= jmax) ? ex2f(s) : 0.f;
                    }
                    rs[half] += pe[0] + pe[1];
                    __half2 h2 = __floats2half2_rn(pe[0], pe[1]);
                    pe2[nt][half] = *(uint32_t*)&h2;
                    *(__half2*)(Pb + (size_t)i_loc * 2048 + j0 + wnA + nt * 8 + c * 2) = h2;
                }
            }

            // PV MMA
            {
                uint32_t vbase = (uint32_t)__cvta_generic_to_shared(v_s + cur * 128 * 72);
#pragma unroll
                for (int kk2 = 0; kk2 < 2; kk2++) {
                    uint32_t bf[8][2];
#pragma unroll
                    for (int p = 0; p < 4; p++) {
                        uint32_t addr = vbase +
                            (uint32_t)(((wnA + kk2 * 16 + lrow) * 72 + p * 16 + lcol) * 2);
                        uint32_t r0, r1, r2, r3;
                        ldsm_x4_t(r0, r1, r2, r3, addr);
                        bf[2 * p][0] = r0; bf[2 * p][1] = r1;
                        bf[2 * p + 1][0] = r2; bf[2 * p + 1][1] = r3;
                    }
                    uint32_t af[4];
                    af[0] = pe2[2 * kk2][0];
                    af[1] = pe2[2 * kk2][1];
                    af[2] = pe2[2 * kk2 + 1][0];
                    af[3] = pe2[2 * kk2 + 1][1];
#pragma unroll
                    for (int nd = 0; nd < 8; nd++)
                        mma_f16(pvacc[nd], af, bf[nd], pvacc[nd]);
                }
            }
        }
        __syncthreads();
    }

    // zero-fill P for skipped tiles
    {
        __half2 hz = __floats2half2_rn(0.f, 0.f);
        for (int jt = ntiles; jt < 16; jt++) {
            int j0 = jt * 128;
#pragma unroll
            for (int half = 0; half < 2; half++) {
                int i_loc = wm + g + half * 8;
#pragma unroll
                for (int nt = 0; nt < 4; nt++)
                    *(__half2*)(Pb + (size_t)i_loc * 2048 + j0 + wnA + nt * 8 + c * 2) = hz;
            }
        }
    }

    atomicAdd(&rows[wm + g], rs[0]);
    atomicAdd(&rows[wm + g + 8], rs[1]);
    __syncthreads();
    if (tid < 64) rows[tid] = 1.f / rows[tid];

    // vb aliases bd_s
    float* vb = bd_s;
    for (int idx = tid; idx < 64 * 68; idx += 512) vb[idx] = 0.f;
    __syncthreads();

    for (int r = 0; r < 4; r++) {
        if (wj == r) {
#pragma unroll
            for (int nd = 0; nd < 8; nd++)
#pragma unroll
                for (int e = 0; e < 4; e++) {
                    int row = wm + g + ((e >> 1) ? 8 : 0);
                    int col = nd * 8 + c * 2 + (e & 1);
                    vb[row * 68 + col] += pvacc[nd][e];
                }
        }
        __syncthreads();
    }

#pragma unroll
    for (int t = 0; t < 4; t++) {
        int e = tid + t * 512;
        int row = e >> 5, cp = e & 31;
        float inv = rows[row];
        float v0 = vb[row * 68 + cp * 2] * inv;
        float v1 = vb[row * 68 + cp * 2 + 1] * inv;
        *(__half2*)(vec + ((size_t)(i0 + row) * 4 + b) * 512 + n * 64 + cp * 2) =
            __floats2half2_rn(v0, v1);
    }
    if (tid < 64)
        rsum[(size_t)bn * 512 + i0 + tid] = rows[tid];
}

// ---------------- attn matrix: preloaded invs, 2-way unrolled loads ---------
__global__ void attn_kernel(const __half* __restrict__ P,
                            const float* __restrict__ rsum,
                            float* __restrict__ attn) {
    __shared__ float invs[32];
    int i = blockIdx.x;
    int tid = threadIdx.x;
    if (tid < 32) invs[tid] = rsum[(size_t)tid * 512 + i];
    __syncthreads();

    float acc[8] = {0.f, 0.f, 0.f, 0.f, 0.f, 0.f, 0.f, 0.f};
    const __half* base = P + (size_t)i * 2048 + tid * 8;
#pragma unroll 4
    for (int bn = 0; bn < 32; bn += 2) {
        uint4 raw0 = *(const uint4*)(base + (size_t)bn * 512 * 2048);
        uint4 raw1 = *(const uint4*)(base + (size_t)(bn + 1) * 512 * 2048);
        float inv0 = invs[bn], inv1 = invs[bn + 1];
        const __half2* h0 = (const __half2*)&raw0;
        const __half2* h1 = (const __half2*)&raw1;
#pragma unroll
        for (int e = 0; e < 4; e++) {
            float2 f0 = __half22float2(h0[e]);
            float2 f1 = __half22float2(h1[e]);
            acc[e * 2]     += inv0 * f0.x + inv1 * f1.x;
            acc[e * 2 + 1] += inv0 * f0.y + inv1 * f1.y;
        }
    }
    float* dst = attn + (size_t)i * 2048 + tid * 8;
#pragma unroll
    for (int e = 0; e < 8; e++) dst[e] = acc[e] * (1.f / 32.f);
}

// ---------------- layernorm ----------------
__global__ void ln_kernel(const float* __restrict__ y, const float* __restrict__ g,
                          const float* __restrict__ be, float* __restrict__ out) {
    __shared__ float red[32];
    int r = blockIdx.x;
    int tid = threadIdx.x;
    float v0 = y[(size_t)r * 512 + tid];
    float v1 = y[(size_t)r * 512 + tid + 256];
    float mean = blockRedSum(v0 + v1, red) * (1.f / 512.f);
    float d0 = v0 - mean, d1 = v1 - mean;
    float var = blockRedSum(d0 * d0 + d1 * d1, red) * (1.f / 512.f);
    float rstd = rsqrtf(var + 1e-5f);
    out[(size_t)r * 512 + tid]       = d0 * rstd * g[tid] + be[tid];
    out[(size_t)r * 512 + tid + 256] = d1 * rstd * g[tid + 256] + be[tid + 256];
}

// ---------------- launch ----------------
#define SMEM_PH  ((3 * 128 * PA_ST + 3 * 32 * PB_ST) * 2)          // 56832
#define SMEM_GH  ((2 * 128 * PA_ST + 2 * 32 * GB_ST) * 2)          // 29696
#define SMEM_SPV ((64*72*2 + 3*2*128*72) * 2 + (2*64*132 + 64 + 256) * 4)  // 197888

extern "C" void kernel_launch(void* const* d_in, const int* in_sizes, int n_in,
                              void* d_out, int out_size) {
    (void)in_sizes; (void)n_in; (void)out_size;
    const float* x       = (const float*)d_in[0];
    const float* memory  = (const float*)d_in[1];
    const float* pos_emb = (const float*)d_in[2];
    const float* pbu     = (const float*)d_in[3];
    const float* pbv     = (const float*)d_in[4];
    const float* ib      = (const float*)d_in[6];
    const float* W_q     = (const float*)d_in[7];
    const float* W_kv    = (const float*)d_in[8];
    const float* W_rel   = (const float*)d_in[9];
    const float* W_o     = (const float*)d_in[10];
    const float* ln_g    = (const float*)d_in[11];
    const float* ln_b    = (const float*)d_in[12];

    float* out  = (float*)d_out;
    float* attn = out + (size_t)Lq * BATCH * 512;

    __half *memh, *xh, *posh, *wkvh, *wrelh, *wqh, *woh;
    __half *kvh, *relh, *prob, *vec;
    float *q, *rs, *y;
    cudaGetSymbolAddress((void**)&memh,  g_memh);
    cudaGetSymbolAddress((void**)&xh,    g_xh);
    cudaGetSymbolAddress((void**)&posh,  g_posh);
    cudaGetSymbolAddress((void**)&wkvh,  g_wkvh);
    cudaGetSymbolAddress((void**)&wrelh, g_wrelh);
    cudaGetSymbolAddress((void**)&wqh,   g_wqh);
    cudaGetSymbolAddress((void**)&woh,   g_woh);
    cudaGetSymbolAddress((void**)&kvh,   g_kv);
    cudaGetSymbolAddress((void**)&relh,  g_rel);
    cudaGetSymbolAddress((void**)&q,     g_q);
    cudaGetSymbolAddress((void**)&prob,  g_prob);
    cudaGetSymbolAddress((void**)&rs,    g_rsum);
    cudaGetSymbolAddress((void**)&vec,   g_vec);
    cudaGetSymbolAddress((void**)&y,     g_y);

    static bool attr_set = false;
    if (!attr_set) {
        cudaFuncSetAttribute(proj_h,
                             cudaFuncAttributeMaxDynamicSharedMemorySize, SMEM_PH);
        cudaFuncSetAttribute(gemm64_h,
                             cudaFuncAttributeMaxDynamicSharedMemorySize, SMEM_GH);
        cudaFuncSetAttribute(score_pv,
                             cudaFuncAttributeMaxDynamicSharedMemorySize, SMEM_SPV);
        attr_set = true;
    }

    // 0) convert fp32 inputs -> fp16
    ConvJob cj;
    cj.src[0] = memory;  cj.dst[0] = memh;  cj.n4[0] = 6144 * 512 / 4;
    cj.src[1] = x;       cj.dst[1] = xh;    cj.n4[1] = 2048 * 512 / 4;
    cj.src[2] = pos_emb; cj.dst[2] = posh;  cj.n4[2] = 8192 * 512 / 4;
    cj.src[3] = W_kv;    cj.dst[3] = wkvh;  cj.n4[3] = 512 * 1024 / 4;
    cj.src[4] = W_rel;   cj.dst[4] = wrelh; cj.n4[4] = 512 * 512 / 4;
    cj.src[5] = W_q;     cj.dst[5] = wqh;   cj.n4[5] = 512 * 512 / 4;
    cj.src[6] = W_o;     cj.dst[6] = woh;   cj.n4[6] = 512 * 512 / 4;
    int total4 = (6144 * 512 + 2048 * 512 + 8192 * 512 +
                  512 * 1024 + 3 * 512 * 512) / 4;
    conv_f2h<<<(total4 + 255) / 256, 256>>>(cj, total4);

    // 1) all 4 projections (fp16 MMA), one launch
    DescH d0 = { memh, wkvh,  (void*)kvh,                         1024, 512, 8, 0,   1 };
    DescH d1 = { xh,   wkvh,  (void*)(kvh + (size_t)6144 * 1024), 1024, 512, 8, 384, 1 };
    DescH d2 = { posh, wrelh, (void*)relh,                        512,  512, 4, 512, 1 };
    DescH d3 = { xh,   wqh,   (void*)q,                           512,  512, 4, 768, 0 };
    proj_h<<<832, 256, SMEM_PH>>>(d0, d1, d2, d3);

    // 2) fused scores + exp + PV (writes prob, rsum, vec fp16)
    score_pv<<<dim3(8, 32), 512, SMEM_SPV>>>(q, pbu, pbv, kvh, relh, ib,
                                             prob, rs, vec);

    // 3) attn matrix from normalized prob
    attn_kernel<<<512, 256>>>(prob, rs, attn);

    // 4) y = x + vec @ W_o (fp16 MMA) ; layernorm
    gemm64_h<<<dim3(8, 16), 256, SMEM_GH>>>(vec, woh, x, y, 2048, 512, 512);
    ln_kernel<<<2048, 256>>>(y, ln_g, ln_b, out);
}

// round 13
// speedup vs baseline: 6.0386x; 1.0207x over previous
#include <cuda_runtime.h>
#include <cuda_fp16.h>
#include <stdint.h>

// Problem constants
#define Lq     512
#define BATCH  4
#define SCALEF 0.125f
#define LOG2E  1.4426950408889634f

// ---------------- scratch ----------------
__device__ __half g_memh[(size_t)6144 * 512];
__device__ __half g_xh  [(size_t)2048 * 512];
__device__ __half g_posh[(size_t)8192 * 512];
__device__ __half g_wkvh[(size_t)512 * 1024];
__device__ __half g_wrelh[(size_t)512 * 512];
__device__ __half g_wqh [(size_t)512 * 512];
__device__ __half g_woh [(size_t)512 * 512];
__device__ __half g_kv  [(size_t)8192 * 1024];
__device__ __half g_rel [(size_t)8192 * 512];
__device__ __half g_qh  [(size_t)2048 * 512];           // q fp16
__device__ __half g_prob[(size_t)32 * 512 * 2048];      // i-major: [i][bn][j]
__device__ float  g_rsum[(size_t)32 * 512];
__device__ __half g_vec [(size_t)2048 * 512];
__device__ float  g_y   [(size_t)2048 * 512];

// ---------------- helpers ----------------
__device__ __forceinline__ void mma_f16(float* d, const uint32_t* a,
                                        const uint32_t* b, const float* c) {
    asm volatile(
        "mma.sync.aligned.m16n8k16.row.col.f32.f16.f16.f32 "
        "{%0,%1,%2,%3}, {%4,%5,%6,%7}, {%8,%9}, {%10,%11,%12,%13};"
        : "=f"(d[0]), "=f"(d[1]), "=f"(d[2]), "=f"(d[3])
        : "r"(a[0]), "r"(a[1]), "r"(a[2]), "r"(a[3]),
          "r"(b[0]), "r"(b[1]),
          "f"(c[0]), "f"(c[1]), "f"(c[2]), "f"(c[3]));
}

__device__ __forceinline__ void ldsm_x4_t(uint32_t& r0, uint32_t& r1,
                                          uint32_t& r2, uint32_t& r3, uint32_t addr) {
    asm volatile("ldmatrix.sync.aligned.m8n8.x4.trans.shared.b16 {%0,%1,%2,%3}, [%4];"
                 : "=r"(r0), "=r"(r1), "=r"(r2), "=r"(r3) : "r"(addr));
}

__device__ __forceinline__ void cp16(void* dst, const void* src) {
    uint32_t d = (uint32_t)__cvta_generic_to_shared(dst);
    asm volatile("cp.async.cg.shared.global [%0], [%1], 16;" :: "r"(d), "l"(src));
}
#define CP_COMMIT() asm volatile("cp.async.commit_group;")
#define CP_WAIT1()  asm volatile("cp.async.wait_group 1;")
#define CP_WAIT2()  asm volatile("cp.async.wait_group 2;")

__device__ __forceinline__ float ex2f(float x) {
    float r;
    asm("ex2.approx.f32 %0, %1;" : "=f"(r) : "f"(x));
    return r;
}

__device__ __forceinline__ float warpRedSum(float v) {
#pragma unroll
    for (int o = 16; o > 0; o >>= 1) v += __shfl_xor_sync(0xffffffffu, v, o);
    return v;
}
__device__ __forceinline__ float blockRedSum(float v, float* red) {
    v = warpRedSum(v);
    int w = threadIdx.x >> 5, l = threadIdx.x & 31;
    if (!l) red[w] = v;
    __syncthreads();
    if (threadIdx.x < 32) {
        float x = (l < 8) ? red[l] : 0.f;
        x = warpRedSum(x);
        if (!l) red[0] = x;
    }
    __syncthreads();
    float r = red[0];
    __syncthreads();
    return r;
}

// ============================================================================
// Fused float->half conversion (7 arrays)
// ============================================================================
struct ConvJob {
    const float* src[7];
    __half* dst[7];
    int n4[7];
};

__global__ void conv_f2h(ConvJob j, int total4) {
    int idx = blockIdx.x * blockDim.x + threadIdx.x;
    if (idx >= total4) return;
    int off = idx, seg = 0;
#pragma unroll
    for (int s = 0; s < 6; s++)
        if (off >= j.n4[seg]) { off -= j.n4[seg]; seg++; }
    float4 v = ((const float4*)j.src[seg])[off];
    __half2* d = (__half2*)j.dst[seg] + off * 2;
    d[0] = __floats2half2_rn(v.x, v.y);
    d[1] = __floats2half2_rn(v.z, v.w);
}

// ============================================================================
// fp16 projection kernel (4 GEMMs, one launch). 3-stage cp.async.
// ============================================================================
struct DescH {
    const __half* A; const __half* B; void* C;
    int N, K, nblk, blk0, h;
};

#define PA_ST 40
#define PB_ST 136
__global__ __launch_bounds__(256) void proj_h(DescH d0, DescH d1, DescH d2, DescH d3) {
    extern __shared__ char smraw[];
    __half* As = (__half*)smraw;
    __half* Bs = As + 3 * 128 * PA_ST;

    DescH d = d3;
    int bid = blockIdx.x;
    if (bid < d1.blk0) d = d0;
    else if (bid < d2.blk0) d = d1;
    else if (bid < d3.blk0) d = d2;
    int local = bid - d.blk0;
    int m0 = (local / d.nblk) * 128, n0 = (local % d.nblk) * 128;
    const int N = d.N, K = d.K;

    int tid = threadIdx.x;
    int warp = tid >> 5, lane = tid & 31;
    int g = lane >> 2, c = lane & 3;
    int wm = (warp >> 2) * 64;
    int wn = (warp & 3) * 32;
    int mat = lane >> 3;
    int lrow = (mat & 1) * 8 + (lane & 7);
    int lcol = (mat >> 1) * 8;

    float acc[4][4][4];
#pragma unroll
    for (int mt = 0; mt < 4; mt++)
#pragma unroll
        for (int nt = 0; nt < 4; nt++)
#pragma unroll
            for (int e = 0; e < 4; e++) acc[mt][nt][e] = 0.f;

    int nk = K >> 5;
    auto loadStage = [&](int st, int k0) {
#pragma unroll
        for (int w = 0; w < 2; w++) {
            int idx = tid + w * 256;
            int r = idx >> 2, ch = (idx & 3) * 8;
            cp16(As + st * 128 * PA_ST + r * PA_ST + ch,
                 d.A + (size_t)(m0 + r) * K + k0 + ch);
        }
#pragma unroll
        for (int w = 0; w < 2; w++) {
            int idx = tid + w * 256;
            int r = idx >> 4, ch = (idx & 15) * 8;
            cp16(Bs + st * 32 * PB_ST + r * PB_ST + ch,
                 d.B + (size_t)(k0 + r) * N + n0 + ch);
        }
    };

    loadStage(0, 0);
    CP_COMMIT();
    loadStage(1, 32);
    CP_COMMIT();

    int st = 0;
    for (int kt = 0; kt < nk; kt++) {
        if (kt + 2 < nk) loadStage((st + 2) % 3, (kt + 2) * 32);
        CP_COMMIT();
        CP_WAIT2();
        __syncthreads();

        const __half* Ac = As + st * 128 * PA_ST;
        uint32_t bbase = (uint32_t)__cvta_generic_to_shared(Bs + st * 32 * PB_ST);
#pragma unroll
        for (int ks = 0; ks < 2; ks++) {
            int k = ks * 16;
            uint32_t af[4][4], bf[4][2];
#pragma unroll
            for (int mt = 0; mt < 4; mt++) {
                const __half* base = Ac + (wm + mt * 16 + g) * PA_ST + k + 2 * c;
                af[mt][0] = *(const uint32_t*)(base);
                af[mt][1] = *(const uint32_t*)(base + 8 * PA_ST);
                af[mt][2] = *(const uint32_t*)(base + 8);
                af[mt][3] = *(const uint32_t*)(base + 8 * PA_ST + 8);
            }
#pragma unroll
            for (int p = 0; p < 2; p++) {
                uint32_t addr = bbase +
                    (uint32_t)(((k + lrow) * PB_ST + wn + p * 16 + lcol) * 2);
                uint32_t r0, r1, r2, r3;
                ldsm_x4_t(r0, r1, r2, r3, addr);
                bf[2 * p][0] = r0; bf[2 * p][1] = r1;
                bf[2 * p + 1][0] = r2; bf[2 * p + 1][1] = r3;
            }
#pragma unroll
            for (int mt = 0; mt < 4; mt++)
#pragma unroll
                for (int nt = 0; nt < 4; nt++)
                    mma_f16(acc[mt][nt], af[mt], bf[nt], acc[mt][nt]);
        }
        __syncthreads();
        st = (st + 1) % 3;
    }

#pragma unroll
    for (int mt = 0; mt < 4; mt++)
#pragma unroll
        for (int nt = 0; nt < 4; nt++) {
            int row = m0 + wm + mt * 16 + g;
            int col = n0 + wn + nt * 8 + c * 2;
            if (d.h) {
                __half* Ch = (__half*)d.C;
                *(__half2*)(Ch + (size_t)row * N + col) =
                    __floats2half2_rn(acc[mt][nt][0], acc[mt][nt][1]);
                *(__half2*)(Ch + (size_t)(row + 8) * N + col) =
                    __floats2half2_rn(acc[mt][nt][2], acc[mt][nt][3]);
            } else {
                float* Cf = (float*)d.C;
                *(float2*)(Cf + (size_t)row * N + col) =
                    make_float2(acc[mt][nt][0], acc[mt][nt][1]);
                *(float2*)(Cf + (size_t)(row + 8) * N + col) =
                    make_float2(acc[mt][nt][2], acc[mt][nt][3]);
            }
        }
}

// ============================================================================
// fp16 GEMM BN=64 with fp32 residual add (W_o)
// ============================================================================
#define GB_ST 72
__global__ __launch_bounds__(256) void gemm64_h(
        const __half* __restrict__ A, const __half* __restrict__ B,
        const float* __restrict__ Cadd, float* __restrict__ C,
        int M, int N, int K) {
    extern __shared__ char smraw[];
    __half* As = (__half*)smraw;
    __half* Bs = As + 2 * 128 * PA_ST;

    int m0 = blockIdx.y * 128, n0 = blockIdx.x * 64;
    int tid = threadIdx.x;
    int warp = tid >> 5, lane = tid & 31;
    int g = lane >> 2, c = lane & 3;
    int wm = (warp >> 2) * 64;
    int wn = (warp & 3) * 16;
    int mat = lane >> 3;
    int lrow = (mat & 1) * 8 + (lane & 7);
    int lcol = (mat >> 1) * 8;

    float acc[4][2][4];
#pragma unroll
    for (int mt = 0; mt < 4; mt++)
#pragma unroll
        for (int nt = 0; nt < 2; nt++)
#pragma unroll
            for (int e = 0; e < 4; e++) acc[mt][nt][e] = 0.f;

    int nk = K >> 5;
    auto loadStage = [&](int st, int k0) {
#pragma unroll
        for (int w = 0; w < 2; w++) {
            int idx = tid + w * 256;
            int r = idx >> 2, ch = (idx & 3) * 8;
            cp16(As + st * 128 * PA_ST + r * PA_ST + ch,
                 A + (size_t)(m0 + r) * K + k0 + ch);
        }
        {
            int r = tid >> 3, ch = (tid & 7) * 8;
            if (r < 32)
                cp16(Bs + st * 32 * GB_ST + r * GB_ST + ch,
                     B + (size_t)(k0 + r) * N + n0 + ch);
        }
    };

    loadStage(0, 0);
    CP_COMMIT();

    for (int kt = 0; kt < nk; kt++) {
        int cur = kt & 1;
        if (kt + 1 < nk) loadStage((kt + 1) & 1, (kt + 1) * 32);
        CP_COMMIT();
        CP_WAIT1();
        __syncthreads();

        const __half* Ac = As + cur * 128 * PA_ST;
        uint32_t bbase = (uint32_t)__cvta_generic_to_shared(Bs + cur * 32 * GB_ST);
#pragma unroll
        for (int ks = 0; ks < 2; ks++) {
            int k = ks * 16;
            uint32_t af[4][4], bf[2][2];
#pragma unroll
            for (int mt = 0; mt < 4; mt++) {
                const __half* base = Ac + (wm + mt * 16 + g) * PA_ST + k + 2 * c;
                af[mt][0] = *(const uint32_t*)(base);
                af[mt][1] = *(const uint32_t*)(base + 8 * PA_ST);
                af[mt][2] = *(const uint32_t*)(base + 8);
                af[mt][3] = *(const uint32_t*)(base + 8 * PA_ST + 8);
            }
            {
                uint32_t addr = bbase +
                    (uint32_t)(((k + lrow) * GB_ST + wn + lcol) * 2);
                uint32_t r0, r1, r2, r3;
                ldsm_x4_t(r0, r1, r2, r3, addr);
                bf[0][0] = r0; bf[0][1] = r1;
                bf[1][0] = r2; bf[1][1] = r3;
            }
#pragma unroll
            for (int mt = 0; mt < 4; mt++)
#pragma unroll
                for (int nt = 0; nt < 2; nt++)
                    mma_f16(acc[mt][nt], af[mt], bf[nt], acc[mt][nt]);
        }
        __syncthreads();
    }

#pragma unroll
    for (int mt = 0; mt < 4; mt++)
#pragma unroll
        for (int nt = 0; nt < 2; nt++) {
            int row = m0 + wm + mt * 16 + g;
            int col = n0 + wn + nt * 8 + c * 2;
            const float* a0 = Cadd + (size_t)row * N + col;
            const float* a1 = Cadd + (size_t)(row + 8) * N + col;
            *(float2*)(C + (size_t)row * N + col) =
                make_float2(acc[mt][nt][0] + a0[0], acc[mt][nt][1] + a0[1]);
            *(float2*)(C + (size_t)(row + 8) * N + col) =
                make_float2(acc[mt][nt][2] + a1[0], acc[mt][nt][3] + a1[1]);
        }
}

// ============================================================================
// FLASH-FUSED score + exp + PV kernel, 512 threads (16 warps: 4 m x 4 j).
// q fragments hoisted into registers (invariant across tiles). P stored
// i-major: P[((i)*32 + bn)*2048 + j].
// ============================================================================
__global__ __launch_bounds__(512, 1) void score_pv(
        const __half* __restrict__ Q, const float* __restrict__ pbu,
        const float* __restrict__ pbv, const __half* __restrict__ KV,
        const __half* __restrict__ REL, const float* __restrict__ ib,
        __half* __restrict__ P, float* __restrict__ rsum,
        __half* __restrict__ vec) {
    extern __shared__ char smraw[];
    __half* qu_s  = (__half*)smraw;               // [64][72]
    __half* qv_s  = qu_s + 64 * 72;               // [64][72]
    __half* k_s   = qv_s + 64 * 72;               // [2][128*72]
    __half* v_s   = k_s + 2 * 128 * 72;           // [2][128*72]
    __half* rel_s = v_s + 2 * 128 * 72;           // [2][128*72]
    float*  bd_s  = (float*)(rel_s + 2 * 128 * 72);  // [2][64*132]
    float*  rows  = bd_s + 2 * 64 * 132;          // [64]
    float*  gate_s = rows + 64;                   // [64][4]

    int bn = blockIdx.y;
    int b = bn >> 3, n = bn & 7;
    int i0 = blockIdx.x * 64;
    int tid = threadIdx.x;
    int m_base = 448 - i0;

    if (tid < 64) rows[tid] = 0.f;
    if (tid < 256)
        gate_s[tid] = ib[((size_t)(i0 + (tid >> 2)) * 4 + b) * 4 + (tid & 3)];

    const float QS = SCALEF * LOG2E;
#pragma unroll
    for (int w = 0; w < 2; w++) {
        int idx = tid + w * 512;
        int r = idx >> 4, c4 = (idx & 15) * 4;
        const __half2* qsrc =
            (const __half2*)(Q + (size_t)(i0 + r) * 2048 + b * 512 + n * 64 + c4);
        float2 q0 = __half22float2(qsrc[0]);
        float2 q1 = __half22float2(qsrc[1]);
        float4 bu = *(const float4*)(pbu + n * 64 + c4);
        float4 bv = *(const float4*)(pbv + n * 64 + c4);
        *(__half2*)(qu_s + r * 72 + c4) =
            __floats2half2_rn((q0.x + bu.x) * QS, (q0.y + bu.y) * QS);
        *(__half2*)(qu_s + r * 72 + c4 + 2) =
            __floats2half2_rn((q1.x + bu.z) * QS, (q1.y + bu.w) * QS);
        *(__half2*)(qv_s + r * 72 + c4) =
            __floats2half2_rn((q0.x + bv.x) * QS, (q0.y + bv.y) * QS);
        *(__half2*)(qv_s + r * 72 + c4 + 2) =
            __floats2half2_rn((q1.x + bv.z) * QS, (q1.y + bv.w) * QS);
    }

    const __half* Kb = KV + b * 1024 + n * 64;
    const __half* Vb = KV + b * 1024 + 512 + n * 64;
    const __half* Rb = REL + b * 512 + n * 64;

    auto loadK = [&](int st, int j0) {
#pragma unroll
        for (int w = 0; w < 2; w++) {
            int idx = tid + w * 512;
            int r = idx >> 3, ch = (idx & 7) * 8;
            cp16(k_s + st * 128 * 72 + r * 72 + ch,
                 Kb + (size_t)(j0 + r) * 4096 + ch);
        }
    };
    auto loadV = [&](int st, int j0) {
#pragma unroll
        for (int w = 0; w < 2; w++) {
            int idx = tid + w * 512;
            int r = idx >> 3, ch = (idx & 7) * 8;
            cp16(v_s + st * 128 * 72 + r * 72 + ch,
                 Vb + (size_t)(j0 + r) * 4096 + ch);
        }
    };
    auto loadR = [&](int chunk) {
        int st = chunk & 1;
        int mc = m_base + chunk * 128;
#pragma unroll
        for (int w = 0; w < 2; w++) {
            int idx = tid + w * 512;
            int r = idx >> 3, ch = (idx & 7) * 8;
            int mr = mc + r; if (mr > 2047) mr = 2047;
            cp16(rel_s + st * 128 * 72 + r * 72 + ch,
                 Rb + (size_t)mr * 2048 + ch);
        }
    };

    int ntiles = ((1599 + i0) >> 7) + 1;
    if (ntiles > 16) ntiles = 16;

    int warp = tid >> 5, lane = tid & 31;
    int g = lane >> 2, c = lane & 3;
    int wm  = (warp >> 2) * 16;
    int wj  = warp & 3;
    int wnA = wj * 32;

    int mat = lane >> 3;
    int lrow = (mat & 1) * 8 + (lane & 7);
    int lcol = (mat >> 1) * 8;

    // prologue: G0 = {R chunk0}; G1 = {K0, V0, R chunk1}
    loadR(0);
    CP_COMMIT();
    loadK(0, 0); loadV(0, 0); loadR(1);
    CP_COMMIT();
    CP_WAIT1();
    __syncthreads();   // q staging + R chunk0 visible

    // hoist q fragments into registers (invariant across tiles)
    uint32_t au_r[4][4], av_r[4][4];
#pragma unroll
    for (int kk = 0; kk < 4; kk++) {
        int k = kk * 16;
        const __half* bu = qu_s + (wm + g) * 72 + k + 2 * c;
        const __half* bv = qv_s + (wm + g) * 72 + k + 2 * c;
        au_r[kk][0] = *(const uint32_t*)(bu);
        au_r[kk][1] = *(const uint32_t*)(bu + 8 * 72);
        au_r[kk][2] = *(const uint32_t*)(bu + 8);
        au_r[kk][3] = *(const uint32_t*)(bu + 8 * 72 + 8);
        av_r[kk][0] = *(const uint32_t*)(bv);
        av_r[kk][1] = *(const uint32_t*)(bv + 8 * 72);
        av_r[kk][2] = *(const uint32_t*)(bv + 8);
        av_r[kk][3] = *(const uint32_t*)(bv + 8 * 72 + 8);
    }

    // BD chunk 0 -> bd_s[0]
    {
        const __half* rc = rel_s;
        float accb[4][4];
#pragma unroll
        for (int nt = 0; nt < 4; nt++)
#pragma unroll
            for (int e = 0; e < 4; e++) accb[nt][e] = 0.f;
#pragma unroll
        for (int kk = 0; kk < 4; kk++) {
            int k = kk * 16;
            uint32_t br[4][2];
#pragma unroll
            for (int nt = 0; nt < 4; nt++) {
                const __half* base = rc + (wnA + nt * 8 + g) * 72 + k + 2 * c;
                br[nt][0] = *(const uint32_t*)(base);
                br[nt][1] = *(const uint32_t*)(base + 8);
            }
#pragma unroll
            for (int nt = 0; nt < 4; nt++)
                mma_f16(accb[nt], av_r[kk], br[nt], accb[nt]);
        }
#pragma unroll
        for (int nt = 0; nt < 4; nt++) {
            int row = wm + g;
            int col = wnA + nt * 8 + c * 2;
            *(float2*)(bd_s + row * 132 + col) = make_float2(accb[nt][0], accb[nt][1]);
            *(float2*)(bd_s + (row + 8) * 132 + col) = make_float2(accb[nt][2], accb[nt][3]);
        }
    }

    float rs[2] = {0.f, 0.f};
    float pvacc[8][4];
#pragma unroll
    for (int nd = 0; nd < 8; nd++)
#pragma unroll
        for (int e = 0; e < 4; e++) pvacc[nd][e] = 0.f;

    __half* Pb = P + ((size_t)i0 * 32 + bn) * 2048;   // i-major layout

    for (int jt = 0; jt < ntiles; jt++) {
        int cur = jt & 1;
        if (jt + 1 < ntiles) {
            loadK((jt + 1) & 1, (jt + 1) * 128);
            loadV((jt + 1) & 1, (jt + 1) * 128);
        }
        if (jt + 2 <= ntiles) loadR(jt + 2);
        CP_COMMIT();
        CP_WAIT1();
        __syncthreads();

        const __half* kc = k_s + cur * 128 * 72;
        const __half* rc = rel_s + ((jt + 1) & 1) * 128 * 72;

        float acca[4][4], accb[4][4];
#pragma unroll
        for (int nt = 0; nt < 4; nt++)
#pragma unroll
            for (int e = 0; e < 4; e++) { acca[nt][e] = 0.f; accb[nt][e] = 0.f; }

#pragma unroll
        for (int kk = 0; kk < 4; kk++) {
            int k = kk * 16;
            uint32_t bk[4][2], br[4][2];
#pragma unroll
            for (int nt = 0; nt < 4; nt++) {
                const __half* base = kc + (wnA + nt * 8 + g) * 72 + k + 2 * c;
                bk[nt][0] = *(const uint32_t*)(base);
                bk[nt][1] = *(const uint32_t*)(base + 8);
            }
#pragma unroll
            for (int nt = 0; nt < 4; nt++) {
                const __half* base = rc + (wnA + nt * 8 + g) * 72 + k + 2 * c;
                br[nt][0] = *(const uint32_t*)(base);
                br[nt][1] = *(const uint32_t*)(base + 8);
            }
#pragma unroll
            for (int nt = 0; nt < 4; nt++) {
                mma_f16(acca[nt], au_r[kk], bk[nt], acca[nt]);
                mma_f16(accb[nt], av_r[kk], br[nt], accb[nt]);
            }
        }

        // store BD chunk jt+1
        float* bdo = bd_s + ((jt + 1) & 1) * 64 * 132;
#pragma unroll
        for (int nt = 0; nt < 4; nt++) {
            int row = wm + g;
            int col = wnA + nt * 8 + c * 2;
            *(float2*)(bdo + row * 132 + col) = make_float2(accb[nt][0], accb[nt][1]);
            *(float2*)(bdo + (row + 8) * 132 + col) = make_float2(accb[nt][2], accb[nt][3]);
        }
        __syncthreads();

        // epilogue: gates + shift + mask + ex2 -> P + PV fragments
        int j0 = jt * 128;
        int segA = j0 >> 9;
        const float* bd_lo = bd_s + (jt & 1) * 64 * 132;
        const float* bd_hi = bd_s + ((jt + 1) & 1) * 64 * 132;
        uint32_t pe2[4][2];
#pragma unroll
        for (int half = 0; half < 2; half++) {
            int i_loc = wm + g + half * 8;
            int i = i0 + i_loc;
            int jmax = 1536 + i;
            float gA = gate_s[i_loc * 4 + segA];
            const float* gt = gate_s + i_loc * 4;
#pragma unroll
            for (int nt = 0; nt < 4; nt++) {
                float a0 = acca[nt][half * 2];
                float a1 = acca[nt][half * 2 + 1];
                float pe[2];
#pragma unroll
                for (int e = 0; e < 2; e++) {
                    int j_loc = wnA + nt * 8 + c * 2 + e;
                    int j = j0 + j_loc;
                    int m = j + 511 - i;
                    int segB = m >> 9; if (segB > 3) segB = 3;
                    int off = j_loc + 63 - i_loc;
                    float bd = (off < 128) ? bd_lo[i_loc * 132 + off]
                                           : bd_hi[i_loc * 132 + off - 128];
                    float ac = e ? a1 : a0;
                    float s = gA * ac + gt[segB] * bd;
                    pe[e] = (j <= jmax) ? ex2f(s) : 0.f;
                }
                rs[half] += pe[0] + pe[1];
                __half2 h2 = __floats2half2_rn(pe[0], pe[1]);
                pe2[nt][half] = *(uint32_t*)&h2;
                *(__half2*)(Pb + (size_t)i_loc * 65536 + j0 + wnA + nt * 8 + c * 2) = h2;
            }
        }

        // PV MMA
        {
            uint32_t vbase = (uint32_t)__cvta_generic_to_shared(v_s + cur * 128 * 72);
#pragma unroll
            for (int kk2 = 0; kk2 < 2; kk2++) {
                uint32_t bf[8][2];
#pragma unroll
                for (int p = 0; p < 4; p++) {
                    uint32_t addr = vbase +
                        (uint32_t)(((wnA + kk2 * 16 + lrow) * 72 + p * 16 + lcol) * 2);
                    uint32_t r0, r1, r2, r3;
                    ldsm_x4_t(r0, r1, r2, r3, addr);
                    bf[2 * p][0] = r0; bf[2 * p][1] = r1;
                    bf[2 * p + 1][0] = r2; bf[2 * p + 1][1] = r3;
                }
                uint32_t af[4];
                af[0] = pe2[2 * kk2][0];
                af[1] = pe2[2 * kk2][1];
                af[2] = pe2[2 * kk2 + 1][0];
                af[3] = pe2[2 * kk2 + 1][1];
#pragma unroll
                for (int nd = 0; nd < 8; nd++)
                    mma_f16(pvacc[nd], af, bf[nd], pvacc[nd]);
            }
        }
        __syncthreads();
    }

    // zero-fill P for skipped tiles
    {
        __half2 hz = __floats2half2_rn(0.f, 0.f);
        for (int jt = ntiles; jt < 16; jt++) {
            int j0 = jt * 128;
#pragma unroll
            for (int half = 0; half < 2; half++) {
                int i_loc = wm + g + half * 8;
#pragma unroll
                for (int nt = 0; nt < 4; nt++)
                    *(__half2*)(Pb + (size_t)i_loc * 65536 + j0 + wnA + nt * 8 + c * 2) = hz;
            }
        }
    }

    atomicAdd(&rows[wm + g], rs[0]);
    atomicAdd(&rows[wm + g + 8], rs[1]);
    __syncthreads();
    if (tid < 64) rows[tid] = 1.f / rows[tid];

    // vb aliases bd_s
    float* vb = bd_s;
    for (int idx = tid; idx < 64 * 68; idx += 512) vb[idx] = 0.f;
    __syncthreads();

    for (int r = 0; r < 4; r++) {
        if (wj == r) {
#pragma unroll
            for (int nd = 0; nd < 8; nd++)
#pragma unroll
                for (int e = 0; e < 4; e++) {
                    int row = wm + g + ((e >> 1) ? 8 : 0);
                    int col = nd * 8 + c * 2 + (e & 1);
                    vb[row * 68 + col] += pvacc[nd][e];
                }
        }
        __syncthreads();
    }

#pragma unroll
    for (int t = 0; t < 4; t++) {
        int e = tid + t * 512;
        int row = e >> 5, cp = e & 31;
        float inv = rows[row];
        float v0 = vb[row * 68 + cp * 2] * inv;
        float v1 = vb[row * 68 + cp * 2 + 1] * inv;
        *(__half2*)(vec + ((size_t)(i0 + row) * 4 + b) * 512 + n * 64 + cp * 2) =
            __floats2half2_rn(v0, v1);
    }
    if (tid < 64)
        rsum[(size_t)bn * 512 + i0 + tid] = rows[tid];
}

// ---------------- attn matrix: contiguous i-major P, 4-deep loads ----------
__global__ void attn_kernel(const __half* __restrict__ P,
                            const float* __restrict__ rsum,
                            float* __restrict__ attn) {
    __shared__ float invs[32];
    int i = blockIdx.x;
    int tid = threadIdx.x;
    if (tid < 32) invs[tid] = rsum[(size_t)tid * 512 + i];
    __syncthreads();

    float acc[8] = {0.f, 0.f, 0.f, 0.f, 0.f, 0.f, 0.f, 0.f};
    const __half* base = P + (size_t)i * 65536 + tid * 8;
#pragma unroll 2
    for (int bn = 0; bn < 32; bn += 4) {
        uint4 raw0 = *(const uint4*)(base + (size_t)(bn + 0) * 2048);
        uint4 raw1 = *(const uint4*)(base + (size_t)(bn + 1) * 2048);
        uint4 raw2 = *(const uint4*)(base + (size_t)(bn + 2) * 2048);
        uint4 raw3 = *(const uint4*)(base + (size_t)(bn + 3) * 2048);
        float i0v = invs[bn], i1v = invs[bn + 1], i2v = invs[bn + 2], i3v = invs[bn + 3];
        const __half2* h0 = (const __half2*)&raw0;
        const __half2* h1 = (const __half2*)&raw1;
        const __half2* h2 = (const __half2*)&raw2;
        const __half2* h3 = (const __half2*)&raw3;
#pragma unroll
        for (int e = 0; e < 4; e++) {
            float2 f0 = __half22float2(h0[e]);
            float2 f1 = __half22float2(h1[e]);
            float2 f2 = __half22float2(h2[e]);
            float2 f3 = __half22float2(h3[e]);
            acc[e * 2]     += i0v * f0.x + i1v * f1.x + i2v * f2.x + i3v * f3.x;
            acc[e * 2 + 1] += i0v * f0.y + i1v * f1.y + i2v * f2.y + i3v * f3.y;
        }
    }
    float* dst = attn + (size_t)i * 2048 + tid * 8;
#pragma unroll
    for (int e = 0; e < 8; e++) dst[e] = acc[e] * (1.f / 32.f);
}

// ---------------- layernorm ----------------
__global__ void ln_kernel(const float* __restrict__ y, const float* __restrict__ g,
                          const float* __restrict__ be, float* __restrict__ out) {
    __shared__ float red[32];
    int r = blockIdx.x;
    int tid = threadIdx.x;
    float v0 = y[(size_t)r * 512 + tid];
    float v1 = y[(size_t)r * 512 + tid + 256];
    float mean = blockRedSum(v0 + v1, red) * (1.f / 512.f);
    float d0 = v0 - mean, d1 = v1 - mean;
    float var = blockRedSum(d0 * d0 + d1 * d1, red) * (1.f / 512.f);
    float rstd = rsqrtf(var + 1e-5f);
    out[(size_t)r * 512 + tid]       = d0 * rstd * g[tid] + be[tid];
    out[(size_t)r * 512 + tid + 256] = d1 * rstd * g[tid + 256] + be[tid + 256];
}

// ---------------- launch ----------------
#define SMEM_PH  ((3 * 128 * PA_ST + 3 * 32 * PB_ST) * 2)
#define SMEM_GH  ((2 * 128 * PA_ST + 2 * 32 * GB_ST) * 2)
#define SMEM_SPV ((64*72*2 + 3*2*128*72) * 2 + (2*64*132 + 64 + 256) * 4)

extern "C" void kernel_launch(void* const* d_in, const int* in_sizes, int n_in,
                              void* d_out, int out_size) {
    (void)in_sizes; (void)n_in; (void)out_size;
    const float* x       = (const float*)d_in[0];
    const float* memory  = (const float*)d_in[1];
    const float* pos_emb = (const float*)d_in[2];
    const float* pbu     = (const float*)d_in[3];
    const float* pbv     = (const float*)d_in[4];
    const float* ib      = (const float*)d_in[6];
    const float* W_q     = (const float*)d_in[7];
    const float* W_kv    = (const float*)d_in[8];
    const float* W_rel   = (const float*)d_in[9];
    const float* W_o     = (const float*)d_in[10];
    const float* ln_g    = (const float*)d_in[11];
    const float* ln_b    = (const float*)d_in[12];

    float* out  = (float*)d_out;
    float* attn = out + (size_t)Lq * BATCH * 512;

    __half *memh, *xh, *posh, *wkvh, *wrelh, *wqh, *woh;
    __half *kvh, *relh, *qh, *prob, *vec;
    float *rs, *y;
    cudaGetSymbolAddress((void**)&memh,  g_memh);
    cudaGetSymbolAddress((void**)&xh,    g_xh);
    cudaGetSymbolAddress((void**)&posh,  g_posh);
    cudaGetSymbolAddress((void**)&wkvh,  g_wkvh);
    cudaGetSymbolAddress((void**)&wrelh, g_wrelh);
    cudaGetSymbolAddress((void**)&wqh,   g_wqh);
    cudaGetSymbolAddress((void**)&woh,   g_woh);
    cudaGetSymbolAddress((void**)&kvh,   g_kv);
    cudaGetSymbolAddress((void**)&relh,  g_rel);
    cudaGetSymbolAddress((void**)&qh,    g_qh);
    cudaGetSymbolAddress((void**)&prob,  g_prob);
    cudaGetSymbolAddress((void**)&rs,    g_rsum);
    cudaGetSymbolAddress((void**)&vec,   g_vec);
    cudaGetSymbolAddress((void**)&y,     g_y);

    static bool attr_set = false;
    if (!attr_set) {
        cudaFuncSetAttribute(proj_h,
                             cudaFuncAttributeMaxDynamicSharedMemorySize, SMEM_PH);
        cudaFuncSetAttribute(gemm64_h,
                             cudaFuncAttributeMaxDynamicSharedMemorySize, SMEM_GH);
        cudaFuncSetAttribute(score_pv,
                             cudaFuncAttributeMaxDynamicSharedMemorySize, SMEM_SPV);
        attr_set = true;
    }

    // 0) convert fp32 inputs -> fp16
    ConvJob cj;
    cj.src[0] = memory;  cj.dst[0] = memh;  cj.n4[0] = 6144 * 512 / 4;
    cj.src[1] = x;       cj.dst[1] = xh;    cj.n4[1] = 2048 * 512 / 4;
    cj.src[2] = pos_emb; cj.dst[2] = posh;  cj.n4[2] = 8192 * 512 / 4;
    cj.src[3] = W_kv;    cj.dst[3] = wkvh;  cj.n4[3] = 512 * 1024 / 4;
    cj.src[4] = W_rel;   cj.dst[4] = wrelh; cj.n4[4] = 512 * 512 / 4;
    cj.src[5] = W_q;     cj.dst[5] = wqh;   cj.n4[5] = 512 * 512 / 4;
    cj.src[6] = W_o;     cj.dst[6] = woh;   cj.n4[6] = 512 * 512 / 4;
    int total4 = (6144 * 512 + 2048 * 512 + 8192 * 512 +
                  512 * 1024 + 3 * 512 * 512) / 4;
    conv_f2h<<<(total4 + 255) / 256, 256>>>(cj, total4);

    // 1) all 4 projections (fp16 MMA), one launch; q now fp16 out
    DescH d0 = { memh, wkvh,  (void*)kvh,                         1024, 512, 8, 0,   1 };
    DescH d1 = { xh,   wkvh,  (void*)(kvh + (size_t)6144 * 1024), 1024, 512, 8, 384, 1 };
    DescH d2 = { posh, wrelh, (void*)relh,                        512,  512, 4, 512, 1 };
    DescH d3 = { xh,   wqh,   (void*)qh,                          512,  512, 4, 768, 1 };
    proj_h<<<832, 256, SMEM_PH>>>(d0, d1, d2, d3);

    // 2) fused scores + exp + PV
    score_pv<<<dim3(8, 32), 512, SMEM_SPV>>>(qh, pbu, pbv, kvh, relh, ib,
                                             prob, rs, vec);

    // 3) attn matrix (contiguous reads)
    attn_kernel<<<512, 256>>>(prob, rs, attn);

    // 4) y = x + vec @ W_o ; layernorm
    gemm64_h<<<dim3(8, 16), 256, SMEM_GH>>>(vec, woh, x, y, 2048, 512, 512);
    ln_kernel<<<2048, 256>>>(y, ln_g, ln_b, out);
}

// round 14
// speedup vs baseline: 6.4485x; 1.0679x over previous
#include <cuda_runtime.h>
#include <cuda_fp16.h>
#include <stdint.h>

// Problem constants
#define Lq     512
#define BATCH  4
#define SCALEF 0.125f
#define LOG2E  1.4426950408889634f

// ---------------- scratch ----------------
__device__ __half g_memh[(size_t)6144 * 512];
__device__ __half g_xh  [(size_t)2048 * 512];
__device__ __half g_posh[(size_t)8192 * 512];
__device__ __half g_wkvh[(size_t)512 * 1024];
__device__ __half g_wrelh[(size_t)512 * 512];
__device__ __half g_wqh [(size_t)512 * 512];
__device__ __half g_woh [(size_t)512 * 512];
__device__ __half g_kv  [(size_t)8192 * 1024];
__device__ __half g_rel [(size_t)8192 * 512];
__device__ __half g_qh  [(size_t)2048 * 512];
__device__ __half g_prob[(size_t)32 * 512 * 2048];      // i-major: [i][bn][j]
__device__ float  g_rsum[(size_t)32 * 512];
__device__ __half g_vec [(size_t)2048 * 512];
__device__ float  g_y   [(size_t)2048 * 512];

// ---------------- helpers ----------------
__device__ __forceinline__ void mma_f16(float* d, const uint32_t* a,
                                        const uint32_t* b, const float* c) {
    asm volatile(
        "mma.sync.aligned.m16n8k16.row.col.f32.f16.f16.f32 "
        "{%0,%1,%2,%3}, {%4,%5,%6,%7}, {%8,%9}, {%10,%11,%12,%13};"
        : "=f"(d[0]), "=f"(d[1]), "=f"(d[2]), "=f"(d[3])
        : "r"(a[0]), "r"(a[1]), "r"(a[2]), "r"(a[3]),
          "r"(b[0]), "r"(b[1]),
          "f"(c[0]), "f"(c[1]), "f"(c[2]), "f"(c[3]));
}

__device__ __forceinline__ void ldsm_x4_t(uint32_t& r0, uint32_t& r1,
                                          uint32_t& r2, uint32_t& r3, uint32_t addr) {
    asm volatile("ldmatrix.sync.aligned.m8n8.x4.trans.shared.b16 {%0,%1,%2,%3}, [%4];"
                 : "=r"(r0), "=r"(r1), "=r"(r2), "=r"(r3) : "r"(addr));
}
__device__ __forceinline__ void ldsm_x4(uint32_t& r0, uint32_t& r1,
                                        uint32_t& r2, uint32_t& r3, uint32_t addr) {
    asm volatile("ldmatrix.sync.aligned.m8n8.x4.shared.b16 {%0,%1,%2,%3}, [%4];"
                 : "=r"(r0), "=r"(r1), "=r"(r2), "=r"(r3) : "r"(addr));
}

__device__ __forceinline__ void cp16(void* dst, const void* src) {
    uint32_t d = (uint32_t)__cvta_generic_to_shared(dst);
    asm volatile("cp.async.cg.shared.global [%0], [%1], 16;" :: "r"(d), "l"(src));
}
#define CP_COMMIT() asm volatile("cp.async.commit_group;")
#define CP_WAIT1()  asm volatile("cp.async.wait_group 1;")
#define CP_WAIT2()  asm volatile("cp.async.wait_group 2;")

__device__ __forceinline__ float ex2f(float x) {
    float r;
    asm("ex2.approx.f32 %0, %1;" : "=f"(r) : "f"(x));
    return r;
}

__device__ __forceinline__ float warpRedSum(float v) {
#pragma unroll
    for (int o = 16; o > 0; o >>= 1) v += __shfl_xor_sync(0xffffffffu, v, o);
    return v;
}
__device__ __forceinline__ float blockRedSum(float v, float* red) {
    v = warpRedSum(v);
    int w = threadIdx.x >> 5, l = threadIdx.x & 31;
    if (!l) red[w] = v;
    __syncthreads();
    if (threadIdx.x < 32) {
        float x = (l < 8) ? red[l] : 0.f;
        x = warpRedSum(x);
        if (!l) red[0] = x;
    }
    __syncthreads();
    float r = red[0];
    __syncthreads();
    return r;
}

// ============================================================================
// Fused float->half conversion (7 arrays)
// ============================================================================
struct ConvJob {
    const float* src[7];
    __half* dst[7];
    int n4[7];
};

__global__ void conv_f2h(ConvJob j, int total4) {
    int idx = blockIdx.x * blockDim.x + threadIdx.x;
    if (idx >= total4) return;
    int off = idx, seg = 0;
#pragma unroll
    for (int s = 0; s < 6; s++)
        if (off >= j.n4[seg]) { off -= j.n4[seg]; seg++; }
    float4 v = ((const float4*)j.src[seg])[off];
    __half2* d = (__half2*)j.dst[seg] + off * 2;
    d[0] = __floats2half2_rn(v.x, v.y);
    d[1] = __floats2half2_rn(v.z, v.w);
}

// ============================================================================
// fp16 projection kernel (4 GEMMs, one launch). 3-stage cp.async.
// ============================================================================
struct DescH {
    const __half* A; const __half* B; void* C;
    int N, K, nblk, blk0, h;
};

#define PA_ST 40
#define PB_ST 136
__global__ __launch_bounds__(256) void proj_h(DescH d0, DescH d1, DescH d2, DescH d3) {
    extern __shared__ char smraw[];
    __half* As = (__half*)smraw;
    __half* Bs = As + 3 * 128 * PA_ST;

    DescH d = d3;
    int bid = blockIdx.x;
    if (bid < d1.blk0) d = d0;
    else if (bid < d2.blk0) d = d1;
    else if (bid < d3.blk0) d = d2;
    int local = bid - d.blk0;
    int m0 = (local / d.nblk) * 128, n0 = (local % d.nblk) * 128;
    const int N = d.N, K = d.K;

    int tid = threadIdx.x;
    int warp = tid >> 5, lane = tid & 31;
    int g = lane >> 2, c = lane & 3;
    int wm = (warp >> 2) * 64;
    int wn = (warp & 3) * 32;
    int mat = lane >> 3;
    int lrow = (mat & 1) * 8 + (lane & 7);
    int lcol = (mat >> 1) * 8;

    float acc[4][4][4];
#pragma unroll
    for (int mt = 0; mt < 4; mt++)
#pragma unroll
        for (int nt = 0; nt < 4; nt++)
#pragma unroll
            for (int e = 0; e < 4; e++) acc[mt][nt][e] = 0.f;

    int nk = K >> 5;
    auto loadStage = [&](int st, int k0) {
#pragma unroll
        for (int w = 0; w < 2; w++) {
            int idx = tid + w * 256;
            int r = idx >> 2, ch = (idx & 3) * 8;
            cp16(As + st * 128 * PA_ST + r * PA_ST + ch,
                 d.A + (size_t)(m0 + r) * K + k0 + ch);
        }
#pragma unroll
        for (int w = 0; w < 2; w++) {
            int idx = tid + w * 256;
            int r = idx >> 4, ch = (idx & 15) * 8;
            cp16(Bs + st * 32 * PB_ST + r * PB_ST + ch,
                 d.B + (size_t)(k0 + r) * N + n0 + ch);
        }
    };

    loadStage(0, 0);
    CP_COMMIT();
    loadStage(1, 32);
    CP_COMMIT();

    int st = 0;
    for (int kt = 0; kt < nk; kt++) {
        if (kt + 2 < nk) loadStage((st + 2) % 3, (kt + 2) * 32);
        CP_COMMIT();
        CP_WAIT2();
        __syncthreads();

        const __half* Ac = As + st * 128 * PA_ST;
        uint32_t bbase = (uint32_t)__cvta_generic_to_shared(Bs + st * 32 * PB_ST);
#pragma unroll
        for (int ks = 0; ks < 2; ks++) {
            int k = ks * 16;
            uint32_t af[4][4], bf[4][2];
#pragma unroll
            for (int mt = 0; mt < 4; mt++) {
                const __half* base = Ac + (wm + mt * 16 + g) * PA_ST + k + 2 * c;
                af[mt][0] = *(const uint32_t*)(base);
                af[mt][1] = *(const uint32_t*)(base + 8 * PA_ST);
                af[mt][2] = *(const uint32_t*)(base + 8);
                af[mt][3] = *(const uint32_t*)(base + 8 * PA_ST + 8);
            }
#pragma unroll
            for (int p = 0; p < 2; p++) {
                uint32_t addr = bbase +
                    (uint32_t)(((k + lrow) * PB_ST + wn + p * 16 + lcol) * 2);
                uint32_t r0, r1, r2, r3;
                ldsm_x4_t(r0, r1, r2, r3, addr);
                bf[2 * p][0] = r0; bf[2 * p][1] = r1;
                bf[2 * p + 1][0] = r2; bf[2 * p + 1][1] = r3;
            }
#pragma unroll
            for (int mt = 0; mt < 4; mt++)
#pragma unroll
                for (int nt = 0; nt < 4; nt++)
                    mma_f16(acc[mt][nt], af[mt], bf[nt], acc[mt][nt]);
        }
        __syncthreads();
        st = (st + 1) % 3;
    }

#pragma unroll
    for (int mt = 0; mt < 4; mt++)
#pragma unroll
        for (int nt = 0; nt < 4; nt++) {
            int row = m0 + wm + mt * 16 + g;
            int col = n0 + wn + nt * 8 + c * 2;
            if (d.h) {
                __half* Ch = (__half*)d.C;
                *(__half2*)(Ch + (size_t)row * N + col) =
                    __floats2half2_rn(acc[mt][nt][0], acc[mt][nt][1]);
                *(__half2*)(Ch + (size_t)(row + 8) * N + col) =
                    __floats2half2_rn(acc[mt][nt][2], acc[mt][nt][3]);
            } else {
                float* Cf = (float*)d.C;
                *(float2*)(Cf + (size_t)row * N + col) =
                    make_float2(acc[mt][nt][0], acc[mt][nt][1]);
                *(float2*)(Cf + (size_t)(row + 8) * N + col) =
                    make_float2(acc[mt][nt][2], acc[mt][nt][3]);
            }
        }
}

// ============================================================================
// fp16 GEMM BN=64 with fp32 residual add (W_o)
// ============================================================================
#define GB_ST 72
__global__ __launch_bounds__(256) void gemm64_h(
        const __half* __restrict__ A, const __half* __restrict__ B,
        const float* __restrict__ Cadd, float* __restrict__ C,
        int M, int N, int K) {
    extern __shared__ char smraw[];
    __half* As = (__half*)smraw;
    __half* Bs = As + 2 * 128 * PA_ST;

    int m0 = blockIdx.y * 128, n0 = blockIdx.x * 64;
    int tid = threadIdx.x;
    int warp = tid >> 5, lane = tid & 31;
    int g = lane >> 2, c = lane & 3;
    int wm = (warp >> 2) * 64;
    int wn = (warp & 3) * 16;
    int mat = lane >> 3;
    int lrow = (mat & 1) * 8 + (lane & 7);
    int lcol = (mat >> 1) * 8;

    float acc[4][2][4];
#pragma unroll
    for (int mt = 0; mt < 4; mt++)
#pragma unroll
        for (int nt = 0; nt < 2; nt++)
#pragma unroll
            for (int e = 0; e < 4; e++) acc[mt][nt][e] = 0.f;

    int nk = K >> 5;
    auto loadStage = [&](int st, int k0) {
#pragma unroll
        for (int w = 0; w < 2; w++) {
            int idx = tid + w * 256;
            int r = idx >> 2, ch = (idx & 3) * 8;
            cp16(As + st * 128 * PA_ST + r * PA_ST + ch,
                 A + (size_t)(m0 + r) * K + k0 + ch);
        }
        {
            int r = tid >> 3, ch = (tid & 7) * 8;
            if (r < 32)
                cp16(Bs + st * 32 * GB_ST + r * GB_ST + ch,
                     B + (size_t)(k0 + r) * N + n0 + ch);
        }
    };

    loadStage(0, 0);
    CP_COMMIT();

    for (int kt = 0; kt < nk; kt++) {
        int cur = kt & 1;
        if (kt + 1 < nk) loadStage((kt + 1) & 1, (kt + 1) * 32);
        CP_COMMIT();
        CP_WAIT1();
        __syncthreads();

        const __half* Ac = As + cur * 128 * PA_ST;
        uint32_t bbase = (uint32_t)__cvta_generic_to_shared(Bs + cur * 32 * GB_ST);
#pragma unroll
        for (int ks = 0; ks < 2; ks++) {
            int k = ks * 16;
            uint32_t af[4][4], bf[2][2];
#pragma unroll
            for (int mt = 0; mt < 4; mt++) {
                const __half* base = Ac + (wm + mt * 16 + g) * PA_ST + k + 2 * c;
                af[mt][0] = *(const uint32_t*)(base);
                af[mt][1] = *(const uint32_t*)(base + 8 * PA_ST);
                af[mt][2] = *(const uint32_t*)(base + 8);
                af[mt][3] = *(const uint32_t*)(base + 8 * PA_ST + 8);
            }
            {
                uint32_t addr = bbase +
                    (uint32_t)(((k + lrow) * GB_ST + wn + lcol) * 2);
                uint32_t r0, r1, r2, r3;
                ldsm_x4_t(r0, r1, r2, r3, addr);
                bf[0][0] = r0; bf[0][1] = r1;
                bf[1][0] = r2; bf[1][1] = r3;
            }
#pragma unroll
            for (int mt = 0; mt < 4; mt++)
#pragma unroll
                for (int nt = 0; nt < 2; nt++)
                    mma_f16(acc[mt][nt], af[mt], bf[nt], acc[mt][nt]);
        }
        __syncthreads();
    }

#pragma unroll
    for (int mt = 0; mt < 4; mt++)
#pragma unroll
        for (int nt = 0; nt < 2; nt++) {
            int row = m0 + wm + mt * 16 + g;
            int col = n0 + wn + nt * 8 + c * 2;
            const float* a0 = Cadd + (size_t)row * N + col;
            const float* a1 = Cadd + (size_t)(row + 8) * N + col;
            *(float2*)(C + (size_t)row * N + col) =
                make_float2(acc[mt][nt][0] + a0[0], acc[mt][nt][1] + a0[1]);
            *(float2*)(C + (size_t)(row + 8) * N + col) =
                make_float2(acc[mt][nt][2] + a1[0], acc[mt][nt][3] + a1[1]);
        }
}

// ============================================================================
// FLASH-FUSED score + exp + PV kernel, 512 threads (16 warps: 4 m x 4 j).
// ldmatrix.x4 for K/rel fragments; strength-reduced epilogue; last-tile-only
// masking. P i-major.
// ============================================================================
__global__ __launch_bounds__(512, 1) void score_pv(
        const __half* __restrict__ Q, const float* __restrict__ pbu,
        const float* __restrict__ pbv, const __half* __restrict__ KV,
        const __half* __restrict__ REL, const float* __restrict__ ib,
        __half* __restrict__ P, float* __restrict__ rsum,
        __half* __restrict__ vec) {
    extern __shared__ char smraw[];
    __half* qu_s  = (__half*)smraw;               // [64][72]
    __half* qv_s  = qu_s + 64 * 72;               // [64][72]
    __half* k_s   = qv_s + 64 * 72;               // [2][128*72]
    __half* v_s   = k_s + 2 * 128 * 72;           // [2][128*72]
    __half* rel_s = v_s + 2 * 128 * 72;           // [2][128*72]
    float*  bd_s  = (float*)(rel_s + 2 * 128 * 72);  // [2][64*132]; vb aliases
    float*  rows  = bd_s + 2 * 64 * 132;          // [64]
    float*  gate_s = rows + 64;                   // [64][4]

    int bn = blockIdx.y;
    int b = bn >> 3, n = bn & 7;
    int i0 = blockIdx.x * 64;
    int tid = threadIdx.x;
    int m_base = 448 - i0;

    if (tid < 64) rows[tid] = 0.f;
    if (tid < 256)
        gate_s[tid] = ib[((size_t)(i0 + (tid >> 2)) * 4 + b) * 4 + (tid & 3)];

    const float QS = SCALEF * LOG2E;
#pragma unroll
    for (int w = 0; w < 2; w++) {
        int idx = tid + w * 512;
        int r = idx >> 4, c4 = (idx & 15) * 4;
        const __half2* qsrc =
            (const __half2*)(Q + (size_t)(i0 + r) * 2048 + b * 512 + n * 64 + c4);
        float2 q0 = __half22float2(qsrc[0]);
        float2 q1 = __half22float2(qsrc[1]);
        float4 bu = *(const float4*)(pbu + n * 64 + c4);
        float4 bv = *(const float4*)(pbv + n * 64 + c4);
        *(__half2*)(qu_s + r * 72 + c4) =
            __floats2half2_rn((q0.x + bu.x) * QS, (q0.y + bu.y) * QS);
        *(__half2*)(qu_s + r * 72 + c4 + 2) =
            __floats2half2_rn((q1.x + bu.z) * QS, (q1.y + bu.w) * QS);
        *(__half2*)(qv_s + r * 72 + c4) =
            __floats2half2_rn((q0.x + bv.x) * QS, (q0.y + bv.y) * QS);
        *(__half2*)(qv_s + r * 72 + c4 + 2) =
            __floats2half2_rn((q1.x + bv.z) * QS, (q1.y + bv.w) * QS);
    }

    const __half* Kb = KV + b * 1024 + n * 64;
    const __half* Vb = KV + b * 1024 + 512 + n * 64;
    const __half* Rb = REL + b * 512 + n * 64;

    auto loadK = [&](int st, int j0) {
#pragma unroll
        for (int w = 0; w < 2; w++) {
            int idx = tid + w * 512;
            int r = idx >> 3, ch = (idx & 7) * 8;
            cp16(k_s + st * 128 * 72 + r * 72 + ch,
                 Kb + (size_t)(j0 + r) * 4096 + ch);
        }
    };
    auto loadV = [&](int st, int j0) {
#pragma unroll
        for (int w = 0; w < 2; w++) {
            int idx = tid + w * 512;
            int r = idx >> 3, ch = (idx & 7) * 8;
            cp16(v_s + st * 128 * 72 + r * 72 + ch,
                 Vb + (size_t)(j0 + r) * 4096 + ch);
        }
    };
    auto loadR = [&](int chunk) {
        int st = chunk & 1;
        int mc = m_base + chunk * 128;
#pragma unroll
        for (int w = 0; w < 2; w++) {
            int idx = tid + w * 512;
            int r = idx >> 3, ch = (idx & 7) * 8;
            int mr = mc + r; if (mr > 2047) mr = 2047;
            cp16(rel_s + st * 128 * 72 + r * 72 + ch,
                 Rb + (size_t)mr * 2048 + ch);
        }
    };

    int ntiles = ((1599 + i0) >> 7) + 1;
    if (ntiles > 16) ntiles = 16;

    int warp = tid >> 5, lane = tid & 31;
    int g = lane >> 2, c = lane & 3;
    int wm  = (warp >> 2) * 16;
    int wj  = warp & 3;
    int wnA = wj * 32;

    int mat = lane >> 3;
    int lrow = (mat & 1) * 8 + (lane & 7);
    int lcol = (mat >> 1) * 8;
    // non-trans ldmatrix lane mapping for bk/br: matrices (nt, dblock)
    int ntq = mat >> 1;           // 0/1 -> nt offset within pair
    int dq  = mat & 1;            // 0/1 -> d block
    int l8  = lane & 7;
    // byte offset term: row = wnA + ntq*8 + l8, col base = dq*8
    uint32_t frag_row_term =
        (uint32_t)(((wnA + ntq * 8 + l8) * 72 + dq * 8) * 2);

    // prologue loads
    loadR(0);
    CP_COMMIT();
    loadK(0, 0); loadV(0, 0); loadR(1);
    CP_COMMIT();
    CP_WAIT1();
    __syncthreads();

    // hoist q fragments (invariant across tiles)
    uint32_t au_r[4][4], av_r[4][4];
#pragma unroll
    for (int kk = 0; kk < 4; kk++) {
        int k = kk * 16;
        const __half* bu = qu_s + (wm + g) * 72 + k + 2 * c;
        const __half* bv = qv_s + (wm + g) * 72 + k + 2 * c;
        au_r[kk][0] = *(const uint32_t*)(bu);
        au_r[kk][1] = *(const uint32_t*)(bu + 8 * 72);
        au_r[kk][2] = *(const uint32_t*)(bu + 8);
        au_r[kk][3] = *(const uint32_t*)(bu + 8 * 72 + 8);
        av_r[kk][0] = *(const uint32_t*)(bv);
        av_r[kk][1] = *(const uint32_t*)(bv + 8 * 72);
        av_r[kk][2] = *(const uint32_t*)(bv + 8);
        av_r[kk][3] = *(const uint32_t*)(bv + 8 * 72 + 8);
    }

    // BD chunk 0 -> bd_s[0]
    {
        uint32_t rbase = (uint32_t)__cvta_generic_to_shared(rel_s) + frag_row_term;
        float accb[4][4];
#pragma unroll
        for (int nt = 0; nt < 4; nt++)
#pragma unroll
            for (int e = 0; e < 4; e++) accb[nt][e] = 0.f;
#pragma unroll
        for (int kk = 0; kk < 4; kk++) {
            uint32_t br[4][2];
            ldsm_x4(br[0][0], br[0][1], br[1][0], br[1][1], rbase + kk * 32);
            ldsm_x4(br[2][0], br[2][1], br[3][0], br[3][1], rbase + 2304 + kk * 32);
#pragma unroll
            for (int nt = 0; nt < 4; nt++)
                mma_f16(accb[nt], av_r[kk], br[nt], accb[nt]);
        }
#pragma unroll
        for (int nt = 0; nt < 4; nt++) {
            int row = wm + g;
            int col = wnA + nt * 8 + c * 2;
            *(float2*)(bd_s + row * 132 + col) = make_float2(accb[nt][0], accb[nt][1]);
            *(float2*)(bd_s + (row + 8) * 132 + col) = make_float2(accb[nt][2], accb[nt][3]);
        }
    }

    float rs[2] = {0.f, 0.f};
    float pvacc[8][4];
#pragma unroll
    for (int nd = 0; nd < 8; nd++)
#pragma unroll
        for (int e = 0; e < 4; e++) pvacc[nd][e] = 0.f;

    __half* Pb = P + ((size_t)i0 * 32 + bn) * 2048;

    for (int jt = 0; jt < ntiles; jt++) {
        int cur = jt & 1;
        if (jt + 1 < ntiles) {
            loadK((jt + 1) & 1, (jt + 1) * 128);
            loadV((jt + 1) & 1, (jt + 1) * 128);
        }
        if (jt + 2 <= ntiles) loadR(jt + 2);
        CP_COMMIT();
        CP_WAIT1();
        __syncthreads();

        uint32_t kfb = (uint32_t)__cvta_generic_to_shared(k_s + cur * 128 * 72) + frag_row_term;
        uint32_t rfb = (uint32_t)__cvta_generic_to_shared(rel_s + ((jt + 1) & 1) * 128 * 72) + frag_row_term;

        float acca[4][4], accb[4][4];
#pragma unroll
        for (int nt = 0; nt < 4; nt++)
#pragma unroll
            for (int e = 0; e < 4; e++) { acca[nt][e] = 0.f; accb[nt][e] = 0.f; }

#pragma unroll
        for (int kk = 0; kk < 4; kk++) {
            uint32_t bk[4][2], br[4][2];
            ldsm_x4(bk[0][0], bk[0][1], bk[1][0], bk[1][1], kfb + kk * 32);
            ldsm_x4(bk[2][0], bk[2][1], bk[3][0], bk[3][1], kfb + 2304 + kk * 32);
            ldsm_x4(br[0][0], br[0][1], br[1][0], br[1][1], rfb + kk * 32);
            ldsm_x4(br[2][0], br[2][1], br[3][0], br[3][1], rfb + 2304 + kk * 32);
#pragma unroll
            for (int nt = 0; nt < 4; nt++) {
                mma_f16(acca[nt], au_r[kk], bk[nt], acca[nt]);
                mma_f16(accb[nt], av_r[kk], br[nt], accb[nt]);
            }
        }

        // store BD chunk jt+1
        float* bdo = bd_s + ((jt + 1) & 1) * 64 * 132;
#pragma unroll
        for (int nt = 0; nt < 4; nt++) {
            int row = wm + g;
            int col = wnA + nt * 8 + c * 2;
            *(float2*)(bdo + row * 132 + col) = make_float2(accb[nt][0], accb[nt][1]);
            *(float2*)(bdo + (row + 8) * 132 + col) = make_float2(accb[nt][2], accb[nt][3]);
        }
        __syncthreads();

        // epilogue
        int j0 = jt * 128;
        int segA = j0 >> 9;
        bool last = (jt == ntiles - 1);
        const float* bd_lo = bd_s + (jt & 1) * 64 * 132;
        const float* bd_hi = bd_s + ((jt + 1) & 1) * 64 * 132;
        uint32_t pe2[4][2];
#pragma unroll
        for (int half = 0; half < 2; half++) {
            int i_loc = wm + g + half * 8;
            int i = i0 + i_loc;
            int mrow = j0 + 511 - i;
            float gA = gate_s[i_loc * 4 + segA];
            const float* gt = gate_s + i_loc * 4;
            int mlo = mrow + wnA;
            int slo = mlo >> 9; if (slo > 3) slo = 3;
            int shi = (mlo + 31) >> 9; if (shi > 3) shi = 3;
            float glo = gt[slo], ghi = gt[shi];
            int jcross = (((mlo >> 9) + 1) << 9) - mrow;   // j_loc threshold
            int ocross = 65 + i_loc;                       // off<128 <=> j_loc<ocross
            const float* bdrow_lo = bd_lo + i_loc * 132 + 63 - i_loc;
            const float* bdrow_hi = bd_hi + i_loc * 132 + 63 - i_loc - 128;
            int jmax_loc = 1536 + i - j0;
#pragma unroll
            for (int nt = 0; nt < 4; nt++) {
                float a0 = acca[nt][half * 2];
                float a1 = acca[nt][half * 2 + 1];
                float pe[2];
#pragma unroll
                for (int e = 0; e < 2; e++) {
                    int j_loc = wnA + nt * 8 + c * 2 + e;
                    float gB = (j_loc >= jcross) ? ghi : glo;
                    const float* bp = (j_loc < ocross) ? bdrow_lo : bdrow_hi;
                    float bd = bp[j_loc];
                    float ac = e ? a1 : a0;
                    float s = fmaf(gA, ac, gB * bd);
                    pe[e] = ex2f(s);
                }
                if (last) {
                    int j_loc0 = wnA + nt * 8 + c * 2;
                    if (j_loc0 > jmax_loc) pe[0] = 0.f;
                    if (j_loc0 + 1 > jmax_loc) pe[1] = 0.f;
                }
                rs[half] += pe[0] + pe[1];
                __half2 h2 = __floats2half2_rn(pe[0], pe[1]);
                pe2[nt][half] = *(uint32_t*)&h2;
                *(__half2*)(Pb + (size_t)i_loc * 65536 + j0 + wnA + nt * 8 + c * 2) = h2;
            }
        }

        // PV MMA
        {
            uint32_t vbase = (uint32_t)__cvta_generic_to_shared(v_s + cur * 128 * 72);
#pragma unroll
            for (int kk2 = 0; kk2 < 2; kk2++) {
                uint32_t bf[8][2];
#pragma unroll
                for (int p = 0; p < 4; p++) {
                    uint32_t addr = vbase +
                        (uint32_t)(((wnA + kk2 * 16 + lrow) * 72 + p * 16 + lcol) * 2);
                    uint32_t r0, r1, r2, r3;
                    ldsm_x4_t(r0, r1, r2, r3, addr);
                    bf[2 * p][0] = r0; bf[2 * p][1] = r1;
                    bf[2 * p + 1][0] = r2; bf[2 * p + 1][1] = r3;
                }
                uint32_t af[4];
                af[0] = pe2[2 * kk2][0];
                af[1] = pe2[2 * kk2][1];
                af[2] = pe2[2 * kk2 + 1][0];
                af[3] = pe2[2 * kk2 + 1][1];
#pragma unroll
                for (int nd = 0; nd < 8; nd++)
                    mma_f16(pvacc[nd], af, bf[nd], pvacc[nd]);
            }
        }
        __syncthreads();
    }

    // zero-fill P for skipped tiles
    {
        __half2 hz = __floats2half2_rn(0.f, 0.f);
        for (int jt = ntiles; jt < 16; jt++) {
            int j0 = jt * 128;
#pragma unroll
            for (int half = 0; half < 2; half++) {
                int i_loc = wm + g + half * 8;
#pragma unroll
                for (int nt = 0; nt < 4; nt++)
                    *(__half2*)(Pb + (size_t)i_loc * 65536 + j0 + wnA + nt * 8 + c * 2) = hz;
            }
        }
    }

    atomicAdd(&rows[wm + g], rs[0]);
    atomicAdd(&rows[wm + g + 8], rs[1]);
    __syncthreads();
    if (tid < 64) rows[tid] = 1.f / rows[tid];

    float* vb = bd_s;
    for (int idx = tid; idx < 64 * 68; idx += 512) vb[idx] = 0.f;
    __syncthreads();

    for (int r = 0; r < 4; r++) {
        if (wj == r) {
#pragma unroll
            for (int nd = 0; nd < 8; nd++)
#pragma unroll
                for (int e = 0; e < 4; e++) {
                    int row = wm + g + ((e >> 1) ? 8 : 0);
                    int col = nd * 8 + c * 2 + (e & 1);
                    vb[row * 68 + col] += pvacc[nd][e];
                }
        }
        __syncthreads();
    }

#pragma unroll
    for (int t = 0; t < 4; t++) {
        int e = tid + t * 512;
        int row = e >> 5, cp = e & 31;
        float inv = rows[row];
        float v0 = vb[row * 68 + cp * 2] * inv;
        float v1 = vb[row * 68 + cp * 2 + 1] * inv;
        *(__half2*)(vec + ((size_t)(i0 + row) * 4 + b) * 512 + n * 64 + cp * 2) =
            __floats2half2_rn(v0, v1);
    }
    if (tid < 64)
        rsum[(size_t)bn * 512 + i0 + tid] = rows[tid];
}

// ---------------- attn matrix: contiguous i-major P, 8-deep loads ----------
__global__ void attn_kernel(const __half* __restrict__ P,
                            const float* __restrict__ rsum,
                            float* __restrict__ attn) {
    __shared__ float invs[32];
    int i = blockIdx.x;
    int tid = threadIdx.x;
    if (tid < 32) invs[tid] = rsum[(size_t)tid * 512 + i];
    __syncthreads();

    float acc[8] = {0.f, 0.f, 0.f, 0.f, 0.f, 0.f, 0.f, 0.f};
    const __half* base = P + (size_t)i * 65536 + tid * 8;
#pragma unroll
    for (int bn = 0; bn < 32; bn += 8) {
        uint4 raw[8];
#pragma unroll
        for (int u = 0; u < 8; u++)
            raw[u] = *(const uint4*)(base + (size_t)(bn + u) * 2048);
#pragma unroll
        for (int u = 0; u < 8; u++) {
            float inv = invs[bn + u];
            const __half2* h = (const __half2*)&raw[u];
#pragma unroll
            for (int e = 0; e < 4; e++) {
                float2 f = __half22float2(h[e]);
                acc[e * 2]     += inv * f.x;
                acc[e * 2 + 1] += inv * f.y;
            }
        }
    }
    float* dst = attn + (size_t)i * 2048 + tid * 8;
#pragma unroll
    for (int e = 0; e < 8; e++) dst[e] = acc[e] * (1.f / 32.f);
}

// ---------------- layernorm ----------------
__global__ void ln_kernel(const float* __restrict__ y, const float* __restrict__ g,
                          const float* __restrict__ be, float* __restrict__ out) {
    __shared__ float red[32];
    int r = blockIdx.x;
    int tid = threadIdx.x;
    float v0 = y[(size_t)r * 512 + tid];
    float v1 = y[(size_t)r * 512 + tid + 256];
    float mean = blockRedSum(v0 + v1, red) * (1.f / 512.f);
    float d0 = v0 - mean, d1 = v1 - mean;
    float var = blockRedSum(d0 * d0 + d1 * d1, red) * (1.f / 512.f);
    float rstd = rsqrtf(var + 1e-5f);
    out[(size_t)r * 512 + tid]       = d0 * rstd * g[tid] + be[tid];
    out[(size_t)r * 512 + tid + 256] = d1 * rstd * g[tid + 256] + be[tid + 256];
}

// ---------------- launch ----------------
#define SMEM_PH  ((3 * 128 * PA_ST + 3 * 32 * PB_ST) * 2)
#define SMEM_GH  ((2 * 128 * PA_ST + 2 * 32 * GB_ST) * 2)
#define SMEM_SPV ((64*72*2 + 3*2*128*72) * 2 + (2*64*132 + 64 + 256) * 4)

extern "C" void kernel_launch(void* const* d_in, const int* in_sizes, int n_in,
                              void* d_out, int out_size) {
    (void)in_sizes; (void)n_in; (void)out_size;
    const float* x       = (const float*)d_in[0];
    const float* memory  = (const float*)d_in[1];
    const float* pos_emb = (const float*)d_in[2];
    const float* pbu     = (const float*)d_in[3];
    const float* pbv     = (const float*)d_in[4];
    const float* ib      = (const float*)d_in[6];
    const float* W_q     = (const float*)d_in[7];
    const float* W_kv    = (const float*)d_in[8];
    const float* W_rel   = (const float*)d_in[9];
    const float* W_o     = (const float*)d_in[10];
    const float* ln_g    = (const float*)d_in[11];
    const float* ln_b    = (const float*)d_in[12];

    float* out  = (float*)d_out;
    float* attn = out + (size_t)Lq * BATCH * 512;

    __half *memh, *xh, *posh, *wkvh, *wrelh, *wqh, *woh;
    __half *kvh, *relh, *qh, *prob, *vec;
    float *rs, *y;
    cudaGetSymbolAddress((void**)&memh,  g_memh);
    cudaGetSymbolAddress((void**)&xh,    g_xh);
    cudaGetSymbolAddress((void**)&posh,  g_posh);
    cudaGetSymbolAddress((void**)&wkvh,  g_wkvh);
    cudaGetSymbolAddress((void**)&wrelh, g_wrelh);
    cudaGetSymbolAddress((void**)&wqh,   g_wqh);
    cudaGetSymbolAddress((void**)&woh,   g_woh);
    cudaGetSymbolAddress((void**)&kvh,   g_kv);
    cudaGetSymbolAddress((void**)&relh,  g_rel);
    cudaGetSymbolAddress((void**)&qh,    g_qh);
    cudaGetSymbolAddress((void**)&prob,  g_prob);
    cudaGetSymbolAddress((void**)&rs,    g_rsum);
    cudaGetSymbolAddress((void**)&vec,   g_vec);
    cudaGetSymbolAddress((void**)&y,     g_y);

    static bool attr_set = false;
    if (!attr_set) {
        cudaFuncSetAttribute(proj_h,
                             cudaFuncAttributeMaxDynamicSharedMemorySize, SMEM_PH);
        cudaFuncSetAttribute(gemm64_h,
                             cudaFuncAttributeMaxDynamicSharedMemorySize, SMEM_GH);
        cudaFuncSetAttribute(score_pv,
                             cudaFuncAttributeMaxDynamicSharedMemorySize, SMEM_SPV);
        attr_set = true;
    }

    // 0) convert fp32 inputs -> fp16
    ConvJob cj;
    cj.src[0] = memory;  cj.dst[0] = memh;  cj.n4[0] = 6144 * 512 / 4;
    cj.src[1] = x;       cj.dst[1] = xh;    cj.n4[1] = 2048 * 512 / 4;
    cj.src[2] = pos_emb; cj.dst[2] = posh;  cj.n4[2] = 8192 * 512 / 4;
    cj.src[3] = W_kv;    cj.dst[3] = wkvh;  cj.n4[3] = 512 * 1024 / 4;
    cj.src[4] = W_rel;   cj.dst[4] = wrelh; cj.n4[4] = 512 * 512 / 4;
    cj.src[5] = W_q;     cj.dst[5] = wqh;   cj.n4[5] = 512 * 512 / 4;
    cj.src[6] = W_o;     cj.dst[6] = woh;   cj.n4[6] = 512 * 512 / 4;
    int total4 = (6144 * 512 + 2048 * 512 + 8192 * 512 +
                  512 * 1024 + 3 * 512 * 512) / 4;
    conv_f2h<<<(total4 + 255) / 256, 256>>>(cj, total4);

    // 1) all 4 projections (fp16 MMA), one launch
    DescH d0 = { memh, wkvh,  (void*)kvh,                         1024, 512, 8, 0,   1 };
    DescH d1 = { xh,   wkvh,  (void*)(kvh + (size_t)6144 * 1024), 1024, 512, 8, 384, 1 };
    DescH d2 = { posh, wrelh, (void*)relh,                        512,  512, 4, 512, 1 };
    DescH d3 = { xh,   wqh,   (void*)qh,                          512,  512, 4, 768, 1 };
    proj_h<<<832, 256, SMEM_PH>>>(d0, d1, d2, d3);

    // 2) fused scores + exp + PV
    score_pv<<<dim3(8, 32), 512, SMEM_SPV>>>(qh, pbu, pbv, kvh, relh, ib,
                                             prob, rs, vec);

    // 3) attn matrix
    attn_kernel<<<512, 256>>>(prob, rs, attn);

    // 4) y = x + vec @ W_o ; layernorm
    gemm64_h<<<dim3(8, 16), 256, SMEM_GH>>>(vec, woh, x, y, 2048, 512, 512);
    ln_kernel<<<2048, 256>>>(y, ln_g, ln_b, out);
}